// round 1
// baseline (speedup 1.0000x reference)
#include <cuda_runtime.h>
#include <cuda_bf16.h>
#include <math.h>

// Problem constants
#define Bb 16
#define Nn 1024
#define Cc 1024
#define Hh 16
#define HD 64
#define Rr 128
#define NH (Nn/2)          // 512
#define NU (NH - Rr)       // 384 unmerged
#define NM (NU + NH)       // 896 merged tokens
#define MROWS (Bb*Nn)      // 16384
#define MROWS2 (Bb*NM)     // 14336

// ---------------- scratch (static device globals; no runtime allocation) ----
__device__ float g_xln  [(size_t)MROWS * Cc];
__device__ float g_qkv  [(size_t)MROWS * 3 * Cc];
__device__ float g_S    [(size_t)Bb * Hh * Nn * Nn];   // 1 GiB attention scores
__device__ float g_attno[(size_t)MROWS * Cc];
__device__ float g_xres [(size_t)MROWS * Cc];
__device__ float g_metric[(size_t)Bb * Nn * HD];
__device__ float g_nodemax[Bb * NH];
__device__ int   g_nodeidx[Bb * NH];
__device__ int   g_srcidx[Bb * Rr];
__device__ int   g_dstidx[Bb * Rr];
__device__ int   g_unmidx[Bb * NU];
__device__ float g_xm   [(size_t)MROWS2 * Cc];
__device__ float g_h2   [(size_t)MROWS2 * Cc];
__device__ float g_fc1  [(size_t)MROWS2 * 4 * Cc];

// ---------------- LayerNorm ----------------
__global__ void __launch_bounds__(256) ln_kernel(
    const float* __restrict__ x, const float* __restrict__ g,
    const float* __restrict__ bta, float* __restrict__ out, int C)
{
    size_t row = blockIdx.x;
    const float* p = x + row * C;
    float* o = out + row * C;
    int tid = threadIdx.x;
    float s = 0.f, s2 = 0.f;
    for (int i = tid; i < C; i += 256) { float v = p[i]; s += v; s2 += v * v; }
    __shared__ float rs[256], rq[256];
    rs[tid] = s; rq[tid] = s2; __syncthreads();
    for (int off = 128; off; off >>= 1) {
        if (tid < off) { rs[tid] += rs[tid + off]; rq[tid] += rq[tid + off]; }
        __syncthreads();
    }
    float mean = rs[0] / (float)C;
    float var  = rq[0] / (float)C - mean * mean;
    float inv  = rsqrtf(var + 1e-5f);
    for (int i = tid; i < C; i += 256)
        o[i] = (p[i] - mean) * inv * g[i] + bta[i];
}

// ---------------- generic SGEMM: out = A(MxK) @ W(NxK)^T + bias [, gelu] [, +res]
__global__ void __launch_bounds__(256) sgemm_nt(
    const float* __restrict__ A, const float* __restrict__ W,
    const float* __restrict__ bias, const float* __restrict__ res,
    float* __restrict__ out, int M, int N, int K, int act)
{
    __shared__ float As[8][128];
    __shared__ float Ws[8][128];
    const int bm = blockIdx.y * 128;
    const int bn = blockIdx.x * 128;
    const int tid = threadIdx.x;
    const int lr = tid >> 1;            // 0..127
    const int lk = (tid & 1) << 2;      // 0 or 4
    const int ty = tid >> 4;            // 0..15
    const int tx = tid & 15;            // 0..15
    const float* Ap = A + (size_t)(bm + lr) * K + lk;
    const float* Wp = W + (size_t)(bn + lr) * K + lk;
    float acc[8][8];
#pragma unroll
    for (int i = 0; i < 8; i++)
#pragma unroll
        for (int j = 0; j < 8; j++) acc[i][j] = 0.f;

    for (int k0 = 0; k0 < K; k0 += 8) {
        float4 av = *(const float4*)(Ap + k0);
        float4 wv = *(const float4*)(Wp + k0);
        As[lk + 0][lr] = av.x; As[lk + 1][lr] = av.y;
        As[lk + 2][lr] = av.z; As[lk + 3][lr] = av.w;
        Ws[lk + 0][lr] = wv.x; Ws[lk + 1][lr] = wv.y;
        Ws[lk + 2][lr] = wv.z; Ws[lk + 3][lr] = wv.w;
        __syncthreads();
#pragma unroll
        for (int kk = 0; kk < 8; kk++) {
            float a[8], b[8];
#pragma unroll
            for (int i = 0; i < 8; i++) a[i] = As[kk][ty * 8 + i];
#pragma unroll
            for (int j = 0; j < 8; j++) b[j] = Ws[kk][tx * 8 + j];
#pragma unroll
            for (int i = 0; i < 8; i++)
#pragma unroll
                for (int j = 0; j < 8; j++) acc[i][j] += a[i] * b[j];
        }
        __syncthreads();
    }
#pragma unroll
    for (int i = 0; i < 8; i++) {
        int m = bm + ty * 8 + i;
#pragma unroll
        for (int j = 0; j < 8; j++) {
            int n = bn + tx * 8 + j;
            float v = acc[i][j] + bias[n];
            if (act == 1) v = 0.5f * v * (1.f + erff(v * 0.70710678118654752f));
            if (res) v += res[(size_t)m * N + n];
            out[(size_t)m * N + n] = v;
        }
    }
}

// ---------------- attention scores: S = scale*Q@K^T + log(size) ----------------
__global__ void __launch_bounds__(256) attn_scores(
    const float* __restrict__ qkv, const float* __restrict__ sz, float* __restrict__ S)
{
    __shared__ float Qs[64][65];
    __shared__ float Ks[64][65];
    const int bh = blockIdx.z;
    const int b = bh >> 4, h = bh & 15;
    const int n0 = blockIdx.y * 64, m0 = blockIdx.x * 64;
    const float* qb = qkv + (size_t)b * Nn * 3072 + h * 64;
    const float* kb = qb + 1024;
    const int tid = threadIdx.x;
#pragma unroll
    for (int t = 0; t < 4; t++) {
        int id = tid + t * 256;           // float4 id 0..1023
        int row = id >> 4;
        int c4 = (id & 15) << 2;
        float4 v = *(const float4*)(qb + (size_t)(n0 + row) * 3072 + c4);
        Qs[row][c4] = v.x; Qs[row][c4 + 1] = v.y; Qs[row][c4 + 2] = v.z; Qs[row][c4 + 3] = v.w;
        float4 w = *(const float4*)(kb + (size_t)(m0 + row) * 3072 + c4);
        Ks[row][c4] = w.x; Ks[row][c4 + 1] = w.y; Ks[row][c4 + 2] = w.z; Ks[row][c4 + 3] = w.w;
    }
    __syncthreads();
    const int ty = tid >> 4, tx = tid & 15;
    float acc[4][4];
#pragma unroll
    for (int i = 0; i < 4; i++)
#pragma unroll
        for (int j = 0; j < 4; j++) acc[i][j] = 0.f;
#pragma unroll
    for (int d = 0; d < 64; d++) {
        float a[4], c[4];
#pragma unroll
        for (int i = 0; i < 4; i++) a[i] = Qs[ty * 4 + i][d];
#pragma unroll
        for (int j = 0; j < 4; j++) c[j] = Ks[tx * 4 + j][d];
#pragma unroll
        for (int i = 0; i < 4; i++)
#pragma unroll
            for (int j = 0; j < 4; j++) acc[i][j] += a[i] * c[j];
    }
    float ls[4];
#pragma unroll
    for (int j = 0; j < 4; j++) ls[j] = logf(sz[b * Nn + m0 + tx * 4 + j]);
    const float scale = 0.125f;
#pragma unroll
    for (int i = 0; i < 4; i++) {
        size_t base = ((size_t)bh * Nn + (n0 + ty * 4 + i)) * Nn + m0 + tx * 4;
#pragma unroll
        for (int j = 0; j < 4; j++)
            S[base + j] = acc[i][j] * scale + ls[j];
    }
}

// ---------------- softmax over rows of S ----------------
__global__ void __launch_bounds__(256) softmax_rows(float* __restrict__ S)
{
    size_t row = blockIdx.x;
    float* p = S + row * Nn;
    int tid = threadIdx.x;
    __shared__ float red[256];
    float m = -3.4e38f;
    for (int i = tid; i < Nn; i += 256) m = fmaxf(m, p[i]);
    red[tid] = m; __syncthreads();
    for (int off = 128; off; off >>= 1) {
        if (tid < off) red[tid] = fmaxf(red[tid], red[tid + off]);
        __syncthreads();
    }
    m = red[0]; __syncthreads();
    float s = 0.f;
    for (int i = tid; i < Nn; i += 256) { float e = expf(p[i] - m); p[i] = e; s += e; }
    red[tid] = s; __syncthreads();
    for (int off = 128; off; off >>= 1) {
        if (tid < off) red[tid] += red[tid + off];
        __syncthreads();
    }
    float inv = 1.f / red[0];
    for (int i = tid; i < Nn; i += 256) p[i] *= inv;
}

// ---------------- PV: out[b,n,h,d] = sum_m P[n,m] V[m,d] ----------------
__global__ void __launch_bounds__(256) attn_av(
    const float* __restrict__ S, const float* __restrict__ qkv, float* __restrict__ out)
{
    __shared__ float Ps[64][17];
    __shared__ float Vs[16][64];
    const int bh = blockIdx.y;
    const int b = bh >> 4, h = bh & 15;
    const int n0 = blockIdx.x * 64;
    const float* Sp = S + ((size_t)bh * Nn + n0) * Nn;
    const float* vb = qkv + (size_t)b * Nn * 3072 + 2048 + h * 64;
    const int tid = threadIdx.x;
    const int ty = tid >> 4, tx = tid & 15;
    float acc[4][4];
#pragma unroll
    for (int i = 0; i < 4; i++)
#pragma unroll
        for (int j = 0; j < 4; j++) acc[i][j] = 0.f;

    const int pr = tid >> 2, pc4 = (tid & 3) << 2;   // P tile: 64x16
    const int vr = tid >> 4, vc4 = (tid & 15) << 2;  // V tile: 16x64
    for (int k0 = 0; k0 < Nn; k0 += 16) {
        float4 pv = *(const float4*)(Sp + (size_t)pr * Nn + k0 + pc4);
        Ps[pr][pc4] = pv.x; Ps[pr][pc4 + 1] = pv.y; Ps[pr][pc4 + 2] = pv.z; Ps[pr][pc4 + 3] = pv.w;
        float4 vv = *(const float4*)(vb + (size_t)(k0 + vr) * 3072 + vc4);
        Vs[vr][vc4] = vv.x; Vs[vr][vc4 + 1] = vv.y; Vs[vr][vc4 + 2] = vv.z; Vs[vr][vc4 + 3] = vv.w;
        __syncthreads();
#pragma unroll
        for (int kk = 0; kk < 16; kk++) {
            float a[4], c[4];
#pragma unroll
            for (int i = 0; i < 4; i++) a[i] = Ps[ty * 4 + i][kk];
#pragma unroll
            for (int j = 0; j < 4; j++) c[j] = Vs[kk][tx * 4 + j];
#pragma unroll
            for (int i = 0; i < 4; i++)
#pragma unroll
                for (int j = 0; j < 4; j++) acc[i][j] += a[i] * c[j];
        }
        __syncthreads();
    }
#pragma unroll
    for (int i = 0; i < 4; i++) {
        size_t base = ((size_t)b * Nn + n0 + ty * 4 + i) * Cc + h * 64 + tx * 4;
#pragma unroll
        for (int j = 0; j < 4; j++) out[base + j] = acc[i][j];
    }
}

// ---------------- metric = normalize(mean_h k) ----------------
__global__ void __launch_bounds__(64) metric_kernel(
    const float* __restrict__ qkv, float* __restrict__ metric)
{
    int bn = blockIdx.x;           // 0..B*N-1
    int d = threadIdx.x;           // 0..63
    const float* kb = qkv + (size_t)bn * 3072 + 1024 + d;
    float s = 0.f;
#pragma unroll
    for (int h = 0; h < 16; h++) s += kb[h * 64];
    s *= (1.f / 16.f);
    __shared__ float sh[64];
    sh[d] = s * s; __syncthreads();
    for (int off = 32; off; off >>= 1) {
        if (d < off) sh[d] += sh[d + off];
        __syncthreads();
    }
    float inv = rsqrtf(sh[0]);
    metric[(size_t)bn * 64 + d] = s * inv;
}

// ---------------- per-row max/argmax of a@bset^T (row 0 forced to -inf) ------
__global__ void __launch_bounds__(256) match_scores(
    const float* __restrict__ metric, float* __restrict__ nodemax, int* __restrict__ nodeidx)
{
    int t = blockIdx.x;            // 0..511
    int b = blockIdx.y;
    const float* mb = metric + (size_t)b * Nn * 64;
    __shared__ float av[64];
    int tid = threadIdx.x;
    if (tid < 64) av[tid] = mb[(size_t)(2 * t) * 64 + tid];
    __syncthreads();
    float best = -INFINITY; int bi = 0;
    for (int s = tid; s < NH; s += 256) {
        const float* bp = mb + (size_t)(2 * s + 1) * 64;
        float dot = 0.f;
#pragma unroll
        for (int d = 0; d < 64; d++) dot += av[d] * bp[d];
        if (dot > best) { best = dot; bi = s; }   // s increases -> ties keep first
    }
    __shared__ float sv[256]; __shared__ int si[256];
    sv[tid] = best; si[tid] = bi; __syncthreads();
    for (int off = 128; off; off >>= 1) {
        if (tid < off) {
            if (sv[tid + off] > sv[tid] ||
                (sv[tid + off] == sv[tid] && si[tid + off] < si[tid])) {
                sv[tid] = sv[tid + off]; si[tid] = si[tid + off];
            }
        }
        __syncthreads();
    }
    if (tid == 0) {
        if (t == 0) { nodemax[b * NH] = -INFINITY; nodeidx[b * NH] = 0; }
        else { nodemax[b * NH + t] = sv[0]; nodeidx[b * NH + t] = si[0]; }
    }
}

// ---------------- stable descending rank-sort + index split ----------------
__global__ void __launch_bounds__(512) match_sort(
    const float* __restrict__ nodemax, const int* __restrict__ nodeidx,
    int* __restrict__ srcidx, int* __restrict__ dstidx, int* __restrict__ unmidx)
{
    int b = blockIdx.x, t = threadIdx.x;
    __shared__ float v[NH]; __shared__ int rk[NH];
    v[t] = nodemax[b * NH + t]; __syncthreads();
    float vt = v[t]; int r = 0;
    for (int j = 0; j < NH; j++) {
        float vj = v[j];
        r += (vj > vt) || (vj == vt && j < t);
    }
    rk[t] = r; __syncthreads();
    if (r < Rr) {
        srcidx[b * Rr + r] = t;
        dstidx[b * Rr + r] = nodeidx[b * NH + t];
    } else {
        int pos = 0;
        for (int j = 0; j < t; j++) pos += (rk[j] >= Rr);
        unmidx[b * NU + pos] = t;
    }
}

// ---------------- weighted merge + divide by new size ----------------
__global__ void __launch_bounds__(256) merge_kernel(
    const float* __restrict__ xres, const float* __restrict__ sz,
    const int* __restrict__ srcidx, const int* __restrict__ dstidx,
    const int* __restrict__ unmidx, float* __restrict__ xm)
{
    int row = blockIdx.x;          // 0..895
    int b = blockIdx.y;
    int tid = threadIdx.x;
    const float* xb = xres + (size_t)b * Nn * Cc;
    const float* szb = sz + b * Nn;
    float* ob = xm + ((size_t)b * NM + row) * Cc;
    __shared__ int ss[Rr], sd[Rr];

    if (row < NU) {
        int t = 2 * unmidx[b * NU + row];
        float s = szb[t];
        float inv = 1.f / s;
        for (int c = tid; c < Cc; c += 256)
            ob[c] = (xb[(size_t)t * Cc + c] * s) * inv;
    } else {
        int j = row - NU;
        if (tid < Rr) { ss[tid] = srcidx[b * Rr + tid]; sd[tid] = dstidx[b * Rr + tid]; }
        __syncthreads();
        int t = 2 * j + 1;
        float ns = szb[t];
        for (int i = 0; i < Rr; i++)
            if (sd[i] == j) ns += szb[2 * ss[i]];
        float inv = 1.f / ns;
        for (int c = tid; c < Cc; c += 256) {
            float val = xb[(size_t)t * Cc + c] * szb[t];
            for (int i = 0; i < Rr; i++) {
                if (sd[i] == j) {
                    int ts = 2 * ss[i];
                    val += xb[(size_t)ts * Cc + c] * szb[ts];
                }
            }
            ob[c] = val * inv;
        }
    }
}

// ---------------- launch ----------------
template <typename T>
static T* sym_addr(const void* sym) {
    void* p = nullptr;
    cudaGetSymbolAddress(&p, sym);
    return (T*)p;
}

extern "C" void kernel_launch(void* const* d_in, const int* in_sizes, int n_in,
                              void* d_out, int out_size)
{
    const float* x      = (const float*)d_in[0];
    const float* sz     = (const float*)d_in[1];
    // d_in[2] = r (constant 128, baked in)
    const float* qkv_w  = (const float*)d_in[3];
    const float* qkv_b  = (const float*)d_in[4];
    const float* proj_w = (const float*)d_in[5];
    const float* proj_b = (const float*)d_in[6];
    const float* n1g    = (const float*)d_in[7];
    const float* n1b    = (const float*)d_in[8];
    const float* n2g    = (const float*)d_in[9];
    const float* n2b    = (const float*)d_in[10];
    const float* fc1_w  = (const float*)d_in[11];
    const float* fc1_b  = (const float*)d_in[12];
    const float* fc2_w  = (const float*)d_in[13];
    const float* fc2_b  = (const float*)d_in[14];
    float* out = (float*)d_out;

    float* xln   = sym_addr<float>(g_xln);
    float* qkv   = sym_addr<float>(g_qkv);
    float* S     = sym_addr<float>(g_S);
    float* attno = sym_addr<float>(g_attno);
    float* xres  = sym_addr<float>(g_xres);
    float* metric= sym_addr<float>(g_metric);
    float* nmax  = sym_addr<float>(g_nodemax);
    int*   nidx  = sym_addr<int>(g_nodeidx);
    int*   sidx  = sym_addr<int>(g_srcidx);
    int*   didx  = sym_addr<int>(g_dstidx);
    int*   uidx  = sym_addr<int>(g_unmidx);
    float* xm    = sym_addr<float>(g_xm);
    float* h2    = sym_addr<float>(g_h2);
    float* fc1   = sym_addr<float>(g_fc1);

    // 1. LN1
    ln_kernel<<<MROWS, 256>>>(x, n1g, n1b, xln, Cc);
    // 2. QKV GEMM: (16384,1024) @ (3072,1024)^T
    sgemm_nt<<<dim3(3072 / 128, MROWS / 128), 256>>>(xln, qkv_w, qkv_b, nullptr, qkv,
                                                     MROWS, 3072, Cc, 0);
    // 3. scores + bias
    attn_scores<<<dim3(16, 16, Bb * Hh), 256>>>(qkv, sz, S);
    // 4. softmax
    softmax_rows<<<Bb * Hh * Nn, 256>>>(S);
    // 5. PV
    attn_av<<<dim3(16, Bb * Hh), 256>>>(S, qkv, attno);
    // 6. proj + residual
    sgemm_nt<<<dim3(Cc / 128, MROWS / 128), 256>>>(attno, proj_w, proj_b, x, xres,
                                                   MROWS, Cc, Cc, 0);
    // 7. metric
    metric_kernel<<<Bb * Nn, 64>>>(qkv, metric);
    // 8. match scores / argmax
    match_scores<<<dim3(NH, Bb), 256>>>(metric, nmax, nidx);
    // 9. stable sort + split
    match_sort<<<Bb, NH>>>(nmax, nidx, sidx, didx, uidx);
    // 10. merge
    merge_kernel<<<dim3(NM, Bb), 256>>>(xres, sz, sidx, didx, uidx, xm);
    // 11. LN2
    ln_kernel<<<MROWS2, 256>>>(xm, n2g, n2b, h2, Cc);
    // 12. fc1 + exact GELU
    sgemm_nt<<<dim3(4096 / 128, MROWS2 / 128), 256>>>(h2, fc1_w, fc1_b, nullptr, fc1,
                                                      MROWS2, 4096, Cc, 1);
    // 13. fc2 + residual -> out
    sgemm_nt<<<dim3(Cc / 128, MROWS2 / 128), 256>>>(fc1, fc2_w, fc2_b, xm, out,
                                                    MROWS2, Cc, 4096, 0);
    (void)in_sizes; (void)n_in; (void)out_size;
}

// round 5
// speedup vs baseline: 1.3506x; 1.3506x over previous
#include <cuda_runtime.h>
#include <cuda_bf16.h>
#include <math.h>
#include <cstdint>
#include <mma.h>

using namespace nvcuda;

// Problem constants
#define Bb 16
#define Nn 1024
#define Cc 1024
#define Hh 16
#define HD 64
#define Rr 128
#define NH (Nn/2)          // 512
#define NU (NH - Rr)       // 384 unmerged
#define NM (NU + NH)       // 896 merged tokens
#define MROWS (Bb*Nn)      // 16384
#define MROWS2 (Bb*NM)     // 14336

// ---------------- scratch (static device globals) ----------------
__device__ float g_xln  [(size_t)MROWS * Cc];
__device__ float g_qkv  [(size_t)MROWS * 3 * Cc];
__device__ float g_S    [(size_t)Bb * Hh * Nn * Nn];   // 1 GiB scores
__device__ float g_attno[(size_t)MROWS * Cc];
__device__ float g_xres [(size_t)MROWS * Cc];
__device__ float g_wm   [64 * 1024];
__device__ float g_wmb  [64];
__device__ float g_metric[(size_t)Bb * Nn * HD];
__device__ float g_nodemax[Bb * NH];
__device__ int   g_nodeidx[Bb * NH];
__device__ int   g_srcidx[Bb * Rr];
__device__ int   g_dstidx[Bb * Rr];
__device__ int   g_unmidx[Bb * NU];
__device__ float g_xm   [(size_t)MROWS2 * Cc];
__device__ float g_h2   [(size_t)MROWS2 * Cc];
__device__ float g_fc1  [(size_t)MROWS2 * 4 * Cc];

__device__ __forceinline__ float f2tf32f(float x) {
    uint32_t r;
    asm("cvt.rna.tf32.f32 %0, %1;" : "=r"(r) : "f"(x));
    return __uint_as_float(r);
}

// ================= tf32 wmma GEMM =================
// out(MxN) = A(MxK) @ W(NxK)^T + bias [,gelu] [,+res]
// CTA tile 128x128, 8 warps (4 along M x 2 along N), warp tile 32x64 = 2x4 wmma 16x16.
// K staged 16, double-buffered SMEM, row stride LDT=24 floats (all accesses 32B aligned).
#define LDT 24

__global__ void __launch_bounds__(256) tf32_gemm(
    const float* __restrict__ A, const float* __restrict__ W,
    const float* __restrict__ bias, const float* __restrict__ res,
    float* __restrict__ out, int M, int N, int K, int act)
{
    __shared__ alignas(128) float sm[2][2][128][LDT];   // [buf][0=A,1=B][row][k] = 48 KB

    const int tid = threadIdx.x;
    const int wid = tid >> 5;
    const int lane = tid & 31;
    const int wm = wid & 3;          // M slot (32 rows)
    const int wn = wid >> 2;         // N slot (64 cols)
    const int bm = blockIdx.y * 128;
    const int bn = blockIdx.x * 128;

    const int rowL = tid >> 2;              // 0..63
    const int c40 = (tid & 3) << 2;         // 0,4,8,12
    const float* Ap0 = A + (size_t)(bm + rowL) * K + c40;
    const float* Ap1 = Ap0 + (size_t)64 * K;
    const float* Wp0 = W + (size_t)(bn + rowL) * K + c40;
    const float* Wp1 = Wp0 + (size_t)64 * K;

    wmma::fragment<wmma::accumulator, 16, 16, 8, float> cfrag[2][4];
#pragma unroll
    for (int mt = 0; mt < 2; mt++)
#pragma unroll
        for (int nt = 0; nt < 4; nt++)
            wmma::fill_fragment(cfrag[mt][nt], 0.f);

    // prologue: stage 0 -> buffer 0
    {
        float4 a0 = *(const float4*)(Ap0);
        float4 a1 = *(const float4*)(Ap1);
        float4 w0 = *(const float4*)(Wp0);
        float4 w1 = *(const float4*)(Wp1);
        *(float4*)&sm[0][0][rowL][c40]      = make_float4(f2tf32f(a0.x), f2tf32f(a0.y), f2tf32f(a0.z), f2tf32f(a0.w));
        *(float4*)&sm[0][0][rowL + 64][c40] = make_float4(f2tf32f(a1.x), f2tf32f(a1.y), f2tf32f(a1.z), f2tf32f(a1.w));
        *(float4*)&sm[0][1][rowL][c40]      = make_float4(f2tf32f(w0.x), f2tf32f(w0.y), f2tf32f(w0.z), f2tf32f(w0.w));
        *(float4*)&sm[0][1][rowL + 64][c40] = make_float4(f2tf32f(w1.x), f2tf32f(w1.y), f2tf32f(w1.z), f2tf32f(w1.w));
    }
    __syncthreads();

    const int NS = K >> 4;
    float4 pa0, pa1, pw0, pw1;
    for (int s = 0; s < NS; s++) {
        const int buf = s & 1;
        const bool has_next = (s + 1 < NS);
        if (has_next) {
            int k0 = (s + 1) << 4;
            pa0 = *(const float4*)(Ap0 + k0);
            pa1 = *(const float4*)(Ap1 + k0);
            pw0 = *(const float4*)(Wp0 + k0);
            pw1 = *(const float4*)(Wp1 + k0);
        }
#pragma unroll
        for (int ks = 0; ks < 16; ks += 8) {
            wmma::fragment<wmma::matrix_a, 16, 16, 8, wmma::precision::tf32, wmma::row_major> af[2];
            wmma::fragment<wmma::matrix_b, 16, 16, 8, wmma::precision::tf32, wmma::col_major> bf[4];
#pragma unroll
            for (int mt = 0; mt < 2; mt++)
                wmma::load_matrix_sync(af[mt], &sm[buf][0][wm * 32 + mt * 16][ks], LDT);
#pragma unroll
            for (int nt = 0; nt < 4; nt++)
                wmma::load_matrix_sync(bf[nt], &sm[buf][1][wn * 64 + nt * 16][ks], LDT);
#pragma unroll
            for (int mt = 0; mt < 2; mt++)
#pragma unroll
                for (int nt = 0; nt < 4; nt++)
                    wmma::mma_sync(cfrag[mt][nt], af[mt], bf[nt], cfrag[mt][nt]);
        }
        if (has_next) {
            int nb = (s + 1) & 1;
            *(float4*)&sm[nb][0][rowL][c40]      = make_float4(f2tf32f(pa0.x), f2tf32f(pa0.y), f2tf32f(pa0.z), f2tf32f(pa0.w));
            *(float4*)&sm[nb][0][rowL + 64][c40] = make_float4(f2tf32f(pa1.x), f2tf32f(pa1.y), f2tf32f(pa1.z), f2tf32f(pa1.w));
            *(float4*)&sm[nb][1][rowL][c40]      = make_float4(f2tf32f(pw0.x), f2tf32f(pw0.y), f2tf32f(pw0.z), f2tf32f(pw0.w));
            *(float4*)&sm[nb][1][rowL + 64][c40] = make_float4(f2tf32f(pw1.x), f2tf32f(pw1.y), f2tf32f(pw1.z), f2tf32f(pw1.w));
            __syncthreads();
        }
    }

    // epilogue: via per-warp SMEM scratch (buffers are dead now)
    __syncthreads();
    float* scratch = (float*)sm + wid * 256;     // 256 floats per warp, 1KB apart
    const int er = lane >> 1;                    // 0..15
    const int ec = (lane & 1) << 3;              // 0 or 8
#pragma unroll
    for (int mt = 0; mt < 2; mt++) {
#pragma unroll
        for (int nt = 0; nt < 4; nt++) {
            wmma::store_matrix_sync(scratch, cfrag[mt][nt], 16, wmma::mem_row_major);
            __syncwarp();
            int gr = bm + wm * 32 + mt * 16 + er;
            int gc = bn + wn * 64 + nt * 16 + ec;
            const float* sp = scratch + er * 16 + ec;
            float v[8];
#pragma unroll
            for (int j = 0; j < 8; j++) v[j] = sp[j] + bias[gc + j];
            if (act) {
#pragma unroll
                for (int j = 0; j < 8; j++)
                    v[j] = 0.5f * v[j] * (1.f + erff(v[j] * 0.70710678118654752f));
            }
            if (res) {
                const float* rp = res + (size_t)gr * N + gc;
#pragma unroll
                for (int j = 0; j < 8; j++) v[j] += rp[j];
            }
            float* op = out + (size_t)gr * N + gc;
            *(float4*)op = make_float4(v[0], v[1], v[2], v[3]);
            *(float4*)(op + 4) = make_float4(v[4], v[5], v[6], v[7]);
            __syncwarp();
        }
    }
}

// ---------------- LayerNorm ----------------
__global__ void __launch_bounds__(256) ln_kernel(
    const float* __restrict__ x, const float* __restrict__ g,
    const float* __restrict__ bta, float* __restrict__ out, int C)
{
    size_t row = blockIdx.x;
    const float* p = x + row * C;
    float* o = out + row * C;
    int tid = threadIdx.x;
    float s = 0.f, s2 = 0.f;
    for (int i = tid; i < C; i += 256) { float v = p[i]; s += v; s2 += v * v; }
    __shared__ float rs[256], rq[256];
    rs[tid] = s; rq[tid] = s2; __syncthreads();
    for (int off = 128; off; off >>= 1) {
        if (tid < off) { rs[tid] += rs[tid + off]; rq[tid] += rq[tid + off]; }
        __syncthreads();
    }
    float mean = rs[0] / (float)C;
    float var  = rq[0] / (float)C - mean * mean;
    float inv  = rsqrtf(var + 1e-5f);
    for (int i = tid; i < C; i += 256)
        o[i] = (p[i] - mean) * inv * g[i] + bta[i];
}

// ---------------- attention scores: S = scale*Q@K^T + log(size) ----------------
__global__ void __launch_bounds__(256) attn_scores(
    const float* __restrict__ qkv, const float* __restrict__ sz, float* __restrict__ S)
{
    __shared__ float Qs[64][65];
    __shared__ float Ks[64][65];
    const int bh = blockIdx.z;
    const int b = bh >> 4, h = bh & 15;
    const int n0 = blockIdx.y * 64, m0 = blockIdx.x * 64;
    const float* qb = qkv + (size_t)b * Nn * 3072 + h * 64;
    const float* kb = qb + 1024;
    const int tid = threadIdx.x;
#pragma unroll
    for (int t = 0; t < 4; t++) {
        int id = tid + t * 256;
        int row = id >> 4;
        int c4 = (id & 15) << 2;
        float4 v = *(const float4*)(qb + (size_t)(n0 + row) * 3072 + c4);
        Qs[row][c4] = v.x; Qs[row][c4 + 1] = v.y; Qs[row][c4 + 2] = v.z; Qs[row][c4 + 3] = v.w;
        float4 w = *(const float4*)(kb + (size_t)(m0 + row) * 3072 + c4);
        Ks[row][c4] = w.x; Ks[row][c4 + 1] = w.y; Ks[row][c4 + 2] = w.z; Ks[row][c4 + 3] = w.w;
    }
    __syncthreads();
    const int ty = tid >> 4, tx = tid & 15;
    float acc[4][4];
#pragma unroll
    for (int i = 0; i < 4; i++)
#pragma unroll
        for (int j = 0; j < 4; j++) acc[i][j] = 0.f;
#pragma unroll
    for (int d = 0; d < 64; d++) {
        float a[4], c[4];
#pragma unroll
        for (int i = 0; i < 4; i++) a[i] = Qs[ty * 4 + i][d];
#pragma unroll
        for (int j = 0; j < 4; j++) c[j] = Ks[tx * 4 + j][d];
#pragma unroll
        for (int i = 0; i < 4; i++)
#pragma unroll
            for (int j = 0; j < 4; j++) acc[i][j] += a[i] * c[j];
    }
    float ls[4];
#pragma unroll
    for (int j = 0; j < 4; j++) ls[j] = logf(sz[b * Nn + m0 + tx * 4 + j]);
    const float scale = 0.125f;
#pragma unroll
    for (int i = 0; i < 4; i++) {
        size_t base = ((size_t)bh * Nn + (n0 + ty * 4 + i)) * Nn + m0 + tx * 4;
#pragma unroll
        for (int j = 0; j < 4; j++)
            S[base + j] = acc[i][j] * scale + ls[j];
    }
}

// ---------------- 1-pass register softmax (N=1024 = 256 thr x float4) ----------
__global__ void __launch_bounds__(256) softmax_rows(float* __restrict__ S)
{
    size_t row = blockIdx.x;
    float4* p = (float4*)(S + row * Nn);
    int tid = threadIdx.x;
    float4 v = p[tid];
    float m = fmaxf(fmaxf(v.x, v.y), fmaxf(v.z, v.w));
#pragma unroll
    for (int o = 16; o; o >>= 1) m = fmaxf(m, __shfl_xor_sync(~0u, m, o));
    __shared__ float smx[8], ssm[8];
    int w = tid >> 5, l = tid & 31;
    if (l == 0) smx[w] = m;
    __syncthreads();
    float M = smx[0];
#pragma unroll
    for (int i = 1; i < 8; i++) M = fmaxf(M, smx[i]);
    v.x = expf(v.x - M); v.y = expf(v.y - M);
    v.z = expf(v.z - M); v.w = expf(v.w - M);
    float s = v.x + v.y + v.z + v.w;
#pragma unroll
    for (int o = 16; o; o >>= 1) s += __shfl_xor_sync(~0u, s, o);
    if (l == 0) ssm[w] = s;
    __syncthreads();
    float T = ssm[0];
#pragma unroll
    for (int i = 1; i < 8; i++) T += ssm[i];
    float inv = 1.f / T;
    v.x *= inv; v.y *= inv; v.z *= inv; v.w *= inv;
    p[tid] = v;
}

// ---------------- PV: out[b,n,h,d] = sum_m P[n,m] V[m,d] ----------------
__global__ void __launch_bounds__(256) attn_av(
    const float* __restrict__ S, const float* __restrict__ qkv, float* __restrict__ out)
{
    __shared__ float Ps[64][17];
    __shared__ float Vs[16][64];
    const int bh = blockIdx.y;
    const int b = bh >> 4, h = bh & 15;
    const int n0 = blockIdx.x * 64;
    const float* Sp = S + ((size_t)bh * Nn + n0) * Nn;
    const float* vb = qkv + (size_t)b * Nn * 3072 + 2048 + h * 64;
    const int tid = threadIdx.x;
    const int ty = tid >> 4, tx = tid & 15;
    float acc[4][4];
#pragma unroll
    for (int i = 0; i < 4; i++)
#pragma unroll
        for (int j = 0; j < 4; j++) acc[i][j] = 0.f;

    const int pr = tid >> 2, pc4 = (tid & 3) << 2;
    const int vr = tid >> 4, vc4 = (tid & 15) << 2;
    for (int k0 = 0; k0 < Nn; k0 += 16) {
        float4 pv = *(const float4*)(Sp + (size_t)pr * Nn + k0 + pc4);
        Ps[pr][pc4] = pv.x; Ps[pr][pc4 + 1] = pv.y; Ps[pr][pc4 + 2] = pv.z; Ps[pr][pc4 + 3] = pv.w;
        float4 vv = *(const float4*)(vb + (size_t)(k0 + vr) * 3072 + vc4);
        Vs[vr][vc4] = vv.x; Vs[vr][vc4 + 1] = vv.y; Vs[vr][vc4 + 2] = vv.z; Vs[vr][vc4 + 3] = vv.w;
        __syncthreads();
#pragma unroll
        for (int kk = 0; kk < 16; kk++) {
            float a[4], c[4];
#pragma unroll
            for (int i = 0; i < 4; i++) a[i] = Ps[ty * 4 + i][kk];
#pragma unroll
            for (int j = 0; j < 4; j++) c[j] = Vs[kk][tx * 4 + j];
#pragma unroll
            for (int i = 0; i < 4; i++)
#pragma unroll
                for (int j = 0; j < 4; j++) acc[i][j] += a[i] * c[j];
        }
        __syncthreads();
    }
#pragma unroll
    for (int i = 0; i < 4; i++) {
        size_t base = ((size_t)b * Nn + n0 + ty * 4 + i) * Cc + h * 64 + tx * 4;
#pragma unroll
        for (int j = 0; j < 4; j++) out[base + j] = acc[i][j];
    }
}

// ---------------- pooled K weight (exact fp32 metric path) ----------------
__global__ void __launch_bounds__(256) pool_wk(
    const float* __restrict__ qkv_w, const float* __restrict__ qkv_b,
    float* __restrict__ wm, float* __restrict__ wmb)
{
    int idx = blockIdx.x * 256 + threadIdx.x;
    if (idx < 64 * 1024) {
        int d = idx >> 10, k = idx & 1023;
        float s = 0.f;
#pragma unroll
        for (int h = 0; h < 16; h++) s += qkv_w[(size_t)(1024 + h * 64 + d) * 1024 + k];
        wm[idx] = s * (1.f / 16.f);
    }
    if (idx < 64) {
        float s = 0.f;
#pragma unroll
        for (int h = 0; h < 16; h++) s += qkv_b[1024 + h * 64 + idx];
        wmb[idx] = s * (1.f / 16.f);
    }
}

// ---------------- fp32 metric GEMM: metric_raw = xln @ wm^T + wmb ----------------
__global__ void __launch_bounds__(256) metric_gemm(
    const float* __restrict__ xln, const float* __restrict__ wm,
    const float* __restrict__ wmb, float* __restrict__ metric)
{
    __shared__ float Xs[32][132];
    __shared__ float Ws[32][68];
    const int bm = blockIdx.x * 128;
    const int tid = threadIdx.x;
    const int ty = tid >> 3;
    const int tx = tid & 7;
    float acc[4][8];
#pragma unroll
    for (int i = 0; i < 4; i++)
#pragma unroll
        for (int j = 0; j < 8; j++) acc[i][j] = 0.f;

    for (int k0 = 0; k0 < 1024; k0 += 32) {
#pragma unroll
        for (int i = 0; i < 4; i++) {
            int idx = tid + i * 256;
            int row = idx >> 3;
            int kq = (idx & 7) << 2;
            float4 v = *(const float4*)(xln + (size_t)(bm + row) * 1024 + k0 + kq);
            Xs[kq][row] = v.x; Xs[kq + 1][row] = v.y; Xs[kq + 2][row] = v.z; Xs[kq + 3][row] = v.w;
        }
        // FIX (R5): 512 items, 256 threads -> strided loop (was `if (tid < 512)`,
        // which left Ws rows d=32..63 uninitialized and corrupted the matching)
        for (int idx = tid; idx < 512; idx += 256) {
            int d = idx >> 3;
            int kq = (idx & 7) << 2;
            float4 v = *(const float4*)(wm + (size_t)d * 1024 + k0 + kq);
            Ws[kq][d] = v.x; Ws[kq + 1][d] = v.y; Ws[kq + 2][d] = v.z; Ws[kq + 3][d] = v.w;
        }
        __syncthreads();
#pragma unroll
        for (int kk = 0; kk < 32; kk++) {
            float a[4], w[8];
#pragma unroll
            for (int i = 0; i < 4; i++) a[i] = Xs[kk][ty * 4 + i];
#pragma unroll
            for (int j = 0; j < 8; j++) w[j] = Ws[kk][tx * 8 + j];
#pragma unroll
            for (int i = 0; i < 4; i++)
#pragma unroll
                for (int j = 0; j < 8; j++) acc[i][j] += a[i] * w[j];
        }
        __syncthreads();
    }
#pragma unroll
    for (int i = 0; i < 4; i++) {
        int row = bm + ty * 4 + i;
#pragma unroll
        for (int j = 0; j < 8; j++)
            metric[(size_t)row * 64 + tx * 8 + j] = acc[i][j] + wmb[tx * 8 + j];
    }
}

__global__ void __launch_bounds__(64) metric_norm(float* __restrict__ metric)
{
    int bn = blockIdx.x;
    int d = threadIdx.x;
    float v = metric[(size_t)bn * 64 + d];
    __shared__ float sh[64];
    sh[d] = v * v; __syncthreads();
    for (int off = 32; off; off >>= 1) {
        if (d < off) sh[d] += sh[d + off];
        __syncthreads();
    }
    float inv = rsqrtf(sh[0]);
    metric[(size_t)bn * 64 + d] = v * inv;
}

// ---------------- per-row max/argmax of a@bset^T (row 0 forced to -inf) ------
__global__ void __launch_bounds__(256) match_scores(
    const float* __restrict__ metric, float* __restrict__ nodemax, int* __restrict__ nodeidx)
{
    int t = blockIdx.x;
    int b = blockIdx.y;
    const float* mb = metric + (size_t)b * Nn * 64;
    __shared__ float av[64];
    int tid = threadIdx.x;
    if (tid < 64) av[tid] = mb[(size_t)(2 * t) * 64 + tid];
    __syncthreads();
    float best = -INFINITY; int bi = 0;
    for (int s = tid; s < NH; s += 256) {
        const float* bp = mb + (size_t)(2 * s + 1) * 64;
        float dot = 0.f;
#pragma unroll
        for (int d = 0; d < 64; d++) dot += av[d] * bp[d];
        if (dot > best) { best = dot; bi = s; }
    }
    __shared__ float sv[256]; __shared__ int si[256];
    sv[tid] = best; si[tid] = bi; __syncthreads();
    for (int off = 128; off; off >>= 1) {
        if (tid < off) {
            if (sv[tid + off] > sv[tid] ||
                (sv[tid + off] == sv[tid] && si[tid + off] < si[tid])) {
                sv[tid] = sv[tid + off]; si[tid] = si[tid + off];
            }
        }
        __syncthreads();
    }
    if (tid == 0) {
        if (t == 0) { nodemax[b * NH] = -INFINITY; nodeidx[b * NH] = 0; }
        else { nodemax[b * NH + t] = sv[0]; nodeidx[b * NH + t] = si[0]; }
    }
}

// ---------------- stable descending rank-sort + index split ----------------
__global__ void __launch_bounds__(512) match_sort(
    const float* __restrict__ nodemax, const int* __restrict__ nodeidx,
    int* __restrict__ srcidx, int* __restrict__ dstidx, int* __restrict__ unmidx)
{
    int b = blockIdx.x, t = threadIdx.x;
    __shared__ float v[NH]; __shared__ int rk[NH];
    v[t] = nodemax[b * NH + t]; __syncthreads();
    float vt = v[t]; int r = 0;
    for (int j = 0; j < NH; j++) {
        float vj = v[j];
        r += (vj > vt) || (vj == vt && j < t);
    }
    rk[t] = r; __syncthreads();
    if (r < Rr) {
        srcidx[b * Rr + r] = t;
        dstidx[b * Rr + r] = nodeidx[b * NH + t];
    } else {
        int pos = 0;
        for (int j = 0; j < t; j++) pos += (rk[j] >= Rr);
        unmidx[b * NU + pos] = t;
    }
}

// ---------------- weighted merge + divide by new size ----------------
__global__ void __launch_bounds__(256) merge_kernel(
    const float* __restrict__ xres, const float* __restrict__ sz,
    const int* __restrict__ srcidx, const int* __restrict__ dstidx,
    const int* __restrict__ unmidx, float* __restrict__ xm)
{
    int row = blockIdx.x;
    int b = blockIdx.y;
    int tid = threadIdx.x;
    const float* xb = xres + (size_t)b * Nn * Cc;
    const float* szb = sz + b * Nn;
    float* ob = xm + ((size_t)b * NM + row) * Cc;
    __shared__ int ss[Rr], sd[Rr];

    if (row < NU) {
        int t = 2 * unmidx[b * NU + row];
        float s = szb[t];
        float inv = 1.f / s;
        for (int c = tid; c < Cc; c += 256)
            ob[c] = (xb[(size_t)t * Cc + c] * s) * inv;
    } else {
        int j = row - NU;
        if (tid < Rr) { ss[tid] = srcidx[b * Rr + tid]; sd[tid] = dstidx[b * Rr + tid]; }
        __syncthreads();
        int t = 2 * j + 1;
        float ns = szb[t];
        for (int i = 0; i < Rr; i++)
            if (sd[i] == j) ns += szb[2 * ss[i]];
        float inv = 1.f / ns;
        for (int c = tid; c < Cc; c += 256) {
            float val = xb[(size_t)t * Cc + c] * szb[t];
            for (int i = 0; i < Rr; i++) {
                if (sd[i] == j) {
                    int ts = 2 * ss[i];
                    val += xb[(size_t)ts * Cc + c] * szb[ts];
                }
            }
            ob[c] = val * inv;
        }
    }
}

// ---------------- launch ----------------
template <typename T>
static T* sym_addr(const void* sym) {
    void* p = nullptr;
    cudaGetSymbolAddress(&p, sym);
    return (T*)p;
}

extern "C" void kernel_launch(void* const* d_in, const int* in_sizes, int n_in,
                              void* d_out, int out_size)
{
    const float* x      = (const float*)d_in[0];
    const float* sz     = (const float*)d_in[1];
    const float* qkv_w  = (const float*)d_in[3];
    const float* qkv_b  = (const float*)d_in[4];
    const float* proj_w = (const float*)d_in[5];
    const float* proj_b = (const float*)d_in[6];
    const float* n1g    = (const float*)d_in[7];
    const float* n1b    = (const float*)d_in[8];
    const float* n2g    = (const float*)d_in[9];
    const float* n2b    = (const float*)d_in[10];
    const float* fc1_w  = (const float*)d_in[11];
    const float* fc1_b  = (const float*)d_in[12];
    const float* fc2_w  = (const float*)d_in[13];
    const float* fc2_b  = (const float*)d_in[14];
    float* out = (float*)d_out;

    float* xln   = sym_addr<float>(g_xln);
    float* qkv   = sym_addr<float>(g_qkv);
    float* S     = sym_addr<float>(g_S);
    float* attno = sym_addr<float>(g_attno);
    float* xres  = sym_addr<float>(g_xres);
    float* wm    = sym_addr<float>(g_wm);
    float* wmb   = sym_addr<float>(g_wmb);
    float* metric= sym_addr<float>(g_metric);
    float* nmax  = sym_addr<float>(g_nodemax);
    int*   nidx  = sym_addr<int>(g_nodeidx);
    int*   sidx  = sym_addr<int>(g_srcidx);
    int*   didx  = sym_addr<int>(g_dstidx);
    int*   uidx  = sym_addr<int>(g_unmidx);
    float* xm    = sym_addr<float>(g_xm);
    float* h2    = sym_addr<float>(g_h2);
    float* fc1   = sym_addr<float>(g_fc1);

    // 1. LN1
    ln_kernel<<<MROWS, 256>>>(x, n1g, n1b, xln, Cc);
    // 2. QKV GEMM (tf32 wmma)
    tf32_gemm<<<dim3(3072 / 128, MROWS / 128), 256>>>(
        xln, qkv_w, qkv_b, nullptr, qkv, MROWS, 3072, Cc, 0);
    // 3. exact fp32 metric path: mean_h(k) == xln @ mean_h(Wk)^T + mean_h(bk)
    pool_wk<<<256, 256>>>(qkv_w, qkv_b, wm, wmb);
    metric_gemm<<<MROWS / 128, 256>>>(xln, wm, wmb, metric);
    metric_norm<<<Bb * Nn, 64>>>(metric);
    // 4. attention scores + bias
    attn_scores<<<dim3(16, 16, Bb * Hh), 256>>>(qkv, sz, S);
    // 5. softmax (1-pass)
    softmax_rows<<<Bb * Hh * Nn, 256>>>(S);
    // 6. PV
    attn_av<<<dim3(16, Bb * Hh), 256>>>(S, qkv, attno);
    // 7. proj + residual (tf32 wmma)
    tf32_gemm<<<dim3(Cc / 128, MROWS / 128), 256>>>(
        attno, proj_w, proj_b, x, xres, MROWS, Cc, Cc, 0);
    // 8. matching
    match_scores<<<dim3(NH, Bb), 256>>>(metric, nmax, nidx);
    match_sort<<<Bb, NH>>>(nmax, nidx, sidx, didx, uidx);
    // 9. merge
    merge_kernel<<<dim3(NM, Bb), 256>>>(xres, sz, sidx, didx, uidx, xm);
    // 10. LN2
    ln_kernel<<<MROWS2, 256>>>(xm, n2g, n2b, h2, Cc);
    // 11. fc1 + exact GELU (tf32 wmma)
    tf32_gemm<<<dim3(4096 / 128, MROWS2 / 128), 256>>>(
        h2, fc1_w, fc1_b, nullptr, fc1, MROWS2, 4096, Cc, 1);
    // 12. fc2 + residual -> out (tf32 wmma)
    tf32_gemm<<<dim3(Cc / 128, MROWS2 / 128), 256>>>(
        fc1, fc2_w, fc2_b, xm, out, MROWS2, Cc, 4096, 0);
    (void)in_sizes; (void)n_in; (void)out_size;
}

// round 6
// speedup vs baseline: 1.7918x; 1.3267x over previous
#include <cuda_runtime.h>
#include <cuda_bf16.h>
#include <math.h>
#include <cstdint>

// Problem constants
#define Bb 16
#define Nn 1024
#define Cc 1024
#define Hh 16
#define HD 64
#define Rr 128
#define NH (Nn/2)          // 512
#define NU (NH - Rr)       // 384 unmerged
#define NM (NU + NH)       // 896 merged tokens
#define MROWS (Bb*Nn)      // 16384
#define MROWS2 (Bb*NM)     // 14336

// ---------------- scratch (static device globals) ----------------
__device__ float g_xln  [(size_t)MROWS * Cc];
__device__ float g_qkv  [(size_t)MROWS * 3 * Cc];
__device__ float g_S    [(size_t)Bb * Hh * Nn * Nn];   // 1 GiB scores
__device__ float g_attno[(size_t)MROWS * Cc];
__device__ float g_xres [(size_t)MROWS * Cc];
__device__ float g_wm   [64 * 1024];
__device__ float g_wmb  [64];
__device__ float g_metric[(size_t)Bb * Nn * HD];
__device__ float g_nodemax[Bb * NH];
__device__ int   g_nodeidx[Bb * NH];
__device__ int   g_srcidx[Bb * Rr];
__device__ int   g_dstidx[Bb * Rr];
__device__ int   g_unmidx[Bb * NU];
__device__ float g_xm   [(size_t)MROWS2 * Cc];
__device__ float g_h2   [(size_t)MROWS2 * Cc];
__device__ float g_fc1  [(size_t)MROWS2 * 4 * Cc];

__device__ __forceinline__ uint32_t f2tf32(float x) {
    uint32_t r;
    asm("cvt.rna.tf32.f32 %0, %1;" : "=r"(r) : "f"(x));
    return r;
}

__device__ __forceinline__ void mma_tf32(float& d0, float& d1, float& d2, float& d3,
                                         uint32_t a0, uint32_t a1, uint32_t a2, uint32_t a3,
                                         uint32_t b0, uint32_t b1)
{
    asm volatile(
        "mma.sync.aligned.m16n8k8.row.col.f32.tf32.tf32.f32 "
        "{%0,%1,%2,%3}, {%4,%5,%6,%7}, {%8,%9}, {%0,%1,%2,%3};\n"
        : "+f"(d0), "+f"(d1), "+f"(d2), "+f"(d3)
        : "r"(a0), "r"(a1), "r"(a2), "r"(a3), "r"(b0), "r"(b1));
}

// ================= tf32 mma.sync GEMM =================
// out(MxN) = A(MxK) @ W(NxK)^T + bias [,gelu] [,+res]
// CTA tile 128x128, 8 warps (4 along M x 2 along N), warp tile 32x64.
// K staged 16, double-buffered SMEM, stride 20 (conflict-free: bank (20g+tg)%32 bijective).
__global__ void __launch_bounds__(256) tf32_gemm(
    const float* __restrict__ A, const float* __restrict__ W,
    const float* __restrict__ bias, const float* __restrict__ res,
    float* __restrict__ out, int M, int N, int K, int act)
{
    __shared__ uint32_t As[2][128][20];
    __shared__ uint32_t Bs[2][128][20];

    const int tid = threadIdx.x;
    const int wid = tid >> 5;
    const int lane = tid & 31;
    const int g = lane >> 2;        // fragment group 0..7
    const int tg = lane & 3;        // thread-in-group 0..3
    const int wm = wid & 3;         // warp M slot (32 rows each)
    const int wn = wid >> 2;        // warp N slot (64 cols each)
    const int bm = blockIdx.y * 128;
    const int bn = blockIdx.x * 128;

    // stage-load addressing: thread covers rows rowA0, rowA0+64 (one float4 each)
    const int rowA0 = tid >> 2;
    const int c40 = (tid & 3) << 2;
    const float* Ap0 = A + (size_t)(bm + rowA0) * K + c40;
    const float* Ap1 = Ap0 + (size_t)64 * K;
    const float* Wp0 = W + (size_t)(bn + rowA0) * K + c40;
    const float* Wp1 = Wp0 + (size_t)64 * K;

    float acc[2][8][4];
#pragma unroll
    for (int i = 0; i < 2; i++)
#pragma unroll
        for (int j = 0; j < 8; j++)
#pragma unroll
            for (int v = 0; v < 4; v++) acc[i][j][v] = 0.f;

    // prologue: stage 0 -> buffer 0
    {
        float4 a0 = *(const float4*)(Ap0);
        float4 a1 = *(const float4*)(Ap1);
        float4 w0 = *(const float4*)(Wp0);
        float4 w1 = *(const float4*)(Wp1);
        *(uint4*)&As[0][rowA0][c40]      = make_uint4(f2tf32(a0.x), f2tf32(a0.y), f2tf32(a0.z), f2tf32(a0.w));
        *(uint4*)&As[0][rowA0 + 64][c40] = make_uint4(f2tf32(a1.x), f2tf32(a1.y), f2tf32(a1.z), f2tf32(a1.w));
        *(uint4*)&Bs[0][rowA0][c40]      = make_uint4(f2tf32(w0.x), f2tf32(w0.y), f2tf32(w0.z), f2tf32(w0.w));
        *(uint4*)&Bs[0][rowA0 + 64][c40] = make_uint4(f2tf32(w1.x), f2tf32(w1.y), f2tf32(w1.z), f2tf32(w1.w));
    }
    __syncthreads();

    const int NS = K >> 4;
    uint4 sa0, sa1, sw0, sw1;
    for (int s = 0; s < NS; s++) {
        const int buf = s & 1;
        const bool has_next = (s + 1 < NS);
        if (has_next) {
            int k0 = (s + 1) << 4;
            float4 a0 = *(const float4*)(Ap0 + k0);
            float4 a1 = *(const float4*)(Ap1 + k0);
            float4 w0 = *(const float4*)(Wp0 + k0);
            float4 w1 = *(const float4*)(Wp1 + k0);
            sa0 = make_uint4(f2tf32(a0.x), f2tf32(a0.y), f2tf32(a0.z), f2tf32(a0.w));
            sa1 = make_uint4(f2tf32(a1.x), f2tf32(a1.y), f2tf32(a1.z), f2tf32(a1.w));
            sw0 = make_uint4(f2tf32(w0.x), f2tf32(w0.y), f2tf32(w0.z), f2tf32(w0.w));
            sw1 = make_uint4(f2tf32(w1.x), f2tf32(w1.y), f2tf32(w1.z), f2tf32(w1.w));
        }
#pragma unroll
        for (int ks = 0; ks < 16; ks += 8) {
            uint32_t af[2][4];
#pragma unroll
            for (int mt = 0; mt < 2; mt++) {
                int ra = wm * 32 + mt * 16 + g;
                af[mt][0] = As[buf][ra][ks + tg];
                af[mt][1] = As[buf][ra + 8][ks + tg];
                af[mt][2] = As[buf][ra][ks + tg + 4];
                af[mt][3] = As[buf][ra + 8][ks + tg + 4];
            }
            uint32_t bf[8][2];
#pragma unroll
            for (int nt = 0; nt < 8; nt++) {
                int cb = wn * 64 + nt * 8 + g;
                bf[nt][0] = Bs[buf][cb][ks + tg];
                bf[nt][1] = Bs[buf][cb][ks + tg + 4];
            }
#pragma unroll
            for (int mt = 0; mt < 2; mt++)
#pragma unroll
                for (int nt = 0; nt < 8; nt++)
                    mma_tf32(acc[mt][nt][0], acc[mt][nt][1], acc[mt][nt][2], acc[mt][nt][3],
                             af[mt][0], af[mt][1], af[mt][2], af[mt][3],
                             bf[nt][0], bf[nt][1]);
        }
        if (has_next) {
            int nb = (s + 1) & 1;
            __syncthreads();                 // mma reads of buf done before overwrite of nb==buf^1? (nb != buf; but ensure prior-iter reads of nb done)
            *(uint4*)&As[nb][rowA0][c40]      = sa0;
            *(uint4*)&As[nb][rowA0 + 64][c40] = sa1;
            *(uint4*)&Bs[nb][rowA0][c40]      = sw0;
            *(uint4*)&Bs[nb][rowA0 + 64][c40] = sw1;
            __syncthreads();
        }
    }

    // epilogue: direct from accumulators (layout per PTX m16n8 C spec)
#pragma unroll
    for (int mt = 0; mt < 2; mt++) {
        int r0 = bm + wm * 32 + mt * 16 + g;
#pragma unroll
        for (int nt = 0; nt < 8; nt++) {
            int col = bn + wn * 64 + nt * 8 + tg * 2;
            float b0 = bias[col], b1 = bias[col + 1];
            float v0 = acc[mt][nt][0] + b0;
            float v1 = acc[mt][nt][1] + b1;
            float v2 = acc[mt][nt][2] + b0;
            float v3 = acc[mt][nt][3] + b1;
            if (act) {
                v0 = 0.5f * v0 * (1.f + erff(v0 * 0.70710678118654752f));
                v1 = 0.5f * v1 * (1.f + erff(v1 * 0.70710678118654752f));
                v2 = 0.5f * v2 * (1.f + erff(v2 * 0.70710678118654752f));
                v3 = 0.5f * v3 * (1.f + erff(v3 * 0.70710678118654752f));
            }
            if (res) {
                const float* rp0 = res + (size_t)r0 * N + col;
                const float* rp1 = rp0 + (size_t)8 * N;
                v0 += rp0[0]; v1 += rp0[1];
                v2 += rp1[0]; v3 += rp1[1];
            }
            *(float2*)(out + (size_t)r0 * N + col) = make_float2(v0, v1);
            *(float2*)(out + (size_t)(r0 + 8) * N + col) = make_float2(v2, v3);
        }
    }
}

// ---------------- LayerNorm ----------------
__global__ void __launch_bounds__(256) ln_kernel(
    const float* __restrict__ x, const float* __restrict__ g,
    const float* __restrict__ bta, float* __restrict__ out, int C)
{
    size_t row = blockIdx.x;
    const float* p = x + row * C;
    float* o = out + row * C;
    int tid = threadIdx.x;
    float s = 0.f, s2 = 0.f;
    for (int i = tid; i < C; i += 256) { float v = p[i]; s += v; s2 += v * v; }
    __shared__ float rs[256], rq[256];
    rs[tid] = s; rq[tid] = s2; __syncthreads();
    for (int off = 128; off; off >>= 1) {
        if (tid < off) { rs[tid] += rs[tid + off]; rq[tid] += rq[tid + off]; }
        __syncthreads();
    }
    float mean = rs[0] / (float)C;
    float var  = rq[0] / (float)C - mean * mean;
    float inv  = rsqrtf(var + 1e-5f);
    for (int i = tid; i < C; i += 256)
        o[i] = (p[i] - mean) * inv * g[i] + bta[i];
}

// ---------------- attention scores: S = scale*Q@K^T + log(size) ----------------
__global__ void __launch_bounds__(256) attn_scores(
    const float* __restrict__ qkv, const float* __restrict__ sz, float* __restrict__ S)
{
    __shared__ float Qs[64][65];
    __shared__ float Ks[64][65];
    const int bh = blockIdx.z;
    const int b = bh >> 4, h = bh & 15;
    const int n0 = blockIdx.y * 64, m0 = blockIdx.x * 64;
    const float* qb = qkv + (size_t)b * Nn * 3072 + h * 64;
    const float* kb = qb + 1024;
    const int tid = threadIdx.x;
#pragma unroll
    for (int t = 0; t < 4; t++) {
        int id = tid + t * 256;
        int row = id >> 4;
        int c4 = (id & 15) << 2;
        float4 v = *(const float4*)(qb + (size_t)(n0 + row) * 3072 + c4);
        Qs[row][c4] = v.x; Qs[row][c4 + 1] = v.y; Qs[row][c4 + 2] = v.z; Qs[row][c4 + 3] = v.w;
        float4 w = *(const float4*)(kb + (size_t)(m0 + row) * 3072 + c4);
        Ks[row][c4] = w.x; Ks[row][c4 + 1] = w.y; Ks[row][c4 + 2] = w.z; Ks[row][c4 + 3] = w.w;
    }
    __syncthreads();
    const int ty = tid >> 4, tx = tid & 15;
    float acc[4][4];
#pragma unroll
    for (int i = 0; i < 4; i++)
#pragma unroll
        for (int j = 0; j < 4; j++) acc[i][j] = 0.f;
#pragma unroll
    for (int d = 0; d < 64; d++) {
        float a[4], c[4];
#pragma unroll
        for (int i = 0; i < 4; i++) a[i] = Qs[ty * 4 + i][d];
#pragma unroll
        for (int j = 0; j < 4; j++) c[j] = Ks[tx * 4 + j][d];
#pragma unroll
        for (int i = 0; i < 4; i++)
#pragma unroll
            for (int j = 0; j < 4; j++) acc[i][j] += a[i] * c[j];
    }
    float ls[4];
#pragma unroll
    for (int j = 0; j < 4; j++) ls[j] = logf(sz[b * Nn + m0 + tx * 4 + j]);
    const float scale = 0.125f;
#pragma unroll
    for (int i = 0; i < 4; i++) {
        size_t base = ((size_t)bh * Nn + (n0 + ty * 4 + i)) * Nn + m0 + tx * 4;
#pragma unroll
        for (int j = 0; j < 4; j++)
            S[base + j] = acc[i][j] * scale + ls[j];
    }
}

// ---------------- 1-pass register softmax (N=1024 = 256 thr x float4) ----------
__global__ void __launch_bounds__(256) softmax_rows(float* __restrict__ S)
{
    size_t row = blockIdx.x;
    float4* p = (float4*)(S + row * Nn);
    int tid = threadIdx.x;
    float4 v = p[tid];
    float m = fmaxf(fmaxf(v.x, v.y), fmaxf(v.z, v.w));
#pragma unroll
    for (int o = 16; o; o >>= 1) m = fmaxf(m, __shfl_xor_sync(~0u, m, o));
    __shared__ float smx[8], ssm[8];
    int w = tid >> 5, l = tid & 31;
    if (l == 0) smx[w] = m;
    __syncthreads();
    float M = smx[0];
#pragma unroll
    for (int i = 1; i < 8; i++) M = fmaxf(M, smx[i]);
    v.x = expf(v.x - M); v.y = expf(v.y - M);
    v.z = expf(v.z - M); v.w = expf(v.w - M);
    float s = v.x + v.y + v.z + v.w;
#pragma unroll
    for (int o = 16; o; o >>= 1) s += __shfl_xor_sync(~0u, s, o);
    if (l == 0) ssm[w] = s;
    __syncthreads();
    float T = ssm[0];
#pragma unroll
    for (int i = 1; i < 8; i++) T += ssm[i];
    float inv = 1.f / T;
    v.x *= inv; v.y *= inv; v.z *= inv; v.w *= inv;
    p[tid] = v;
}

// ---------------- PV: out[b,n,h,d] = sum_m P[n,m] V[m,d] ----------------
__global__ void __launch_bounds__(256) attn_av(
    const float* __restrict__ S, const float* __restrict__ qkv, float* __restrict__ out)
{
    __shared__ float Ps[64][17];
    __shared__ float Vs[16][64];
    const int bh = blockIdx.y;
    const int b = bh >> 4, h = bh & 15;
    const int n0 = blockIdx.x * 64;
    const float* Sp = S + ((size_t)bh * Nn + n0) * Nn;
    const float* vb = qkv + (size_t)b * Nn * 3072 + 2048 + h * 64;
    const int tid = threadIdx.x;
    const int ty = tid >> 4, tx = tid & 15;
    float acc[4][4];
#pragma unroll
    for (int i = 0; i < 4; i++)
#pragma unroll
        for (int j = 0; j < 4; j++) acc[i][j] = 0.f;

    const int pr = tid >> 2, pc4 = (tid & 3) << 2;
    const int vr = tid >> 4, vc4 = (tid & 15) << 2;
    for (int k0 = 0; k0 < Nn; k0 += 16) {
        float4 pv = *(const float4*)(Sp + (size_t)pr * Nn + k0 + pc4);
        Ps[pr][pc4] = pv.x; Ps[pr][pc4 + 1] = pv.y; Ps[pr][pc4 + 2] = pv.z; Ps[pr][pc4 + 3] = pv.w;
        float4 vv = *(const float4*)(vb + (size_t)(k0 + vr) * 3072 + vc4);
        Vs[vr][vc4] = vv.x; Vs[vr][vc4 + 1] = vv.y; Vs[vr][vc4 + 2] = vv.z; Vs[vr][vc4 + 3] = vv.w;
        __syncthreads();
#pragma unroll
        for (int kk = 0; kk < 16; kk++) {
            float a[4], c[4];
#pragma unroll
            for (int i = 0; i < 4; i++) a[i] = Ps[ty * 4 + i][kk];
#pragma unroll
            for (int j = 0; j < 4; j++) c[j] = Vs[kk][tx * 4 + j];
#pragma unroll
            for (int i = 0; i < 4; i++)
#pragma unroll
                for (int j = 0; j < 4; j++) acc[i][j] += a[i] * c[j];
        }
        __syncthreads();
    }
#pragma unroll
    for (int i = 0; i < 4; i++) {
        size_t base = ((size_t)b * Nn + n0 + ty * 4 + i) * Cc + h * 64 + tx * 4;
#pragma unroll
        for (int j = 0; j < 4; j++) out[base + j] = acc[i][j];
    }
}

// ---------------- pooled K weight (exact fp32 metric path) ----------------
__global__ void __launch_bounds__(256) pool_wk(
    const float* __restrict__ qkv_w, const float* __restrict__ qkv_b,
    float* __restrict__ wm, float* __restrict__ wmb)
{
    int idx = blockIdx.x * 256 + threadIdx.x;
    if (idx < 64 * 1024) {
        int d = idx >> 10, k = idx & 1023;
        float s = 0.f;
#pragma unroll
        for (int h = 0; h < 16; h++) s += qkv_w[(size_t)(1024 + h * 64 + d) * 1024 + k];
        wm[idx] = s * (1.f / 16.f);
    }
    if (idx < 64) {
        float s = 0.f;
#pragma unroll
        for (int h = 0; h < 16; h++) s += qkv_b[1024 + h * 64 + idx];
        wmb[idx] = s * (1.f / 16.f);
    }
}

// ---------------- fp32 metric GEMM: metric_raw = xln @ wm^T + wmb ----------------
__global__ void __launch_bounds__(256) metric_gemm(
    const float* __restrict__ xln, const float* __restrict__ wm,
    const float* __restrict__ wmb, float* __restrict__ metric)
{
    __shared__ float Xs[32][132];
    __shared__ float Ws[32][68];
    const int bm = blockIdx.x * 128;
    const int tid = threadIdx.x;
    const int ty = tid >> 3;
    const int tx = tid & 7;
    float acc[4][8];
#pragma unroll
    for (int i = 0; i < 4; i++)
#pragma unroll
        for (int j = 0; j < 8; j++) acc[i][j] = 0.f;

    for (int k0 = 0; k0 < 1024; k0 += 32) {
#pragma unroll
        for (int i = 0; i < 4; i++) {
            int idx = tid + i * 256;
            int row = idx >> 3;
            int kq = (idx & 7) << 2;
            float4 v = *(const float4*)(xln + (size_t)(bm + row) * 1024 + k0 + kq);
            Xs[kq][row] = v.x; Xs[kq + 1][row] = v.y; Xs[kq + 2][row] = v.z; Xs[kq + 3][row] = v.w;
        }
        for (int idx = tid; idx < 512; idx += 256) {
            int d = idx >> 3;
            int kq = (idx & 7) << 2;
            float4 v = *(const float4*)(wm + (size_t)d * 1024 + k0 + kq);
            Ws[kq][d] = v.x; Ws[kq + 1][d] = v.y; Ws[kq + 2][d] = v.z; Ws[kq + 3][d] = v.w;
        }
        __syncthreads();
#pragma unroll
        for (int kk = 0; kk < 32; kk++) {
            float a[4], w[8];
#pragma unroll
            for (int i = 0; i < 4; i++) a[i] = Xs[kk][ty * 4 + i];
#pragma unroll
            for (int j = 0; j < 8; j++) w[j] = Ws[kk][tx * 8 + j];
#pragma unroll
            for (int i = 0; i < 4; i++)
#pragma unroll
                for (int j = 0; j < 8; j++) acc[i][j] += a[i] * w[j];
        }
        __syncthreads();
    }
#pragma unroll
    for (int i = 0; i < 4; i++) {
        int row = bm + ty * 4 + i;
#pragma unroll
        for (int j = 0; j < 8; j++)
            metric[(size_t)row * 64 + tx * 8 + j] = acc[i][j] + wmb[tx * 8 + j];
    }
}

__global__ void __launch_bounds__(64) metric_norm(float* __restrict__ metric)
{
    int bn = blockIdx.x;
    int d = threadIdx.x;
    float v = metric[(size_t)bn * 64 + d];
    __shared__ float sh[64];
    sh[d] = v * v; __syncthreads();
    for (int off = 32; off; off >>= 1) {
        if (d < off) sh[d] += sh[d + off];
        __syncthreads();
    }
    float inv = rsqrtf(sh[0]);
    metric[(size_t)bn * 64 + d] = v * inv;
}

// ---------------- per-row max/argmax of a@bset^T (row 0 forced to -inf) ------
__global__ void __launch_bounds__(256) match_scores(
    const float* __restrict__ metric, float* __restrict__ nodemax, int* __restrict__ nodeidx)
{
    int t = blockIdx.x;
    int b = blockIdx.y;
    const float* mb = metric + (size_t)b * Nn * 64;
    __shared__ float av[64];
    int tid = threadIdx.x;
    if (tid < 64) av[tid] = mb[(size_t)(2 * t) * 64 + tid];
    __syncthreads();
    float best = -INFINITY; int bi = 0;
    for (int s = tid; s < NH; s += 256) {
        const float* bp = mb + (size_t)(2 * s + 1) * 64;
        float dot = 0.f;
#pragma unroll
        for (int d = 0; d < 64; d++) dot += av[d] * bp[d];
        if (dot > best) { best = dot; bi = s; }
    }
    __shared__ float sv[256]; __shared__ int si[256];
    sv[tid] = best; si[tid] = bi; __syncthreads();
    for (int off = 128; off; off >>= 1) {
        if (tid < off) {
            if (sv[tid + off] > sv[tid] ||
                (sv[tid + off] == sv[tid] && si[tid + off] < si[tid])) {
                sv[tid] = sv[tid + off]; si[tid] = si[tid + off];
            }
        }
        __syncthreads();
    }
    if (tid == 0) {
        if (t == 0) { nodemax[b * NH] = -INFINITY; nodeidx[b * NH] = 0; }
        else { nodemax[b * NH + t] = sv[0]; nodeidx[b * NH + t] = si[0]; }
    }
}

// ---------------- stable descending rank-sort + index split ----------------
__global__ void __launch_bounds__(512) match_sort(
    const float* __restrict__ nodemax, const int* __restrict__ nodeidx,
    int* __restrict__ srcidx, int* __restrict__ dstidx, int* __restrict__ unmidx)
{
    int b = blockIdx.x, t = threadIdx.x;
    __shared__ float v[NH]; __shared__ int rk[NH];
    v[t] = nodemax[b * NH + t]; __syncthreads();
    float vt = v[t]; int r = 0;
    for (int j = 0; j < NH; j++) {
        float vj = v[j];
        r += (vj > vt) || (vj == vt && j < t);
    }
    rk[t] = r; __syncthreads();
    if (r < Rr) {
        srcidx[b * Rr + r] = t;
        dstidx[b * Rr + r] = nodeidx[b * NH + t];
    } else {
        int pos = 0;
        for (int j = 0; j < t; j++) pos += (rk[j] >= Rr);
        unmidx[b * NU + pos] = t;
    }
}

// ---------------- weighted merge + divide by new size ----------------
__global__ void __launch_bounds__(256) merge_kernel(
    const float* __restrict__ xres, const float* __restrict__ sz,
    const int* __restrict__ srcidx, const int* __restrict__ dstidx,
    const int* __restrict__ unmidx, float* __restrict__ xm)
{
    int row = blockIdx.x;
    int b = blockIdx.y;
    int tid = threadIdx.x;
    const float* xb = xres + (size_t)b * Nn * Cc;
    const float* szb = sz + b * Nn;
    float* ob = xm + ((size_t)b * NM + row) * Cc;
    __shared__ int ss[Rr], sd[Rr];

    if (row < NU) {
        int t = 2 * unmidx[b * NU + row];
        float s = szb[t];
        float inv = 1.f / s;
        for (int c = tid; c < Cc; c += 256)
            ob[c] = (xb[(size_t)t * Cc + c] * s) * inv;
    } else {
        int j = row - NU;
        if (tid < Rr) { ss[tid] = srcidx[b * Rr + tid]; sd[tid] = dstidx[b * Rr + tid]; }
        __syncthreads();
        int t = 2 * j + 1;
        float ns = szb[t];
        for (int i = 0; i < Rr; i++)
            if (sd[i] == j) ns += szb[2 * ss[i]];
        float inv = 1.f / ns;
        for (int c = tid; c < Cc; c += 256) {
            float val = xb[(size_t)t * Cc + c] * szb[t];
            for (int i = 0; i < Rr; i++) {
                if (sd[i] == j) {
                    int ts = 2 * ss[i];
                    val += xb[(size_t)ts * Cc + c] * szb[ts];
                }
            }
            ob[c] = val * inv;
        }
    }
}

// ---------------- launch ----------------
template <typename T>
static T* sym_addr(const void* sym) {
    void* p = nullptr;
    cudaGetSymbolAddress(&p, sym);
    return (T*)p;
}

extern "C" void kernel_launch(void* const* d_in, const int* in_sizes, int n_in,
                              void* d_out, int out_size)
{
    const float* x      = (const float*)d_in[0];
    const float* sz     = (const float*)d_in[1];
    const float* qkv_w  = (const float*)d_in[3];
    const float* qkv_b  = (const float*)d_in[4];
    const float* proj_w = (const float*)d_in[5];
    const float* proj_b = (const float*)d_in[6];
    const float* n1g    = (const float*)d_in[7];
    const float* n1b    = (const float*)d_in[8];
    const float* n2g    = (const float*)d_in[9];
    const float* n2b    = (const float*)d_in[10];
    const float* fc1_w  = (const float*)d_in[11];
    const float* fc1_b  = (const float*)d_in[12];
    const float* fc2_w  = (const float*)d_in[13];
    const float* fc2_b  = (const float*)d_in[14];
    float* out = (float*)d_out;

    float* xln   = sym_addr<float>(g_xln);
    float* qkv   = sym_addr<float>(g_qkv);
    float* S     = sym_addr<float>(g_S);
    float* attno = sym_addr<float>(g_attno);
    float* xres  = sym_addr<float>(g_xres);
    float* wm    = sym_addr<float>(g_wm);
    float* wmb   = sym_addr<float>(g_wmb);
    float* metric= sym_addr<float>(g_metric);
    float* nmax  = sym_addr<float>(g_nodemax);
    int*   nidx  = sym_addr<int>(g_nodeidx);
    int*   sidx  = sym_addr<int>(g_srcidx);
    int*   didx  = sym_addr<int>(g_dstidx);
    int*   uidx  = sym_addr<int>(g_unmidx);
    float* xm    = sym_addr<float>(g_xm);
    float* h2    = sym_addr<float>(g_h2);
    float* fc1   = sym_addr<float>(g_fc1);

    // 1. LN1
    ln_kernel<<<MROWS, 256>>>(x, n1g, n1b, xln, Cc);
    // 2. QKV GEMM (tf32 mma.sync)
    tf32_gemm<<<dim3(3072 / 128, MROWS / 128), 256>>>(
        xln, qkv_w, qkv_b, nullptr, qkv, MROWS, 3072, Cc, 0);
    // 3. exact fp32 metric path: mean_h(k) == xln @ mean_h(Wk)^T + mean_h(bk)
    pool_wk<<<256, 256>>>(qkv_w, qkv_b, wm, wmb);
    metric_gemm<<<MROWS / 128, 256>>>(xln, wm, wmb, metric);
    metric_norm<<<Bb * Nn, 64>>>(metric);
    // 4. attention scores + bias
    attn_scores<<<dim3(16, 16, Bb * Hh), 256>>>(qkv, sz, S);
    // 5. softmax (1-pass)
    softmax_rows<<<Bb * Hh * Nn, 256>>>(S);
    // 6. PV
    attn_av<<<dim3(16, Bb * Hh), 256>>>(S, qkv, attno);
    // 7. proj + residual (tf32 mma.sync)
    tf32_gemm<<<dim3(Cc / 128, MROWS / 128), 256>>>(
        attno, proj_w, proj_b, x, xres, MROWS, Cc, Cc, 0);
    // 8. matching
    match_scores<<<dim3(NH, Bb), 256>>>(metric, nmax, nidx);
    match_sort<<<Bb, NH>>>(nmax, nidx, sidx, didx, uidx);
    // 9. merge
    merge_kernel<<<dim3(NM, Bb), 256>>>(xres, sz, sidx, didx, uidx, xm);
    // 10. LN2
    ln_kernel<<<MROWS2, 256>>>(xm, n2g, n2b, h2, Cc);
    // 11. fc1 + exact GELU (tf32 mma.sync)
    tf32_gemm<<<dim3(4096 / 128, MROWS2 / 128), 256>>>(
        h2, fc1_w, fc1_b, nullptr, fc1, MROWS2, 4096, Cc, 1);
    // 12. fc2 + residual -> out (tf32 mma.sync)
    tf32_gemm<<<dim3(Cc / 128, MROWS2 / 128), 256>>>(
        fc1, fc2_w, fc2_b, xm, out, MROWS2, Cc, 4096, 0);
    (void)in_sizes; (void)n_in; (void)out_size;
}

// round 7
// speedup vs baseline: 2.1706x; 1.2114x over previous
#include <cuda_runtime.h>
#include <cuda_bf16.h>
#include <math.h>
#include <cstdint>

// Problem constants
#define Bb 16
#define Nn 1024
#define Cc 1024
#define Hh 16
#define HD 64
#define Rr 128
#define NH (Nn/2)          // 512
#define NU (NH - Rr)       // 384 unmerged
#define NM (NU + NH)       // 896 merged tokens
#define MROWS (Bb*Nn)      // 16384
#define MROWS2 (Bb*NM)     // 14336

// ---------------- scratch (static device globals) ----------------
__device__ float g_xln  [(size_t)MROWS * Cc];
__device__ float g_qkv  [(size_t)MROWS * 3 * Cc];
__device__ float g_S    [(size_t)Bb * Hh * Nn * Nn];   // 1 GiB scores
__device__ float g_attno[(size_t)MROWS * Cc];
__device__ float g_xres [(size_t)MROWS * Cc];
__device__ float g_wm   [64 * 1024];
__device__ float g_wmb  [64];
__device__ float g_metric[(size_t)Bb * Nn * HD];
__device__ float g_nodemax[Bb * NH];
__device__ int   g_nodeidx[Bb * NH];
__device__ int   g_srcidx[Bb * Rr];
__device__ int   g_dstidx[Bb * Rr];
__device__ int   g_unmidx[Bb * NU];
__device__ float g_xm   [(size_t)MROWS2 * Cc];
__device__ float g_h2   [(size_t)MROWS2 * Cc];
__device__ float g_fc1  [(size_t)MROWS2 * 4 * Cc];

__device__ __forceinline__ uint32_t f2tf32(float x) {
    uint32_t r;
    asm("cvt.rna.tf32.f32 %0, %1;" : "=r"(r) : "f"(x));
    return r;
}

__device__ __forceinline__ void mma_tf32(float& d0, float& d1, float& d2, float& d3,
                                         uint32_t a0, uint32_t a1, uint32_t a2, uint32_t a3,
                                         uint32_t b0, uint32_t b1)
{
    asm volatile(
        "mma.sync.aligned.m16n8k8.row.col.f32.tf32.tf32.f32 "
        "{%0,%1,%2,%3}, {%4,%5,%6,%7}, {%8,%9}, {%0,%1,%2,%3};\n"
        : "+f"(d0), "+f"(d1), "+f"(d2), "+f"(d3)
        : "r"(a0), "r"(a1), "r"(a2), "r"(a3), "r"(b0), "r"(b1));
}

// ================= tf32 mma.sync GEMM (verified R6) =================
__global__ void __launch_bounds__(256) tf32_gemm(
    const float* __restrict__ A, const float* __restrict__ W,
    const float* __restrict__ bias, const float* __restrict__ res,
    float* __restrict__ out, int M, int N, int K, int act)
{
    __shared__ uint32_t As[2][128][20];
    __shared__ uint32_t Bs[2][128][20];

    const int tid = threadIdx.x;
    const int wid = tid >> 5;
    const int lane = tid & 31;
    const int g = lane >> 2;
    const int tg = lane & 3;
    const int wm = wid & 3;
    const int wn = wid >> 2;
    const int bm = blockIdx.y * 128;
    const int bn = blockIdx.x * 128;

    const int rowA0 = tid >> 2;
    const int c40 = (tid & 3) << 2;
    const float* Ap0 = A + (size_t)(bm + rowA0) * K + c40;
    const float* Ap1 = Ap0 + (size_t)64 * K;
    const float* Wp0 = W + (size_t)(bn + rowA0) * K + c40;
    const float* Wp1 = Wp0 + (size_t)64 * K;

    float acc[2][8][4];
#pragma unroll
    for (int i = 0; i < 2; i++)
#pragma unroll
        for (int j = 0; j < 8; j++)
#pragma unroll
            for (int v = 0; v < 4; v++) acc[i][j][v] = 0.f;

    {
        float4 a0 = *(const float4*)(Ap0);
        float4 a1 = *(const float4*)(Ap1);
        float4 w0 = *(const float4*)(Wp0);
        float4 w1 = *(const float4*)(Wp1);
        *(uint4*)&As[0][rowA0][c40]      = make_uint4(f2tf32(a0.x), f2tf32(a0.y), f2tf32(a0.z), f2tf32(a0.w));
        *(uint4*)&As[0][rowA0 + 64][c40] = make_uint4(f2tf32(a1.x), f2tf32(a1.y), f2tf32(a1.z), f2tf32(a1.w));
        *(uint4*)&Bs[0][rowA0][c40]      = make_uint4(f2tf32(w0.x), f2tf32(w0.y), f2tf32(w0.z), f2tf32(w0.w));
        *(uint4*)&Bs[0][rowA0 + 64][c40] = make_uint4(f2tf32(w1.x), f2tf32(w1.y), f2tf32(w1.z), f2tf32(w1.w));
    }
    __syncthreads();

    const int NS = K >> 4;
    uint4 sa0, sa1, sw0, sw1;
    for (int s = 0; s < NS; s++) {
        const int buf = s & 1;
        const bool has_next = (s + 1 < NS);
        if (has_next) {
            int k0 = (s + 1) << 4;
            float4 a0 = *(const float4*)(Ap0 + k0);
            float4 a1 = *(const float4*)(Ap1 + k0);
            float4 w0 = *(const float4*)(Wp0 + k0);
            float4 w1 = *(const float4*)(Wp1 + k0);
            sa0 = make_uint4(f2tf32(a0.x), f2tf32(a0.y), f2tf32(a0.z), f2tf32(a0.w));
            sa1 = make_uint4(f2tf32(a1.x), f2tf32(a1.y), f2tf32(a1.z), f2tf32(a1.w));
            sw0 = make_uint4(f2tf32(w0.x), f2tf32(w0.y), f2tf32(w0.z), f2tf32(w0.w));
            sw1 = make_uint4(f2tf32(w1.x), f2tf32(w1.y), f2tf32(w1.z), f2tf32(w1.w));
        }
#pragma unroll
        for (int ks = 0; ks < 16; ks += 8) {
            uint32_t af[2][4];
#pragma unroll
            for (int mt = 0; mt < 2; mt++) {
                int ra = wm * 32 + mt * 16 + g;
                af[mt][0] = As[buf][ra][ks + tg];
                af[mt][1] = As[buf][ra + 8][ks + tg];
                af[mt][2] = As[buf][ra][ks + tg + 4];
                af[mt][3] = As[buf][ra + 8][ks + tg + 4];
            }
            uint32_t bf[8][2];
#pragma unroll
            for (int nt = 0; nt < 8; nt++) {
                int cb = wn * 64 + nt * 8 + g;
                bf[nt][0] = Bs[buf][cb][ks + tg];
                bf[nt][1] = Bs[buf][cb][ks + tg + 4];
            }
#pragma unroll
            for (int mt = 0; mt < 2; mt++)
#pragma unroll
                for (int nt = 0; nt < 8; nt++)
                    mma_tf32(acc[mt][nt][0], acc[mt][nt][1], acc[mt][nt][2], acc[mt][nt][3],
                             af[mt][0], af[mt][1], af[mt][2], af[mt][3],
                             bf[nt][0], bf[nt][1]);
        }
        if (has_next) {
            int nb = (s + 1) & 1;
            __syncthreads();
            *(uint4*)&As[nb][rowA0][c40]      = sa0;
            *(uint4*)&As[nb][rowA0 + 64][c40] = sa1;
            *(uint4*)&Bs[nb][rowA0][c40]      = sw0;
            *(uint4*)&Bs[nb][rowA0 + 64][c40] = sw1;
            __syncthreads();
        }
    }

#pragma unroll
    for (int mt = 0; mt < 2; mt++) {
        int r0 = bm + wm * 32 + mt * 16 + g;
#pragma unroll
        for (int nt = 0; nt < 8; nt++) {
            int col = bn + wn * 64 + nt * 8 + tg * 2;
            float b0 = bias[col], b1 = bias[col + 1];
            float v0 = acc[mt][nt][0] + b0;
            float v1 = acc[mt][nt][1] + b1;
            float v2 = acc[mt][nt][2] + b0;
            float v3 = acc[mt][nt][3] + b1;
            if (act) {
                v0 = 0.5f * v0 * (1.f + erff(v0 * 0.70710678118654752f));
                v1 = 0.5f * v1 * (1.f + erff(v1 * 0.70710678118654752f));
                v2 = 0.5f * v2 * (1.f + erff(v2 * 0.70710678118654752f));
                v3 = 0.5f * v3 * (1.f + erff(v3 * 0.70710678118654752f));
            }
            if (res) {
                const float* rp0 = res + (size_t)r0 * N + col;
                const float* rp1 = rp0 + (size_t)8 * N;
                v0 += rp0[0]; v1 += rp0[1];
                v2 += rp1[0]; v3 += rp1[1];
            }
            *(float2*)(out + (size_t)r0 * N + col) = make_float2(v0, v1);
            *(float2*)(out + (size_t)(r0 + 8) * N + col) = make_float2(v2, v3);
        }
    }
}

// ================= attention scores via mma: S = 0.125*Q@K^T + log(size) =====
// CTA 128(n) x 128(m), K=64 in two 32-wide SMEM stages, stride 36 (banks (4g+tg)%32 bijective).
__global__ void __launch_bounds__(256) attn_scores_mma(
    const float* __restrict__ qkv, const float* __restrict__ sz, float* __restrict__ S)
{
    __shared__ uint32_t Qs[128][36];
    __shared__ uint32_t Ks[128][36];
    const int tid = threadIdx.x;
    const int wid = tid >> 5;
    const int lane = tid & 31;
    const int g = lane >> 2;
    const int tg = lane & 3;
    const int wm = wid & 3;
    const int wn = wid >> 2;
    const int bh = blockIdx.z;
    const int b = bh >> 4, h = bh & 15;
    const int n0 = blockIdx.y * 128, m0 = blockIdx.x * 128;
    const float* qb = qkv + (size_t)b * Nn * 3072 + h * 64;
    const float* kb = qb + 1024;

    float acc[2][8][4];
#pragma unroll
    for (int i = 0; i < 2; i++)
#pragma unroll
        for (int j = 0; j < 8; j++)
#pragma unroll
            for (int v = 0; v < 4; v++) acc[i][j][v] = 0.f;

#pragma unroll
    for (int half = 0; half < 2; half++) {
        const int k0 = half << 5;
        __syncthreads();     // protect previous-stage reads (no-op cost at half=0)
#pragma unroll
        for (int i = 0; i < 4; i++) {
            int idx = tid + i * 256;          // 0..1023
            int row = idx >> 3;
            int c4 = (idx & 7) << 2;
            float4 q = *(const float4*)(qb + (size_t)(n0 + row) * 3072 + k0 + c4);
            *(uint4*)&Qs[row][c4] = make_uint4(f2tf32(q.x), f2tf32(q.y), f2tf32(q.z), f2tf32(q.w));
            float4 k = *(const float4*)(kb + (size_t)(m0 + row) * 3072 + k0 + c4);
            *(uint4*)&Ks[row][c4] = make_uint4(f2tf32(k.x), f2tf32(k.y), f2tf32(k.z), f2tf32(k.w));
        }
        __syncthreads();
#pragma unroll
        for (int ks = 0; ks < 32; ks += 8) {
            uint32_t af[2][4];
#pragma unroll
            for (int mt = 0; mt < 2; mt++) {
                int ra = wm * 32 + mt * 16 + g;
                af[mt][0] = Qs[ra][ks + tg];
                af[mt][1] = Qs[ra + 8][ks + tg];
                af[mt][2] = Qs[ra][ks + tg + 4];
                af[mt][3] = Qs[ra + 8][ks + tg + 4];
            }
            uint32_t bf[8][2];
#pragma unroll
            for (int nt = 0; nt < 8; nt++) {
                int cb = wn * 64 + nt * 8 + g;
                bf[nt][0] = Ks[cb][ks + tg];
                bf[nt][1] = Ks[cb][ks + tg + 4];
            }
#pragma unroll
            for (int mt = 0; mt < 2; mt++)
#pragma unroll
                for (int nt = 0; nt < 8; nt++)
                    mma_tf32(acc[mt][nt][0], acc[mt][nt][1], acc[mt][nt][2], acc[mt][nt][3],
                             af[mt][0], af[mt][1], af[mt][2], af[mt][3],
                             bf[nt][0], bf[nt][1]);
        }
    }

    const float scale = 0.125f;
#pragma unroll
    for (int nt = 0; nt < 8; nt++) {
        int col = m0 + wn * 64 + nt * 8 + tg * 2;
        float ls0 = logf(sz[b * Nn + col]);
        float ls1 = logf(sz[b * Nn + col + 1]);
#pragma unroll
        for (int mt = 0; mt < 2; mt++) {
            int r0 = n0 + wm * 32 + mt * 16 + g;
            float v0 = acc[mt][nt][0] * scale + ls0;
            float v1 = acc[mt][nt][1] * scale + ls1;
            float v2 = acc[mt][nt][2] * scale + ls0;
            float v3 = acc[mt][nt][3] * scale + ls1;
            *(float2*)(S + ((size_t)bh * Nn + r0) * Nn + col) = make_float2(v0, v1);
            *(float2*)(S + ((size_t)bh * Nn + r0 + 8) * Nn + col) = make_float2(v2, v3);
        }
    }
}

// ================= PV via mma: attno[b,n,h*64+d] = sum_m P[n,m] V[m,d] =======
// CTA 128(n) x 64(d), K=1024 staged 16, double-buffered. Warp tile 32x32.
__global__ void __launch_bounds__(256) attn_av_mma(
    const float* __restrict__ S, const float* __restrict__ qkv, float* __restrict__ out)
{
    __shared__ uint32_t Ps[2][128][20];
    __shared__ uint32_t Vs[2][64][20];
    const int tid = threadIdx.x;
    const int wid = tid >> 5;
    const int lane = tid & 31;
    const int g = lane >> 2;
    const int tg = lane & 3;
    const int wm = wid & 3;          // n slot (32 rows)
    const int wn = wid >> 2;         // d slot (32 cols)
    const int bh = blockIdx.y;
    const int b = bh >> 4, h = bh & 15;
    const int n0 = blockIdx.x * 128;
    const float* Sp = S + ((size_t)bh * Nn + n0) * Nn;
    const float* vb = qkv + (size_t)b * Nn * 3072 + 2048 + h * 64;

    // P stage load: idx 0..511 -> row=idx>>2, c4=(idx&3)<<2
    const int prow = tid >> 1;                 // for i-loop formulation below
    // V stage load: m = tid>>4 (0..15), d4 = (tid&15)<<2
    const int vm = tid >> 4;
    const int vd4 = (tid & 15) << 2;

    float acc[2][4][4];
#pragma unroll
    for (int i = 0; i < 2; i++)
#pragma unroll
        for (int j = 0; j < 4; j++)
#pragma unroll
            for (int v = 0; v < 4; v++) acc[i][j][v] = 0.f;

    // prologue: stage 0
    {
#pragma unroll
        for (int i = 0; i < 2; i++) {
            int idx = tid + i * 256;          // 0..511
            int row = idx >> 2;
            int c4 = (idx & 3) << 2;
            float4 p = *(const float4*)(Sp + (size_t)row * Nn + c4);
            *(uint4*)&Ps[0][row][c4] = make_uint4(f2tf32(p.x), f2tf32(p.y), f2tf32(p.z), f2tf32(p.w));
        }
        float4 v = *(const float4*)(vb + (size_t)vm * 3072 + vd4);
        Vs[0][vd4 + 0][vm] = f2tf32(v.x);
        Vs[0][vd4 + 1][vm] = f2tf32(v.y);
        Vs[0][vd4 + 2][vm] = f2tf32(v.z);
        Vs[0][vd4 + 3][vm] = f2tf32(v.w);
    }
    __syncthreads();

    const int NS = Nn >> 4;     // 64 stages
    uint4 sp0, sp1; uint4 svv;
    for (int s = 0; s < NS; s++) {
        const int buf = s & 1;
        const bool has_next = (s + 1 < NS);
        if (has_next) {
            int k0 = (s + 1) << 4;
            {
                int idx = tid;
                int row = idx >> 2, c4 = (idx & 3) << 2;
                float4 p = *(const float4*)(Sp + (size_t)row * Nn + k0 + c4);
                sp0 = make_uint4(f2tf32(p.x), f2tf32(p.y), f2tf32(p.z), f2tf32(p.w));
            }
            {
                int idx = tid + 256;
                int row = idx >> 2, c4 = (idx & 3) << 2;
                float4 p = *(const float4*)(Sp + (size_t)row * Nn + k0 + c4);
                sp1 = make_uint4(f2tf32(p.x), f2tf32(p.y), f2tf32(p.z), f2tf32(p.w));
            }
            {
                float4 v = *(const float4*)(vb + (size_t)(k0 + vm) * 3072 + vd4);
                svv = make_uint4(f2tf32(v.x), f2tf32(v.y), f2tf32(v.z), f2tf32(v.w));
            }
        }
#pragma unroll
        for (int ks = 0; ks < 16; ks += 8) {
            uint32_t af[2][4];
#pragma unroll
            for (int mt = 0; mt < 2; mt++) {
                int ra = wm * 32 + mt * 16 + g;
                af[mt][0] = Ps[buf][ra][ks + tg];
                af[mt][1] = Ps[buf][ra + 8][ks + tg];
                af[mt][2] = Ps[buf][ra][ks + tg + 4];
                af[mt][3] = Ps[buf][ra + 8][ks + tg + 4];
            }
            uint32_t bf[4][2];
#pragma unroll
            for (int nt = 0; nt < 4; nt++) {
                int cb = wn * 32 + nt * 8 + g;
                bf[nt][0] = Vs[buf][cb][ks + tg];
                bf[nt][1] = Vs[buf][cb][ks + tg + 4];
            }
#pragma unroll
            for (int mt = 0; mt < 2; mt++)
#pragma unroll
                for (int nt = 0; nt < 4; nt++)
                    mma_tf32(acc[mt][nt][0], acc[mt][nt][1], acc[mt][nt][2], acc[mt][nt][3],
                             af[mt][0], af[mt][1], af[mt][2], af[mt][3],
                             bf[nt][0], bf[nt][1]);
        }
        if (has_next) {
            int nb = (s + 1) & 1;
            __syncthreads();
            {
                int idx = tid;
                int row = idx >> 2, c4 = (idx & 3) << 2;
                *(uint4*)&Ps[nb][row][c4] = sp0;
            }
            {
                int idx = tid + 256;
                int row = idx >> 2, c4 = (idx & 3) << 2;
                *(uint4*)&Ps[nb][row][c4] = sp1;
            }
            Vs[nb][vd4 + 0][vm] = svv.x;
            Vs[nb][vd4 + 1][vm] = svv.y;
            Vs[nb][vd4 + 2][vm] = svv.z;
            Vs[nb][vd4 + 3][vm] = svv.w;
            __syncthreads();
        }
    }

#pragma unroll
    for (int mt = 0; mt < 2; mt++) {
        int r0 = n0 + wm * 32 + mt * 16 + g;
#pragma unroll
        for (int nt = 0; nt < 4; nt++) {
            int col = h * 64 + wn * 32 + nt * 8 + tg * 2;
            *(float2*)(out + ((size_t)b * Nn + r0) * Cc + col) =
                make_float2(acc[mt][nt][0], acc[mt][nt][1]);
            *(float2*)(out + ((size_t)b * Nn + r0 + 8) * Cc + col) =
                make_float2(acc[mt][nt][2], acc[mt][nt][3]);
        }
    }
    (void)prow;
}

// ---------------- LayerNorm ----------------
__global__ void __launch_bounds__(256) ln_kernel(
    const float* __restrict__ x, const float* __restrict__ g,
    const float* __restrict__ bta, float* __restrict__ out, int C)
{
    size_t row = blockIdx.x;
    const float* p = x + row * C;
    float* o = out + row * C;
    int tid = threadIdx.x;
    float s = 0.f, s2 = 0.f;
    for (int i = tid; i < C; i += 256) { float v = p[i]; s += v; s2 += v * v; }
    __shared__ float rs[256], rq[256];
    rs[tid] = s; rq[tid] = s2; __syncthreads();
    for (int off = 128; off; off >>= 1) {
        if (tid < off) { rs[tid] += rs[tid + off]; rq[tid] += rq[tid + off]; }
        __syncthreads();
    }
    float mean = rs[0] / (float)C;
    float var  = rq[0] / (float)C - mean * mean;
    float inv  = rsqrtf(var + 1e-5f);
    for (int i = tid; i < C; i += 256)
        o[i] = (p[i] - mean) * inv * g[i] + bta[i];
}

// ---------------- 1-pass register softmax ----------------
__global__ void __launch_bounds__(256) softmax_rows(float* __restrict__ S)
{
    size_t row = blockIdx.x;
    float4* p = (float4*)(S + row * Nn);
    int tid = threadIdx.x;
    float4 v = p[tid];
    float m = fmaxf(fmaxf(v.x, v.y), fmaxf(v.z, v.w));
#pragma unroll
    for (int o = 16; o; o >>= 1) m = fmaxf(m, __shfl_xor_sync(~0u, m, o));
    __shared__ float smx[8], ssm[8];
    int w = tid >> 5, l = tid & 31;
    if (l == 0) smx[w] = m;
    __syncthreads();
    float M = smx[0];
#pragma unroll
    for (int i = 1; i < 8; i++) M = fmaxf(M, smx[i]);
    v.x = expf(v.x - M); v.y = expf(v.y - M);
    v.z = expf(v.z - M); v.w = expf(v.w - M);
    float s = v.x + v.y + v.z + v.w;
#pragma unroll
    for (int o = 16; o; o >>= 1) s += __shfl_xor_sync(~0u, s, o);
    if (l == 0) ssm[w] = s;
    __syncthreads();
    float T = ssm[0];
#pragma unroll
    for (int i = 1; i < 8; i++) T += ssm[i];
    float inv = 1.f / T;
    v.x *= inv; v.y *= inv; v.z *= inv; v.w *= inv;
    p[tid] = v;
}

// ---------------- pooled K weight (exact fp32 metric path) ----------------
__global__ void __launch_bounds__(256) pool_wk(
    const float* __restrict__ qkv_w, const float* __restrict__ qkv_b,
    float* __restrict__ wm, float* __restrict__ wmb)
{
    int idx = blockIdx.x * 256 + threadIdx.x;
    if (idx < 64 * 1024) {
        int d = idx >> 10, k = idx & 1023;
        float s = 0.f;
#pragma unroll
        for (int h = 0; h < 16; h++) s += qkv_w[(size_t)(1024 + h * 64 + d) * 1024 + k];
        wm[idx] = s * (1.f / 16.f);
    }
    if (idx < 64) {
        float s = 0.f;
#pragma unroll
        for (int h = 0; h < 16; h++) s += qkv_b[1024 + h * 64 + idx];
        wmb[idx] = s * (1.f / 16.f);
    }
}

// ---------------- fp32 metric GEMM ----------------
__global__ void __launch_bounds__(256) metric_gemm(
    const float* __restrict__ xln, const float* __restrict__ wm,
    const float* __restrict__ wmb, float* __restrict__ metric)
{
    __shared__ float Xs[32][132];
    __shared__ float Ws[32][68];
    const int bm = blockIdx.x * 128;
    const int tid = threadIdx.x;
    const int ty = tid >> 3;
    const int tx = tid & 7;
    float acc[4][8];
#pragma unroll
    for (int i = 0; i < 4; i++)
#pragma unroll
        for (int j = 0; j < 8; j++) acc[i][j] = 0.f;

    for (int k0 = 0; k0 < 1024; k0 += 32) {
#pragma unroll
        for (int i = 0; i < 4; i++) {
            int idx = tid + i * 256;
            int row = idx >> 3;
            int kq = (idx & 7) << 2;
            float4 v = *(const float4*)(xln + (size_t)(bm + row) * 1024 + k0 + kq);
            Xs[kq][row] = v.x; Xs[kq + 1][row] = v.y; Xs[kq + 2][row] = v.z; Xs[kq + 3][row] = v.w;
        }
        for (int idx = tid; idx < 512; idx += 256) {
            int d = idx >> 3;
            int kq = (idx & 7) << 2;
            float4 v = *(const float4*)(wm + (size_t)d * 1024 + k0 + kq);
            Ws[kq][d] = v.x; Ws[kq + 1][d] = v.y; Ws[kq + 2][d] = v.z; Ws[kq + 3][d] = v.w;
        }
        __syncthreads();
#pragma unroll
        for (int kk = 0; kk < 32; kk++) {
            float a[4], w[8];
#pragma unroll
            for (int i = 0; i < 4; i++) a[i] = Xs[kk][ty * 4 + i];
#pragma unroll
            for (int j = 0; j < 8; j++) w[j] = Ws[kk][tx * 8 + j];
#pragma unroll
            for (int i = 0; i < 4; i++)
#pragma unroll
                for (int j = 0; j < 8; j++) acc[i][j] += a[i] * w[j];
        }
        __syncthreads();
    }
#pragma unroll
    for (int i = 0; i < 4; i++) {
        int row = bm + ty * 4 + i;
#pragma unroll
        for (int j = 0; j < 8; j++)
            metric[(size_t)row * 64 + tx * 8 + j] = acc[i][j] + wmb[tx * 8 + j];
    }
}

__global__ void __launch_bounds__(64) metric_norm(float* __restrict__ metric)
{
    int bn = blockIdx.x;
    int d = threadIdx.x;
    float v = metric[(size_t)bn * 64 + d];
    __shared__ float sh[64];
    sh[d] = v * v; __syncthreads();
    for (int off = 32; off; off >>= 1) {
        if (d < off) sh[d] += sh[d + off];
        __syncthreads();
    }
    float inv = rsqrtf(sh[0]);
    metric[(size_t)bn * 64 + d] = v * inv;
}

// ---------------- matching ----------------
__global__ void __launch_bounds__(256) match_scores(
    const float* __restrict__ metric, float* __restrict__ nodemax, int* __restrict__ nodeidx)
{
    int t = blockIdx.x;
    int b = blockIdx.y;
    const float* mb = metric + (size_t)b * Nn * 64;
    __shared__ float av[64];
    int tid = threadIdx.x;
    if (tid < 64) av[tid] = mb[(size_t)(2 * t) * 64 + tid];
    __syncthreads();
    float best = -INFINITY; int bi = 0;
    for (int s = tid; s < NH; s += 256) {
        const float* bp = mb + (size_t)(2 * s + 1) * 64;
        float dot = 0.f;
#pragma unroll
        for (int d = 0; d < 64; d++) dot += av[d] * bp[d];
        if (dot > best) { best = dot; bi = s; }
    }
    __shared__ float sv[256]; __shared__ int si[256];
    sv[tid] = best; si[tid] = bi; __syncthreads();
    for (int off = 128; off; off >>= 1) {
        if (tid < off) {
            if (sv[tid + off] > sv[tid] ||
                (sv[tid + off] == sv[tid] && si[tid + off] < si[tid])) {
                sv[tid] = sv[tid + off]; si[tid] = si[tid + off];
            }
        }
        __syncthreads();
    }
    if (tid == 0) {
        if (t == 0) { nodemax[b * NH] = -INFINITY; nodeidx[b * NH] = 0; }
        else { nodemax[b * NH + t] = sv[0]; nodeidx[b * NH + t] = si[0]; }
    }
}

__global__ void __launch_bounds__(512) match_sort(
    const float* __restrict__ nodemax, const int* __restrict__ nodeidx,
    int* __restrict__ srcidx, int* __restrict__ dstidx, int* __restrict__ unmidx)
{
    int b = blockIdx.x, t = threadIdx.x;
    __shared__ float v[NH]; __shared__ int rk[NH];
    v[t] = nodemax[b * NH + t]; __syncthreads();
    float vt = v[t]; int r = 0;
    for (int j = 0; j < NH; j++) {
        float vj = v[j];
        r += (vj > vt) || (vj == vt && j < t);
    }
    rk[t] = r; __syncthreads();
    if (r < Rr) {
        srcidx[b * Rr + r] = t;
        dstidx[b * Rr + r] = nodeidx[b * NH + t];
    } else {
        int pos = 0;
        for (int j = 0; j < t; j++) pos += (rk[j] >= Rr);
        unmidx[b * NU + pos] = t;
    }
}

// ---------------- weighted merge + divide by new size ----------------
__global__ void __launch_bounds__(256) merge_kernel(
    const float* __restrict__ xres, const float* __restrict__ sz,
    const int* __restrict__ srcidx, const int* __restrict__ dstidx,
    const int* __restrict__ unmidx, float* __restrict__ xm)
{
    int row = blockIdx.x;
    int b = blockIdx.y;
    int tid = threadIdx.x;
    const float* xb = xres + (size_t)b * Nn * Cc;
    const float* szb = sz + b * Nn;
    float* ob = xm + ((size_t)b * NM + row) * Cc;
    __shared__ int ss[Rr], sd[Rr];

    if (row < NU) {
        int t = 2 * unmidx[b * NU + row];
        float s = szb[t];
        float inv = 1.f / s;
        for (int c = tid; c < Cc; c += 256)
            ob[c] = (xb[(size_t)t * Cc + c] * s) * inv;
    } else {
        int j = row - NU;
        if (tid < Rr) { ss[tid] = srcidx[b * Rr + tid]; sd[tid] = dstidx[b * Rr + tid]; }
        __syncthreads();
        int t = 2 * j + 1;
        float ns = szb[t];
        for (int i = 0; i < Rr; i++)
            if (sd[i] == j) ns += szb[2 * ss[i]];
        float inv = 1.f / ns;
        for (int c = tid; c < Cc; c += 256) {
            float val = xb[(size_t)t * Cc + c] * szb[t];
            for (int i = 0; i < Rr; i++) {
                if (sd[i] == j) {
                    int ts = 2 * ss[i];
                    val += xb[(size_t)ts * Cc + c] * szb[ts];
                }
            }
            ob[c] = val * inv;
        }
    }
}

// ---------------- launch ----------------
template <typename T>
static T* sym_addr(const void* sym) {
    void* p = nullptr;
    cudaGetSymbolAddress(&p, sym);
    return (T*)p;
}

extern "C" void kernel_launch(void* const* d_in, const int* in_sizes, int n_in,
                              void* d_out, int out_size)
{
    const float* x      = (const float*)d_in[0];
    const float* sz     = (const float*)d_in[1];
    const float* qkv_w  = (const float*)d_in[3];
    const float* qkv_b  = (const float*)d_in[4];
    const float* proj_w = (const float*)d_in[5];
    const float* proj_b = (const float*)d_in[6];
    const float* n1g    = (const float*)d_in[7];
    const float* n1b    = (const float*)d_in[8];
    const float* n2g    = (const float*)d_in[9];
    const float* n2b    = (const float*)d_in[10];
    const float* fc1_w  = (const float*)d_in[11];
    const float* fc1_b  = (const float*)d_in[12];
    const float* fc2_w  = (const float*)d_in[13];
    const float* fc2_b  = (const float*)d_in[14];
    float* out = (float*)d_out;

    float* xln   = sym_addr<float>(g_xln);
    float* qkv   = sym_addr<float>(g_qkv);
    float* S     = sym_addr<float>(g_S);
    float* attno = sym_addr<float>(g_attno);
    float* xres  = sym_addr<float>(g_xres);
    float* wm    = sym_addr<float>(g_wm);
    float* wmb   = sym_addr<float>(g_wmb);
    float* metric= sym_addr<float>(g_metric);
    float* nmax  = sym_addr<float>(g_nodemax);
    int*   nidx  = sym_addr<int>(g_nodeidx);
    int*   sidx  = sym_addr<int>(g_srcidx);
    int*   didx  = sym_addr<int>(g_dstidx);
    int*   uidx  = sym_addr<int>(g_unmidx);
    float* xm    = sym_addr<float>(g_xm);
    float* h2    = sym_addr<float>(g_h2);
    float* fc1   = sym_addr<float>(g_fc1);

    // 1. LN1
    ln_kernel<<<MROWS, 256>>>(x, n1g, n1b, xln, Cc);
    // 2. QKV GEMM (tf32 mma.sync)
    tf32_gemm<<<dim3(3072 / 128, MROWS / 128), 256>>>(
        xln, qkv_w, qkv_b, nullptr, qkv, MROWS, 3072, Cc, 0);
    // 3. exact fp32 metric path
    pool_wk<<<256, 256>>>(qkv_w, qkv_b, wm, wmb);
    metric_gemm<<<MROWS / 128, 256>>>(xln, wm, wmb, metric);
    metric_norm<<<Bb * Nn, 64>>>(metric);
    // 4. attention scores + bias (tf32 mma)
    attn_scores_mma<<<dim3(8, 8, Bb * Hh), 256>>>(qkv, sz, S);
    // 5. softmax (1-pass)
    softmax_rows<<<Bb * Hh * Nn, 256>>>(S);
    // 6. PV (tf32 mma)
    attn_av_mma<<<dim3(8, Bb * Hh), 256>>>(S, qkv, attno);
    // 7. proj + residual (tf32 mma.sync)
    tf32_gemm<<<dim3(Cc / 128, MROWS / 128), 256>>>(
        attno, proj_w, proj_b, x, xres, MROWS, Cc, Cc, 0);
    // 8. matching
    match_scores<<<dim3(NH, Bb), 256>>>(metric, nmax, nidx);
    match_sort<<<Bb, NH>>>(nmax, nidx, sidx, didx, uidx);
    // 9. merge
    merge_kernel<<<dim3(NM, Bb), 256>>>(xres, sz, sidx, didx, uidx, xm);
    // 10. LN2
    ln_kernel<<<MROWS2, 256>>>(xm, n2g, n2b, h2, Cc);
    // 11. fc1 + exact GELU (tf32 mma.sync)
    tf32_gemm<<<dim3(4096 / 128, MROWS2 / 128), 256>>>(
        h2, fc1_w, fc1_b, nullptr, fc1, MROWS2, 4096, Cc, 1);
    // 12. fc2 + residual -> out (tf32 mma.sync)
    tf32_gemm<<<dim3(Cc / 128, MROWS2 / 128), 256>>>(
        fc1, fc2_w, fc2_b, xm, out, MROWS2, Cc, 4096, 0);
    (void)in_sizes; (void)n_in; (void)out_size;
}

// round 8
// speedup vs baseline: 2.3783x; 1.0957x over previous
#include <cuda_runtime.h>
#include <cuda_bf16.h>
#include <math.h>
#include <cstdint>

// Problem constants
#define Bb 16
#define Nn 1024
#define Cc 1024
#define Hh 16
#define HD 64
#define Rr 128
#define NH (Nn/2)          // 512
#define NU (NH - Rr)       // 384 unmerged
#define NM (NU + NH)       // 896 merged tokens
#define MROWS (Bb*Nn)      // 16384
#define MROWS2 (Bb*NM)     // 14336

// ---------------- scratch (static device globals) ----------------
__device__ float g_xln  [(size_t)MROWS * Cc];
__device__ float g_qkv  [(size_t)MROWS * 3 * Cc];
__device__ float g_attno[(size_t)MROWS * Cc];
__device__ float g_xres [(size_t)MROWS * Cc];
__device__ float g_wm   [64 * 1024];
__device__ float g_wmb  [64];
__device__ float g_metric[(size_t)Bb * Nn * HD];
__device__ float g_nodemax[Bb * NH];
__device__ int   g_nodeidx[Bb * NH];
__device__ int   g_srcidx[Bb * Rr];
__device__ int   g_dstidx[Bb * Rr];
__device__ int   g_unmidx[Bb * NU];
__device__ float g_xm   [(size_t)MROWS2 * Cc];
__device__ float g_h2   [(size_t)MROWS2 * Cc];
__device__ float g_fc1  [(size_t)MROWS2 * 4 * Cc];

__device__ __forceinline__ uint32_t f2tf32(float x) {
    uint32_t r;
    asm("cvt.rna.tf32.f32 %0, %1;" : "=r"(r) : "f"(x));
    return r;
}

__device__ __forceinline__ void mma_tf32(float& d0, float& d1, float& d2, float& d3,
                                         uint32_t a0, uint32_t a1, uint32_t a2, uint32_t a3,
                                         uint32_t b0, uint32_t b1)
{
    asm volatile(
        "mma.sync.aligned.m16n8k8.row.col.f32.tf32.tf32.f32 "
        "{%0,%1,%2,%3}, {%4,%5,%6,%7}, {%8,%9}, {%0,%1,%2,%3};\n"
        : "+f"(d0), "+f"(d1), "+f"(d2), "+f"(d3)
        : "r"(a0), "r"(a1), "r"(a2), "r"(a3), "r"(b0), "r"(b1));
}

// ================= tf32 mma.sync GEMM (verified R6) =================
__global__ void __launch_bounds__(256) tf32_gemm(
    const float* __restrict__ A, const float* __restrict__ W,
    const float* __restrict__ bias, const float* __restrict__ res,
    float* __restrict__ out, int M, int N, int K, int act)
{
    __shared__ uint32_t As[2][128][20];
    __shared__ uint32_t Bs[2][128][20];

    const int tid = threadIdx.x;
    const int wid = tid >> 5;
    const int lane = tid & 31;
    const int g = lane >> 2;
    const int tg = lane & 3;
    const int wm = wid & 3;
    const int wn = wid >> 2;
    const int bm = blockIdx.y * 128;
    const int bn = blockIdx.x * 128;

    const int rowA0 = tid >> 2;
    const int c40 = (tid & 3) << 2;
    const float* Ap0 = A + (size_t)(bm + rowA0) * K + c40;
    const float* Ap1 = Ap0 + (size_t)64 * K;
    const float* Wp0 = W + (size_t)(bn + rowA0) * K + c40;
    const float* Wp1 = Wp0 + (size_t)64 * K;

    float acc[2][8][4];
#pragma unroll
    for (int i = 0; i < 2; i++)
#pragma unroll
        for (int j = 0; j < 8; j++)
#pragma unroll
            for (int v = 0; v < 4; v++) acc[i][j][v] = 0.f;

    {
        float4 a0 = *(const float4*)(Ap0);
        float4 a1 = *(const float4*)(Ap1);
        float4 w0 = *(const float4*)(Wp0);
        float4 w1 = *(const float4*)(Wp1);
        *(uint4*)&As[0][rowA0][c40]      = make_uint4(f2tf32(a0.x), f2tf32(a0.y), f2tf32(a0.z), f2tf32(a0.w));
        *(uint4*)&As[0][rowA0 + 64][c40] = make_uint4(f2tf32(a1.x), f2tf32(a1.y), f2tf32(a1.z), f2tf32(a1.w));
        *(uint4*)&Bs[0][rowA0][c40]      = make_uint4(f2tf32(w0.x), f2tf32(w0.y), f2tf32(w0.z), f2tf32(w0.w));
        *(uint4*)&Bs[0][rowA0 + 64][c40] = make_uint4(f2tf32(w1.x), f2tf32(w1.y), f2tf32(w1.z), f2tf32(w1.w));
    }
    __syncthreads();

    const int NS = K >> 4;
    uint4 sa0, sa1, sw0, sw1;
    for (int s = 0; s < NS; s++) {
        const int buf = s & 1;
        const bool has_next = (s + 1 < NS);
        if (has_next) {
            int k0 = (s + 1) << 4;
            float4 a0 = *(const float4*)(Ap0 + k0);
            float4 a1 = *(const float4*)(Ap1 + k0);
            float4 w0 = *(const float4*)(Wp0 + k0);
            float4 w1 = *(const float4*)(Wp1 + k0);
            sa0 = make_uint4(f2tf32(a0.x), f2tf32(a0.y), f2tf32(a0.z), f2tf32(a0.w));
            sa1 = make_uint4(f2tf32(a1.x), f2tf32(a1.y), f2tf32(a1.z), f2tf32(a1.w));
            sw0 = make_uint4(f2tf32(w0.x), f2tf32(w0.y), f2tf32(w0.z), f2tf32(w0.w));
            sw1 = make_uint4(f2tf32(w1.x), f2tf32(w1.y), f2tf32(w1.z), f2tf32(w1.w));
        }
#pragma unroll
        for (int ks = 0; ks < 16; ks += 8) {
            uint32_t af[2][4];
#pragma unroll
            for (int mt = 0; mt < 2; mt++) {
                int ra = wm * 32 + mt * 16 + g;
                af[mt][0] = As[buf][ra][ks + tg];
                af[mt][1] = As[buf][ra + 8][ks + tg];
                af[mt][2] = As[buf][ra][ks + tg + 4];
                af[mt][3] = As[buf][ra + 8][ks + tg + 4];
            }
            uint32_t bf[8][2];
#pragma unroll
            for (int nt = 0; nt < 8; nt++) {
                int cb = wn * 64 + nt * 8 + g;
                bf[nt][0] = Bs[buf][cb][ks + tg];
                bf[nt][1] = Bs[buf][cb][ks + tg + 4];
            }
#pragma unroll
            for (int mt = 0; mt < 2; mt++)
#pragma unroll
                for (int nt = 0; nt < 8; nt++)
                    mma_tf32(acc[mt][nt][0], acc[mt][nt][1], acc[mt][nt][2], acc[mt][nt][3],
                             af[mt][0], af[mt][1], af[mt][2], af[mt][3],
                             bf[nt][0], bf[nt][1]);
        }
        if (has_next) {
            int nb = (s + 1) & 1;
            __syncthreads();
            *(uint4*)&As[nb][rowA0][c40]      = sa0;
            *(uint4*)&As[nb][rowA0 + 64][c40] = sa1;
            *(uint4*)&Bs[nb][rowA0][c40]      = sw0;
            *(uint4*)&Bs[nb][rowA0 + 64][c40] = sw1;
            __syncthreads();
        }
    }

#pragma unroll
    for (int mt = 0; mt < 2; mt++) {
        int r0 = bm + wm * 32 + mt * 16 + g;
#pragma unroll
        for (int nt = 0; nt < 8; nt++) {
            int col = bn + wn * 64 + nt * 8 + tg * 2;
            float b0 = bias[col], b1 = bias[col + 1];
            float v0 = acc[mt][nt][0] + b0;
            float v1 = acc[mt][nt][1] + b1;
            float v2 = acc[mt][nt][2] + b0;
            float v3 = acc[mt][nt][3] + b1;
            if (act) {
                v0 = 0.5f * v0 * (1.f + erff(v0 * 0.70710678118654752f));
                v1 = 0.5f * v1 * (1.f + erff(v1 * 0.70710678118654752f));
                v2 = 0.5f * v2 * (1.f + erff(v2 * 0.70710678118654752f));
                v3 = 0.5f * v3 * (1.f + erff(v3 * 0.70710678118654752f));
            }
            if (res) {
                const float* rp0 = res + (size_t)r0 * N + col;
                const float* rp1 = rp0 + (size_t)8 * N;
                v0 += rp0[0]; v1 += rp0[1];
                v2 += rp1[0]; v3 += rp1[1];
            }
            *(float2*)(out + (size_t)r0 * N + col) = make_float2(v0, v1);
            *(float2*)(out + (size_t)(r0 + 8) * N + col) = make_float2(v2, v3);
        }
    }
}

// ================= fused flash attention =================
// One CTA = (b,h, 128 q-rows). Online softmax; S never leaves the SM.
// SMEM strides chosen bank-bijective for fragment loads:
//   Qs 68 (4g+tg), KP 132 (4g+tg), Vs 140 (12g+tg).
#define QS_STRIDE 68
#define KP_STRIDE 132
#define VS_STRIDE 140
#define FLASH_SMEM ((128*QS_STRIDE + 128*KP_STRIDE + 64*VS_STRIDE + 1024 + 256 + 256) * 4)

__global__ void __launch_bounds__(256) flash_attn(
    const float* __restrict__ qkv, const float* __restrict__ sz, float* __restrict__ out)
{
    extern __shared__ uint32_t smw[];
    uint32_t* Qs = smw;                          // [128][68]
    uint32_t* KP = Qs + 128 * QS_STRIDE;         // [128][132]  K tile, then P tile
    uint32_t* Vs = KP + 128 * KP_STRIDE;         // [64][140]   V^T tile
    float* logls = (float*)(Vs + 64 * VS_STRIDE);// [1024]
    float* redm  = logls + 1024;                 // [2][128]
    float* reds  = redm + 256;                   // [2][128]

    const int tid = threadIdx.x;
    const int wid = tid >> 5, lane = tid & 31;
    const int g = lane >> 2, tg = lane & 3;
    const int wm = wid & 3, wn = wid >> 5 ? 0 : (wid >> 2); // wid>>2 is 0..1
    const int wnn = wid >> 2;
    const int bh = blockIdx.y;
    const int b = bh >> 4, h = bh & 15;
    const int n0 = blockIdx.x * 128;
    const float* qb = qkv + (size_t)b * Nn * 3072 + h * 64;
    const float* kb = qb + 1024;
    const float* vb = qb + 2048;

    // precompute log(size)
    for (int i = tid; i < 1024; i += 256)
        logls[i] = __logf(sz[b * Nn + i]);

    // load Q tile (128 x 64)
#pragma unroll
    for (int i = 0; i < 8; i++) {
        int idx = tid + i * 256;            // 0..2047 float4 ids
        int row = idx >> 4;
        int c4 = (idx & 15) << 2;
        float4 q = *(const float4*)(qb + (size_t)(n0 + row) * 3072 + c4);
        *(uint4*)&Qs[row * QS_STRIDE + c4] =
            make_uint4(f2tf32(q.x), f2tf32(q.y), f2tf32(q.z), f2tf32(q.w));
    }

    float m_i[2][2], l_i[2][2];
    float acc[2][4][4];
#pragma unroll
    for (int mt = 0; mt < 2; mt++)
#pragma unroll
        for (int rh = 0; rh < 2; rh++) { m_i[mt][rh] = -INFINITY; l_i[mt][rh] = 0.f; }
#pragma unroll
    for (int mt = 0; mt < 2; mt++)
#pragma unroll
        for (int nt = 0; nt < 4; nt++)
#pragma unroll
            for (int v = 0; v < 4; v++) acc[mt][nt][v] = 0.f;

    for (int m0 = 0; m0 < Nn; m0 += 128) {
        __syncthreads();     // previous PV reads of KP/Vs complete
        // load K tile -> KP, V tile transposed -> Vs
#pragma unroll
        for (int i = 0; i < 8; i++) {
            int idx = tid + i * 256;
            int row = idx >> 4;
            int c4 = (idx & 15) << 2;
            float4 k = *(const float4*)(kb + (size_t)(m0 + row) * 3072 + c4);
            *(uint4*)&KP[row * KP_STRIDE + c4] =
                make_uint4(f2tf32(k.x), f2tf32(k.y), f2tf32(k.z), f2tf32(k.w));
            float4 v = *(const float4*)(vb + (size_t)(m0 + row) * 3072 + c4);
            Vs[(c4 + 0) * VS_STRIDE + row] = f2tf32(v.x);
            Vs[(c4 + 1) * VS_STRIDE + row] = f2tf32(v.y);
            Vs[(c4 + 2) * VS_STRIDE + row] = f2tf32(v.z);
            Vs[(c4 + 3) * VS_STRIDE + row] = f2tf32(v.w);
        }
        __syncthreads();

        // S tile = Q @ K^T  (128 x 128), warp covers rows wm*32.., cols wnn*64..
        float s[2][8][4];
#pragma unroll
        for (int mt = 0; mt < 2; mt++)
#pragma unroll
            for (int nt = 0; nt < 8; nt++)
#pragma unroll
                for (int v = 0; v < 4; v++) s[mt][nt][v] = 0.f;
#pragma unroll
        for (int ks = 0; ks < 64; ks += 8) {
            uint32_t af[2][4];
#pragma unroll
            for (int mt = 0; mt < 2; mt++) {
                int ra = wm * 32 + mt * 16 + g;
                af[mt][0] = Qs[ra * QS_STRIDE + ks + tg];
                af[mt][1] = Qs[(ra + 8) * QS_STRIDE + ks + tg];
                af[mt][2] = Qs[ra * QS_STRIDE + ks + tg + 4];
                af[mt][3] = Qs[(ra + 8) * QS_STRIDE + ks + tg + 4];
            }
            uint32_t bf[8][2];
#pragma unroll
            for (int nt = 0; nt < 8; nt++) {
                int cb = wnn * 64 + nt * 8 + g;
                bf[nt][0] = KP[cb * KP_STRIDE + ks + tg];
                bf[nt][1] = KP[cb * KP_STRIDE + ks + tg + 4];
            }
#pragma unroll
            for (int mt = 0; mt < 2; mt++)
#pragma unroll
                for (int nt = 0; nt < 8; nt++)
                    mma_tf32(s[mt][nt][0], s[mt][nt][1], s[mt][nt][2], s[mt][nt][3],
                             af[mt][0], af[mt][1], af[mt][2], af[mt][3],
                             bf[nt][0], bf[nt][1]);
        }

        // scale + log(size) bias; per-thread row maxima
        float tmax[2][2];
#pragma unroll
        for (int mt = 0; mt < 2; mt++) { tmax[mt][0] = -INFINITY; tmax[mt][1] = -INFINITY; }
#pragma unroll
        for (int mt = 0; mt < 2; mt++)
#pragma unroll
            for (int nt = 0; nt < 8; nt++) {
                int col = wnn * 64 + nt * 8 + tg * 2;
                float ls0 = logls[m0 + col];
                float ls1 = logls[m0 + col + 1];
                s[mt][nt][0] = s[mt][nt][0] * 0.125f + ls0;
                s[mt][nt][1] = s[mt][nt][1] * 0.125f + ls1;
                s[mt][nt][2] = s[mt][nt][2] * 0.125f + ls0;
                s[mt][nt][3] = s[mt][nt][3] * 0.125f + ls1;
                tmax[mt][0] = fmaxf(tmax[mt][0], fmaxf(s[mt][nt][0], s[mt][nt][1]));
                tmax[mt][1] = fmaxf(tmax[mt][1], fmaxf(s[mt][nt][2], s[mt][nt][3]));
            }
        // reduce max over quad (tg)
#pragma unroll
        for (int mt = 0; mt < 2; mt++)
#pragma unroll
            for (int rh = 0; rh < 2; rh++) {
                float v = tmax[mt][rh];
                v = fmaxf(v, __shfl_xor_sync(~0u, v, 1));
                v = fmaxf(v, __shfl_xor_sync(~0u, v, 2));
                tmax[mt][rh] = v;
            }
        if (tg == 0) {
#pragma unroll
            for (int mt = 0; mt < 2; mt++)
#pragma unroll
                for (int rh = 0; rh < 2; rh++)
                    redm[wnn * 128 + wm * 32 + mt * 16 + rh * 8 + g] = tmax[mt][rh];
        }
        __syncthreads();    // redm ready; also all S-mma reads of KP done

        // combine cross-warp max, online update of m / rescale
        float sc[2][2];
#pragma unroll
        for (int mt = 0; mt < 2; mt++)
#pragma unroll
            for (int rh = 0; rh < 2; rh++) {
                int row = wm * 32 + mt * 16 + rh * 8 + g;
                float mx = fmaxf(redm[row], redm[128 + row]);
                float mnew = fmaxf(m_i[mt][rh], mx);
                sc[mt][rh] = __expf(m_i[mt][rh] - mnew);
                m_i[mt][rh] = mnew;
                l_i[mt][rh] *= sc[mt][rh];
            }
#pragma unroll
        for (int mt = 0; mt < 2; mt++)
#pragma unroll
            for (int nt = 0; nt < 4; nt++) {
                acc[mt][nt][0] *= sc[mt][0];
                acc[mt][nt][1] *= sc[mt][0];
                acc[mt][nt][2] *= sc[mt][1];
                acc[mt][nt][3] *= sc[mt][1];
            }

        // exponentiate, accumulate partial row sums, write P tile into KP
        float tsum[2][2];
#pragma unroll
        for (int mt = 0; mt < 2; mt++) { tsum[mt][0] = 0.f; tsum[mt][1] = 0.f; }
#pragma unroll
        for (int mt = 0; mt < 2; mt++) {
            int r0 = wm * 32 + mt * 16 + g;
#pragma unroll
            for (int nt = 0; nt < 8; nt++) {
                int col = wnn * 64 + nt * 8 + tg * 2;
                float p0 = __expf(s[mt][nt][0] - m_i[mt][0]);
                float p1 = __expf(s[mt][nt][1] - m_i[mt][0]);
                float p2 = __expf(s[mt][nt][2] - m_i[mt][1]);
                float p3 = __expf(s[mt][nt][3] - m_i[mt][1]);
                tsum[mt][0] += p0 + p1;
                tsum[mt][1] += p2 + p3;
                KP[r0 * KP_STRIDE + col] = f2tf32(p0);
                KP[r0 * KP_STRIDE + col + 1] = f2tf32(p1);
                KP[(r0 + 8) * KP_STRIDE + col] = f2tf32(p2);
                KP[(r0 + 8) * KP_STRIDE + col + 1] = f2tf32(p3);
            }
        }
        // reduce sums over quad, publish cross-warp
#pragma unroll
        for (int mt = 0; mt < 2; mt++)
#pragma unroll
            for (int rh = 0; rh < 2; rh++) {
                float v = tsum[mt][rh];
                v += __shfl_xor_sync(~0u, v, 1);
                v += __shfl_xor_sync(~0u, v, 2);
                tsum[mt][rh] = v;
            }
        if (tg == 0) {
#pragma unroll
            for (int mt = 0; mt < 2; mt++)
#pragma unroll
                for (int rh = 0; rh < 2; rh++)
                    reds[wnn * 128 + wm * 32 + mt * 16 + rh * 8 + g] = tsum[mt][rh];
        }
        __syncthreads();    // P tile + reds visible
#pragma unroll
        for (int mt = 0; mt < 2; mt++)
#pragma unroll
            for (int rh = 0; rh < 2; rh++) {
                int row = wm * 32 + mt * 16 + rh * 8 + g;
                l_i[mt][rh] += reds[row] + reds[128 + row];
            }

        // PV: acc += P (128x128) @ V (128x64); warp covers d-cols wnn*32..+32
#pragma unroll
        for (int ks = 0; ks < 128; ks += 8) {
            uint32_t af[2][4];
#pragma unroll
            for (int mt = 0; mt < 2; mt++) {
                int ra = wm * 32 + mt * 16 + g;
                af[mt][0] = KP[ra * KP_STRIDE + ks + tg];
                af[mt][1] = KP[(ra + 8) * KP_STRIDE + ks + tg];
                af[mt][2] = KP[ra * KP_STRIDE + ks + tg + 4];
                af[mt][3] = KP[(ra + 8) * KP_STRIDE + ks + tg + 4];
            }
            uint32_t bf[4][2];
#pragma unroll
            for (int nt = 0; nt < 4; nt++) {
                int cb = wnn * 32 + nt * 8 + g;
                bf[nt][0] = Vs[cb * VS_STRIDE + ks + tg];
                bf[nt][1] = Vs[cb * VS_STRIDE + ks + tg + 4];
            }
#pragma unroll
            for (int mt = 0; mt < 2; mt++)
#pragma unroll
                for (int nt = 0; nt < 4; nt++)
                    mma_tf32(acc[mt][nt][0], acc[mt][nt][1], acc[mt][nt][2], acc[mt][nt][3],
                             af[mt][0], af[mt][1], af[mt][2], af[mt][3],
                             bf[nt][0], bf[nt][1]);
        }
    }

    // normalize and write out[b, n, h*64+d]
#pragma unroll
    for (int mt = 0; mt < 2; mt++) {
        float inv0 = 1.f / l_i[mt][0];
        float inv1 = 1.f / l_i[mt][1];
        int r0 = n0 + wm * 32 + mt * 16 + g;
#pragma unroll
        for (int nt = 0; nt < 4; nt++) {
            int col = h * 64 + wnn * 32 + nt * 8 + tg * 2;
            *(float2*)(out + ((size_t)b * Nn + r0) * Cc + col) =
                make_float2(acc[mt][nt][0] * inv0, acc[mt][nt][1] * inv0);
            *(float2*)(out + ((size_t)b * Nn + r0 + 8) * Cc + col) =
                make_float2(acc[mt][nt][2] * inv1, acc[mt][nt][3] * inv1);
        }
    }
    (void)wn;
}

// ---------------- LayerNorm ----------------
__global__ void __launch_bounds__(256) ln_kernel(
    const float* __restrict__ x, const float* __restrict__ g,
    const float* __restrict__ bta, float* __restrict__ out, int C)
{
    size_t row = blockIdx.x;
    const float* p = x + row * C;
    float* o = out + row * C;
    int tid = threadIdx.x;
    float s = 0.f, s2 = 0.f;
    for (int i = tid; i < C; i += 256) { float v = p[i]; s += v; s2 += v * v; }
    __shared__ float rs[256], rq[256];
    rs[tid] = s; rq[tid] = s2; __syncthreads();
    for (int off = 128; off; off >>= 1) {
        if (tid < off) { rs[tid] += rs[tid + off]; rq[tid] += rq[tid + off]; }
        __syncthreads();
    }
    float mean = rs[0] / (float)C;
    float var  = rq[0] / (float)C - mean * mean;
    float inv  = rsqrtf(var + 1e-5f);
    for (int i = tid; i < C; i += 256)
        o[i] = (p[i] - mean) * inv * g[i] + bta[i];
}

// ---------------- pooled K weight (exact fp32 metric path) ----------------
__global__ void __launch_bounds__(256) pool_wk(
    const float* __restrict__ qkv_w, const float* __restrict__ qkv_b,
    float* __restrict__ wm, float* __restrict__ wmb)
{
    int idx = blockIdx.x * 256 + threadIdx.x;
    if (idx < 64 * 1024) {
        int d = idx >> 10, k = idx & 1023;
        float s = 0.f;
#pragma unroll
        for (int h = 0; h < 16; h++) s += qkv_w[(size_t)(1024 + h * 64 + d) * 1024 + k];
        wm[idx] = s * (1.f / 16.f);
    }
    if (idx < 64) {
        float s = 0.f;
#pragma unroll
        for (int h = 0; h < 16; h++) s += qkv_b[1024 + h * 64 + idx];
        wmb[idx] = s * (1.f / 16.f);
    }
}

// ---------------- fp32 metric GEMM ----------------
__global__ void __launch_bounds__(256) metric_gemm(
    const float* __restrict__ xln, const float* __restrict__ wm,
    const float* __restrict__ wmb, float* __restrict__ metric)
{
    __shared__ float Xs[32][132];
    __shared__ float Ws[32][68];
    const int bm = blockIdx.x * 128;
    const int tid = threadIdx.x;
    const int ty = tid >> 3;
    const int tx = tid & 7;
    float acc[4][8];
#pragma unroll
    for (int i = 0; i < 4; i++)
#pragma unroll
        for (int j = 0; j < 8; j++) acc[i][j] = 0.f;

    for (int k0 = 0; k0 < 1024; k0 += 32) {
#pragma unroll
        for (int i = 0; i < 4; i++) {
            int idx = tid + i * 256;
            int row = idx >> 3;
            int kq = (idx & 7) << 2;
            float4 v = *(const float4*)(xln + (size_t)(bm + row) * 1024 + k0 + kq);
            Xs[kq][row] = v.x; Xs[kq + 1][row] = v.y; Xs[kq + 2][row] = v.z; Xs[kq + 3][row] = v.w;
        }
        for (int idx = tid; idx < 512; idx += 256) {
            int d = idx >> 3;
            int kq = (idx & 7) << 2;
            float4 v = *(const float4*)(wm + (size_t)d * 1024 + k0 + kq);
            Ws[kq][d] = v.x; Ws[kq + 1][d] = v.y; Ws[kq + 2][d] = v.z; Ws[kq + 3][d] = v.w;
        }
        __syncthreads();
#pragma unroll
        for (int kk = 0; kk < 32; kk++) {
            float a[4], w[8];
#pragma unroll
            for (int i = 0; i < 4; i++) a[i] = Xs[kk][ty * 4 + i];
#pragma unroll
            for (int j = 0; j < 8; j++) w[j] = Ws[kk][tx * 8 + j];
#pragma unroll
            for (int i = 0; i < 4; i++)
#pragma unroll
                for (int j = 0; j < 8; j++) acc[i][j] += a[i] * w[j];
        }
        __syncthreads();
    }
#pragma unroll
    for (int i = 0; i < 4; i++) {
        int row = bm + ty * 4 + i;
#pragma unroll
        for (int j = 0; j < 8; j++)
            metric[(size_t)row * 64 + tx * 8 + j] = acc[i][j] + wmb[tx * 8 + j];
    }
}

__global__ void __launch_bounds__(64) metric_norm(float* __restrict__ metric)
{
    int bn = blockIdx.x;
    int d = threadIdx.x;
    float v = metric[(size_t)bn * 64 + d];
    __shared__ float sh[64];
    sh[d] = v * v; __syncthreads();
    for (int off = 32; off; off >>= 1) {
        if (d < off) sh[d] += sh[d + off];
        __syncthreads();
    }
    float inv = rsqrtf(sh[0]);
    metric[(size_t)bn * 64 + d] = v * inv;
}

// ---------------- matching ----------------
__global__ void __launch_bounds__(256) match_scores(
    const float* __restrict__ metric, float* __restrict__ nodemax, int* __restrict__ nodeidx)
{
    int t = blockIdx.x;
    int b = blockIdx.y;
    const float* mb = metric + (size_t)b * Nn * 64;
    __shared__ float av[64];
    int tid = threadIdx.x;
    if (tid < 64) av[tid] = mb[(size_t)(2 * t) * 64 + tid];
    __syncthreads();
    float best = -INFINITY; int bi = 0;
    for (int s = tid; s < NH; s += 256) {
        const float* bp = mb + (size_t)(2 * s + 1) * 64;
        float dot = 0.f;
#pragma unroll
        for (int d = 0; d < 64; d++) dot += av[d] * bp[d];
        if (dot > best) { best = dot; bi = s; }
    }
    __shared__ float sv[256]; __shared__ int si[256];
    sv[tid] = best; si[tid] = bi; __syncthreads();
    for (int off = 128; off; off >>= 1) {
        if (tid < off) {
            if (sv[tid + off] > sv[tid] ||
                (sv[tid + off] == sv[tid] && si[tid + off] < si[tid])) {
                sv[tid] = sv[tid + off]; si[tid] = si[tid + off];
            }
        }
        __syncthreads();
    }
    if (tid == 0) {
        if (t == 0) { nodemax[b * NH] = -INFINITY; nodeidx[b * NH] = 0; }
        else { nodemax[b * NH + t] = sv[0]; nodeidx[b * NH + t] = si[0]; }
    }
}

__global__ void __launch_bounds__(512) match_sort(
    const float* __restrict__ nodemax, const int* __restrict__ nodeidx,
    int* __restrict__ srcidx, int* __restrict__ dstidx, int* __restrict__ unmidx)
{
    int b = blockIdx.x, t = threadIdx.x;
    __shared__ float v[NH]; __shared__ int rk[NH];
    v[t] = nodemax[b * NH + t]; __syncthreads();
    float vt = v[t]; int r = 0;
    for (int j = 0; j < NH; j++) {
        float vj = v[j];
        r += (vj > vt) || (vj == vt && j < t);
    }
    rk[t] = r; __syncthreads();
    if (r < Rr) {
        srcidx[b * Rr + r] = t;
        dstidx[b * Rr + r] = nodeidx[b * NH + t];
    } else {
        int pos = 0;
        for (int j = 0; j < t; j++) pos += (rk[j] >= Rr);
        unmidx[b * NU + pos] = t;
    }
}

// ---------------- weighted merge + divide by new size ----------------
__global__ void __launch_bounds__(256) merge_kernel(
    const float* __restrict__ xres, const float* __restrict__ sz,
    const int* __restrict__ srcidx, const int* __restrict__ dstidx,
    const int* __restrict__ unmidx, float* __restrict__ xm)
{
    int row = blockIdx.x;
    int b = blockIdx.y;
    int tid = threadIdx.x;
    const float* xb = xres + (size_t)b * Nn * Cc;
    const float* szb = sz + b * Nn;
    float* ob = xm + ((size_t)b * NM + row) * Cc;
    __shared__ int ss[Rr], sd[Rr];

    if (row < NU) {
        int t = 2 * unmidx[b * NU + row];
        float s = szb[t];
        float inv = 1.f / s;
        for (int c = tid; c < Cc; c += 256)
            ob[c] = (xb[(size_t)t * Cc + c] * s) * inv;
    } else {
        int j = row - NU;
        if (tid < Rr) { ss[tid] = srcidx[b * Rr + tid]; sd[tid] = dstidx[b * Rr + tid]; }
        __syncthreads();
        int t = 2 * j + 1;
        float ns = szb[t];
        for (int i = 0; i < Rr; i++)
            if (sd[i] == j) ns += szb[2 * ss[i]];
        float inv = 1.f / ns;
        for (int c = tid; c < Cc; c += 256) {
            float val = xb[(size_t)t * Cc + c] * szb[t];
            for (int i = 0; i < Rr; i++) {
                if (sd[i] == j) {
                    int ts = 2 * ss[i];
                    val += xb[(size_t)ts * Cc + c] * szb[ts];
                }
            }
            ob[c] = val * inv;
        }
    }
}

// ---------------- launch ----------------
template <typename T>
static T* sym_addr(const void* sym) {
    void* p = nullptr;
    cudaGetSymbolAddress(&p, sym);
    return (T*)p;
}

extern "C" void kernel_launch(void* const* d_in, const int* in_sizes, int n_in,
                              void* d_out, int out_size)
{
    const float* x      = (const float*)d_in[0];
    const float* sz     = (const float*)d_in[1];
    const float* qkv_w  = (const float*)d_in[3];
    const float* qkv_b  = (const float*)d_in[4];
    const float* proj_w = (const float*)d_in[5];
    const float* proj_b = (const float*)d_in[6];
    const float* n1g    = (const float*)d_in[7];
    const float* n1b    = (const float*)d_in[8];
    const float* n2g    = (const float*)d_in[9];
    const float* n2b    = (const float*)d_in[10];
    const float* fc1_w  = (const float*)d_in[11];
    const float* fc1_b  = (const float*)d_in[12];
    const float* fc2_w  = (const float*)d_in[13];
    const float* fc2_b  = (const float*)d_in[14];
    float* out = (float*)d_out;

    float* xln   = sym_addr<float>(g_xln);
    float* qkv   = sym_addr<float>(g_qkv);
    float* attno = sym_addr<float>(g_attno);
    float* xres  = sym_addr<float>(g_xres);
    float* wm    = sym_addr<float>(g_wm);
    float* wmb   = sym_addr<float>(g_wmb);
    float* metric= sym_addr<float>(g_metric);
    float* nmax  = sym_addr<float>(g_nodemax);
    int*   nidx  = sym_addr<int>(g_nodeidx);
    int*   sidx  = sym_addr<int>(g_srcidx);
    int*   didx  = sym_addr<int>(g_dstidx);
    int*   uidx  = sym_addr<int>(g_unmidx);
    float* xm    = sym_addr<float>(g_xm);
    float* h2    = sym_addr<float>(g_h2);
    float* fc1   = sym_addr<float>(g_fc1);

    cudaFuncSetAttribute(flash_attn, cudaFuncAttributeMaxDynamicSharedMemorySize, FLASH_SMEM);

    // 1. LN1
    ln_kernel<<<MROWS, 256>>>(x, n1g, n1b, xln, Cc);
    // 2. QKV GEMM (tf32 mma.sync)
    tf32_gemm<<<dim3(3072 / 128, MROWS / 128), 256>>>(
        xln, qkv_w, qkv_b, nullptr, qkv, MROWS, 3072, Cc, 0);
    // 3. exact fp32 metric path
    pool_wk<<<256, 256>>>(qkv_w, qkv_b, wm, wmb);
    metric_gemm<<<MROWS / 128, 256>>>(xln, wm, wmb, metric);
    metric_norm<<<Bb * Nn, 64>>>(metric);
    // 4. fused flash attention (scores + softmax + PV)
    flash_attn<<<dim3(8, Bb * Hh), 256, FLASH_SMEM>>>(qkv, sz, attno);
    // 5. proj + residual (tf32 mma.sync)
    tf32_gemm<<<dim3(Cc / 128, MROWS / 128), 256>>>(
        attno, proj_w, proj_b, x, xres, MROWS, Cc, Cc, 0);
    // 6. matching
    match_scores<<<dim3(NH, Bb), 256>>>(metric, nmax, nidx);
    match_sort<<<Bb, NH>>>(nmax, nidx, sidx, didx, uidx);
    // 7. merge
    merge_kernel<<<dim3(NM, Bb), 256>>>(xres, sz, sidx, didx, uidx, xm);
    // 8. LN2
    ln_kernel<<<MROWS2, 256>>>(xm, n2g, n2b, h2, Cc);
    // 9. fc1 + exact GELU (tf32 mma.sync)
    tf32_gemm<<<dim3(4096 / 128, MROWS2 / 128), 256>>>(
        h2, fc1_w, fc1_b, nullptr, fc1, MROWS2, 4096, Cc, 1);
    // 10. fc2 + residual -> out (tf32 mma.sync)
    tf32_gemm<<<dim3(Cc / 128, MROWS2 / 128), 256>>>(
        fc1, fc2_w, fc2_b, xm, out, MROWS2, Cc, 4096, 0);
    (void)in_sizes; (void)n_in; (void)out_size;
}

// round 9
// speedup vs baseline: 2.8790x; 1.2105x over previous
#include <cuda_runtime.h>
#include <cuda_bf16.h>
#include <cuda_fp16.h>
#include <math.h>
#include <cstdint>

// Problem constants
#define Bb 16
#define Nn 1024
#define Cc 1024
#define Hh 16
#define HD 64
#define Rr 128
#define NH (Nn/2)          // 512
#define NU (NH - Rr)       // 384 unmerged
#define NM (NU + NH)       // 896 merged tokens
#define MROWS (Bb*Nn)      // 16384
#define MROWS2 (Bb*NM)     // 14336

// ---------------- scratch (static device globals) ----------------
__device__ float g_xln  [(size_t)MROWS * Cc];
__device__ float g_qkv  [(size_t)MROWS * 3 * Cc];
__device__ float g_attno[(size_t)MROWS * Cc];
__device__ float g_xres [(size_t)MROWS * Cc];
__device__ float g_wm   [64 * 1024];
__device__ float g_wmb  [64];
__device__ float g_metric[(size_t)Bb * Nn * HD];
__device__ float g_nodemax[Bb * NH];
__device__ int   g_nodeidx[Bb * NH];
__device__ int   g_srcidx[Bb * Rr];
__device__ int   g_dstidx[Bb * Rr];
__device__ int   g_unmidx[Bb * NU];
__device__ float g_xm   [(size_t)MROWS2 * Cc];
__device__ float g_h2   [(size_t)MROWS2 * Cc];
__device__ float g_fc1  [(size_t)MROWS2 * 4 * Cc];

__device__ __forceinline__ uint32_t f2tf32(float x) {
    uint32_t r;
    asm("cvt.rna.tf32.f32 %0, %1;" : "=r"(r) : "f"(x));
    return r;
}
__device__ __forceinline__ uint32_t packh2(float x, float y) {
    __half2 h = __floats2half2_rn(x, y);
    return *(uint32_t*)&h;
}

__device__ __forceinline__ void mma_tf32(float& d0, float& d1, float& d2, float& d3,
                                         uint32_t a0, uint32_t a1, uint32_t a2, uint32_t a3,
                                         uint32_t b0, uint32_t b1)
{
    asm volatile(
        "mma.sync.aligned.m16n8k8.row.col.f32.tf32.tf32.f32 "
        "{%0,%1,%2,%3}, {%4,%5,%6,%7}, {%8,%9}, {%0,%1,%2,%3};\n"
        : "+f"(d0), "+f"(d1), "+f"(d2), "+f"(d3)
        : "r"(a0), "r"(a1), "r"(a2), "r"(a3), "r"(b0), "r"(b1));
}

__device__ __forceinline__ void mma_f16(float& d0, float& d1, float& d2, float& d3,
                                        uint32_t a0, uint32_t a1, uint32_t a2, uint32_t a3,
                                        uint32_t b0, uint32_t b1)
{
    asm volatile(
        "mma.sync.aligned.m16n8k16.row.col.f32.f16.f16.f32 "
        "{%0,%1,%2,%3}, {%4,%5,%6,%7}, {%8,%9}, {%0,%1,%2,%3};\n"
        : "+f"(d0), "+f"(d1), "+f"(d2), "+f"(d3)
        : "r"(a0), "r"(a1), "r"(a2), "r"(a3), "r"(b0), "r"(b1));
}

// ================= fp16 m16n8k16 GEMM =================
// out(MxN) = A(MxK) @ W(NxK)^T + bias [,gelu] [,+res]
// CTA 128x128, 8 warps (4M x 2N), warp tile 32x64. K staged 16, double-buffered.
// SMEM rows hold 8 half2 words, stride 12 -> fragment banks (12g+tg)%32 bijective.
__global__ void __launch_bounds__(256) fp16_gemm(
    const float* __restrict__ A, const float* __restrict__ W,
    const float* __restrict__ bias, const float* __restrict__ res,
    float* __restrict__ out, int M, int N, int K, int act)
{
    __shared__ uint32_t As[2][128][12];
    __shared__ uint32_t Bs[2][128][12];

    const int tid = threadIdx.x;
    const int wid = tid >> 5;
    const int lane = tid & 31;
    const int g = lane >> 2;
    const int tg = lane & 3;
    const int wm = wid & 3;
    const int wn = wid >> 2;
    const int bm = blockIdx.y * 128;
    const int bn = blockIdx.x * 128;

    const int rowA0 = tid >> 2;              // 0..63
    const int c40 = (tid & 3) << 2;          // float col 0,4,8,12
    const int h20 = c40 >> 1;                // half2 col 0,2,4,6
    const float* Ap0 = A + (size_t)(bm + rowA0) * K + c40;
    const float* Ap1 = Ap0 + (size_t)64 * K;
    const float* Wp0 = W + (size_t)(bn + rowA0) * K + c40;
    const float* Wp1 = Wp0 + (size_t)64 * K;

    float acc[2][8][4];
#pragma unroll
    for (int i = 0; i < 2; i++)
#pragma unroll
        for (int j = 0; j < 8; j++)
#pragma unroll
            for (int v = 0; v < 4; v++) acc[i][j][v] = 0.f;

    // prologue: stage 0 -> buffer 0
    {
        float4 a0 = *(const float4*)(Ap0);
        float4 a1 = *(const float4*)(Ap1);
        float4 w0 = *(const float4*)(Wp0);
        float4 w1 = *(const float4*)(Wp1);
        *(uint2*)&As[0][rowA0][h20]      = make_uint2(packh2(a0.x, a0.y), packh2(a0.z, a0.w));
        *(uint2*)&As[0][rowA0 + 64][h20] = make_uint2(packh2(a1.x, a1.y), packh2(a1.z, a1.w));
        *(uint2*)&Bs[0][rowA0][h20]      = make_uint2(packh2(w0.x, w0.y), packh2(w0.z, w0.w));
        *(uint2*)&Bs[0][rowA0 + 64][h20] = make_uint2(packh2(w1.x, w1.y), packh2(w1.z, w1.w));
    }
    __syncthreads();

    const int NS = K >> 4;
    uint2 sa0, sa1, sw0, sw1;
    for (int s = 0; s < NS; s++) {
        const int buf = s & 1;
        const bool has_next = (s + 1 < NS);
        if (has_next) {
            int k0 = (s + 1) << 4;
            float4 a0 = *(const float4*)(Ap0 + k0);
            float4 a1 = *(const float4*)(Ap1 + k0);
            float4 w0 = *(const float4*)(Wp0 + k0);
            float4 w1 = *(const float4*)(Wp1 + k0);
            sa0 = make_uint2(packh2(a0.x, a0.y), packh2(a0.z, a0.w));
            sa1 = make_uint2(packh2(a1.x, a1.y), packh2(a1.z, a1.w));
            sw0 = make_uint2(packh2(w0.x, w0.y), packh2(w0.z, w0.w));
            sw1 = make_uint2(packh2(w1.x, w1.y), packh2(w1.z, w1.w));
        }
        // one k16 mma step (fragment indices: half2 col tg and tg+4)
        {
            uint32_t af[2][4];
#pragma unroll
            for (int mt = 0; mt < 2; mt++) {
                int ra = wm * 32 + mt * 16 + g;
                af[mt][0] = As[buf][ra][tg];
                af[mt][1] = As[buf][ra + 8][tg];
                af[mt][2] = As[buf][ra][tg + 4];
                af[mt][3] = As[buf][ra + 8][tg + 4];
            }
            uint32_t bf[8][2];
#pragma unroll
            for (int nt = 0; nt < 8; nt++) {
                int cb = wn * 64 + nt * 8 + g;
                bf[nt][0] = Bs[buf][cb][tg];
                bf[nt][1] = Bs[buf][cb][tg + 4];
            }
#pragma unroll
            for (int mt = 0; mt < 2; mt++)
#pragma unroll
                for (int nt = 0; nt < 8; nt++)
                    mma_f16(acc[mt][nt][0], acc[mt][nt][1], acc[mt][nt][2], acc[mt][nt][3],
                            af[mt][0], af[mt][1], af[mt][2], af[mt][3],
                            bf[nt][0], bf[nt][1]);
        }
        if (has_next) {
            int nb = (s + 1) & 1;
            __syncthreads();
            *(uint2*)&As[nb][rowA0][h20]      = sa0;
            *(uint2*)&As[nb][rowA0 + 64][h20] = sa1;
            *(uint2*)&Bs[nb][rowA0][h20]      = sw0;
            *(uint2*)&Bs[nb][rowA0 + 64][h20] = sw1;
            __syncthreads();
        }
    }

    // epilogue: direct from accumulators (m16n8 C layout, verified R6)
#pragma unroll
    for (int mt = 0; mt < 2; mt++) {
        int r0 = bm + wm * 32 + mt * 16 + g;
#pragma unroll
        for (int nt = 0; nt < 8; nt++) {
            int col = bn + wn * 64 + nt * 8 + tg * 2;
            float b0 = bias[col], b1 = bias[col + 1];
            float v0 = acc[mt][nt][0] + b0;
            float v1 = acc[mt][nt][1] + b1;
            float v2 = acc[mt][nt][2] + b0;
            float v3 = acc[mt][nt][3] + b1;
            if (act) {
                v0 = 0.5f * v0 * (1.f + erff(v0 * 0.70710678118654752f));
                v1 = 0.5f * v1 * (1.f + erff(v1 * 0.70710678118654752f));
                v2 = 0.5f * v2 * (1.f + erff(v2 * 0.70710678118654752f));
                v3 = 0.5f * v3 * (1.f + erff(v3 * 0.70710678118654752f));
            }
            if (res) {
                const float* rp0 = res + (size_t)r0 * N + col;
                const float* rp1 = rp0 + (size_t)8 * N;
                v0 += rp0[0]; v1 += rp0[1];
                v2 += rp1[0]; v3 += rp1[1];
            }
            *(float2*)(out + (size_t)r0 * N + col) = make_float2(v0, v1);
            *(float2*)(out + (size_t)(r0 + 8) * N + col) = make_float2(v2, v3);
        }
    }
}

// ================= fused flash attention (tf32, verified R8) =================
#define QS_STRIDE 68
#define KP_STRIDE 132
#define VS_STRIDE 140
#define FLASH_SMEM ((128*QS_STRIDE + 128*KP_STRIDE + 64*VS_STRIDE + 1024 + 256 + 256) * 4)

__global__ void __launch_bounds__(256) flash_attn(
    const float* __restrict__ qkv, const float* __restrict__ sz, float* __restrict__ out)
{
    extern __shared__ uint32_t smw[];
    uint32_t* Qs = smw;
    uint32_t* KP = Qs + 128 * QS_STRIDE;
    uint32_t* Vs = KP + 128 * KP_STRIDE;
    float* logls = (float*)(Vs + 64 * VS_STRIDE);
    float* redm  = logls + 1024;
    float* reds  = redm + 256;

    const int tid = threadIdx.x;
    const int wid = tid >> 5, lane = tid & 31;
    const int g = lane >> 2, tg = lane & 3;
    const int wm = wid & 3;
    const int wnn = wid >> 2;
    const int bh = blockIdx.y;
    const int b = bh >> 4, h = bh & 15;
    const int n0 = blockIdx.x * 128;
    const float* qb = qkv + (size_t)b * Nn * 3072 + h * 64;
    const float* kb = qb + 1024;
    const float* vb = qb + 2048;

    for (int i = tid; i < 1024; i += 256)
        logls[i] = __logf(sz[b * Nn + i]);

#pragma unroll
    for (int i = 0; i < 8; i++) {
        int idx = tid + i * 256;
        int row = idx >> 4;
        int c4 = (idx & 15) << 2;
        float4 q = *(const float4*)(qb + (size_t)(n0 + row) * 3072 + c4);
        *(uint4*)&Qs[row * QS_STRIDE + c4] =
            make_uint4(f2tf32(q.x), f2tf32(q.y), f2tf32(q.z), f2tf32(q.w));
    }

    float m_i[2][2], l_i[2][2];
    float acc[2][4][4];
#pragma unroll
    for (int mt = 0; mt < 2; mt++)
#pragma unroll
        for (int rh = 0; rh < 2; rh++) { m_i[mt][rh] = -INFINITY; l_i[mt][rh] = 0.f; }
#pragma unroll
    for (int mt = 0; mt < 2; mt++)
#pragma unroll
        for (int nt = 0; nt < 4; nt++)
#pragma unroll
            for (int v = 0; v < 4; v++) acc[mt][nt][v] = 0.f;

    for (int m0 = 0; m0 < Nn; m0 += 128) {
        __syncthreads();
#pragma unroll
        for (int i = 0; i < 8; i++) {
            int idx = tid + i * 256;
            int row = idx >> 4;
            int c4 = (idx & 15) << 2;
            float4 k = *(const float4*)(kb + (size_t)(m0 + row) * 3072 + c4);
            *(uint4*)&KP[row * KP_STRIDE + c4] =
                make_uint4(f2tf32(k.x), f2tf32(k.y), f2tf32(k.z), f2tf32(k.w));
            float4 v = *(const float4*)(vb + (size_t)(m0 + row) * 3072 + c4);
            Vs[(c4 + 0) * VS_STRIDE + row] = f2tf32(v.x);
            Vs[(c4 + 1) * VS_STRIDE + row] = f2tf32(v.y);
            Vs[(c4 + 2) * VS_STRIDE + row] = f2tf32(v.z);
            Vs[(c4 + 3) * VS_STRIDE + row] = f2tf32(v.w);
        }
        __syncthreads();

        float s[2][8][4];
#pragma unroll
        for (int mt = 0; mt < 2; mt++)
#pragma unroll
            for (int nt = 0; nt < 8; nt++)
#pragma unroll
                for (int v = 0; v < 4; v++) s[mt][nt][v] = 0.f;
#pragma unroll
        for (int ks = 0; ks < 64; ks += 8) {
            uint32_t af[2][4];
#pragma unroll
            for (int mt = 0; mt < 2; mt++) {
                int ra = wm * 32 + mt * 16 + g;
                af[mt][0] = Qs[ra * QS_STRIDE + ks + tg];
                af[mt][1] = Qs[(ra + 8) * QS_STRIDE + ks + tg];
                af[mt][2] = Qs[ra * QS_STRIDE + ks + tg + 4];
                af[mt][3] = Qs[(ra + 8) * QS_STRIDE + ks + tg + 4];
            }
            uint32_t bf[8][2];
#pragma unroll
            for (int nt = 0; nt < 8; nt++) {
                int cb = wnn * 64 + nt * 8 + g;
                bf[nt][0] = KP[cb * KP_STRIDE + ks + tg];
                bf[nt][1] = KP[cb * KP_STRIDE + ks + tg + 4];
            }
#pragma unroll
            for (int mt = 0; mt < 2; mt++)
#pragma unroll
                for (int nt = 0; nt < 8; nt++)
                    mma_tf32(s[mt][nt][0], s[mt][nt][1], s[mt][nt][2], s[mt][nt][3],
                             af[mt][0], af[mt][1], af[mt][2], af[mt][3],
                             bf[nt][0], bf[nt][1]);
        }

        float tmax[2][2];
#pragma unroll
        for (int mt = 0; mt < 2; mt++) { tmax[mt][0] = -INFINITY; tmax[mt][1] = -INFINITY; }
#pragma unroll
        for (int mt = 0; mt < 2; mt++)
#pragma unroll
            for (int nt = 0; nt < 8; nt++) {
                int col = wnn * 64 + nt * 8 + tg * 2;
                float ls0 = logls[m0 + col];
                float ls1 = logls[m0 + col + 1];
                s[mt][nt][0] = s[mt][nt][0] * 0.125f + ls0;
                s[mt][nt][1] = s[mt][nt][1] * 0.125f + ls1;
                s[mt][nt][2] = s[mt][nt][2] * 0.125f + ls0;
                s[mt][nt][3] = s[mt][nt][3] * 0.125f + ls1;
                tmax[mt][0] = fmaxf(tmax[mt][0], fmaxf(s[mt][nt][0], s[mt][nt][1]));
                tmax[mt][1] = fmaxf(tmax[mt][1], fmaxf(s[mt][nt][2], s[mt][nt][3]));
            }
#pragma unroll
        for (int mt = 0; mt < 2; mt++)
#pragma unroll
            for (int rh = 0; rh < 2; rh++) {
                float v = tmax[mt][rh];
                v = fmaxf(v, __shfl_xor_sync(~0u, v, 1));
                v = fmaxf(v, __shfl_xor_sync(~0u, v, 2));
                tmax[mt][rh] = v;
            }
        if (tg == 0) {
#pragma unroll
            for (int mt = 0; mt < 2; mt++)
#pragma unroll
                for (int rh = 0; rh < 2; rh++)
                    redm[wnn * 128 + wm * 32 + mt * 16 + rh * 8 + g] = tmax[mt][rh];
        }
        __syncthreads();

        float sc[2][2];
#pragma unroll
        for (int mt = 0; mt < 2; mt++)
#pragma unroll
            for (int rh = 0; rh < 2; rh++) {
                int row = wm * 32 + mt * 16 + rh * 8 + g;
                float mx = fmaxf(redm[row], redm[128 + row]);
                float mnew = fmaxf(m_i[mt][rh], mx);
                sc[mt][rh] = __expf(m_i[mt][rh] - mnew);
                m_i[mt][rh] = mnew;
                l_i[mt][rh] *= sc[mt][rh];
            }
#pragma unroll
        for (int mt = 0; mt < 2; mt++)
#pragma unroll
            for (int nt = 0; nt < 4; nt++) {
                acc[mt][nt][0] *= sc[mt][0];
                acc[mt][nt][1] *= sc[mt][0];
                acc[mt][nt][2] *= sc[mt][1];
                acc[mt][nt][3] *= sc[mt][1];
            }

        float tsum[2][2];
#pragma unroll
        for (int mt = 0; mt < 2; mt++) { tsum[mt][0] = 0.f; tsum[mt][1] = 0.f; }
#pragma unroll
        for (int mt = 0; mt < 2; mt++) {
            int r0 = wm * 32 + mt * 16 + g;
#pragma unroll
            for (int nt = 0; nt < 8; nt++) {
                int col = wnn * 64 + nt * 8 + tg * 2;
                float p0 = __expf(s[mt][nt][0] - m_i[mt][0]);
                float p1 = __expf(s[mt][nt][1] - m_i[mt][0]);
                float p2 = __expf(s[mt][nt][2] - m_i[mt][1]);
                float p3 = __expf(s[mt][nt][3] - m_i[mt][1]);
                tsum[mt][0] += p0 + p1;
                tsum[mt][1] += p2 + p3;
                KP[r0 * KP_STRIDE + col] = f2tf32(p0);
                KP[r0 * KP_STRIDE + col + 1] = f2tf32(p1);
                KP[(r0 + 8) * KP_STRIDE + col] = f2tf32(p2);
                KP[(r0 + 8) * KP_STRIDE + col + 1] = f2tf32(p3);
            }
        }
#pragma unroll
        for (int mt = 0; mt < 2; mt++)
#pragma unroll
            for (int rh = 0; rh < 2; rh++) {
                float v = tsum[mt][rh];
                v += __shfl_xor_sync(~0u, v, 1);
                v += __shfl_xor_sync(~0u, v, 2);
                tsum[mt][rh] = v;
            }
        if (tg == 0) {
#pragma unroll
            for (int mt = 0; mt < 2; mt++)
#pragma unroll
                for (int rh = 0; rh < 2; rh++)
                    reds[wnn * 128 + wm * 32 + mt * 16 + rh * 8 + g] = tsum[mt][rh];
        }
        __syncthreads();
#pragma unroll
        for (int mt = 0; mt < 2; mt++)
#pragma unroll
            for (int rh = 0; rh < 2; rh++) {
                int row = wm * 32 + mt * 16 + rh * 8 + g;
                l_i[mt][rh] += reds[row] + reds[128 + row];
            }

#pragma unroll
        for (int ks = 0; ks < 128; ks += 8) {
            uint32_t af[2][4];
#pragma unroll
            for (int mt = 0; mt < 2; mt++) {
                int ra = wm * 32 + mt * 16 + g;
                af[mt][0] = KP[ra * KP_STRIDE + ks + tg];
                af[mt][1] = KP[(ra + 8) * KP_STRIDE + ks + tg];
                af[mt][2] = KP[ra * KP_STRIDE + ks + tg + 4];
                af[mt][3] = KP[(ra + 8) * KP_STRIDE + ks + tg + 4];
            }
            uint32_t bf[4][2];
#pragma unroll
            for (int nt = 0; nt < 4; nt++) {
                int cb = wnn * 32 + nt * 8 + g;
                bf[nt][0] = Vs[cb * VS_STRIDE + ks + tg];
                bf[nt][1] = Vs[cb * VS_STRIDE + ks + tg + 4];
            }
#pragma unroll
            for (int mt = 0; mt < 2; mt++)
#pragma unroll
                for (int nt = 0; nt < 4; nt++)
                    mma_tf32(acc[mt][nt][0], acc[mt][nt][1], acc[mt][nt][2], acc[mt][nt][3],
                             af[mt][0], af[mt][1], af[mt][2], af[mt][3],
                             bf[nt][0], bf[nt][1]);
        }
    }

#pragma unroll
    for (int mt = 0; mt < 2; mt++) {
        float inv0 = 1.f / l_i[mt][0];
        float inv1 = 1.f / l_i[mt][1];
        int r0 = n0 + wm * 32 + mt * 16 + g;
#pragma unroll
        for (int nt = 0; nt < 4; nt++) {
            int col = h * 64 + wnn * 32 + nt * 8 + tg * 2;
            *(float2*)(out + ((size_t)b * Nn + r0) * Cc + col) =
                make_float2(acc[mt][nt][0] * inv0, acc[mt][nt][1] * inv0);
            *(float2*)(out + ((size_t)b * Nn + r0 + 8) * Cc + col) =
                make_float2(acc[mt][nt][2] * inv1, acc[mt][nt][3] * inv1);
        }
    }
}

// ---------------- LayerNorm ----------------
__global__ void __launch_bounds__(256) ln_kernel(
    const float* __restrict__ x, const float* __restrict__ g,
    const float* __restrict__ bta, float* __restrict__ out, int C)
{
    size_t row = blockIdx.x;
    const float* p = x + row * C;
    float* o = out + row * C;
    int tid = threadIdx.x;
    float s = 0.f, s2 = 0.f;
    for (int i = tid; i < C; i += 256) { float v = p[i]; s += v; s2 += v * v; }
    __shared__ float rs[256], rq[256];
    rs[tid] = s; rq[tid] = s2; __syncthreads();
    for (int off = 128; off; off >>= 1) {
        if (tid < off) { rs[tid] += rs[tid + off]; rq[tid] += rq[tid + off]; }
        __syncthreads();
    }
    float mean = rs[0] / (float)C;
    float var  = rq[0] / (float)C - mean * mean;
    float inv  = rsqrtf(var + 1e-5f);
    for (int i = tid; i < C; i += 256)
        o[i] = (p[i] - mean) * inv * g[i] + bta[i];
}

// ---------------- pooled K weight (exact fp32 metric path) ----------------
__global__ void __launch_bounds__(256) pool_wk(
    const float* __restrict__ qkv_w, const float* __restrict__ qkv_b,
    float* __restrict__ wm, float* __restrict__ wmb)
{
    int idx = blockIdx.x * 256 + threadIdx.x;
    if (idx < 64 * 1024) {
        int d = idx >> 10, k = idx & 1023;
        float s = 0.f;
#pragma unroll
        for (int h = 0; h < 16; h++) s += qkv_w[(size_t)(1024 + h * 64 + d) * 1024 + k];
        wm[idx] = s * (1.f / 16.f);
    }
    if (idx < 64) {
        float s = 0.f;
#pragma unroll
        for (int h = 0; h < 16; h++) s += qkv_b[1024 + h * 64 + idx];
        wmb[idx] = s * (1.f / 16.f);
    }
}

// ---------------- fp32 metric GEMM ----------------
__global__ void __launch_bounds__(256) metric_gemm(
    const float* __restrict__ xln, const float* __restrict__ wm,
    const float* __restrict__ wmb, float* __restrict__ metric)
{
    __shared__ float Xs[32][132];
    __shared__ float Ws[32][68];
    const int bm = blockIdx.x * 128;
    const int tid = threadIdx.x;
    const int ty = tid >> 3;
    const int tx = tid & 7;
    float acc[4][8];
#pragma unroll
    for (int i = 0; i < 4; i++)
#pragma unroll
        for (int j = 0; j < 8; j++) acc[i][j] = 0.f;

    for (int k0 = 0; k0 < 1024; k0 += 32) {
#pragma unroll
        for (int i = 0; i < 4; i++) {
            int idx = tid + i * 256;
            int row = idx >> 3;
            int kq = (idx & 7) << 2;
            float4 v = *(const float4*)(xln + (size_t)(bm + row) * 1024 + k0 + kq);
            Xs[kq][row] = v.x; Xs[kq + 1][row] = v.y; Xs[kq + 2][row] = v.z; Xs[kq + 3][row] = v.w;
        }
        for (int idx = tid; idx < 512; idx += 256) {
            int d = idx >> 3;
            int kq = (idx & 7) << 2;
            float4 v = *(const float4*)(wm + (size_t)d * 1024 + k0 + kq);
            Ws[kq][d] = v.x; Ws[kq + 1][d] = v.y; Ws[kq + 2][d] = v.z; Ws[kq + 3][d] = v.w;
        }
        __syncthreads();
#pragma unroll
        for (int kk = 0; kk < 32; kk++) {
            float a[4], w[8];
#pragma unroll
            for (int i = 0; i < 4; i++) a[i] = Xs[kk][ty * 4 + i];
#pragma unroll
            for (int j = 0; j < 8; j++) w[j] = Ws[kk][tx * 8 + j];
#pragma unroll
            for (int i = 0; i < 4; i++)
#pragma unroll
                for (int j = 0; j < 8; j++) acc[i][j] += a[i] * w[j];
        }
        __syncthreads();
    }
#pragma unroll
    for (int i = 0; i < 4; i++) {
        int row = bm + ty * 4 + i;
#pragma unroll
        for (int j = 0; j < 8; j++)
            metric[(size_t)row * 64 + tx * 8 + j] = acc[i][j] + wmb[tx * 8 + j];
    }
}

__global__ void __launch_bounds__(64) metric_norm(float* __restrict__ metric)
{
    int bn = blockIdx.x;
    int d = threadIdx.x;
    float v = metric[(size_t)bn * 64 + d];
    __shared__ float sh[64];
    sh[d] = v * v; __syncthreads();
    for (int off = 32; off; off >>= 1) {
        if (d < off) sh[d] += sh[d + off];
        __syncthreads();
    }
    float inv = rsqrtf(sh[0]);
    metric[(size_t)bn * 64 + d] = v * inv;
}

// ---------------- matching ----------------
__global__ void __launch_bounds__(256) match_scores(
    const float* __restrict__ metric, float* __restrict__ nodemax, int* __restrict__ nodeidx)
{
    int t = blockIdx.x;
    int b = blockIdx.y;
    const float* mb = metric + (size_t)b * Nn * 64;
    __shared__ float av[64];
    int tid = threadIdx.x;
    if (tid < 64) av[tid] = mb[(size_t)(2 * t) * 64 + tid];
    __syncthreads();
    float best = -INFINITY; int bi = 0;
    for (int s = tid; s < NH; s += 256) {
        const float* bp = mb + (size_t)(2 * s + 1) * 64;
        float dot = 0.f;
#pragma unroll
        for (int d = 0; d < 64; d++) dot += av[d] * bp[d];
        if (dot > best) { best = dot; bi = s; }
    }
    __shared__ float sv[256]; __shared__ int si[256];
    sv[tid] = best; si[tid] = bi; __syncthreads();
    for (int off = 128; off; off >>= 1) {
        if (tid < off) {
            if (sv[tid + off] > sv[tid] ||
                (sv[tid + off] == sv[tid] && si[tid + off] < si[tid])) {
                sv[tid] = sv[tid + off]; si[tid] = si[tid + off];
            }
        }
        __syncthreads();
    }
    if (tid == 0) {
        if (t == 0) { nodemax[b * NH] = -INFINITY; nodeidx[b * NH] = 0; }
        else { nodemax[b * NH + t] = sv[0]; nodeidx[b * NH + t] = si[0]; }
    }
}

__global__ void __launch_bounds__(512) match_sort(
    const float* __restrict__ nodemax, const int* __restrict__ nodeidx,
    int* __restrict__ srcidx, int* __restrict__ dstidx, int* __restrict__ unmidx)
{
    int b = blockIdx.x, t = threadIdx.x;
    __shared__ float v[NH]; __shared__ int rk[NH];
    v[t] = nodemax[b * NH + t]; __syncthreads();
    float vt = v[t]; int r = 0;
    for (int j = 0; j < NH; j++) {
        float vj = v[j];
        r += (vj > vt) || (vj == vt && j < t);
    }
    rk[t] = r; __syncthreads();
    if (r < Rr) {
        srcidx[b * Rr + r] = t;
        dstidx[b * Rr + r] = nodeidx[b * NH + t];
    } else {
        int pos = 0;
        for (int j = 0; j < t; j++) pos += (rk[j] >= Rr);
        unmidx[b * NU + pos] = t;
    }
}

// ---------------- weighted merge + divide by new size ----------------
__global__ void __launch_bounds__(256) merge_kernel(
    const float* __restrict__ xres, const float* __restrict__ sz,
    const int* __restrict__ srcidx, const int* __restrict__ dstidx,
    const int* __restrict__ unmidx, float* __restrict__ xm)
{
    int row = blockIdx.x;
    int b = blockIdx.y;
    int tid = threadIdx.x;
    const float* xb = xres + (size_t)b * Nn * Cc;
    const float* szb = sz + b * Nn;
    float* ob = xm + ((size_t)b * NM + row) * Cc;
    __shared__ int ss[Rr], sd[Rr];

    if (row < NU) {
        int t = 2 * unmidx[b * NU + row];
        float s = szb[t];
        float inv = 1.f / s;
        for (int c = tid; c < Cc; c += 256)
            ob[c] = (xb[(size_t)t * Cc + c] * s) * inv;
    } else {
        int j = row - NU;
        if (tid < Rr) { ss[tid] = srcidx[b * Rr + tid]; sd[tid] = dstidx[b * Rr + tid]; }
        __syncthreads();
        int t = 2 * j + 1;
        float ns = szb[t];
        for (int i = 0; i < Rr; i++)
            if (sd[i] == j) ns += szb[2 * ss[i]];
        float inv = 1.f / ns;
        for (int c = tid; c < Cc; c += 256) {
            float val = xb[(size_t)t * Cc + c] * szb[t];
            for (int i = 0; i < Rr; i++) {
                if (sd[i] == j) {
                    int ts = 2 * ss[i];
                    val += xb[(size_t)ts * Cc + c] * szb[ts];
                }
            }
            ob[c] = val * inv;
        }
    }
}

// ---------------- launch ----------------
template <typename T>
static T* sym_addr(const void* sym) {
    void* p = nullptr;
    cudaGetSymbolAddress(&p, sym);
    return (T*)p;
}

extern "C" void kernel_launch(void* const* d_in, const int* in_sizes, int n_in,
                              void* d_out, int out_size)
{
    const float* x      = (const float*)d_in[0];
    const float* sz     = (const float*)d_in[1];
    const float* qkv_w  = (const float*)d_in[3];
    const float* qkv_b  = (const float*)d_in[4];
    const float* proj_w = (const float*)d_in[5];
    const float* proj_b = (const float*)d_in[6];
    const float* n1g    = (const float*)d_in[7];
    const float* n1b    = (const float*)d_in[8];
    const float* n2g    = (const float*)d_in[9];
    const float* n2b    = (const float*)d_in[10];
    const float* fc1_w  = (const float*)d_in[11];
    const float* fc1_b  = (const float*)d_in[12];
    const float* fc2_w  = (const float*)d_in[13];
    const float* fc2_b  = (const float*)d_in[14];
    float* out = (float*)d_out;

    float* xln   = sym_addr<float>(g_xln);
    float* qkv   = sym_addr<float>(g_qkv);
    float* attno = sym_addr<float>(g_attno);
    float* xres  = sym_addr<float>(g_xres);
    float* wm    = sym_addr<float>(g_wm);
    float* wmb   = sym_addr<float>(g_wmb);
    float* metric= sym_addr<float>(g_metric);
    float* nmax  = sym_addr<float>(g_nodemax);
    int*   nidx  = sym_addr<int>(g_nodeidx);
    int*   sidx  = sym_addr<int>(g_srcidx);
    int*   didx  = sym_addr<int>(g_dstidx);
    int*   uidx  = sym_addr<int>(g_unmidx);
    float* xm    = sym_addr<float>(g_xm);
    float* h2    = sym_addr<float>(g_h2);
    float* fc1   = sym_addr<float>(g_fc1);

    cudaFuncSetAttribute(flash_attn, cudaFuncAttributeMaxDynamicSharedMemorySize, FLASH_SMEM);

    // 1. LN1
    ln_kernel<<<MROWS, 256>>>(x, n1g, n1b, xln, Cc);
    // 2. QKV GEMM (fp16 mma)
    fp16_gemm<<<dim3(3072 / 128, MROWS / 128), 256>>>(
        xln, qkv_w, qkv_b, nullptr, qkv, MROWS, 3072, Cc, 0);
    // 3. exact fp32 metric path
    pool_wk<<<256, 256>>>(qkv_w, qkv_b, wm, wmb);
    metric_gemm<<<MROWS / 128, 256>>>(xln, wm, wmb, metric);
    metric_norm<<<Bb * Nn, 64>>>(metric);
    // 4. fused flash attention (scores + softmax + PV)
    flash_attn<<<dim3(8, Bb * Hh), 256, FLASH_SMEM>>>(qkv, sz, attno);
    // 5. proj + residual (fp16 mma)
    fp16_gemm<<<dim3(Cc / 128, MROWS / 128), 256>>>(
        attno, proj_w, proj_b, x, xres, MROWS, Cc, Cc, 0);
    // 6. matching
    match_scores<<<dim3(NH, Bb), 256>>>(metric, nmax, nidx);
    match_sort<<<Bb, NH>>>(nmax, nidx, sidx, didx, uidx);
    // 7. merge
    merge_kernel<<<dim3(NM, Bb), 256>>>(xres, sz, sidx, didx, uidx, xm);
    // 8. LN2
    ln_kernel<<<MROWS2, 256>>>(xm, n2g, n2b, h2, Cc);
    // 9. fc1 + exact GELU (fp16 mma)
    fp16_gemm<<<dim3(4096 / 128, MROWS2 / 128), 256>>>(
        h2, fc1_w, fc1_b, nullptr, fc1, MROWS2, 4096, Cc, 1);
    // 10. fc2 + residual -> out (fp16 mma)
    fp16_gemm<<<dim3(Cc / 128, MROWS2 / 128), 256>>>(
        fc1, fc2_w, fc2_b, xm, out, MROWS2, Cc, 4096, 0);
    (void)in_sizes; (void)n_in; (void)out_size;
}

// round 10
// speedup vs baseline: 3.0530x; 1.0604x over previous
#include <cuda_runtime.h>
#include <cuda_bf16.h>
#include <cuda_fp16.h>
#include <math.h>
#include <cstdint>

// Problem constants
#define Bb 16
#define Nn 1024
#define Cc 1024
#define Hh 16
#define HD 64
#define Rr 128
#define NH (Nn/2)          // 512
#define NU (NH - Rr)       // 384 unmerged
#define NM (NU + NH)       // 896 merged tokens
#define MROWS (Bb*Nn)      // 16384
#define MROWS2 (Bb*NM)     // 14336

// ---------------- scratch (static device globals) ----------------
__device__ float  g_xln  [(size_t)MROWS * Cc];           // fp32 (metric path)
__device__ __half g_xln_h[(size_t)MROWS * Cc];           // fp16 (qkv GEMM input)
__device__ __half g_qkv_h[(size_t)MROWS * 3 * Cc];
__device__ __half g_attno_h[(size_t)MROWS * Cc];
__device__ float  g_xres [(size_t)MROWS * Cc];
__device__ __half g_h2_h [(size_t)MROWS2 * Cc];
__device__ __half g_fc1_h[(size_t)MROWS2 * 4 * Cc];
__device__ __half g_wqkv_h[(size_t)3 * Cc * Cc];
__device__ __half g_wproj_h[(size_t)Cc * Cc];
__device__ __half g_wfc1_h[(size_t)4 * Cc * Cc];
__device__ __half g_wfc2_h[(size_t)Cc * 4 * Cc];
__device__ float g_wm   [64 * 1024];
__device__ float g_wmb  [64];
__device__ float g_metric[(size_t)Bb * Nn * HD];
__device__ float g_nodemax[Bb * NH];
__device__ int   g_nodeidx[Bb * NH];
__device__ int   g_srcidx[Bb * Rr];
__device__ int   g_dstidx[Bb * Rr];
__device__ int   g_unmidx[Bb * NU];
__device__ float g_xm   [(size_t)MROWS2 * Cc];

__device__ __forceinline__ uint32_t packh2(float x, float y) {
    __half2 h = __floats2half2_rn(x, y);
    return *(uint32_t*)&h;
}

__device__ __forceinline__ void mma_f16(float& d0, float& d1, float& d2, float& d3,
                                        uint32_t a0, uint32_t a1, uint32_t a2, uint32_t a3,
                                        uint32_t b0, uint32_t b1)
{
    asm volatile(
        "mma.sync.aligned.m16n8k16.row.col.f32.f16.f16.f32 "
        "{%0,%1,%2,%3}, {%4,%5,%6,%7}, {%8,%9}, {%0,%1,%2,%3};\n"
        : "+f"(d0), "+f"(d1), "+f"(d2), "+f"(d3)
        : "r"(a0), "r"(a1), "r"(a2), "r"(a3), "r"(b0), "r"(b1));
}

// ---------------- f32 -> f16 converter ----------------
__global__ void __launch_bounds__(256) cvt_f2h(
    const float* __restrict__ src, __half* __restrict__ dst, int n4)
{
    int i = blockIdx.x * 256 + threadIdx.x;
    if (i < n4) {
        float4 v = *(const float4*)(src + (size_t)i * 4);
        uint2 p = make_uint2(packh2(v.x, v.y), packh2(v.z, v.w));
        *(uint2*)(dst + (size_t)i * 4) = p;
    }
}

// ================= fp16 m16n8k16 GEMM, half storage =================
// out(MxN) = A(MxK) @ W(NxK)^T + bias [,gelu] [,+res]; A,W half; out f32 or half.
// CTA 128x128, 8 warps (4M x 2N), warp tile 32x64. K staged 16, double-buffered.
// SMEM row = 8 uint32 (16 halves), stride 12 -> fragment banks (12g+tg)%32 bijective.
__global__ void __launch_bounds__(256) fp16_gemm(
    const __half* __restrict__ A, const __half* __restrict__ W,
    const float* __restrict__ bias, const float* __restrict__ res,
    float* __restrict__ out32, __half* __restrict__ out16,
    int M, int N, int K, int act)
{
    __shared__ uint32_t As[2][128][12];
    __shared__ uint32_t Bs[2][128][12];

    const int tid = threadIdx.x;
    const int wid = tid >> 5;
    const int lane = tid & 31;
    const int g = lane >> 2;
    const int tg = lane & 3;
    const int wm = wid & 3;
    const int wn = wid >> 2;
    const int bm = blockIdx.y * 128;
    const int bn = blockIdx.x * 128;

    const int rowL = tid >> 1;               // 0..127
    const int seg = tid & 1;                 // 8-half segment
    const __half* Ap = A + (size_t)(bm + rowL) * K + seg * 8;
    const __half* Wp = W + (size_t)(bn + rowL) * K + seg * 8;

    float acc[2][8][4];
#pragma unroll
    for (int i = 0; i < 2; i++)
#pragma unroll
        for (int j = 0; j < 8; j++)
#pragma unroll
            for (int v = 0; v < 4; v++) acc[i][j][v] = 0.f;

    // prologue
    *(uint4*)&As[0][rowL][seg * 4] = *(const uint4*)(Ap);
    *(uint4*)&Bs[0][rowL][seg * 4] = *(const uint4*)(Wp);
    __syncthreads();

    const int NS = K >> 4;
    uint4 sa, sw;
    for (int s = 0; s < NS; s++) {
        const int buf = s & 1;
        const bool has_next = (s + 1 < NS);
        if (has_next) {
            int k0 = (s + 1) << 4;
            sa = *(const uint4*)(Ap + k0);
            sw = *(const uint4*)(Wp + k0);
        }
        {
            uint32_t af[2][4];
#pragma unroll
            for (int mt = 0; mt < 2; mt++) {
                int ra = wm * 32 + mt * 16 + g;
                af[mt][0] = As[buf][ra][tg];
                af[mt][1] = As[buf][ra + 8][tg];
                af[mt][2] = As[buf][ra][tg + 4];
                af[mt][3] = As[buf][ra + 8][tg + 4];
            }
            uint32_t bf[8][2];
#pragma unroll
            for (int nt = 0; nt < 8; nt++) {
                int cb = wn * 64 + nt * 8 + g;
                bf[nt][0] = Bs[buf][cb][tg];
                bf[nt][1] = Bs[buf][cb][tg + 4];
            }
#pragma unroll
            for (int mt = 0; mt < 2; mt++)
#pragma unroll
                for (int nt = 0; nt < 8; nt++)
                    mma_f16(acc[mt][nt][0], acc[mt][nt][1], acc[mt][nt][2], acc[mt][nt][3],
                            af[mt][0], af[mt][1], af[mt][2], af[mt][3],
                            bf[nt][0], bf[nt][1]);
        }
        if (has_next) {
            int nb = (s + 1) & 1;
            __syncthreads();
            *(uint4*)&As[nb][rowL][seg * 4] = sa;
            *(uint4*)&Bs[nb][rowL][seg * 4] = sw;
            __syncthreads();
        }
    }

    // epilogue (m16n8 C layout, verified)
#pragma unroll
    for (int mt = 0; mt < 2; mt++) {
        int r0 = bm + wm * 32 + mt * 16 + g;
#pragma unroll
        for (int nt = 0; nt < 8; nt++) {
            int col = bn + wn * 64 + nt * 8 + tg * 2;
            float b0 = bias[col], b1 = bias[col + 1];
            float v0 = acc[mt][nt][0] + b0;
            float v1 = acc[mt][nt][1] + b1;
            float v2 = acc[mt][nt][2] + b0;
            float v3 = acc[mt][nt][3] + b1;
            if (act) {
                v0 = 0.5f * v0 * (1.f + erff(v0 * 0.70710678118654752f));
                v1 = 0.5f * v1 * (1.f + erff(v1 * 0.70710678118654752f));
                v2 = 0.5f * v2 * (1.f + erff(v2 * 0.70710678118654752f));
                v3 = 0.5f * v3 * (1.f + erff(v3 * 0.70710678118654752f));
            }
            if (res) {
                const float* rp0 = res + (size_t)r0 * N + col;
                const float* rp1 = rp0 + (size_t)8 * N;
                v0 += rp0[0]; v1 += rp0[1];
                v2 += rp1[0]; v3 += rp1[1];
            }
            if (out32) {
                *(float2*)(out32 + (size_t)r0 * N + col) = make_float2(v0, v1);
                *(float2*)(out32 + (size_t)(r0 + 8) * N + col) = make_float2(v2, v3);
            } else {
                *(uint32_t*)(out16 + (size_t)r0 * N + col) = packh2(v0, v1);
                *(uint32_t*)(out16 + (size_t)(r0 + 8) * N + col) = packh2(v2, v3);
            }
        }
    }
}

// ================= fused flash attention, fp16 mma =================
// Qs stride 36 words (32 data), KP stride 68 (K tile 32 words, P tile 64 words),
// Vs stride 68 (64 data words = 128 halves).  All fragment banks (4g+tg)%32 bijective.
#define QS_ST 36
#define KP_ST 68
#define VS_ST 68
#define FLASH_SMEM ((128*QS_ST + 128*KP_ST + 64*VS_ST + 1024 + 256 + 256) * 4)

__global__ void __launch_bounds__(256) flash_attn(
    const __half* __restrict__ qkv, const float* __restrict__ sz, __half* __restrict__ out)
{
    extern __shared__ uint32_t smw[];
    uint32_t* Qs = smw;                          // [128][36]
    uint32_t* KP = Qs + 128 * QS_ST;             // [128][68]
    uint32_t* Vs = KP + 128 * KP_ST;             // [64][68]  V^T halves
    float* logls = (float*)(Vs + 64 * VS_ST);    // [1024]
    float* redm  = logls + 1024;                 // [2][128]
    float* reds  = redm + 256;                   // [2][128]
    __half* Vs_h = (__half*)Vs;

    const int tid = threadIdx.x;
    const int wid = tid >> 5, lane = tid & 31;
    const int g = lane >> 2, tg = lane & 3;
    const int wm = wid & 3;
    const int wnn = wid >> 2;
    const int bh = blockIdx.y;
    const int b = bh >> 4, h = bh & 15;
    const int n0 = blockIdx.x * 128;
    const __half* qb = qkv + (size_t)b * Nn * 3072 + h * 64;
    const __half* kb = qb + 1024;
    const __half* vb = qb + 2048;

    for (int i = tid; i < 1024; i += 256)
        logls[i] = __logf(sz[b * Nn + i]);

    // load Q (128 x 64 halves): 1024 chunks of 8 halves
#pragma unroll
    for (int i = 0; i < 4; i++) {
        int idx = tid + i * 256;
        int row = idx >> 3;
        int seg = idx & 7;
        *(uint4*)&Qs[row * QS_ST + seg * 4] =
            *(const uint4*)(qb + (size_t)(n0 + row) * 3072 + seg * 8);
    }

    float m_i[2][2], l_i[2][2];
    float acc[2][4][4];
#pragma unroll
    for (int mt = 0; mt < 2; mt++)
#pragma unroll
        for (int rh = 0; rh < 2; rh++) { m_i[mt][rh] = -INFINITY; l_i[mt][rh] = 0.f; }
#pragma unroll
    for (int mt = 0; mt < 2; mt++)
#pragma unroll
        for (int nt = 0; nt < 4; nt++)
#pragma unroll
            for (int v = 0; v < 4; v++) acc[mt][nt][v] = 0.f;

    for (int m0 = 0; m0 < Nn; m0 += 128) {
        __syncthreads();
        // K tile into KP; V tile transposed (halves) into Vs
#pragma unroll
        for (int i = 0; i < 4; i++) {
            int idx = tid + i * 256;
            int row = idx >> 3;
            int seg = idx & 7;
            *(uint4*)&KP[row * KP_ST + seg * 4] =
                *(const uint4*)(kb + (size_t)(m0 + row) * 3072 + seg * 8);
            uint4 vv = *(const uint4*)(vb + (size_t)(m0 + row) * 3072 + seg * 8);
            const __half* vh = (const __half*)&vv;
#pragma unroll
            for (int j = 0; j < 8; j++)
                Vs_h[(seg * 8 + j) * (VS_ST * 2) + row] = vh[j];
        }
        __syncthreads();

        // S = Q @ K^T (128x128), fp16 k16 mma, 4 steps
        float s[2][8][4];
#pragma unroll
        for (int mt = 0; mt < 2; mt++)
#pragma unroll
            for (int nt = 0; nt < 8; nt++)
#pragma unroll
                for (int v = 0; v < 4; v++) s[mt][nt][v] = 0.f;
#pragma unroll
        for (int ks = 0; ks < 32; ks += 8) {     // half2-word steps
            uint32_t af[2][4];
#pragma unroll
            for (int mt = 0; mt < 2; mt++) {
                int ra = wm * 32 + mt * 16 + g;
                af[mt][0] = Qs[ra * QS_ST + ks + tg];
                af[mt][1] = Qs[(ra + 8) * QS_ST + ks + tg];
                af[mt][2] = Qs[ra * QS_ST + ks + tg + 4];
                af[mt][3] = Qs[(ra + 8) * QS_ST + ks + tg + 4];
            }
            uint32_t bf[8][2];
#pragma unroll
            for (int nt = 0; nt < 8; nt++) {
                int cb = wnn * 64 + nt * 8 + g;
                bf[nt][0] = KP[cb * KP_ST + ks + tg];
                bf[nt][1] = KP[cb * KP_ST + ks + tg + 4];
            }
#pragma unroll
            for (int mt = 0; mt < 2; mt++)
#pragma unroll
                for (int nt = 0; nt < 8; nt++)
                    mma_f16(s[mt][nt][0], s[mt][nt][1], s[mt][nt][2], s[mt][nt][3],
                            af[mt][0], af[mt][1], af[mt][2], af[mt][3],
                            bf[nt][0], bf[nt][1]);
        }

        // scale + bias, row maxima
        float tmax[2][2];
#pragma unroll
        for (int mt = 0; mt < 2; mt++) { tmax[mt][0] = -INFINITY; tmax[mt][1] = -INFINITY; }
#pragma unroll
        for (int mt = 0; mt < 2; mt++)
#pragma unroll
            for (int nt = 0; nt < 8; nt++) {
                int col = wnn * 64 + nt * 8 + tg * 2;
                float ls0 = logls[m0 + col];
                float ls1 = logls[m0 + col + 1];
                s[mt][nt][0] = s[mt][nt][0] * 0.125f + ls0;
                s[mt][nt][1] = s[mt][nt][1] * 0.125f + ls1;
                s[mt][nt][2] = s[mt][nt][2] * 0.125f + ls0;
                s[mt][nt][3] = s[mt][nt][3] * 0.125f + ls1;
                tmax[mt][0] = fmaxf(tmax[mt][0], fmaxf(s[mt][nt][0], s[mt][nt][1]));
                tmax[mt][1] = fmaxf(tmax[mt][1], fmaxf(s[mt][nt][2], s[mt][nt][3]));
            }
#pragma unroll
        for (int mt = 0; mt < 2; mt++)
#pragma unroll
            for (int rh = 0; rh < 2; rh++) {
                float v = tmax[mt][rh];
                v = fmaxf(v, __shfl_xor_sync(~0u, v, 1));
                v = fmaxf(v, __shfl_xor_sync(~0u, v, 2));
                tmax[mt][rh] = v;
            }
        if (tg == 0) {
#pragma unroll
            for (int mt = 0; mt < 2; mt++)
#pragma unroll
                for (int rh = 0; rh < 2; rh++)
                    redm[wnn * 128 + wm * 32 + mt * 16 + rh * 8 + g] = tmax[mt][rh];
        }
        __syncthreads();

        float sc[2][2];
#pragma unroll
        for (int mt = 0; mt < 2; mt++)
#pragma unroll
            for (int rh = 0; rh < 2; rh++) {
                int row = wm * 32 + mt * 16 + rh * 8 + g;
                float mx = fmaxf(redm[row], redm[128 + row]);
                float mnew = fmaxf(m_i[mt][rh], mx);
                sc[mt][rh] = __expf(m_i[mt][rh] - mnew);
                m_i[mt][rh] = mnew;
                l_i[mt][rh] *= sc[mt][rh];
            }
#pragma unroll
        for (int mt = 0; mt < 2; mt++)
#pragma unroll
            for (int nt = 0; nt < 4; nt++) {
                acc[mt][nt][0] *= sc[mt][0];
                acc[mt][nt][1] *= sc[mt][0];
                acc[mt][nt][2] *= sc[mt][1];
                acc[mt][nt][3] *= sc[mt][1];
            }

        // exp -> P (half2 packed), partial sums
        float tsum[2][2];
#pragma unroll
        for (int mt = 0; mt < 2; mt++) { tsum[mt][0] = 0.f; tsum[mt][1] = 0.f; }
#pragma unroll
        for (int mt = 0; mt < 2; mt++) {
            int r0 = wm * 32 + mt * 16 + g;
#pragma unroll
            for (int nt = 0; nt < 8; nt++) {
                int w2 = wnn * 32 + nt * 4 + tg;        // half2 word index
                float p0 = __expf(s[mt][nt][0] - m_i[mt][0]);
                float p1 = __expf(s[mt][nt][1] - m_i[mt][0]);
                float p2 = __expf(s[mt][nt][2] - m_i[mt][1]);
                float p3 = __expf(s[mt][nt][3] - m_i[mt][1]);
                tsum[mt][0] += p0 + p1;
                tsum[mt][1] += p2 + p3;
                KP[r0 * KP_ST + w2] = packh2(p0, p1);
                KP[(r0 + 8) * KP_ST + w2] = packh2(p2, p3);
            }
        }
#pragma unroll
        for (int mt = 0; mt < 2; mt++)
#pragma unroll
            for (int rh = 0; rh < 2; rh++) {
                float v = tsum[mt][rh];
                v += __shfl_xor_sync(~0u, v, 1);
                v += __shfl_xor_sync(~0u, v, 2);
                tsum[mt][rh] = v;
            }
        if (tg == 0) {
#pragma unroll
            for (int mt = 0; mt < 2; mt++)
#pragma unroll
                for (int rh = 0; rh < 2; rh++)
                    reds[wnn * 128 + wm * 32 + mt * 16 + rh * 8 + g] = tsum[mt][rh];
        }
        __syncthreads();
#pragma unroll
        for (int mt = 0; mt < 2; mt++)
#pragma unroll
            for (int rh = 0; rh < 2; rh++) {
                int row = wm * 32 + mt * 16 + rh * 8 + g;
                l_i[mt][rh] += reds[row] + reds[128 + row];
            }

        // PV: acc += P(128x128) @ V(128x64), fp16 k16, 8 steps
#pragma unroll
        for (int ks = 0; ks < 64; ks += 8) {     // half2-word steps over 128 k
            uint32_t af[2][4];
#pragma unroll
            for (int mt = 0; mt < 2; mt++) {
                int ra = wm * 32 + mt * 16 + g;
                af[mt][0] = KP[ra * KP_ST + ks + tg];
                af[mt][1] = KP[(ra + 8) * KP_ST + ks + tg];
                af[mt][2] = KP[ra * KP_ST + ks + tg + 4];
                af[mt][3] = KP[(ra + 8) * KP_ST + ks + tg + 4];
            }
            uint32_t bf[4][2];
#pragma unroll
            for (int nt = 0; nt < 4; nt++) {
                int cb = wnn * 32 + nt * 8 + g;
                bf[nt][0] = Vs[cb * VS_ST + ks + tg];
                bf[nt][1] = Vs[cb * VS_ST + ks + tg + 4];
            }
#pragma unroll
            for (int mt = 0; mt < 2; mt++)
#pragma unroll
                for (int nt = 0; nt < 4; nt++)
                    mma_f16(acc[mt][nt][0], acc[mt][nt][1], acc[mt][nt][2], acc[mt][nt][3],
                            af[mt][0], af[mt][1], af[mt][2], af[mt][3],
                            bf[nt][0], bf[nt][1]);
        }
    }

    // normalize, write half2 out[b, n, h*64+d]
#pragma unroll
    for (int mt = 0; mt < 2; mt++) {
        float inv0 = 1.f / l_i[mt][0];
        float inv1 = 1.f / l_i[mt][1];
        int r0 = n0 + wm * 32 + mt * 16 + g;
#pragma unroll
        for (int nt = 0; nt < 4; nt++) {
            int col = h * 64 + wnn * 32 + nt * 8 + tg * 2;
            *(uint32_t*)(out + ((size_t)b * Nn + r0) * Cc + col) =
                packh2(acc[mt][nt][0] * inv0, acc[mt][nt][1] * inv0);
            *(uint32_t*)(out + ((size_t)b * Nn + r0 + 8) * Cc + col) =
                packh2(acc[mt][nt][2] * inv1, acc[mt][nt][3] * inv1);
        }
    }
}

// ---------------- LayerNorm (optional dual fp32 + fp16 output) ----------------
__global__ void __launch_bounds__(256) ln_kernel(
    const float* __restrict__ x, const float* __restrict__ g,
    const float* __restrict__ bta, float* __restrict__ out32,
    __half* __restrict__ out16, int C)
{
    size_t row = blockIdx.x;
    const float* p = x + row * C;
    int tid = threadIdx.x;
    float s = 0.f, s2 = 0.f;
    for (int i = tid; i < C; i += 256) { float v = p[i]; s += v; s2 += v * v; }
    __shared__ float rs[256], rq[256];
    rs[tid] = s; rq[tid] = s2; __syncthreads();
    for (int off = 128; off; off >>= 1) {
        if (tid < off) { rs[tid] += rs[tid + off]; rq[tid] += rq[tid + off]; }
        __syncthreads();
    }
    float mean = rs[0] / (float)C;
    float var  = rq[0] / (float)C - mean * mean;
    float inv  = rsqrtf(var + 1e-5f);
    for (int i = tid; i < C; i += 256) {
        float v = (p[i] - mean) * inv * g[i] + bta[i];
        if (out32) out32[row * C + i] = v;
        out16[row * C + i] = __float2half_rn(v);
    }
}

// ---------------- pooled K weight (exact fp32 metric path) ----------------
__global__ void __launch_bounds__(256) pool_wk(
    const float* __restrict__ qkv_w, const float* __restrict__ qkv_b,
    float* __restrict__ wm, float* __restrict__ wmb)
{
    int idx = blockIdx.x * 256 + threadIdx.x;
    if (idx < 64 * 1024) {
        int d = idx >> 10, k = idx & 1023;
        float s = 0.f;
#pragma unroll
        for (int h = 0; h < 16; h++) s += qkv_w[(size_t)(1024 + h * 64 + d) * 1024 + k];
        wm[idx] = s * (1.f / 16.f);
    }
    if (idx < 64) {
        float s = 0.f;
#pragma unroll
        for (int h = 0; h < 16; h++) s += qkv_b[1024 + h * 64 + idx];
        wmb[idx] = s * (1.f / 16.f);
    }
}

// ---------------- fp32 metric GEMM ----------------
__global__ void __launch_bounds__(256) metric_gemm(
    const float* __restrict__ xln, const float* __restrict__ wm,
    const float* __restrict__ wmb, float* __restrict__ metric)
{
    __shared__ float Xs[32][132];
    __shared__ float Ws[32][68];
    const int bm = blockIdx.x * 128;
    const int tid = threadIdx.x;
    const int ty = tid >> 3;
    const int tx = tid & 7;
    float acc[4][8];
#pragma unroll
    for (int i = 0; i < 4; i++)
#pragma unroll
        for (int j = 0; j < 8; j++) acc[i][j] = 0.f;

    for (int k0 = 0; k0 < 1024; k0 += 32) {
#pragma unroll
        for (int i = 0; i < 4; i++) {
            int idx = tid + i * 256;
            int row = idx >> 3;
            int kq = (idx & 7) << 2;
            float4 v = *(const float4*)(xln + (size_t)(bm + row) * 1024 + k0 + kq);
            Xs[kq][row] = v.x; Xs[kq + 1][row] = v.y; Xs[kq + 2][row] = v.z; Xs[kq + 3][row] = v.w;
        }
        for (int idx = tid; idx < 512; idx += 256) {
            int d = idx >> 3;
            int kq = (idx & 7) << 2;
            float4 v = *(const float4*)(wm + (size_t)d * 1024 + k0 + kq);
            Ws[kq][d] = v.x; Ws[kq + 1][d] = v.y; Ws[kq + 2][d] = v.z; Ws[kq + 3][d] = v.w;
        }
        __syncthreads();
#pragma unroll
        for (int kk = 0; kk < 32; kk++) {
            float a[4], w[8];
#pragma unroll
            for (int i = 0; i < 4; i++) a[i] = Xs[kk][ty * 4 + i];
#pragma unroll
            for (int j = 0; j < 8; j++) w[j] = Ws[kk][tx * 8 + j];
#pragma unroll
            for (int i = 0; i < 4; i++)
#pragma unroll
                for (int j = 0; j < 8; j++) acc[i][j] += a[i] * w[j];
        }
        __syncthreads();
    }
#pragma unroll
    for (int i = 0; i < 4; i++) {
        int row = bm + ty * 4 + i;
#pragma unroll
        for (int j = 0; j < 8; j++)
            metric[(size_t)row * 64 + tx * 8 + j] = acc[i][j] + wmb[tx * 8 + j];
    }
}

__global__ void __launch_bounds__(64) metric_norm(float* __restrict__ metric)
{
    int bn = blockIdx.x;
    int d = threadIdx.x;
    float v = metric[(size_t)bn * 64 + d];
    __shared__ float sh[64];
    sh[d] = v * v; __syncthreads();
    for (int off = 32; off; off >>= 1) {
        if (d < off) sh[d] += sh[d + off];
        __syncthreads();
    }
    float inv = rsqrtf(sh[0]);
    metric[(size_t)bn * 64 + d] = v * inv;
}

// ---------------- matching ----------------
__global__ void __launch_bounds__(256) match_scores(
    const float* __restrict__ metric, float* __restrict__ nodemax, int* __restrict__ nodeidx)
{
    int t = blockIdx.x;
    int b = blockIdx.y;
    const float* mb = metric + (size_t)b * Nn * 64;
    __shared__ float av[64];
    int tid = threadIdx.x;
    if (tid < 64) av[tid] = mb[(size_t)(2 * t) * 64 + tid];
    __syncthreads();
    float best = -INFINITY; int bi = 0;
    for (int s = tid; s < NH; s += 256) {
        const float* bp = mb + (size_t)(2 * s + 1) * 64;
        float dot = 0.f;
#pragma unroll
        for (int d = 0; d < 64; d++) dot += av[d] * bp[d];
        if (dot > best) { best = dot; bi = s; }
    }
    __shared__ float sv[256]; __shared__ int si[256];
    sv[tid] = best; si[tid] = bi; __syncthreads();
    for (int off = 128; off; off >>= 1) {
        if (tid < off) {
            if (sv[tid + off] > sv[tid] ||
                (sv[tid + off] == sv[tid] && si[tid + off] < si[tid])) {
                sv[tid] = sv[tid + off]; si[tid] = si[tid + off];
            }
        }
        __syncthreads();
    }
    if (tid == 0) {
        if (t == 0) { nodemax[b * NH] = -INFINITY; nodeidx[b * NH] = 0; }
        else { nodemax[b * NH + t] = sv[0]; nodeidx[b * NH + t] = si[0]; }
    }
}

__global__ void __launch_bounds__(512) match_sort(
    const float* __restrict__ nodemax, const int* __restrict__ nodeidx,
    int* __restrict__ srcidx, int* __restrict__ dstidx, int* __restrict__ unmidx)
{
    int b = blockIdx.x, t = threadIdx.x;
    __shared__ float v[NH]; __shared__ int rk[NH];
    v[t] = nodemax[b * NH + t]; __syncthreads();
    float vt = v[t]; int r = 0;
    for (int j = 0; j < NH; j++) {
        float vj = v[j];
        r += (vj > vt) || (vj == vt && j < t);
    }
    rk[t] = r; __syncthreads();
    if (r < Rr) {
        srcidx[b * Rr + r] = t;
        dstidx[b * Rr + r] = nodeidx[b * NH + t];
    } else {
        int pos = 0;
        for (int j = 0; j < t; j++) pos += (rk[j] >= Rr);
        unmidx[b * NU + pos] = t;
    }
}

// ---------------- weighted merge + divide by new size ----------------
__global__ void __launch_bounds__(256) merge_kernel(
    const float* __restrict__ xres, const float* __restrict__ sz,
    const int* __restrict__ srcidx, const int* __restrict__ dstidx,
    const int* __restrict__ unmidx, float* __restrict__ xm)
{
    int row = blockIdx.x;
    int b = blockIdx.y;
    int tid = threadIdx.x;
    const float* xb = xres + (size_t)b * Nn * Cc;
    const float* szb = sz + b * Nn;
    float* ob = xm + ((size_t)b * NM + row) * Cc;
    __shared__ int ss[Rr], sd[Rr];

    if (row < NU) {
        int t = 2 * unmidx[b * NU + row];
        float s = szb[t];
        float inv = 1.f / s;
        for (int c = tid; c < Cc; c += 256)
            ob[c] = (xb[(size_t)t * Cc + c] * s) * inv;
    } else {
        int j = row - NU;
        if (tid < Rr) { ss[tid] = srcidx[b * Rr + tid]; sd[tid] = dstidx[b * Rr + tid]; }
        __syncthreads();
        int t = 2 * j + 1;
        float ns = szb[t];
        for (int i = 0; i < Rr; i++)
            if (sd[i] == j) ns += szb[2 * ss[i]];
        float inv = 1.f / ns;
        for (int c = tid; c < Cc; c += 256) {
            float val = xb[(size_t)t * Cc + c] * szb[t];
            for (int i = 0; i < Rr; i++) {
                if (sd[i] == j) {
                    int ts = 2 * ss[i];
                    val += xb[(size_t)ts * Cc + c] * szb[ts];
                }
            }
            ob[c] = val * inv;
        }
    }
}

// ---------------- launch ----------------
template <typename T>
static T* sym_addr(const void* sym) {
    void* p = nullptr;
    cudaGetSymbolAddress(&p, sym);
    return (T*)p;
}

extern "C" void kernel_launch(void* const* d_in, const int* in_sizes, int n_in,
                              void* d_out, int out_size)
{
    const float* x      = (const float*)d_in[0];
    const float* sz     = (const float*)d_in[1];
    const float* qkv_w  = (const float*)d_in[3];
    const float* qkv_b  = (const float*)d_in[4];
    const float* proj_w = (const float*)d_in[5];
    const float* proj_b = (const float*)d_in[6];
    const float* n1g    = (const float*)d_in[7];
    const float* n1b    = (const float*)d_in[8];
    const float* n2g    = (const float*)d_in[9];
    const float* n2b    = (const float*)d_in[10];
    const float* fc1_w  = (const float*)d_in[11];
    const float* fc1_b  = (const float*)d_in[12];
    const float* fc2_w  = (const float*)d_in[13];
    const float* fc2_b  = (const float*)d_in[14];
    float* out = (float*)d_out;

    float*  xln    = sym_addr<float>(g_xln);
    __half* xln_h  = sym_addr<__half>(g_xln_h);
    __half* qkv_h  = sym_addr<__half>(g_qkv_h);
    __half* attno_h= sym_addr<__half>(g_attno_h);
    float*  xres   = sym_addr<float>(g_xres);
    __half* h2_h   = sym_addr<__half>(g_h2_h);
    __half* fc1_h  = sym_addr<__half>(g_fc1_h);
    __half* wqkv_h = sym_addr<__half>(g_wqkv_h);
    __half* wproj_h= sym_addr<__half>(g_wproj_h);
    __half* wfc1_h = sym_addr<__half>(g_wfc1_h);
    __half* wfc2_h = sym_addr<__half>(g_wfc2_h);
    float* wm    = sym_addr<float>(g_wm);
    float* wmb   = sym_addr<float>(g_wmb);
    float* metric= sym_addr<float>(g_metric);
    float* nmax  = sym_addr<float>(g_nodemax);
    int*   nidx  = sym_addr<int>(g_nodeidx);
    int*   sidx  = sym_addr<int>(g_srcidx);
    int*   didx  = sym_addr<int>(g_dstidx);
    int*   uidx  = sym_addr<int>(g_unmidx);
    float* xm    = sym_addr<float>(g_xm);

    cudaFuncSetAttribute(flash_attn, cudaFuncAttributeMaxDynamicSharedMemorySize, FLASH_SMEM);

    // 0. weight conversion (fp32 -> fp16, once per graph replay)
    cvt_f2h<<<(3 * 1024 * 1024 / 4 + 255) / 256, 256>>>(qkv_w, wqkv_h, 3 * 1024 * 1024 / 4);
    cvt_f2h<<<(1024 * 1024 / 4 + 255) / 256, 256>>>(proj_w, wproj_h, 1024 * 1024 / 4);
    cvt_f2h<<<(4 * 1024 * 1024 / 4 + 255) / 256, 256>>>(fc1_w, wfc1_h, 4 * 1024 * 1024 / 4);
    cvt_f2h<<<(4 * 1024 * 1024 / 4 + 255) / 256, 256>>>(fc2_w, wfc2_h, 4 * 1024 * 1024 / 4);

    // 1. LN1 (dual output)
    ln_kernel<<<MROWS, 256>>>(x, n1g, n1b, xln, xln_h, Cc);
    // 2. QKV GEMM -> half
    fp16_gemm<<<dim3(3072 / 128, MROWS / 128), 256>>>(
        xln_h, wqkv_h, qkv_b, nullptr, nullptr, qkv_h, MROWS, 3072, Cc, 0);
    // 3. exact fp32 metric path
    pool_wk<<<256, 256>>>(qkv_w, qkv_b, wm, wmb);
    metric_gemm<<<MROWS / 128, 256>>>(xln, wm, wmb, metric);
    metric_norm<<<Bb * Nn, 64>>>(metric);
    // 4. fused flash attention (fp16) -> half
    flash_attn<<<dim3(8, Bb * Hh), 256, FLASH_SMEM>>>(qkv_h, sz, attno_h);
    // 5. proj + residual -> fp32
    fp16_gemm<<<dim3(Cc / 128, MROWS / 128), 256>>>(
        attno_h, wproj_h, proj_b, x, xres, nullptr, MROWS, Cc, Cc, 0);
    // 6. matching
    match_scores<<<dim3(NH, Bb), 256>>>(metric, nmax, nidx);
    match_sort<<<Bb, NH>>>(nmax, nidx, sidx, didx, uidx);
    // 7. merge
    merge_kernel<<<dim3(NM, Bb), 256>>>(xres, sz, sidx, didx, uidx, xm);
    // 8. LN2 -> half only
    ln_kernel<<<MROWS2, 256>>>(xm, n2g, n2b, nullptr, h2_h, Cc);
    // 9. fc1 + GELU -> half
    fp16_gemm<<<dim3(4096 / 128, MROWS2 / 128), 256>>>(
        h2_h, wfc1_h, fc1_b, nullptr, nullptr, fc1_h, MROWS2, 4096, Cc, 1);
    // 10. fc2 + residual -> out (fp32)
    fp16_gemm<<<dim3(Cc / 128, MROWS2 / 128), 256>>>(
        fc1_h, wfc2_h, fc2_b, xm, out, nullptr, MROWS2, Cc, 4096, 0);
    (void)in_sizes; (void)n_in; (void)out_size;
}

// round 11
// speedup vs baseline: 3.5361x; 1.1582x over previous
#include <cuda_runtime.h>
#include <cuda_bf16.h>
#include <cuda_fp16.h>
#include <math.h>
#include <cstdint>

// Problem constants
#define Bb 16
#define Nn 1024
#define Cc 1024
#define Hh 16
#define HD 64
#define Rr 128
#define NH (Nn/2)          // 512
#define NU (NH - Rr)       // 384 unmerged
#define NM (NU + NH)       // 896 merged tokens
#define MROWS (Bb*Nn)      // 16384
#define MROWS2 (Bb*NM)     // 14336

// ---------------- scratch (static device globals) ----------------
__device__ float  g_xln  [(size_t)MROWS * Cc];           // fp32 (metric path)
__device__ __half g_xln_h[(size_t)MROWS * Cc];
__device__ __half g_qkv_h[(size_t)MROWS * 3 * Cc];
__device__ __half g_attno_h[(size_t)MROWS * Cc];
__device__ float  g_xres [(size_t)MROWS * Cc];
__device__ __half g_h2_h [(size_t)MROWS2 * Cc];
__device__ __half g_fc1_h[(size_t)MROWS2 * 4 * Cc];
__device__ __half g_wqkv_h[(size_t)3 * Cc * Cc];
__device__ __half g_wproj_h[(size_t)Cc * Cc];
__device__ __half g_wfc1_h[(size_t)4 * Cc * Cc];
__device__ __half g_wfc2_h[(size_t)Cc * 4 * Cc];
__device__ float g_wm   [64 * 1024];
__device__ float g_wmb  [64];
__device__ float g_metric[(size_t)Bb * Nn * HD];
__device__ float g_nodemax[Bb * NH];
__device__ int   g_nodeidx[Bb * NH];
__device__ int   g_srcidx[Bb * Rr];
__device__ int   g_dstidx[Bb * Rr];
__device__ int   g_unmidx[Bb * NU];
__device__ float g_xm   [(size_t)MROWS2 * Cc];

__device__ __forceinline__ uint32_t packh2(float x, float y) {
    __half2 h = __floats2half2_rn(x, y);
    return *(uint32_t*)&h;
}

__device__ __forceinline__ void mma_f16(float& d0, float& d1, float& d2, float& d3,
                                        uint32_t a0, uint32_t a1, uint32_t a2, uint32_t a3,
                                        uint32_t b0, uint32_t b1)
{
    asm volatile(
        "mma.sync.aligned.m16n8k16.row.col.f32.f16.f16.f32 "
        "{%0,%1,%2,%3}, {%4,%5,%6,%7}, {%8,%9}, {%0,%1,%2,%3};\n"
        : "+f"(d0), "+f"(d1), "+f"(d2), "+f"(d3)
        : "r"(a0), "r"(a1), "r"(a2), "r"(a3), "r"(b0), "r"(b1));
}

// ---------------- f32 -> f16 converter ----------------
__global__ void __launch_bounds__(256) cvt_f2h(
    const float* __restrict__ src, __half* __restrict__ dst, int n4)
{
    int i = blockIdx.x * 256 + threadIdx.x;
    if (i < n4) {
        float4 v = *(const float4*)(src + (size_t)i * 4);
        uint2 p = make_uint2(packh2(v.x, v.y), packh2(v.z, v.w));
        *(uint2*)(dst + (size_t)i * 4) = p;
    }
}

// ================= fp16 m16n8k16 GEMM, K-stage 32, single-sync =================
// out(MxN) = A(MxK) @ W(NxK)^T + bias [,gelu] [,+res]; A,W half; out f32 or half.
// CTA 128x128, 8 warps (4M x 2N). Stage = 32 halves (16 words), 2 mma bundles/stage.
// SMEM stride 20 words -> fragment banks (20g+tg)%32 bijective (verified R6).
__global__ void __launch_bounds__(256) fp16_gemm(
    const __half* __restrict__ A, const __half* __restrict__ W,
    const float* __restrict__ bias, const float* __restrict__ res,
    float* __restrict__ out32, __half* __restrict__ out16,
    int M, int N, int K, int act)
{
    __shared__ uint32_t As[2][128][20];
    __shared__ uint32_t Bs[2][128][20];

    const int tid = threadIdx.x;
    const int wid = tid >> 5;
    const int lane = tid & 31;
    const int g = lane >> 2;
    const int tg = lane & 3;
    const int wm = wid & 3;
    const int wn = wid >> 2;
    const int bm = blockIdx.y * 128;
    const int bn = blockIdx.x * 128;

    const int rowL = tid >> 1;               // 0..127
    const int half16 = (tid & 1) * 16;       // half offset within the 32-half stage
    const int w8 = (tid & 1) * 8;            // word offset within SMEM row
    const __half* Ap = A + (size_t)(bm + rowL) * K + half16;
    const __half* Wp = W + (size_t)(bn + rowL) * K + half16;

    float acc[2][8][4];
#pragma unroll
    for (int i = 0; i < 2; i++)
#pragma unroll
        for (int j = 0; j < 8; j++)
#pragma unroll
            for (int v = 0; v < 4; v++) acc[i][j][v] = 0.f;

    // prologue: stage 0
    *(uint4*)&As[0][rowL][w8]     = *(const uint4*)(Ap);
    *(uint4*)&As[0][rowL][w8 + 4] = *(const uint4*)(Ap + 8);
    *(uint4*)&Bs[0][rowL][w8]     = *(const uint4*)(Wp);
    *(uint4*)&Bs[0][rowL][w8 + 4] = *(const uint4*)(Wp + 8);
    __syncthreads();

    const int NS = K >> 5;
    uint4 sa0, sa1, sw0, sw1;
    for (int s = 0; s < NS; s++) {
        const int buf = s & 1;
        const bool has_next = (s + 1 < NS);
        if (has_next) {
            int k0 = (s + 1) << 5;
            sa0 = *(const uint4*)(Ap + k0);
            sa1 = *(const uint4*)(Ap + k0 + 8);
            sw0 = *(const uint4*)(Wp + k0);
            sw1 = *(const uint4*)(Wp + k0 + 8);
        }
#pragma unroll
        for (int ks = 0; ks < 16; ks += 8) {
            uint32_t af[2][4];
#pragma unroll
            for (int mt = 0; mt < 2; mt++) {
                int ra = wm * 32 + mt * 16 + g;
                af[mt][0] = As[buf][ra][ks + tg];
                af[mt][1] = As[buf][ra + 8][ks + tg];
                af[mt][2] = As[buf][ra][ks + tg + 4];
                af[mt][3] = As[buf][ra + 8][ks + tg + 4];
            }
            uint32_t bf[8][2];
#pragma unroll
            for (int nt = 0; nt < 8; nt++) {
                int cb = wn * 64 + nt * 8 + g;
                bf[nt][0] = Bs[buf][cb][ks + tg];
                bf[nt][1] = Bs[buf][cb][ks + tg + 4];
            }
#pragma unroll
            for (int mt = 0; mt < 2; mt++)
#pragma unroll
                for (int nt = 0; nt < 8; nt++)
                    mma_f16(acc[mt][nt][0], acc[mt][nt][1], acc[mt][nt][2], acc[mt][nt][3],
                            af[mt][0], af[mt][1], af[mt][2], af[mt][3],
                            bf[nt][0], bf[nt][1]);
        }
        if (has_next) {
            // safe without pre-sync: buf^1 was last READ in stage s-1, which completed
            // before that stage's closing barrier.
            int nb = buf ^ 1;
            *(uint4*)&As[nb][rowL][w8]     = sa0;
            *(uint4*)&As[nb][rowL][w8 + 4] = sa1;
            *(uint4*)&Bs[nb][rowL][w8]     = sw0;
            *(uint4*)&Bs[nb][rowL][w8 + 4] = sw1;
            __syncthreads();
        }
    }

    // epilogue (m16n8 C layout, verified)
#pragma unroll
    for (int mt = 0; mt < 2; mt++) {
        int r0 = bm + wm * 32 + mt * 16 + g;
#pragma unroll
        for (int nt = 0; nt < 8; nt++) {
            int col = bn + wn * 64 + nt * 8 + tg * 2;
            float b0 = bias[col], b1 = bias[col + 1];
            float v0 = acc[mt][nt][0] + b0;
            float v1 = acc[mt][nt][1] + b1;
            float v2 = acc[mt][nt][2] + b0;
            float v3 = acc[mt][nt][3] + b1;
            if (act) {
                v0 = 0.5f * v0 * (1.f + erff(v0 * 0.70710678118654752f));
                v1 = 0.5f * v1 * (1.f + erff(v1 * 0.70710678118654752f));
                v2 = 0.5f * v2 * (1.f + erff(v2 * 0.70710678118654752f));
                v3 = 0.5f * v3 * (1.f + erff(v3 * 0.70710678118654752f));
            }
            if (res) {
                const float* rp0 = res + (size_t)r0 * N + col;
                const float* rp1 = rp0 + (size_t)8 * N;
                v0 += rp0[0]; v1 += rp0[1];
                v2 += rp1[0]; v3 += rp1[1];
            }
            if (out32) {
                *(float2*)(out32 + (size_t)r0 * N + col) = make_float2(v0, v1);
                *(float2*)(out32 + (size_t)(r0 + 8) * N + col) = make_float2(v2, v3);
            } else {
                *(uint32_t*)(out16 + (size_t)r0 * N + col) = packh2(v0, v1);
                *(uint32_t*)(out16 + (size_t)(r0 + 8) * N + col) = packh2(v2, v3);
            }
        }
    }
}

// ================= fused flash attention, fp16 mma (verified R10) =================
#define QS_ST 36
#define KP_ST 68
#define VS_ST 68
#define FLASH_SMEM ((128*QS_ST + 128*KP_ST + 64*VS_ST + 1024 + 256 + 256) * 4)

__global__ void __launch_bounds__(256) flash_attn(
    const __half* __restrict__ qkv, const float* __restrict__ sz, __half* __restrict__ out)
{
    extern __shared__ uint32_t smw[];
    uint32_t* Qs = smw;
    uint32_t* KP = Qs + 128 * QS_ST;
    uint32_t* Vs = KP + 128 * KP_ST;
    float* logls = (float*)(Vs + 64 * VS_ST);
    float* redm  = logls + 1024;
    float* reds  = redm + 256;
    __half* Vs_h = (__half*)Vs;

    const int tid = threadIdx.x;
    const int wid = tid >> 5, lane = tid & 31;
    const int g = lane >> 2, tg = lane & 3;
    const int wm = wid & 3;
    const int wnn = wid >> 2;
    const int bh = blockIdx.y;
    const int b = bh >> 4, h = bh & 15;
    const int n0 = blockIdx.x * 128;
    const __half* qb = qkv + (size_t)b * Nn * 3072 + h * 64;
    const __half* kb = qb + 1024;
    const __half* vb = qb + 2048;

    for (int i = tid; i < 1024; i += 256)
        logls[i] = __logf(sz[b * Nn + i]);

#pragma unroll
    for (int i = 0; i < 4; i++) {
        int idx = tid + i * 256;
        int row = idx >> 3;
        int seg = idx & 7;
        *(uint4*)&Qs[row * QS_ST + seg * 4] =
            *(const uint4*)(qb + (size_t)(n0 + row) * 3072 + seg * 8);
    }

    float m_i[2][2], l_i[2][2];
    float acc[2][4][4];
#pragma unroll
    for (int mt = 0; mt < 2; mt++)
#pragma unroll
        for (int rh = 0; rh < 2; rh++) { m_i[mt][rh] = -INFINITY; l_i[mt][rh] = 0.f; }
#pragma unroll
    for (int mt = 0; mt < 2; mt++)
#pragma unroll
        for (int nt = 0; nt < 4; nt++)
#pragma unroll
            for (int v = 0; v < 4; v++) acc[mt][nt][v] = 0.f;

    for (int m0 = 0; m0 < Nn; m0 += 128) {
        __syncthreads();
#pragma unroll
        for (int i = 0; i < 4; i++) {
            int idx = tid + i * 256;
            int row = idx >> 3;
            int seg = idx & 7;
            *(uint4*)&KP[row * KP_ST + seg * 4] =
                *(const uint4*)(kb + (size_t)(m0 + row) * 3072 + seg * 8);
            uint4 vv = *(const uint4*)(vb + (size_t)(m0 + row) * 3072 + seg * 8);
            const __half* vh = (const __half*)&vv;
#pragma unroll
            for (int j = 0; j < 8; j++)
                Vs_h[(seg * 8 + j) * (VS_ST * 2) + row] = vh[j];
        }
        __syncthreads();

        float s[2][8][4];
#pragma unroll
        for (int mt = 0; mt < 2; mt++)
#pragma unroll
            for (int nt = 0; nt < 8; nt++)
#pragma unroll
                for (int v = 0; v < 4; v++) s[mt][nt][v] = 0.f;
#pragma unroll
        for (int ks = 0; ks < 32; ks += 8) {
            uint32_t af[2][4];
#pragma unroll
            for (int mt = 0; mt < 2; mt++) {
                int ra = wm * 32 + mt * 16 + g;
                af[mt][0] = Qs[ra * QS_ST + ks + tg];
                af[mt][1] = Qs[(ra + 8) * QS_ST + ks + tg];
                af[mt][2] = Qs[ra * QS_ST + ks + tg + 4];
                af[mt][3] = Qs[(ra + 8) * QS_ST + ks + tg + 4];
            }
            uint32_t bf[8][2];
#pragma unroll
            for (int nt = 0; nt < 8; nt++) {
                int cb = wnn * 64 + nt * 8 + g;
                bf[nt][0] = KP[cb * KP_ST + ks + tg];
                bf[nt][1] = KP[cb * KP_ST + ks + tg + 4];
            }
#pragma unroll
            for (int mt = 0; mt < 2; mt++)
#pragma unroll
                for (int nt = 0; nt < 8; nt++)
                    mma_f16(s[mt][nt][0], s[mt][nt][1], s[mt][nt][2], s[mt][nt][3],
                            af[mt][0], af[mt][1], af[mt][2], af[mt][3],
                            bf[nt][0], bf[nt][1]);
        }

        float tmax[2][2];
#pragma unroll
        for (int mt = 0; mt < 2; mt++) { tmax[mt][0] = -INFINITY; tmax[mt][1] = -INFINITY; }
#pragma unroll
        for (int mt = 0; mt < 2; mt++)
#pragma unroll
            for (int nt = 0; nt < 8; nt++) {
                int col = wnn * 64 + nt * 8 + tg * 2;
                float ls0 = logls[m0 + col];
                float ls1 = logls[m0 + col + 1];
                s[mt][nt][0] = s[mt][nt][0] * 0.125f + ls0;
                s[mt][nt][1] = s[mt][nt][1] * 0.125f + ls1;
                s[mt][nt][2] = s[mt][nt][2] * 0.125f + ls0;
                s[mt][nt][3] = s[mt][nt][3] * 0.125f + ls1;
                tmax[mt][0] = fmaxf(tmax[mt][0], fmaxf(s[mt][nt][0], s[mt][nt][1]));
                tmax[mt][1] = fmaxf(tmax[mt][1], fmaxf(s[mt][nt][2], s[mt][nt][3]));
            }
#pragma unroll
        for (int mt = 0; mt < 2; mt++)
#pragma unroll
            for (int rh = 0; rh < 2; rh++) {
                float v = tmax[mt][rh];
                v = fmaxf(v, __shfl_xor_sync(~0u, v, 1));
                v = fmaxf(v, __shfl_xor_sync(~0u, v, 2));
                tmax[mt][rh] = v;
            }
        if (tg == 0) {
#pragma unroll
            for (int mt = 0; mt < 2; mt++)
#pragma unroll
                for (int rh = 0; rh < 2; rh++)
                    redm[wnn * 128 + wm * 32 + mt * 16 + rh * 8 + g] = tmax[mt][rh];
        }
        __syncthreads();

        float sc[2][2];
#pragma unroll
        for (int mt = 0; mt < 2; mt++)
#pragma unroll
            for (int rh = 0; rh < 2; rh++) {
                int row = wm * 32 + mt * 16 + rh * 8 + g;
                float mx = fmaxf(redm[row], redm[128 + row]);
                float mnew = fmaxf(m_i[mt][rh], mx);
                sc[mt][rh] = __expf(m_i[mt][rh] - mnew);
                m_i[mt][rh] = mnew;
                l_i[mt][rh] *= sc[mt][rh];
            }
#pragma unroll
        for (int mt = 0; mt < 2; mt++)
#pragma unroll
            for (int nt = 0; nt < 4; nt++) {
                acc[mt][nt][0] *= sc[mt][0];
                acc[mt][nt][1] *= sc[mt][0];
                acc[mt][nt][2] *= sc[mt][1];
                acc[mt][nt][3] *= sc[mt][1];
            }

        float tsum[2][2];
#pragma unroll
        for (int mt = 0; mt < 2; mt++) { tsum[mt][0] = 0.f; tsum[mt][1] = 0.f; }
#pragma unroll
        for (int mt = 0; mt < 2; mt++) {
            int r0 = wm * 32 + mt * 16 + g;
#pragma unroll
            for (int nt = 0; nt < 8; nt++) {
                int w2 = wnn * 32 + nt * 4 + tg;
                float p0 = __expf(s[mt][nt][0] - m_i[mt][0]);
                float p1 = __expf(s[mt][nt][1] - m_i[mt][0]);
                float p2 = __expf(s[mt][nt][2] - m_i[mt][1]);
                float p3 = __expf(s[mt][nt][3] - m_i[mt][1]);
                tsum[mt][0] += p0 + p1;
                tsum[mt][1] += p2 + p3;
                KP[r0 * KP_ST + w2] = packh2(p0, p1);
                KP[(r0 + 8) * KP_ST + w2] = packh2(p2, p3);
            }
        }
#pragma unroll
        for (int mt = 0; mt < 2; mt++)
#pragma unroll
            for (int rh = 0; rh < 2; rh++) {
                float v = tsum[mt][rh];
                v += __shfl_xor_sync(~0u, v, 1);
                v += __shfl_xor_sync(~0u, v, 2);
                tsum[mt][rh] = v;
            }
        if (tg == 0) {
#pragma unroll
            for (int mt = 0; mt < 2; mt++)
#pragma unroll
                for (int rh = 0; rh < 2; rh++)
                    reds[wnn * 128 + wm * 32 + mt * 16 + rh * 8 + g] = tsum[mt][rh];
        }
        __syncthreads();
#pragma unroll
        for (int mt = 0; mt < 2; mt++)
#pragma unroll
            for (int rh = 0; rh < 2; rh++) {
                int row = wm * 32 + mt * 16 + rh * 8 + g;
                l_i[mt][rh] += reds[row] + reds[128 + row];
            }

#pragma unroll
        for (int ks = 0; ks < 64; ks += 8) {
            uint32_t af[2][4];
#pragma unroll
            for (int mt = 0; mt < 2; mt++) {
                int ra = wm * 32 + mt * 16 + g;
                af[mt][0] = KP[ra * KP_ST + ks + tg];
                af[mt][1] = KP[(ra + 8) * KP_ST + ks + tg];
                af[mt][2] = KP[ra * KP_ST + ks + tg + 4];
                af[mt][3] = KP[(ra + 8) * KP_ST + ks + tg + 4];
            }
            uint32_t bf[4][2];
#pragma unroll
            for (int nt = 0; nt < 4; nt++) {
                int cb = wnn * 32 + nt * 8 + g;
                bf[nt][0] = Vs[cb * VS_ST + ks + tg];
                bf[nt][1] = Vs[cb * VS_ST + ks + tg + 4];
            }
#pragma unroll
            for (int mt = 0; mt < 2; mt++)
#pragma unroll
                for (int nt = 0; nt < 4; nt++)
                    mma_f16(acc[mt][nt][0], acc[mt][nt][1], acc[mt][nt][2], acc[mt][nt][3],
                            af[mt][0], af[mt][1], af[mt][2], af[mt][3],
                            bf[nt][0], bf[nt][1]);
        }
    }

#pragma unroll
    for (int mt = 0; mt < 2; mt++) {
        float inv0 = 1.f / l_i[mt][0];
        float inv1 = 1.f / l_i[mt][1];
        int r0 = n0 + wm * 32 + mt * 16 + g;
#pragma unroll
        for (int nt = 0; nt < 4; nt++) {
            int col = h * 64 + wnn * 32 + nt * 8 + tg * 2;
            *(uint32_t*)(out + ((size_t)b * Nn + r0) * Cc + col) =
                packh2(acc[mt][nt][0] * inv0, acc[mt][nt][1] * inv0);
            *(uint32_t*)(out + ((size_t)b * Nn + r0 + 8) * Cc + col) =
                packh2(acc[mt][nt][2] * inv1, acc[mt][nt][3] * inv1);
        }
    }
}

// ---------------- LayerNorm (optional dual fp32 + fp16 output) ----------------
__global__ void __launch_bounds__(256) ln_kernel(
    const float* __restrict__ x, const float* __restrict__ g,
    const float* __restrict__ bta, float* __restrict__ out32,
    __half* __restrict__ out16, int C)
{
    size_t row = blockIdx.x;
    const float* p = x + row * C;
    int tid = threadIdx.x;
    float s = 0.f, s2 = 0.f;
    for (int i = tid; i < C; i += 256) { float v = p[i]; s += v; s2 += v * v; }
    __shared__ float rs[256], rq[256];
    rs[tid] = s; rq[tid] = s2; __syncthreads();
    for (int off = 128; off; off >>= 1) {
        if (tid < off) { rs[tid] += rs[tid + off]; rq[tid] += rq[tid + off]; }
        __syncthreads();
    }
    float mean = rs[0] / (float)C;
    float var  = rq[0] / (float)C - mean * mean;
    float inv  = rsqrtf(var + 1e-5f);
    for (int i = tid; i < C; i += 256) {
        float v = (p[i] - mean) * inv * g[i] + bta[i];
        if (out32) out32[row * C + i] = v;
        out16[row * C + i] = __float2half_rn(v);
    }
}

// ---------------- pooled K weight (exact fp32 metric path) ----------------
__global__ void __launch_bounds__(256) pool_wk(
    const float* __restrict__ qkv_w, const float* __restrict__ qkv_b,
    float* __restrict__ wm, float* __restrict__ wmb)
{
    int idx = blockIdx.x * 256 + threadIdx.x;
    if (idx < 64 * 1024) {
        int d = idx >> 10, k = idx & 1023;
        float s = 0.f;
#pragma unroll
        for (int h = 0; h < 16; h++) s += qkv_w[(size_t)(1024 + h * 64 + d) * 1024 + k];
        wm[idx] = s * (1.f / 16.f);
    }
    if (idx < 64) {
        float s = 0.f;
#pragma unroll
        for (int h = 0; h < 16; h++) s += qkv_b[1024 + h * 64 + idx];
        wmb[idx] = s * (1.f / 16.f);
    }
}

// ---------------- fp32 metric GEMM ----------------
__global__ void __launch_bounds__(256) metric_gemm(
    const float* __restrict__ xln, const float* __restrict__ wm,
    const float* __restrict__ wmb, float* __restrict__ metric)
{
    __shared__ float Xs[32][132];
    __shared__ float Ws[32][68];
    const int bm = blockIdx.x * 128;
    const int tid = threadIdx.x;
    const int ty = tid >> 3;
    const int tx = tid & 7;
    float acc[4][8];
#pragma unroll
    for (int i = 0; i < 4; i++)
#pragma unroll
        for (int j = 0; j < 8; j++) acc[i][j] = 0.f;

    for (int k0 = 0; k0 < 1024; k0 += 32) {
#pragma unroll
        for (int i = 0; i < 4; i++) {
            int idx = tid + i * 256;
            int row = idx >> 3;
            int kq = (idx & 7) << 2;
            float4 v = *(const float4*)(xln + (size_t)(bm + row) * 1024 + k0 + kq);
            Xs[kq][row] = v.x; Xs[kq + 1][row] = v.y; Xs[kq + 2][row] = v.z; Xs[kq + 3][row] = v.w;
        }
        for (int idx = tid; idx < 512; idx += 256) {
            int d = idx >> 3;
            int kq = (idx & 7) << 2;
            float4 v = *(const float4*)(wm + (size_t)d * 1024 + k0 + kq);
            Ws[kq][d] = v.x; Ws[kq + 1][d] = v.y; Ws[kq + 2][d] = v.z; Ws[kq + 3][d] = v.w;
        }
        __syncthreads();
#pragma unroll
        for (int kk = 0; kk < 32; kk++) {
            float a[4], w[8];
#pragma unroll
            for (int i = 0; i < 4; i++) a[i] = Xs[kk][ty * 4 + i];
#pragma unroll
            for (int j = 0; j < 8; j++) w[j] = Ws[kk][tx * 8 + j];
#pragma unroll
            for (int i = 0; i < 4; i++)
#pragma unroll
                for (int j = 0; j < 8; j++) acc[i][j] += a[i] * w[j];
        }
        __syncthreads();
    }
#pragma unroll
    for (int i = 0; i < 4; i++) {
        int row = bm + ty * 4 + i;
#pragma unroll
        for (int j = 0; j < 8; j++)
            metric[(size_t)row * 64 + tx * 8 + j] = acc[i][j] + wmb[tx * 8 + j];
    }
}

__global__ void __launch_bounds__(64) metric_norm(float* __restrict__ metric)
{
    int bn = blockIdx.x;
    int d = threadIdx.x;
    float v = metric[(size_t)bn * 64 + d];
    __shared__ float sh[64];
    sh[d] = v * v; __syncthreads();
    for (int off = 32; off; off >>= 1) {
        if (d < off) sh[d] += sh[d + off];
        __syncthreads();
    }
    float inv = rsqrtf(sh[0]);
    metric[(size_t)bn * 64 + d] = v * inv;
}

// ---------------- matching ----------------
__global__ void __launch_bounds__(256) match_scores(
    const float* __restrict__ metric, float* __restrict__ nodemax, int* __restrict__ nodeidx)
{
    int t = blockIdx.x;
    int b = blockIdx.y;
    const float* mb = metric + (size_t)b * Nn * 64;
    __shared__ float av[64];
    int tid = threadIdx.x;
    if (tid < 64) av[tid] = mb[(size_t)(2 * t) * 64 + tid];
    __syncthreads();
    float best = -INFINITY; int bi = 0;
    for (int s = tid; s < NH; s += 256) {
        const float* bp = mb + (size_t)(2 * s + 1) * 64;
        float dot = 0.f;
#pragma unroll
        for (int d = 0; d < 64; d++) dot += av[d] * bp[d];
        if (dot > best) { best = dot; bi = s; }
    }
    __shared__ float sv[256]; __shared__ int si[256];
    sv[tid] = best; si[tid] = bi; __syncthreads();
    for (int off = 128; off; off >>= 1) {
        if (tid < off) {
            if (sv[tid + off] > sv[tid] ||
                (sv[tid + off] == sv[tid] && si[tid + off] < si[tid])) {
                sv[tid] = sv[tid + off]; si[tid] = si[tid + off];
            }
        }
        __syncthreads();
    }
    if (tid == 0) {
        if (t == 0) { nodemax[b * NH] = -INFINITY; nodeidx[b * NH] = 0; }
        else { nodemax[b * NH + t] = sv[0]; nodeidx[b * NH + t] = si[0]; }
    }
}

__global__ void __launch_bounds__(512) match_sort(
    const float* __restrict__ nodemax, const int* __restrict__ nodeidx,
    int* __restrict__ srcidx, int* __restrict__ dstidx, int* __restrict__ unmidx)
{
    int b = blockIdx.x, t = threadIdx.x;
    __shared__ float v[NH]; __shared__ int rk[NH];
    v[t] = nodemax[b * NH + t]; __syncthreads();
    float vt = v[t]; int r = 0;
    for (int j = 0; j < NH; j++) {
        float vj = v[j];
        r += (vj > vt) || (vj == vt && j < t);
    }
    rk[t] = r; __syncthreads();
    if (r < Rr) {
        srcidx[b * Rr + r] = t;
        dstidx[b * Rr + r] = nodeidx[b * NH + t];
    } else {
        int pos = 0;
        for (int j = 0; j < t; j++) pos += (rk[j] >= Rr);
        unmidx[b * NU + pos] = t;
    }
}

// ---------------- weighted merge + divide by new size (match-list version) ----
__global__ void __launch_bounds__(256) merge_kernel(
    const float* __restrict__ xres, const float* __restrict__ sz,
    const int* __restrict__ srcidx, const int* __restrict__ dstidx,
    const int* __restrict__ unmidx, float* __restrict__ xm)
{
    int row = blockIdx.x;
    int b = blockIdx.y;
    int tid = threadIdx.x;
    const float* xb = xres + (size_t)b * Nn * Cc;
    const float* szb = sz + b * Nn;
    float* ob = xm + ((size_t)b * NM + row) * Cc;

    if (row < NU) {
        int t = 2 * unmidx[b * NU + row];
        float s = szb[t];
        float inv = 1.f / s;
        for (int c = tid; c < Cc; c += 256)
            ob[c] = (xb[(size_t)t * Cc + c] * s) * inv;
    } else {
        int j = row - NU;
        __shared__ int sd[Rr], ss[Rr];
        __shared__ int mls[Rr]; __shared__ float msz[Rr];
        __shared__ int nmz; __shared__ float nsz;
        if (tid < Rr) { ss[tid] = srcidx[b * Rr + tid]; sd[tid] = dstidx[b * Rr + tid]; }
        __syncthreads();
        int t = 2 * j + 1;
        if (tid == 0) {
            int n = 0;
            float ns = szb[t];
            for (int i = 0; i < Rr; i++) {
                if (sd[i] == j) {
                    int ts = 2 * ss[i];
                    float s2 = szb[ts];
                    mls[n] = ts; msz[n] = s2; ns += s2; n++;
                }
            }
            nmz = n; nsz = ns;
        }
        __syncthreads();
        int nm = nmz;
        float inv = 1.f / nsz;
        float st = szb[t];
        for (int c = tid; c < Cc; c += 256) {
            float val = xb[(size_t)t * Cc + c] * st;
            for (int i = 0; i < nm; i++)
                val += xb[(size_t)mls[i] * Cc + c] * msz[i];
            ob[c] = val * inv;
        }
    }
}

// ---------------- launch ----------------
template <typename T>
static T* sym_addr(const void* sym) {
    void* p = nullptr;
    cudaGetSymbolAddress(&p, sym);
    return (T*)p;
}

extern "C" void kernel_launch(void* const* d_in, const int* in_sizes, int n_in,
                              void* d_out, int out_size)
{
    const float* x      = (const float*)d_in[0];
    const float* sz     = (const float*)d_in[1];
    const float* qkv_w  = (const float*)d_in[3];
    const float* qkv_b  = (const float*)d_in[4];
    const float* proj_w = (const float*)d_in[5];
    const float* proj_b = (const float*)d_in[6];
    const float* n1g    = (const float*)d_in[7];
    const float* n1b    = (const float*)d_in[8];
    const float* n2g    = (const float*)d_in[9];
    const float* n2b    = (const float*)d_in[10];
    const float* fc1_w  = (const float*)d_in[11];
    const float* fc1_b  = (const float*)d_in[12];
    const float* fc2_w  = (const float*)d_in[13];
    const float* fc2_b  = (const float*)d_in[14];
    float* out = (float*)d_out;

    float*  xln    = sym_addr<float>(g_xln);
    __half* xln_h  = sym_addr<__half>(g_xln_h);
    __half* qkv_h  = sym_addr<__half>(g_qkv_h);
    __half* attno_h= sym_addr<__half>(g_attno_h);
    float*  xres   = sym_addr<float>(g_xres);
    __half* h2_h   = sym_addr<__half>(g_h2_h);
    __half* fc1_h  = sym_addr<__half>(g_fc1_h);
    __half* wqkv_h = sym_addr<__half>(g_wqkv_h);
    __half* wproj_h= sym_addr<__half>(g_wproj_h);
    __half* wfc1_h = sym_addr<__half>(g_wfc1_h);
    __half* wfc2_h = sym_addr<__half>(g_wfc2_h);
    float* wm    = sym_addr<float>(g_wm);
    float* wmb   = sym_addr<float>(g_wmb);
    float* metric= sym_addr<float>(g_metric);
    float* nmax  = sym_addr<float>(g_nodemax);
    int*   nidx  = sym_addr<int>(g_nodeidx);
    int*   sidx  = sym_addr<int>(g_srcidx);
    int*   didx  = sym_addr<int>(g_dstidx);
    int*   uidx  = sym_addr<int>(g_unmidx);
    float* xm    = sym_addr<float>(g_xm);

    cudaFuncSetAttribute(flash_attn, cudaFuncAttributeMaxDynamicSharedMemorySize, FLASH_SMEM);

    // 0. weight conversion (fp32 -> fp16)
    cvt_f2h<<<(3 * 1024 * 1024 / 4 + 255) / 256, 256>>>(qkv_w, wqkv_h, 3 * 1024 * 1024 / 4);
    cvt_f2h<<<(1024 * 1024 / 4 + 255) / 256, 256>>>(proj_w, wproj_h, 1024 * 1024 / 4);
    cvt_f2h<<<(4 * 1024 * 1024 / 4 + 255) / 256, 256>>>(fc1_w, wfc1_h, 4 * 1024 * 1024 / 4);
    cvt_f2h<<<(4 * 1024 * 1024 / 4 + 255) / 256, 256>>>(fc2_w, wfc2_h, 4 * 1024 * 1024 / 4);

    // 1. LN1 (dual output)
    ln_kernel<<<MROWS, 256>>>(x, n1g, n1b, xln, xln_h, Cc);
    // 2. QKV GEMM -> half
    fp16_gemm<<<dim3(3072 / 128, MROWS / 128), 256>>>(
        xln_h, wqkv_h, qkv_b, nullptr, nullptr, qkv_h, MROWS, 3072, Cc, 0);
    // 3. exact fp32 metric path
    pool_wk<<<256, 256>>>(qkv_w, qkv_b, wm, wmb);
    metric_gemm<<<MROWS / 128, 256>>>(xln, wm, wmb, metric);
    metric_norm<<<Bb * Nn, 64>>>(metric);
    // 4. fused flash attention (fp16) -> half
    flash_attn<<<dim3(8, Bb * Hh), 256, FLASH_SMEM>>>(qkv_h, sz, attno_h);
    // 5. proj + residual -> fp32
    fp16_gemm<<<dim3(Cc / 128, MROWS / 128), 256>>>(
        attno_h, wproj_h, proj_b, x, xres, nullptr, MROWS, Cc, Cc, 0);
    // 6. matching
    match_scores<<<dim3(NH, Bb), 256>>>(metric, nmax, nidx);
    match_sort<<<Bb, NH>>>(nmax, nidx, sidx, didx, uidx);
    // 7. merge
    merge_kernel<<<dim3(NM, Bb), 256>>>(xres, sz, sidx, didx, uidx, xm);
    // 8. LN2 -> half only
    ln_kernel<<<MROWS2, 256>>>(xm, n2g, n2b, nullptr, h2_h, Cc);
    // 9. fc1 + GELU -> half
    fp16_gemm<<<dim3(4096 / 128, MROWS2 / 128), 256>>>(
        h2_h, wfc1_h, fc1_b, nullptr, nullptr, fc1_h, MROWS2, 4096, Cc, 1);
    // 10. fc2 + residual -> out (fp32)
    fp16_gemm<<<dim3(Cc / 128, MROWS2 / 128), 256>>>(
        fc1_h, wfc2_h, fc2_b, xm, out, nullptr, MROWS2, Cc, 4096, 0);
    (void)in_sizes; (void)n_in; (void)out_size;
}

// round 12
// speedup vs baseline: 4.2922x; 1.2138x over previous
#include <cuda_runtime.h>
#include <cuda_bf16.h>
#include <cuda_fp16.h>
#include <math.h>
#include <cstdint>

// Problem constants
#define Bb 16
#define Nn 1024
#define Cc 1024
#define Hh 16
#define HD 64
#define Rr 128
#define NH (Nn/2)          // 512
#define NU (NH - Rr)       // 384 unmerged
#define NM (NU + NH)       // 896 merged tokens
#define MROWS (Bb*Nn)      // 16384
#define MROWS2 (Bb*NM)     // 14336

// ---------------- scratch (static device globals) ----------------
__device__ float  g_xln  [(size_t)MROWS * Cc];           // fp32 (metric path)
__device__ __half g_xln_h[(size_t)MROWS * Cc];
__device__ __half g_qkv_h[(size_t)MROWS * 3 * Cc];
__device__ __half g_attno_h[(size_t)MROWS * Cc];
__device__ float  g_xres [(size_t)MROWS * Cc];
__device__ __half g_h2_h [(size_t)MROWS2 * Cc];
__device__ __half g_fc1_h[(size_t)MROWS2 * 4 * Cc];
__device__ __half g_wqkv_h[(size_t)3 * Cc * Cc];
__device__ __half g_wproj_h[(size_t)Cc * Cc];
__device__ __half g_wfc1_h[(size_t)4 * Cc * Cc];
__device__ __half g_wfc2_h[(size_t)Cc * 4 * Cc];
__device__ float g_wm   [64 * 1024];
__device__ float g_wmb  [64];
__device__ float g_metric[(size_t)Bb * Nn * HD];
__device__ float g_nodemax[Bb * NH];
__device__ int   g_nodeidx[Bb * NH];
__device__ int   g_srcidx[Bb * Rr];
__device__ int   g_dstidx[Bb * Rr];
__device__ int   g_unmidx[Bb * NU];
__device__ float g_xm   [(size_t)MROWS2 * Cc];

__device__ __forceinline__ uint32_t packh2(float x, float y) {
    __half2 h = __floats2half2_rn(x, y);
    return *(uint32_t*)&h;
}
__device__ __forceinline__ uint32_t smem_u32(const void* p) {
    uint32_t a;
    asm("{ .reg .u64 t; cvta.to.shared.u64 t, %1; cvt.u32.u64 %0, t; }" : "=r"(a) : "l"(p));
    return a;
}
#define CPA16(dst, src) \
    asm volatile("cp.async.cg.shared.global [%0], [%1], 16;" :: "r"(dst), "l"(src))
#define CP_COMMIT() asm volatile("cp.async.commit_group;" ::: "memory")
#define CP_WAIT1()  asm volatile("cp.async.wait_group 1;" ::: "memory")

__device__ __forceinline__ void mma_f16(float& d0, float& d1, float& d2, float& d3,
                                        uint32_t a0, uint32_t a1, uint32_t a2, uint32_t a3,
                                        uint32_t b0, uint32_t b1)
{
    asm volatile(
        "mma.sync.aligned.m16n8k16.row.col.f32.f16.f16.f32 "
        "{%0,%1,%2,%3}, {%4,%5,%6,%7}, {%8,%9}, {%0,%1,%2,%3};\n"
        : "+f"(d0), "+f"(d1), "+f"(d2), "+f"(d3)
        : "r"(a0), "r"(a1), "r"(a2), "r"(a3), "r"(b0), "r"(b1));
}

// ---------------- f32 -> f16 converter ----------------
__global__ void __launch_bounds__(256) cvt_f2h(
    const float* __restrict__ src, __half* __restrict__ dst, int n4)
{
    int i = blockIdx.x * 256 + threadIdx.x;
    if (i < n4) {
        float4 v = *(const float4*)(src + (size_t)i * 4);
        uint2 p = make_uint2(packh2(v.x, v.y), packh2(v.z, v.w));
        *(uint2*)(dst + (size_t)i * 4) = p;
    }
}

// ================= fp16 m16n8k16 GEMM, cp.async 3-stage pipeline =================
// out(MxN) = A(MxK) @ W(NxK)^T + bias [,gelu] [,+res]; A,W half; out f32 or half.
// CTA 128x128, 8 warps (4M x 2N). Stage = 32 halves. SMEM ring of 3 buffers,
// stride 20 words -> fragment banks (20g+tg)%32 bijective (verified R6).
#define GEMM_BUF_WORDS (128 * 20)
#define GEMM_SMEM (3 * GEMM_BUF_WORDS * 4 * 2)

__global__ void __launch_bounds__(256) fp16_gemm(
    const __half* __restrict__ A, const __half* __restrict__ W,
    const float* __restrict__ bias, const float* __restrict__ res,
    float* __restrict__ out32, __half* __restrict__ out16,
    int M, int N, int K, int act)
{
    extern __shared__ uint32_t smg[];
    uint32_t* As = smg;                          // [3][128][20]
    uint32_t* Bs = smg + 3 * GEMM_BUF_WORDS;     // [3][128][20]

    const int tid = threadIdx.x;
    const int wid = tid >> 5;
    const int lane = tid & 31;
    const int g = lane >> 2;
    const int tg = lane & 3;
    const int wm = wid & 3;
    const int wn = wid >> 2;
    const int bm = blockIdx.y * 128;
    const int bn = blockIdx.x * 128;

    const int rowL = tid >> 1;               // 0..127
    const int half16 = (tid & 1) * 16;
    const int w8 = (tid & 1) * 8;
    const __half* Ap = A + (size_t)(bm + rowL) * K + half16;
    const __half* Wp = W + (size_t)(bn + rowL) * K + half16;
    const uint32_t aDst = smem_u32(&As[rowL * 20 + w8]);
    const uint32_t bDst = smem_u32(&Bs[rowL * 20 + w8]);
    const uint32_t BUFB = GEMM_BUF_WORDS * 4;    // bytes per buffer

    float acc[2][8][4];
#pragma unroll
    for (int i = 0; i < 2; i++)
#pragma unroll
        for (int j = 0; j < 8; j++)
#pragma unroll
            for (int v = 0; v < 4; v++) acc[i][j][v] = 0.f;

    const int NS = K >> 5;
    // prologue: stages 0,1 in flight
    {
        CPA16(aDst, Ap); CPA16(aDst + 16, Ap + 8);
        CPA16(bDst, Wp); CPA16(bDst + 16, Wp + 8);
        CP_COMMIT();
        if (NS > 1) {
            size_t k0 = 32;
            CPA16(aDst + BUFB, Ap + k0); CPA16(aDst + BUFB + 16, Ap + k0 + 8);
            CPA16(bDst + BUFB, Wp + k0); CPA16(bDst + BUFB + 16, Wp + k0 + 8);
        }
        CP_COMMIT();
        CP_WAIT1();            // stage 0 resident
        __syncthreads();
    }

    for (int s = 0; s < NS; s++) {
        const int buf = s % 3;
        const uint32_t* Ab = As + buf * GEMM_BUF_WORDS;
        const uint32_t* Bbp = Bs + buf * GEMM_BUF_WORDS;
#pragma unroll
        for (int ks = 0; ks < 16; ks += 8) {
            uint32_t af[2][4];
#pragma unroll
            for (int mt = 0; mt < 2; mt++) {
                int ra = wm * 32 + mt * 16 + g;
                af[mt][0] = Ab[ra * 20 + ks + tg];
                af[mt][1] = Ab[(ra + 8) * 20 + ks + tg];
                af[mt][2] = Ab[ra * 20 + ks + tg + 4];
                af[mt][3] = Ab[(ra + 8) * 20 + ks + tg + 4];
            }
            uint32_t bf[8][2];
#pragma unroll
            for (int nt = 0; nt < 8; nt++) {
                int cb = wn * 64 + nt * 8 + g;
                bf[nt][0] = Bbp[cb * 20 + ks + tg];
                bf[nt][1] = Bbp[cb * 20 + ks + tg + 4];
            }
#pragma unroll
            for (int mt = 0; mt < 2; mt++)
#pragma unroll
                for (int nt = 0; nt < 8; nt++)
                    mma_f16(acc[mt][nt][0], acc[mt][nt][1], acc[mt][nt][2], acc[mt][nt][3],
                            af[mt][0], af[mt][1], af[mt][2], af[mt][3],
                            bf[nt][0], bf[nt][1]);
        }
        if (s + 1 < NS) {
            if (s + 2 < NS) {
                // buffer (s+2)%3 was last READ in stage s-1 (all threads past that
                // stage's closing barrier) -> safe to overwrite.
                int q = (s + 2) % 3;
                size_t k0 = (size_t)(s + 2) << 5;
                CPA16(aDst + q * BUFB, Ap + k0); CPA16(aDst + q * BUFB + 16, Ap + k0 + 8);
                CPA16(bDst + q * BUFB, Wp + k0); CPA16(bDst + q * BUFB + 16, Wp + k0 + 8);
            }
            CP_COMMIT();       // group for stage s+2 (possibly empty)
            CP_WAIT1();        // everything except newest -> stage s+1 resident
            __syncthreads();
        }
    }

    // epilogue (m16n8 C layout, verified)
#pragma unroll
    for (int mt = 0; mt < 2; mt++) {
        int r0 = bm + wm * 32 + mt * 16 + g;
#pragma unroll
        for (int nt = 0; nt < 8; nt++) {
            int col = bn + wn * 64 + nt * 8 + tg * 2;
            float b0 = bias[col], b1 = bias[col + 1];
            float v0 = acc[mt][nt][0] + b0;
            float v1 = acc[mt][nt][1] + b1;
            float v2 = acc[mt][nt][2] + b0;
            float v3 = acc[mt][nt][3] + b1;
            if (act) {
                v0 = 0.5f * v0 * (1.f + erff(v0 * 0.70710678118654752f));
                v1 = 0.5f * v1 * (1.f + erff(v1 * 0.70710678118654752f));
                v2 = 0.5f * v2 * (1.f + erff(v2 * 0.70710678118654752f));
                v3 = 0.5f * v3 * (1.f + erff(v3 * 0.70710678118654752f));
            }
            if (res) {
                const float* rp0 = res + (size_t)r0 * N + col;
                const float* rp1 = rp0 + (size_t)8 * N;
                v0 += rp0[0]; v1 += rp0[1];
                v2 += rp1[0]; v3 += rp1[1];
            }
            if (out32) {
                *(float2*)(out32 + (size_t)r0 * N + col) = make_float2(v0, v1);
                *(float2*)(out32 + (size_t)(r0 + 8) * N + col) = make_float2(v2, v3);
            } else {
                *(uint32_t*)(out16 + (size_t)r0 * N + col) = packh2(v0, v1);
                *(uint32_t*)(out16 + (size_t)(r0 + 8) * N + col) = packh2(v2, v3);
            }
        }
    }
}

// ================= fused flash attention, fp16 mma (verified R10) =================
#define QS_ST 36
#define KP_ST 68
#define VS_ST 68
#define FLASH_SMEM ((128*QS_ST + 128*KP_ST + 64*VS_ST + 1024 + 256 + 256) * 4)

__global__ void __launch_bounds__(256) flash_attn(
    const __half* __restrict__ qkv, const float* __restrict__ sz, __half* __restrict__ out)
{
    extern __shared__ uint32_t smw[];
    uint32_t* Qs = smw;
    uint32_t* KP = Qs + 128 * QS_ST;
    uint32_t* Vs = KP + 128 * KP_ST;
    float* logls = (float*)(Vs + 64 * VS_ST);
    float* redm  = logls + 1024;
    float* reds  = redm + 256;
    __half* Vs_h = (__half*)Vs;

    const int tid = threadIdx.x;
    const int wid = tid >> 5, lane = tid & 31;
    const int g = lane >> 2, tg = lane & 3;
    const int wm = wid & 3;
    const int wnn = wid >> 2;
    const int bh = blockIdx.y;
    const int b = bh >> 4, h = bh & 15;
    const int n0 = blockIdx.x * 128;
    const __half* qb = qkv + (size_t)b * Nn * 3072 + h * 64;
    const __half* kb = qb + 1024;
    const __half* vb = qb + 2048;

    for (int i = tid; i < 1024; i += 256)
        logls[i] = __logf(sz[b * Nn + i]);

#pragma unroll
    for (int i = 0; i < 4; i++) {
        int idx = tid + i * 256;
        int row = idx >> 3;
        int seg = idx & 7;
        *(uint4*)&Qs[row * QS_ST + seg * 4] =
            *(const uint4*)(qb + (size_t)(n0 + row) * 3072 + seg * 8);
    }

    float m_i[2][2], l_i[2][2];
    float acc[2][4][4];
#pragma unroll
    for (int mt = 0; mt < 2; mt++)
#pragma unroll
        for (int rh = 0; rh < 2; rh++) { m_i[mt][rh] = -INFINITY; l_i[mt][rh] = 0.f; }
#pragma unroll
    for (int mt = 0; mt < 2; mt++)
#pragma unroll
        for (int nt = 0; nt < 4; nt++)
#pragma unroll
            for (int v = 0; v < 4; v++) acc[mt][nt][v] = 0.f;

    for (int m0 = 0; m0 < Nn; m0 += 128) {
        __syncthreads();
#pragma unroll
        for (int i = 0; i < 4; i++) {
            int idx = tid + i * 256;
            int row = idx >> 3;
            int seg = idx & 7;
            *(uint4*)&KP[row * KP_ST + seg * 4] =
                *(const uint4*)(kb + (size_t)(m0 + row) * 3072 + seg * 8);
            uint4 vv = *(const uint4*)(vb + (size_t)(m0 + row) * 3072 + seg * 8);
            const __half* vh = (const __half*)&vv;
#pragma unroll
            for (int j = 0; j < 8; j++)
                Vs_h[(seg * 8 + j) * (VS_ST * 2) + row] = vh[j];
        }
        __syncthreads();

        float s[2][8][4];
#pragma unroll
        for (int mt = 0; mt < 2; mt++)
#pragma unroll
            for (int nt = 0; nt < 8; nt++)
#pragma unroll
                for (int v = 0; v < 4; v++) s[mt][nt][v] = 0.f;
#pragma unroll
        for (int ks = 0; ks < 32; ks += 8) {
            uint32_t af[2][4];
#pragma unroll
            for (int mt = 0; mt < 2; mt++) {
                int ra = wm * 32 + mt * 16 + g;
                af[mt][0] = Qs[ra * QS_ST + ks + tg];
                af[mt][1] = Qs[(ra + 8) * QS_ST + ks + tg];
                af[mt][2] = Qs[ra * QS_ST + ks + tg + 4];
                af[mt][3] = Qs[(ra + 8) * QS_ST + ks + tg + 4];
            }
            uint32_t bf[8][2];
#pragma unroll
            for (int nt = 0; nt < 8; nt++) {
                int cb = wnn * 64 + nt * 8 + g;
                bf[nt][0] = KP[cb * KP_ST + ks + tg];
                bf[nt][1] = KP[cb * KP_ST + ks + tg + 4];
            }
#pragma unroll
            for (int mt = 0; mt < 2; mt++)
#pragma unroll
                for (int nt = 0; nt < 8; nt++)
                    mma_f16(s[mt][nt][0], s[mt][nt][1], s[mt][nt][2], s[mt][nt][3],
                            af[mt][0], af[mt][1], af[mt][2], af[mt][3],
                            bf[nt][0], bf[nt][1]);
        }

        float tmax[2][2];
#pragma unroll
        for (int mt = 0; mt < 2; mt++) { tmax[mt][0] = -INFINITY; tmax[mt][1] = -INFINITY; }
#pragma unroll
        for (int mt = 0; mt < 2; mt++)
#pragma unroll
            for (int nt = 0; nt < 8; nt++) {
                int col = wnn * 64 + nt * 8 + tg * 2;
                float ls0 = logls[m0 + col];
                float ls1 = logls[m0 + col + 1];
                s[mt][nt][0] = s[mt][nt][0] * 0.125f + ls0;
                s[mt][nt][1] = s[mt][nt][1] * 0.125f + ls1;
                s[mt][nt][2] = s[mt][nt][2] * 0.125f + ls0;
                s[mt][nt][3] = s[mt][nt][3] * 0.125f + ls1;
                tmax[mt][0] = fmaxf(tmax[mt][0], fmaxf(s[mt][nt][0], s[mt][nt][1]));
                tmax[mt][1] = fmaxf(tmax[mt][1], fmaxf(s[mt][nt][2], s[mt][nt][3]));
            }
#pragma unroll
        for (int mt = 0; mt < 2; mt++)
#pragma unroll
            for (int rh = 0; rh < 2; rh++) {
                float v = tmax[mt][rh];
                v = fmaxf(v, __shfl_xor_sync(~0u, v, 1));
                v = fmaxf(v, __shfl_xor_sync(~0u, v, 2));
                tmax[mt][rh] = v;
            }
        if (tg == 0) {
#pragma unroll
            for (int mt = 0; mt < 2; mt++)
#pragma unroll
                for (int rh = 0; rh < 2; rh++)
                    redm[wnn * 128 + wm * 32 + mt * 16 + rh * 8 + g] = tmax[mt][rh];
        }
        __syncthreads();

        float sc[2][2];
#pragma unroll
        for (int mt = 0; mt < 2; mt++)
#pragma unroll
            for (int rh = 0; rh < 2; rh++) {
                int row = wm * 32 + mt * 16 + rh * 8 + g;
                float mx = fmaxf(redm[row], redm[128 + row]);
                float mnew = fmaxf(m_i[mt][rh], mx);
                sc[mt][rh] = __expf(m_i[mt][rh] - mnew);
                m_i[mt][rh] = mnew;
                l_i[mt][rh] *= sc[mt][rh];
            }
#pragma unroll
        for (int mt = 0; mt < 2; mt++)
#pragma unroll
            for (int nt = 0; nt < 4; nt++) {
                acc[mt][nt][0] *= sc[mt][0];
                acc[mt][nt][1] *= sc[mt][0];
                acc[mt][nt][2] *= sc[mt][1];
                acc[mt][nt][3] *= sc[mt][1];
            }

        float tsum[2][2];
#pragma unroll
        for (int mt = 0; mt < 2; mt++) { tsum[mt][0] = 0.f; tsum[mt][1] = 0.f; }
#pragma unroll
        for (int mt = 0; mt < 2; mt++) {
            int r0 = wm * 32 + mt * 16 + g;
#pragma unroll
            for (int nt = 0; nt < 8; nt++) {
                int w2 = wnn * 32 + nt * 4 + tg;
                float p0 = __expf(s[mt][nt][0] - m_i[mt][0]);
                float p1 = __expf(s[mt][nt][1] - m_i[mt][0]);
                float p2 = __expf(s[mt][nt][2] - m_i[mt][1]);
                float p3 = __expf(s[mt][nt][3] - m_i[mt][1]);
                tsum[mt][0] += p0 + p1;
                tsum[mt][1] += p2 + p3;
                KP[r0 * KP_ST + w2] = packh2(p0, p1);
                KP[(r0 + 8) * KP_ST + w2] = packh2(p2, p3);
            }
        }
#pragma unroll
        for (int mt = 0; mt < 2; mt++)
#pragma unroll
            for (int rh = 0; rh < 2; rh++) {
                float v = tsum[mt][rh];
                v += __shfl_xor_sync(~0u, v, 1);
                v += __shfl_xor_sync(~0u, v, 2);
                tsum[mt][rh] = v;
            }
        if (tg == 0) {
#pragma unroll
            for (int mt = 0; mt < 2; mt++)
#pragma unroll
                for (int rh = 0; rh < 2; rh++)
                    reds[wnn * 128 + wm * 32 + mt * 16 + rh * 8 + g] = tsum[mt][rh];
        }
        __syncthreads();
#pragma unroll
        for (int mt = 0; mt < 2; mt++)
#pragma unroll
            for (int rh = 0; rh < 2; rh++) {
                int row = wm * 32 + mt * 16 + rh * 8 + g;
                l_i[mt][rh] += reds[row] + reds[128 + row];
            }

#pragma unroll
        for (int ks = 0; ks < 64; ks += 8) {
            uint32_t af[2][4];
#pragma unroll
            for (int mt = 0; mt < 2; mt++) {
                int ra = wm * 32 + mt * 16 + g;
                af[mt][0] = KP[ra * KP_ST + ks + tg];
                af[mt][1] = KP[(ra + 8) * KP_ST + ks + tg];
                af[mt][2] = KP[ra * KP_ST + ks + tg + 4];
                af[mt][3] = KP[(ra + 8) * KP_ST + ks + tg + 4];
            }
            uint32_t bf[4][2];
#pragma unroll
            for (int nt = 0; nt < 4; nt++) {
                int cb = wnn * 32 + nt * 8 + g;
                bf[nt][0] = Vs[cb * VS_ST + ks + tg];
                bf[nt][1] = Vs[cb * VS_ST + ks + tg + 4];
            }
#pragma unroll
            for (int mt = 0; mt < 2; mt++)
#pragma unroll
                for (int nt = 0; nt < 4; nt++)
                    mma_f16(acc[mt][nt][0], acc[mt][nt][1], acc[mt][nt][2], acc[mt][nt][3],
                            af[mt][0], af[mt][1], af[mt][2], af[mt][3],
                            bf[nt][0], bf[nt][1]);
        }
    }

#pragma unroll
    for (int mt = 0; mt < 2; mt++) {
        float inv0 = 1.f / l_i[mt][0];
        float inv1 = 1.f / l_i[mt][1];
        int r0 = n0 + wm * 32 + mt * 16 + g;
#pragma unroll
        for (int nt = 0; nt < 4; nt++) {
            int col = h * 64 + wnn * 32 + nt * 8 + tg * 2;
            *(uint32_t*)(out + ((size_t)b * Nn + r0) * Cc + col) =
                packh2(acc[mt][nt][0] * inv0, acc[mt][nt][1] * inv0);
            *(uint32_t*)(out + ((size_t)b * Nn + r0 + 8) * Cc + col) =
                packh2(acc[mt][nt][2] * inv1, acc[mt][nt][3] * inv1);
        }
    }
}

// ---------------- single-pass LayerNorm (float4, 1 barrier) ----------------
__global__ void __launch_bounds__(256) ln_kernel(
    const float* __restrict__ x, const float* __restrict__ g,
    const float* __restrict__ bta, float* __restrict__ out32,
    __half* __restrict__ out16, int C)
{
    size_t row = blockIdx.x;
    int tid = threadIdx.x;
    float4 v = ((const float4*)(x + row * 1024))[tid];
    float s = v.x + v.y + v.z + v.w;
    float s2 = v.x * v.x + v.y * v.y + v.z * v.z + v.w * v.w;
#pragma unroll
    for (int o = 16; o; o >>= 1) {
        s += __shfl_xor_sync(~0u, s, o);
        s2 += __shfl_xor_sync(~0u, s2, o);
    }
    __shared__ float ws[8], wq[8];
    int w = tid >> 5, l = tid & 31;
    if (l == 0) { ws[w] = s; wq[w] = s2; }
    __syncthreads();
    float S = 0.f, S2 = 0.f;
#pragma unroll
    for (int i = 0; i < 8; i++) { S += ws[i]; S2 += wq[i]; }
    float mean = S * (1.f / 1024.f);
    float var  = S2 * (1.f / 1024.f) - mean * mean;
    float inv  = rsqrtf(var + 1e-5f);
    float4 gg = ((const float4*)g)[tid];
    float4 bb = ((const float4*)bta)[tid];
    float4 o;
    o.x = (v.x - mean) * inv * gg.x + bb.x;
    o.y = (v.y - mean) * inv * gg.y + bb.y;
    o.z = (v.z - mean) * inv * gg.z + bb.z;
    o.w = (v.w - mean) * inv * gg.w + bb.w;
    if (out32) ((float4*)(out32 + row * 1024))[tid] = o;
    uint2 p = make_uint2(packh2(o.x, o.y), packh2(o.z, o.w));
    *(uint2*)(out16 + row * 1024 + tid * 4) = p;
    (void)C;
}

// ---------------- pooled K weight (exact fp32 metric path) ----------------
__global__ void __launch_bounds__(256) pool_wk(
    const float* __restrict__ qkv_w, const float* __restrict__ qkv_b,
    float* __restrict__ wm, float* __restrict__ wmb)
{
    int idx = blockIdx.x * 256 + threadIdx.x;
    if (idx < 64 * 1024) {
        int d = idx >> 10, k = idx & 1023;
        float s = 0.f;
#pragma unroll
        for (int h = 0; h < 16; h++) s += qkv_w[(size_t)(1024 + h * 64 + d) * 1024 + k];
        wm[idx] = s * (1.f / 16.f);
    }
    if (idx < 64) {
        float s = 0.f;
#pragma unroll
        for (int h = 0; h < 16; h++) s += qkv_b[1024 + h * 64 + idx];
        wmb[idx] = s * (1.f / 16.f);
    }
}

// ---------------- fp32 metric GEMM, 64-row tiles (256 CTAs) ----------------
__global__ void __launch_bounds__(256) metric_gemm(
    const float* __restrict__ xln, const float* __restrict__ wm,
    const float* __restrict__ wmb, float* __restrict__ metric)
{
    __shared__ float Xs[32][68];
    __shared__ float Ws[32][68];
    const int bm = blockIdx.x * 64;
    const int tid = threadIdx.x;
    const int ty = tid >> 3;          // 0..31 -> rows ty*2
    const int tx = tid & 7;           // dims tx*8
    float acc[2][8];
#pragma unroll
    for (int i = 0; i < 2; i++)
#pragma unroll
        for (int j = 0; j < 8; j++) acc[i][j] = 0.f;

    for (int k0 = 0; k0 < 1024; k0 += 32) {
#pragma unroll
        for (int i = 0; i < 2; i++) {
            int idx = tid + i * 256;          // 0..511
            int row = idx >> 3;               // 0..63
            int kq = (idx & 7) << 2;
            float4 v = *(const float4*)(xln + (size_t)(bm + row) * 1024 + k0 + kq);
            Xs[kq][row] = v.x; Xs[kq + 1][row] = v.y; Xs[kq + 2][row] = v.z; Xs[kq + 3][row] = v.w;
        }
        for (int idx = tid; idx < 512; idx += 256) {
            int d = idx >> 3;
            int kq = (idx & 7) << 2;
            float4 v = *(const float4*)(wm + (size_t)d * 1024 + k0 + kq);
            Ws[kq][d] = v.x; Ws[kq + 1][d] = v.y; Ws[kq + 2][d] = v.z; Ws[kq + 3][d] = v.w;
        }
        __syncthreads();
#pragma unroll
        for (int kk = 0; kk < 32; kk++) {
            float a[2], w[8];
#pragma unroll
            for (int i = 0; i < 2; i++) a[i] = Xs[kk][ty * 2 + i];
#pragma unroll
            for (int j = 0; j < 8; j++) w[j] = Ws[kk][tx * 8 + j];
#pragma unroll
            for (int i = 0; i < 2; i++)
#pragma unroll
                for (int j = 0; j < 8; j++) acc[i][j] += a[i] * w[j];
        }
        __syncthreads();
    }
#pragma unroll
    for (int i = 0; i < 2; i++) {
        int row = bm + ty * 2 + i;
#pragma unroll
        for (int j = 0; j < 8; j++)
            metric[(size_t)row * 64 + tx * 8 + j] = acc[i][j] + wmb[tx * 8 + j];
    }
}

__global__ void __launch_bounds__(64) metric_norm(float* __restrict__ metric)
{
    int bn = blockIdx.x;
    int d = threadIdx.x;
    float v = metric[(size_t)bn * 64 + d];
    __shared__ float sh[64];
    sh[d] = v * v; __syncthreads();
    for (int off = 32; off; off >>= 1) {
        if (d < off) sh[d] += sh[d + off];
        __syncthreads();
    }
    float inv = rsqrtf(sh[0]);
    metric[(size_t)bn * 64 + d] = v * inv;
}

// ---------------- matching ----------------
__global__ void __launch_bounds__(256) match_scores(
    const float* __restrict__ metric, float* __restrict__ nodemax, int* __restrict__ nodeidx)
{
    int t = blockIdx.x;
    int b = blockIdx.y;
    const float* mb = metric + (size_t)b * Nn * 64;
    __shared__ float av[64];
    int tid = threadIdx.x;
    if (tid < 64) av[tid] = mb[(size_t)(2 * t) * 64 + tid];
    __syncthreads();
    float best = -INFINITY; int bi = 0;
    for (int s = tid; s < NH; s += 256) {
        const float* bp = mb + (size_t)(2 * s + 1) * 64;
        float dot = 0.f;
#pragma unroll
        for (int d = 0; d < 64; d++) dot += av[d] * bp[d];
        if (dot > best) { best = dot; bi = s; }
    }
    __shared__ float sv[256]; __shared__ int si[256];
    sv[tid] = best; si[tid] = bi; __syncthreads();
    for (int off = 128; off; off >>= 1) {
        if (tid < off) {
            if (sv[tid + off] > sv[tid] ||
                (sv[tid + off] == sv[tid] && si[tid + off] < si[tid])) {
                sv[tid] = sv[tid + off]; si[tid] = si[tid + off];
            }
        }
        __syncthreads();
    }
    if (tid == 0) {
        if (t == 0) { nodemax[b * NH] = -INFINITY; nodeidx[b * NH] = 0; }
        else { nodemax[b * NH + t] = sv[0]; nodeidx[b * NH + t] = si[0]; }
    }
}

__global__ void __launch_bounds__(512) match_sort(
    const float* __restrict__ nodemax, const int* __restrict__ nodeidx,
    int* __restrict__ srcidx, int* __restrict__ dstidx, int* __restrict__ unmidx)
{
    int b = blockIdx.x, t = threadIdx.x;
    __shared__ float v[NH]; __shared__ int rk[NH];
    v[t] = nodemax[b * NH + t]; __syncthreads();
    float vt = v[t]; int r = 0;
    for (int j = 0; j < NH; j++) {
        float vj = v[j];
        r += (vj > vt) || (vj == vt && j < t);
    }
    rk[t] = r; __syncthreads();
    if (r < Rr) {
        srcidx[b * Rr + r] = t;
        dstidx[b * Rr + r] = nodeidx[b * NH + t];
    } else {
        int pos = 0;
        for (int j = 0; j < t; j++) pos += (rk[j] >= Rr);
        unmidx[b * NU + pos] = t;
    }
}

// ---------------- weighted merge + divide by new size (match-list) ----------
__global__ void __launch_bounds__(256) merge_kernel(
    const float* __restrict__ xres, const float* __restrict__ sz,
    const int* __restrict__ srcidx, const int* __restrict__ dstidx,
    const int* __restrict__ unmidx, float* __restrict__ xm)
{
    int row = blockIdx.x;
    int b = blockIdx.y;
    int tid = threadIdx.x;
    const float* xb = xres + (size_t)b * Nn * Cc;
    const float* szb = sz + b * Nn;
    float* ob = xm + ((size_t)b * NM + row) * Cc;

    if (row < NU) {
        int t = 2 * unmidx[b * NU + row];
        float s = szb[t];
        float inv = 1.f / s;
        for (int c = tid; c < Cc; c += 256)
            ob[c] = (xb[(size_t)t * Cc + c] * s) * inv;
    } else {
        int j = row - NU;
        __shared__ int sd[Rr], ss[Rr];
        __shared__ int mls[Rr]; __shared__ float msz[Rr];
        __shared__ int nmz; __shared__ float nsz;
        if (tid < Rr) { ss[tid] = srcidx[b * Rr + tid]; sd[tid] = dstidx[b * Rr + tid]; }
        __syncthreads();
        int t = 2 * j + 1;
        if (tid == 0) {
            int n = 0;
            float ns = szb[t];
            for (int i = 0; i < Rr; i++) {
                if (sd[i] == j) {
                    int ts = 2 * ss[i];
                    float s2 = szb[ts];
                    mls[n] = ts; msz[n] = s2; ns += s2; n++;
                }
            }
            nmz = n; nsz = ns;
        }
        __syncthreads();
        int nm = nmz;
        float inv = 1.f / nsz;
        float st = szb[t];
        for (int c = tid; c < Cc; c += 256) {
            float val = xb[(size_t)t * Cc + c] * st;
            for (int i = 0; i < nm; i++)
                val += xb[(size_t)mls[i] * Cc + c] * msz[i];
            ob[c] = val * inv;
        }
    }
}

// ---------------- launch ----------------
template <typename T>
static T* sym_addr(const void* sym) {
    void* p = nullptr;
    cudaGetSymbolAddress(&p, sym);
    return (T*)p;
}

extern "C" void kernel_launch(void* const* d_in, const int* in_sizes, int n_in,
                              void* d_out, int out_size)
{
    const float* x      = (const float*)d_in[0];
    const float* sz     = (const float*)d_in[1];
    const float* qkv_w  = (const float*)d_in[3];
    const float* qkv_b  = (const float*)d_in[4];
    const float* proj_w = (const float*)d_in[5];
    const float* proj_b = (const float*)d_in[6];
    const float* n1g    = (const float*)d_in[7];
    const float* n1b    = (const float*)d_in[8];
    const float* n2g    = (const float*)d_in[9];
    const float* n2b    = (const float*)d_in[10];
    const float* fc1_w  = (const float*)d_in[11];
    const float* fc1_b  = (const float*)d_in[12];
    const float* fc2_w  = (const float*)d_in[13];
    const float* fc2_b  = (const float*)d_in[14];
    float* out = (float*)d_out;

    float*  xln    = sym_addr<float>(g_xln);
    __half* xln_h  = sym_addr<__half>(g_xln_h);
    __half* qkv_h  = sym_addr<__half>(g_qkv_h);
    __half* attno_h= sym_addr<__half>(g_attno_h);
    float*  xres   = sym_addr<float>(g_xres);
    __half* h2_h   = sym_addr<__half>(g_h2_h);
    __half* fc1_h  = sym_addr<__half>(g_fc1_h);
    __half* wqkv_h = sym_addr<__half>(g_wqkv_h);
    __half* wproj_h= sym_addr<__half>(g_wproj_h);
    __half* wfc1_h = sym_addr<__half>(g_wfc1_h);
    __half* wfc2_h = sym_addr<__half>(g_wfc2_h);
    float* wm    = sym_addr<float>(g_wm);
    float* wmb   = sym_addr<float>(g_wmb);
    float* metric= sym_addr<float>(g_metric);
    float* nmax  = sym_addr<float>(g_nodemax);
    int*   nidx  = sym_addr<int>(g_nodeidx);
    int*   sidx  = sym_addr<int>(g_srcidx);
    int*   didx  = sym_addr<int>(g_dstidx);
    int*   uidx  = sym_addr<int>(g_unmidx);
    float* xm    = sym_addr<float>(g_xm);

    cudaFuncSetAttribute(flash_attn, cudaFuncAttributeMaxDynamicSharedMemorySize, FLASH_SMEM);
    cudaFuncSetAttribute(fp16_gemm, cudaFuncAttributeMaxDynamicSharedMemorySize, GEMM_SMEM);

    // 0. weight conversion (fp32 -> fp16)
    cvt_f2h<<<(3 * 1024 * 1024 / 4 + 255) / 256, 256>>>(qkv_w, wqkv_h, 3 * 1024 * 1024 / 4);
    cvt_f2h<<<(1024 * 1024 / 4 + 255) / 256, 256>>>(proj_w, wproj_h, 1024 * 1024 / 4);
    cvt_f2h<<<(4 * 1024 * 1024 / 4 + 255) / 256, 256>>>(fc1_w, wfc1_h, 4 * 1024 * 1024 / 4);
    cvt_f2h<<<(4 * 1024 * 1024 / 4 + 255) / 256, 256>>>(fc2_w, wfc2_h, 4 * 1024 * 1024 / 4);

    // 1. LN1 (dual output)
    ln_kernel<<<MROWS, 256>>>(x, n1g, n1b, xln, xln_h, Cc);
    // 2. QKV GEMM -> half
    fp16_gemm<<<dim3(3072 / 128, MROWS / 128), 256, GEMM_SMEM>>>(
        xln_h, wqkv_h, qkv_b, nullptr, nullptr, qkv_h, MROWS, 3072, Cc, 0);
    // 3. exact fp32 metric path
    pool_wk<<<256, 256>>>(qkv_w, qkv_b, wm, wmb);
    metric_gemm<<<MROWS / 64, 256>>>(xln, wm, wmb, metric);
    metric_norm<<<Bb * Nn, 64>>>(metric);
    // 4. fused flash attention (fp16) -> half
    flash_attn<<<dim3(8, Bb * Hh), 256, FLASH_SMEM>>>(qkv_h, sz, attno_h);
    // 5. proj + residual -> fp32
    fp16_gemm<<<dim3(Cc / 128, MROWS / 128), 256, GEMM_SMEM>>>(
        attno_h, wproj_h, proj_b, x, xres, nullptr, MROWS, Cc, Cc, 0);
    // 6. matching
    match_scores<<<dim3(NH, Bb), 256>>>(metric, nmax, nidx);
    match_sort<<<Bb, NH>>>(nmax, nidx, sidx, didx, uidx);
    // 7. merge
    merge_kernel<<<dim3(NM, Bb), 256>>>(xres, sz, sidx, didx, uidx, xm);
    // 8. LN2 -> half only
    ln_kernel<<<MROWS2, 256>>>(xm, n2g, n2b, nullptr, h2_h, Cc);
    // 9. fc1 + GELU -> half
    fp16_gemm<<<dim3(4096 / 128, MROWS2 / 128), 256, GEMM_SMEM>>>(
        h2_h, wfc1_h, fc1_b, nullptr, nullptr, fc1_h, MROWS2, 4096, Cc, 1);
    // 10. fc2 + residual -> out (fp32)
    fp16_gemm<<<dim3(Cc / 128, MROWS2 / 128), 256, GEMM_SMEM>>>(
        fc1_h, wfc2_h, fc2_b, xm, out, nullptr, MROWS2, Cc, 4096, 0);
    (void)in_sizes; (void)n_in; (void)out_size;
}

// round 13
// speedup vs baseline: 4.7542x; 1.1076x over previous
#include <cuda_runtime.h>
#include <cuda_bf16.h>
#include <cuda_fp16.h>
#include <math.h>
#include <cstdint>

// Problem constants
#define Bb 16
#define Nn 1024
#define Cc 1024
#define Hh 16
#define HD 64
#define Rr 128
#define NH (Nn/2)          // 512
#define NU (NH - Rr)       // 384 unmerged
#define NM (NU + NH)       // 896 merged tokens
#define MROWS (Bb*Nn)      // 16384
#define MROWS2 (Bb*NM)     // 14336

// ---------------- scratch (static device globals) ----------------
__device__ float  g_xln  [(size_t)MROWS * Cc];           // fp32 (metric path)
__device__ __half g_xln_h[(size_t)MROWS * Cc];
__device__ __half g_qkv_h[(size_t)MROWS * 3 * Cc];
__device__ __half g_attno_h[(size_t)MROWS * Cc];
__device__ float  g_xres [(size_t)MROWS * Cc];
__device__ __half g_h2_h [(size_t)MROWS2 * Cc];
__device__ __half g_fc1_h[(size_t)MROWS2 * 4 * Cc];
__device__ __half g_wqkv_h[(size_t)3 * Cc * Cc];
__device__ __half g_wproj_h[(size_t)Cc * Cc];
__device__ __half g_wfc1_h[(size_t)4 * Cc * Cc];
__device__ __half g_wfc2_h[(size_t)Cc * 4 * Cc];
__device__ float g_wm   [64 * 1024];
__device__ float g_wmb  [64];
__device__ float g_metric[(size_t)Bb * Nn * HD];
__device__ float g_nodemax[Bb * NH];
__device__ int   g_nodeidx[Bb * NH];
__device__ int   g_srcidx[Bb * Rr];
__device__ int   g_dstidx[Bb * Rr];
__device__ int   g_unmidx[Bb * NU];
__device__ float g_xm   [(size_t)MROWS2 * Cc];

__device__ __forceinline__ uint32_t packh2(float x, float y) {
    __half2 h = __floats2half2_rn(x, y);
    return *(uint32_t*)&h;
}
__device__ __forceinline__ uint32_t smem_u32(const void* p) {
    uint32_t a;
    asm("{ .reg .u64 t; cvta.to.shared.u64 t, %1; cvt.u32.u64 %0, t; }" : "=r"(a) : "l"(p));
    return a;
}
#define CPA16(dst, src) \
    asm volatile("cp.async.cg.shared.global [%0], [%1], 16;" :: "r"(dst), "l"(src))
#define CP_COMMIT() asm volatile("cp.async.commit_group;" ::: "memory")
#define CP_WAIT1()  asm volatile("cp.async.wait_group 1;" ::: "memory")
#define LDMX4(r0, r1, r2, r3, addr) \
    asm volatile("ldmatrix.sync.aligned.m8n8.x4.shared.b16 {%0,%1,%2,%3}, [%4];" \
        : "=r"(r0), "=r"(r1), "=r"(r2), "=r"(r3) : "r"(addr))

__device__ __forceinline__ void mma_f16(float& d0, float& d1, float& d2, float& d3,
                                        uint32_t a0, uint32_t a1, uint32_t a2, uint32_t a3,
                                        uint32_t b0, uint32_t b1)
{
    asm volatile(
        "mma.sync.aligned.m16n8k16.row.col.f32.f16.f16.f32 "
        "{%0,%1,%2,%3}, {%4,%5,%6,%7}, {%8,%9}, {%0,%1,%2,%3};\n"
        : "+f"(d0), "+f"(d1), "+f"(d2), "+f"(d3)
        : "r"(a0), "r"(a1), "r"(a2), "r"(a3), "r"(b0), "r"(b1));
}

// ---------------- f32 -> f16 converter ----------------
__global__ void __launch_bounds__(256) cvt_f2h(
    const float* __restrict__ src, __half* __restrict__ dst, int n4)
{
    int i = blockIdx.x * 256 + threadIdx.x;
    if (i < n4) {
        float4 v = *(const float4*)(src + (size_t)i * 4);
        uint2 p = make_uint2(packh2(v.x, v.y), packh2(v.z, v.w));
        *(uint2*)(dst + (size_t)i * 4) = p;
    }
}

// ================= fp16 GEMM: ldmatrix + XOR swizzle + cp.async 3-stage =====
// out(MxN) = A(MxK) @ W(NxK)^T + bias [,gelu] [,+res]; A,W half; out f32 or half.
// CTA 128x128, 8 warps (4M x 2N). K-stage = 64 halves (128B rows).
// SMEM layout per tile: row r (128B), chunk c (16B): phys chunk = c ^ (r&7).
// ldmatrix 8-lane quadrant map (addr>>4)&7 = c_phys -> permutation -> conflict-free.
#define GEMM_BUFB 16384                 // 128 rows * 128 B
#define GEMM_SMEM (3 * 2 * GEMM_BUFB)   // 96 KB

__global__ void __launch_bounds__(256) fp16_gemm(
    const __half* __restrict__ A, const __half* __restrict__ W,
    const float* __restrict__ bias, const float* __restrict__ res,
    float* __restrict__ out32, __half* __restrict__ out16,
    int M, int N, int K, int act)
{
    extern __shared__ char smg[];
    const uint32_t sA = smem_u32(smg);
    const uint32_t sB = sA + 3 * GEMM_BUFB;

    const int tid = threadIdx.x;
    const int wid = tid >> 5;
    const int lane = tid & 31;
    const int g = lane >> 2;
    const int tg = lane & 3;
    const int wm = wid & 3;
    const int wn = wid >> 2;
    const int bm = blockIdx.y * 128;
    const int bn = blockIdx.x * 128;

    // cp.async mapping: 4 chunks/thread/tile (1024 chunks = 128 rows x 8)
    uint32_t dstoff[4]; size_t srcoffA[4], srcoffW[4];
#pragma unroll
    for (int i = 0; i < 4; i++) {
        int idx = tid + i * 256;
        int row = idx >> 3, c = idx & 7;
        dstoff[i] = row * 128 + ((c ^ (row & 7)) << 4);
        srcoffA[i] = (size_t)(bm + row) * K + c * 8;
        srcoffW[i] = (size_t)(bn + row) * K + c * 8;
    }

    // ldmatrix per-lane bases
    const int sel = lane >> 3;          // 0..3
    const int lrow = lane & 7;
    const int csel = sel >> 1;          // chunk +0/+1 within k16
    const int rsel = sel & 1;           // row +0/+8
    uint32_t aBase[2]; int aRow7[2];
#pragma unroll
    for (int mt = 0; mt < 2; mt++) {
        int ra = wm * 32 + mt * 16 + rsel * 8 + lrow;
        aBase[mt] = ra * 128; aRow7[mt] = ra & 7;
    }
    uint32_t bBase[4]; int bRow7[4];
#pragma unroll
    for (int p = 0; p < 4; p++) {
        int nb = wn * 64 + p * 16 + rsel * 8 + lrow;
        bBase[p] = nb * 128; bRow7[p] = nb & 7;
    }

    float acc[2][8][4];
#pragma unroll
    for (int i = 0; i < 2; i++)
#pragma unroll
        for (int j = 0; j < 8; j++)
#pragma unroll
            for (int v = 0; v < 4; v++) acc[i][j][v] = 0.f;

    const int NS = K >> 6;              // 64-half stages
    // prologue: stages 0,1 in flight
    {
#pragma unroll
        for (int i = 0; i < 4; i++) {
            CPA16(sA + dstoff[i], A + srcoffA[i]);
            CPA16(sB + dstoff[i], W + srcoffW[i]);
        }
        CP_COMMIT();
        if (NS > 1) {
#pragma unroll
            for (int i = 0; i < 4; i++) {
                CPA16(sA + GEMM_BUFB + dstoff[i], A + srcoffA[i] + 64);
                CPA16(sB + GEMM_BUFB + dstoff[i], W + srcoffW[i] + 64);
            }
        }
        CP_COMMIT();
        CP_WAIT1();
        __syncthreads();
    }

    for (int s = 0; s < NS; s++) {
        const uint32_t bufA = sA + (s % 3) * GEMM_BUFB;
        const uint32_t bufB = sB + (s % 3) * GEMM_BUFB;
#pragma unroll
        for (int kq = 0; kq < 4; kq++) {        // k16 quarters; chunk base kq*2
            const int cc = kq * 2 + csel;
            uint32_t a[2][4];
#pragma unroll
            for (int mt = 0; mt < 2; mt++)
                LDMX4(a[mt][0], a[mt][1], a[mt][2], a[mt][3],
                      bufA + aBase[mt] + (uint32_t)(((cc ^ aRow7[mt])) << 4));
            uint32_t bm4[4][4];
#pragma unroll
            for (int p = 0; p < 4; p++)
                LDMX4(bm4[p][0], bm4[p][1], bm4[p][2], bm4[p][3],
                      bufB + bBase[p] + (uint32_t)(((cc ^ bRow7[p])) << 4));
#pragma unroll
            for (int mt = 0; mt < 2; mt++)
#pragma unroll
                for (int p = 0; p < 4; p++) {
                    mma_f16(acc[mt][2 * p][0], acc[mt][2 * p][1],
                            acc[mt][2 * p][2], acc[mt][2 * p][3],
                            a[mt][0], a[mt][1], a[mt][2], a[mt][3],
                            bm4[p][0], bm4[p][2]);
                    mma_f16(acc[mt][2 * p + 1][0], acc[mt][2 * p + 1][1],
                            acc[mt][2 * p + 1][2], acc[mt][2 * p + 1][3],
                            a[mt][0], a[mt][1], a[mt][2], a[mt][3],
                            bm4[p][1], bm4[p][3]);
                }
        }
        if (s + 1 < NS) {
            if (s + 2 < NS) {
                // buffer (s+2)%3 last read in stage s-1 (behind its closing barrier)
                uint32_t qA = sA + ((s + 2) % 3) * GEMM_BUFB;
                uint32_t qB = sB + ((s + 2) % 3) * GEMM_BUFB;
                size_t k0 = (size_t)(s + 2) << 6;
#pragma unroll
                for (int i = 0; i < 4; i++) {
                    CPA16(qA + dstoff[i], A + srcoffA[i] + k0);
                    CPA16(qB + dstoff[i], W + srcoffW[i] + k0);
                }
            }
            CP_COMMIT();
            CP_WAIT1();
            __syncthreads();
        }
    }

    // epilogue (m16n8 C layout, verified)
#pragma unroll
    for (int mt = 0; mt < 2; mt++) {
        int r0 = bm + wm * 32 + mt * 16 + g;
#pragma unroll
        for (int nt = 0; nt < 8; nt++) {
            int col = bn + wn * 64 + nt * 8 + tg * 2;
            float b0 = bias[col], b1 = bias[col + 1];
            float v0 = acc[mt][nt][0] + b0;
            float v1 = acc[mt][nt][1] + b1;
            float v2 = acc[mt][nt][2] + b0;
            float v3 = acc[mt][nt][3] + b1;
            if (act) {
                v0 = 0.5f * v0 * (1.f + erff(v0 * 0.70710678118654752f));
                v1 = 0.5f * v1 * (1.f + erff(v1 * 0.70710678118654752f));
                v2 = 0.5f * v2 * (1.f + erff(v2 * 0.70710678118654752f));
                v3 = 0.5f * v3 * (1.f + erff(v3 * 0.70710678118654752f));
            }
            if (res) {
                const float* rp0 = res + (size_t)r0 * N + col;
                const float* rp1 = rp0 + (size_t)8 * N;
                v0 += rp0[0]; v1 += rp0[1];
                v2 += rp1[0]; v3 += rp1[1];
            }
            if (out32) {
                *(float2*)(out32 + (size_t)r0 * N + col) = make_float2(v0, v1);
                *(float2*)(out32 + (size_t)(r0 + 8) * N + col) = make_float2(v2, v3);
            } else {
                *(uint32_t*)(out16 + (size_t)r0 * N + col) = packh2(v0, v1);
                *(uint32_t*)(out16 + (size_t)(r0 + 8) * N + col) = packh2(v2, v3);
            }
        }
    }
}

// ================= fused flash attention, fp16 mma (verified R10) =================
#define QS_ST 36
#define KP_ST 68
#define VS_ST 68
#define FLASH_SMEM ((128*QS_ST + 128*KP_ST + 64*VS_ST + 1024 + 256 + 256) * 4)

__global__ void __launch_bounds__(256) flash_attn(
    const __half* __restrict__ qkv, const float* __restrict__ sz, __half* __restrict__ out)
{
    extern __shared__ uint32_t smw[];
    uint32_t* Qs = smw;
    uint32_t* KP = Qs + 128 * QS_ST;
    uint32_t* Vs = KP + 128 * KP_ST;
    float* logls = (float*)(Vs + 64 * VS_ST);
    float* redm  = logls + 1024;
    float* reds  = redm + 256;
    __half* Vs_h = (__half*)Vs;

    const int tid = threadIdx.x;
    const int wid = tid >> 5, lane = tid & 31;
    const int g = lane >> 2, tg = lane & 3;
    const int wm = wid & 3;
    const int wnn = wid >> 2;
    const int bh = blockIdx.y;
    const int b = bh >> 4, h = bh & 15;
    const int n0 = blockIdx.x * 128;
    const __half* qb = qkv + (size_t)b * Nn * 3072 + h * 64;
    const __half* kb = qb + 1024;
    const __half* vb = qb + 2048;

    for (int i = tid; i < 1024; i += 256)
        logls[i] = __logf(sz[b * Nn + i]);

#pragma unroll
    for (int i = 0; i < 4; i++) {
        int idx = tid + i * 256;
        int row = idx >> 3;
        int seg = idx & 7;
        *(uint4*)&Qs[row * QS_ST + seg * 4] =
            *(const uint4*)(qb + (size_t)(n0 + row) * 3072 + seg * 8);
    }

    float m_i[2][2], l_i[2][2];
    float acc[2][4][4];
#pragma unroll
    for (int mt = 0; mt < 2; mt++)
#pragma unroll
        for (int rh = 0; rh < 2; rh++) { m_i[mt][rh] = -INFINITY; l_i[mt][rh] = 0.f; }
#pragma unroll
    for (int mt = 0; mt < 2; mt++)
#pragma unroll
        for (int nt = 0; nt < 4; nt++)
#pragma unroll
            for (int v = 0; v < 4; v++) acc[mt][nt][v] = 0.f;

    for (int m0 = 0; m0 < Nn; m0 += 128) {
        __syncthreads();
#pragma unroll
        for (int i = 0; i < 4; i++) {
            int idx = tid + i * 256;
            int row = idx >> 3;
            int seg = idx & 7;
            *(uint4*)&KP[row * KP_ST + seg * 4] =
                *(const uint4*)(kb + (size_t)(m0 + row) * 3072 + seg * 8);
            uint4 vv = *(const uint4*)(vb + (size_t)(m0 + row) * 3072 + seg * 8);
            const __half* vh = (const __half*)&vv;
#pragma unroll
            for (int j = 0; j < 8; j++)
                Vs_h[(seg * 8 + j) * (VS_ST * 2) + row] = vh[j];
        }
        __syncthreads();

        float s[2][8][4];
#pragma unroll
        for (int mt = 0; mt < 2; mt++)
#pragma unroll
            for (int nt = 0; nt < 8; nt++)
#pragma unroll
                for (int v = 0; v < 4; v++) s[mt][nt][v] = 0.f;
#pragma unroll
        for (int ks = 0; ks < 32; ks += 8) {
            uint32_t af[2][4];
#pragma unroll
            for (int mt = 0; mt < 2; mt++) {
                int ra = wm * 32 + mt * 16 + g;
                af[mt][0] = Qs[ra * QS_ST + ks + tg];
                af[mt][1] = Qs[(ra + 8) * QS_ST + ks + tg];
                af[mt][2] = Qs[ra * QS_ST + ks + tg + 4];
                af[mt][3] = Qs[(ra + 8) * QS_ST + ks + tg + 4];
            }
            uint32_t bf[8][2];
#pragma unroll
            for (int nt = 0; nt < 8; nt++) {
                int cb = wnn * 64 + nt * 8 + g;
                bf[nt][0] = KP[cb * KP_ST + ks + tg];
                bf[nt][1] = KP[cb * KP_ST + ks + tg + 4];
            }
#pragma unroll
            for (int mt = 0; mt < 2; mt++)
#pragma unroll
                for (int nt = 0; nt < 8; nt++)
                    mma_f16(s[mt][nt][0], s[mt][nt][1], s[mt][nt][2], s[mt][nt][3],
                            af[mt][0], af[mt][1], af[mt][2], af[mt][3],
                            bf[nt][0], bf[nt][1]);
        }

        float tmax[2][2];
#pragma unroll
        for (int mt = 0; mt < 2; mt++) { tmax[mt][0] = -INFINITY; tmax[mt][1] = -INFINITY; }
#pragma unroll
        for (int mt = 0; mt < 2; mt++)
#pragma unroll
            for (int nt = 0; nt < 8; nt++) {
                int col = wnn * 64 + nt * 8 + tg * 2;
                float ls0 = logls[m0 + col];
                float ls1 = logls[m0 + col + 1];
                s[mt][nt][0] = s[mt][nt][0] * 0.125f + ls0;
                s[mt][nt][1] = s[mt][nt][1] * 0.125f + ls1;
                s[mt][nt][2] = s[mt][nt][2] * 0.125f + ls0;
                s[mt][nt][3] = s[mt][nt][3] * 0.125f + ls1;
                tmax[mt][0] = fmaxf(tmax[mt][0], fmaxf(s[mt][nt][0], s[mt][nt][1]));
                tmax[mt][1] = fmaxf(tmax[mt][1], fmaxf(s[mt][nt][2], s[mt][nt][3]));
            }
#pragma unroll
        for (int mt = 0; mt < 2; mt++)
#pragma unroll
            for (int rh = 0; rh < 2; rh++) {
                float v = tmax[mt][rh];
                v = fmaxf(v, __shfl_xor_sync(~0u, v, 1));
                v = fmaxf(v, __shfl_xor_sync(~0u, v, 2));
                tmax[mt][rh] = v;
            }
        if (tg == 0) {
#pragma unroll
            for (int mt = 0; mt < 2; mt++)
#pragma unroll
                for (int rh = 0; rh < 2; rh++)
                    redm[wnn * 128 + wm * 32 + mt * 16 + rh * 8 + g] = tmax[mt][rh];
        }
        __syncthreads();

        float sc[2][2];
#pragma unroll
        for (int mt = 0; mt < 2; mt++)
#pragma unroll
            for (int rh = 0; rh < 2; rh++) {
                int row = wm * 32 + mt * 16 + rh * 8 + g;
                float mx = fmaxf(redm[row], redm[128 + row]);
                float mnew = fmaxf(m_i[mt][rh], mx);
                sc[mt][rh] = __expf(m_i[mt][rh] - mnew);
                m_i[mt][rh] = mnew;
                l_i[mt][rh] *= sc[mt][rh];
            }
#pragma unroll
        for (int mt = 0; mt < 2; mt++)
#pragma unroll
            for (int nt = 0; nt < 4; nt++) {
                acc[mt][nt][0] *= sc[mt][0];
                acc[mt][nt][1] *= sc[mt][0];
                acc[mt][nt][2] *= sc[mt][1];
                acc[mt][nt][3] *= sc[mt][1];
            }

        float tsum[2][2];
#pragma unroll
        for (int mt = 0; mt < 2; mt++) { tsum[mt][0] = 0.f; tsum[mt][1] = 0.f; }
#pragma unroll
        for (int mt = 0; mt < 2; mt++) {
            int r0 = wm * 32 + mt * 16 + g;
#pragma unroll
            for (int nt = 0; nt < 8; nt++) {
                int w2 = wnn * 32 + nt * 4 + tg;
                float p0 = __expf(s[mt][nt][0] - m_i[mt][0]);
                float p1 = __expf(s[mt][nt][1] - m_i[mt][0]);
                float p2 = __expf(s[mt][nt][2] - m_i[mt][1]);
                float p3 = __expf(s[mt][nt][3] - m_i[mt][1]);
                tsum[mt][0] += p0 + p1;
                tsum[mt][1] += p2 + p3;
                KP[r0 * KP_ST + w2] = packh2(p0, p1);
                KP[(r0 + 8) * KP_ST + w2] = packh2(p2, p3);
            }
        }
#pragma unroll
        for (int mt = 0; mt < 2; mt++)
#pragma unroll
            for (int rh = 0; rh < 2; rh++) {
                float v = tsum[mt][rh];
                v += __shfl_xor_sync(~0u, v, 1);
                v += __shfl_xor_sync(~0u, v, 2);
                tsum[mt][rh] = v;
            }
        if (tg == 0) {
#pragma unroll
            for (int mt = 0; mt < 2; mt++)
#pragma unroll
                for (int rh = 0; rh < 2; rh++)
                    reds[wnn * 128 + wm * 32 + mt * 16 + rh * 8 + g] = tsum[mt][rh];
        }
        __syncthreads();
#pragma unroll
        for (int mt = 0; mt < 2; mt++)
#pragma unroll
            for (int rh = 0; rh < 2; rh++) {
                int row = wm * 32 + mt * 16 + rh * 8 + g;
                l_i[mt][rh] += reds[row] + reds[128 + row];
            }

#pragma unroll
        for (int ks = 0; ks < 64; ks += 8) {
            uint32_t af[2][4];
#pragma unroll
            for (int mt = 0; mt < 2; mt++) {
                int ra = wm * 32 + mt * 16 + g;
                af[mt][0] = KP[ra * KP_ST + ks + tg];
                af[mt][1] = KP[(ra + 8) * KP_ST + ks + tg];
                af[mt][2] = KP[ra * KP_ST + ks + tg + 4];
                af[mt][3] = KP[(ra + 8) * KP_ST + ks + tg + 4];
            }
            uint32_t bf[4][2];
#pragma unroll
            for (int nt = 0; nt < 4; nt++) {
                int cb = wnn * 32 + nt * 8 + g;
                bf[nt][0] = Vs[cb * VS_ST + ks + tg];
                bf[nt][1] = Vs[cb * VS_ST + ks + tg + 4];
            }
#pragma unroll
            for (int mt = 0; mt < 2; mt++)
#pragma unroll
                for (int nt = 0; nt < 4; nt++)
                    mma_f16(acc[mt][nt][0], acc[mt][nt][1], acc[mt][nt][2], acc[mt][nt][3],
                            af[mt][0], af[mt][1], af[mt][2], af[mt][3],
                            bf[nt][0], bf[nt][1]);
        }
    }

#pragma unroll
    for (int mt = 0; mt < 2; mt++) {
        float inv0 = 1.f / l_i[mt][0];
        float inv1 = 1.f / l_i[mt][1];
        int r0 = n0 + wm * 32 + mt * 16 + g;
#pragma unroll
        for (int nt = 0; nt < 4; nt++) {
            int col = h * 64 + wnn * 32 + nt * 8 + tg * 2;
            *(uint32_t*)(out + ((size_t)b * Nn + r0) * Cc + col) =
                packh2(acc[mt][nt][0] * inv0, acc[mt][nt][1] * inv0);
            *(uint32_t*)(out + ((size_t)b * Nn + r0 + 8) * Cc + col) =
                packh2(acc[mt][nt][2] * inv1, acc[mt][nt][3] * inv1);
        }
    }
}

// ---------------- single-pass LayerNorm (float4, 1 barrier) ----------------
__global__ void __launch_bounds__(256) ln_kernel(
    const float* __restrict__ x, const float* __restrict__ g,
    const float* __restrict__ bta, float* __restrict__ out32,
    __half* __restrict__ out16, int C)
{
    size_t row = blockIdx.x;
    int tid = threadIdx.x;
    float4 v = ((const float4*)(x + row * 1024))[tid];
    float s = v.x + v.y + v.z + v.w;
    float s2 = v.x * v.x + v.y * v.y + v.z * v.z + v.w * v.w;
#pragma unroll
    for (int o = 16; o; o >>= 1) {
        s += __shfl_xor_sync(~0u, s, o);
        s2 += __shfl_xor_sync(~0u, s2, o);
    }
    __shared__ float ws[8], wq[8];
    int w = tid >> 5, l = tid & 31;
    if (l == 0) { ws[w] = s; wq[w] = s2; }
    __syncthreads();
    float S = 0.f, S2 = 0.f;
#pragma unroll
    for (int i = 0; i < 8; i++) { S += ws[i]; S2 += wq[i]; }
    float mean = S * (1.f / 1024.f);
    float var  = S2 * (1.f / 1024.f) - mean * mean;
    float inv  = rsqrtf(var + 1e-5f);
    float4 gg = ((const float4*)g)[tid];
    float4 bb = ((const float4*)bta)[tid];
    float4 o;
    o.x = (v.x - mean) * inv * gg.x + bb.x;
    o.y = (v.y - mean) * inv * gg.y + bb.y;
    o.z = (v.z - mean) * inv * gg.z + bb.z;
    o.w = (v.w - mean) * inv * gg.w + bb.w;
    if (out32) ((float4*)(out32 + row * 1024))[tid] = o;
    uint2 p = make_uint2(packh2(o.x, o.y), packh2(o.z, o.w));
    *(uint2*)(out16 + row * 1024 + tid * 4) = p;
    (void)C;
}

// ---------------- pooled K weight (exact fp32 metric path) ----------------
__global__ void __launch_bounds__(256) pool_wk(
    const float* __restrict__ qkv_w, const float* __restrict__ qkv_b,
    float* __restrict__ wm, float* __restrict__ wmb)
{
    int idx = blockIdx.x * 256 + threadIdx.x;
    if (idx < 64 * 1024) {
        int d = idx >> 10, k = idx & 1023;
        float s = 0.f;
#pragma unroll
        for (int h = 0; h < 16; h++) s += qkv_w[(size_t)(1024 + h * 64 + d) * 1024 + k];
        wm[idx] = s * (1.f / 16.f);
    }
    if (idx < 64) {
        float s = 0.f;
#pragma unroll
        for (int h = 0; h < 16; h++) s += qkv_b[1024 + h * 64 + idx];
        wmb[idx] = s * (1.f / 16.f);
    }
}

// ---------------- fp32 metric GEMM, 64-row tiles (256 CTAs) ----------------
__global__ void __launch_bounds__(256) metric_gemm(
    const float* __restrict__ xln, const float* __restrict__ wm,
    const float* __restrict__ wmb, float* __restrict__ metric)
{
    __shared__ float Xs[32][68];
    __shared__ float Ws[32][68];
    const int bm = blockIdx.x * 64;
    const int tid = threadIdx.x;
    const int ty = tid >> 3;
    const int tx = tid & 7;
    float acc[2][8];
#pragma unroll
    for (int i = 0; i < 2; i++)
#pragma unroll
        for (int j = 0; j < 8; j++) acc[i][j] = 0.f;

    for (int k0 = 0; k0 < 1024; k0 += 32) {
#pragma unroll
        for (int i = 0; i < 2; i++) {
            int idx = tid + i * 256;
            int row = idx >> 3;
            int kq = (idx & 7) << 2;
            float4 v = *(const float4*)(xln + (size_t)(bm + row) * 1024 + k0 + kq);
            Xs[kq][row] = v.x; Xs[kq + 1][row] = v.y; Xs[kq + 2][row] = v.z; Xs[kq + 3][row] = v.w;
        }
        for (int idx = tid; idx < 512; idx += 256) {
            int d = idx >> 3;
            int kq = (idx & 7) << 2;
            float4 v = *(const float4*)(wm + (size_t)d * 1024 + k0 + kq);
            Ws[kq][d] = v.x; Ws[kq + 1][d] = v.y; Ws[kq + 2][d] = v.z; Ws[kq + 3][d] = v.w;
        }
        __syncthreads();
#pragma unroll
        for (int kk = 0; kk < 32; kk++) {
            float a[2], w[8];
#pragma unroll
            for (int i = 0; i < 2; i++) a[i] = Xs[kk][ty * 2 + i];
#pragma unroll
            for (int j = 0; j < 8; j++) w[j] = Ws[kk][tx * 8 + j];
#pragma unroll
            for (int i = 0; i < 2; i++)
#pragma unroll
                for (int j = 0; j < 8; j++) acc[i][j] += a[i] * w[j];
        }
        __syncthreads();
    }
#pragma unroll
    for (int i = 0; i < 2; i++) {
        int row = bm + ty * 2 + i;
#pragma unroll
        for (int j = 0; j < 8; j++)
            metric[(size_t)row * 64 + tx * 8 + j] = acc[i][j] + wmb[tx * 8 + j];
    }
}

__global__ void __launch_bounds__(64) metric_norm(float* __restrict__ metric)
{
    int bn = blockIdx.x;
    int d = threadIdx.x;
    float v = metric[(size_t)bn * 64 + d];
    __shared__ float sh[64];
    sh[d] = v * v; __syncthreads();
    for (int off = 32; off; off >>= 1) {
        if (d < off) sh[d] += sh[d + off];
        __syncthreads();
    }
    float inv = rsqrtf(sh[0]);
    metric[(size_t)bn * 64 + d] = v * inv;
}

// ---------------- matching ----------------
__global__ void __launch_bounds__(256) match_scores(
    const float* __restrict__ metric, float* __restrict__ nodemax, int* __restrict__ nodeidx)
{
    int t = blockIdx.x;
    int b = blockIdx.y;
    const float* mb = metric + (size_t)b * Nn * 64;
    __shared__ float av[64];
    int tid = threadIdx.x;
    if (tid < 64) av[tid] = mb[(size_t)(2 * t) * 64 + tid];
    __syncthreads();
    float best = -INFINITY; int bi = 0;
    for (int s = tid; s < NH; s += 256) {
        const float* bp = mb + (size_t)(2 * s + 1) * 64;
        float dot = 0.f;
#pragma unroll
        for (int d = 0; d < 64; d++) dot += av[d] * bp[d];
        if (dot > best) { best = dot; bi = s; }
    }
    __shared__ float sv[256]; __shared__ int si[256];
    sv[tid] = best; si[tid] = bi; __syncthreads();
    for (int off = 128; off; off >>= 1) {
        if (tid < off) {
            if (sv[tid + off] > sv[tid] ||
                (sv[tid + off] == sv[tid] && si[tid + off] < si[tid])) {
                sv[tid] = sv[tid + off]; si[tid] = si[tid + off];
            }
        }
        __syncthreads();
    }
    if (tid == 0) {
        if (t == 0) { nodemax[b * NH] = -INFINITY; nodeidx[b * NH] = 0; }
        else { nodemax[b * NH + t] = sv[0]; nodeidx[b * NH + t] = si[0]; }
    }
}

__global__ void __launch_bounds__(512) match_sort(
    const float* __restrict__ nodemax, const int* __restrict__ nodeidx,
    int* __restrict__ srcidx, int* __restrict__ dstidx, int* __restrict__ unmidx)
{
    int b = blockIdx.x, t = threadIdx.x;
    __shared__ float v[NH]; __shared__ int rk[NH];
    v[t] = nodemax[b * NH + t]; __syncthreads();
    float vt = v[t]; int r = 0;
    for (int j = 0; j < NH; j++) {
        float vj = v[j];
        r += (vj > vt) || (vj == vt && j < t);
    }
    rk[t] = r; __syncthreads();
    if (r < Rr) {
        srcidx[b * Rr + r] = t;
        dstidx[b * Rr + r] = nodeidx[b * NH + t];
    } else {
        int pos = 0;
        for (int j = 0; j < t; j++) pos += (rk[j] >= Rr);
        unmidx[b * NU + pos] = t;
    }
}

// ---------------- weighted merge + divide by new size (match-list) ----------
__global__ void __launch_bounds__(256) merge_kernel(
    const float* __restrict__ xres, const float* __restrict__ sz,
    const int* __restrict__ srcidx, const int* __restrict__ dstidx,
    const int* __restrict__ unmidx, float* __restrict__ xm)
{
    int row = blockIdx.x;
    int b = blockIdx.y;
    int tid = threadIdx.x;
    const float* xb = xres + (size_t)b * Nn * Cc;
    const float* szb = sz + b * Nn;
    float* ob = xm + ((size_t)b * NM + row) * Cc;

    if (row < NU) {
        int t = 2 * unmidx[b * NU + row];
        float s = szb[t];
        float inv = 1.f / s;
        for (int c = tid; c < Cc; c += 256)
            ob[c] = (xb[(size_t)t * Cc + c] * s) * inv;
    } else {
        int j = row - NU;
        __shared__ int sd[Rr], ss[Rr];
        __shared__ int mls[Rr]; __shared__ float msz[Rr];
        __shared__ int nmz; __shared__ float nsz;
        if (tid < Rr) { ss[tid] = srcidx[b * Rr + tid]; sd[tid] = dstidx[b * Rr + tid]; }
        __syncthreads();
        int t = 2 * j + 1;
        if (tid == 0) {
            int n = 0;
            float ns = szb[t];
            for (int i = 0; i < Rr; i++) {
                if (sd[i] == j) {
                    int ts = 2 * ss[i];
                    float s2 = szb[ts];
                    mls[n] = ts; msz[n] = s2; ns += s2; n++;
                }
            }
            nmz = n; nsz = ns;
        }
        __syncthreads();
        int nm = nmz;
        float inv = 1.f / nsz;
        float st = szb[t];
        for (int c = tid; c < Cc; c += 256) {
            float val = xb[(size_t)t * Cc + c] * st;
            for (int i = 0; i < nm; i++)
                val += xb[(size_t)mls[i] * Cc + c] * msz[i];
            ob[c] = val * inv;
        }
    }
}

// ---------------- launch ----------------
template <typename T>
static T* sym_addr(const void* sym) {
    void* p = nullptr;
    cudaGetSymbolAddress(&p, sym);
    return (T*)p;
}

extern "C" void kernel_launch(void* const* d_in, const int* in_sizes, int n_in,
                              void* d_out, int out_size)
{
    const float* x      = (const float*)d_in[0];
    const float* sz     = (const float*)d_in[1];
    const float* qkv_w  = (const float*)d_in[3];
    const float* qkv_b  = (const float*)d_in[4];
    const float* proj_w = (const float*)d_in[5];
    const float* proj_b = (const float*)d_in[6];
    const float* n1g    = (const float*)d_in[7];
    const float* n1b    = (const float*)d_in[8];
    const float* n2g    = (const float*)d_in[9];
    const float* n2b    = (const float*)d_in[10];
    const float* fc1_w  = (const float*)d_in[11];
    const float* fc1_b  = (const float*)d_in[12];
    const float* fc2_w  = (const float*)d_in[13];
    const float* fc2_b  = (const float*)d_in[14];
    float* out = (float*)d_out;

    float*  xln    = sym_addr<float>(g_xln);
    __half* xln_h  = sym_addr<__half>(g_xln_h);
    __half* qkv_h  = sym_addr<__half>(g_qkv_h);
    __half* attno_h= sym_addr<__half>(g_attno_h);
    float*  xres   = sym_addr<float>(g_xres);
    __half* h2_h   = sym_addr<__half>(g_h2_h);
    __half* fc1_h  = sym_addr<__half>(g_fc1_h);
    __half* wqkv_h = sym_addr<__half>(g_wqkv_h);
    __half* wproj_h= sym_addr<__half>(g_wproj_h);
    __half* wfc1_h = sym_addr<__half>(g_wfc1_h);
    __half* wfc2_h = sym_addr<__half>(g_wfc2_h);
    float* wm    = sym_addr<float>(g_wm);
    float* wmb   = sym_addr<float>(g_wmb);
    float* metric= sym_addr<float>(g_metric);
    float* nmax  = sym_addr<float>(g_nodemax);
    int*   nidx  = sym_addr<int>(g_nodeidx);
    int*   sidx  = sym_addr<int>(g_srcidx);
    int*   didx  = sym_addr<int>(g_dstidx);
    int*   uidx  = sym_addr<int>(g_unmidx);
    float* xm    = sym_addr<float>(g_xm);

    cudaFuncSetAttribute(flash_attn, cudaFuncAttributeMaxDynamicSharedMemorySize, FLASH_SMEM);
    cudaFuncSetAttribute(fp16_gemm, cudaFuncAttributeMaxDynamicSharedMemorySize, GEMM_SMEM);

    // 0. weight conversion (fp32 -> fp16)
    cvt_f2h<<<(3 * 1024 * 1024 / 4 + 255) / 256, 256>>>(qkv_w, wqkv_h, 3 * 1024 * 1024 / 4);
    cvt_f2h<<<(1024 * 1024 / 4 + 255) / 256, 256>>>(proj_w, wproj_h, 1024 * 1024 / 4);
    cvt_f2h<<<(4 * 1024 * 1024 / 4 + 255) / 256, 256>>>(fc1_w, wfc1_h, 4 * 1024 * 1024 / 4);
    cvt_f2h<<<(4 * 1024 * 1024 / 4 + 255) / 256, 256>>>(fc2_w, wfc2_h, 4 * 1024 * 1024 / 4);

    // 1. LN1 (dual output)
    ln_kernel<<<MROWS, 256>>>(x, n1g, n1b, xln, xln_h, Cc);
    // 2. QKV GEMM -> half
    fp16_gemm<<<dim3(3072 / 128, MROWS / 128), 256, GEMM_SMEM>>>(
        xln_h, wqkv_h, qkv_b, nullptr, nullptr, qkv_h, MROWS, 3072, Cc, 0);
    // 3. exact fp32 metric path
    pool_wk<<<256, 256>>>(qkv_w, qkv_b, wm, wmb);
    metric_gemm<<<MROWS / 64, 256>>>(xln, wm, wmb, metric);
    metric_norm<<<Bb * Nn, 64>>>(metric);
    // 4. fused flash attention (fp16) -> half
    flash_attn<<<dim3(8, Bb * Hh), 256, FLASH_SMEM>>>(qkv_h, sz, attno_h);
    // 5. proj + residual -> fp32
    fp16_gemm<<<dim3(Cc / 128, MROWS / 128), 256, GEMM_SMEM>>>(
        attno_h, wproj_h, proj_b, x, xres, nullptr, MROWS, Cc, Cc, 0);
    // 6. matching
    match_scores<<<dim3(NH, Bb), 256>>>(metric, nmax, nidx);
    match_sort<<<Bb, NH>>>(nmax, nidx, sidx, didx, uidx);
    // 7. merge
    merge_kernel<<<dim3(NM, Bb), 256>>>(xres, sz, sidx, didx, uidx, xm);
    // 8. LN2 -> half only
    ln_kernel<<<MROWS2, 256>>>(xm, n2g, n2b, nullptr, h2_h, Cc);
    // 9. fc1 + GELU -> half
    fp16_gemm<<<dim3(4096 / 128, MROWS2 / 128), 256, GEMM_SMEM>>>(
        h2_h, wfc1_h, fc1_b, nullptr, nullptr, fc1_h, MROWS2, 4096, Cc, 1);
    // 10. fc2 + residual -> out (fp32)
    fp16_gemm<<<dim3(Cc / 128, MROWS2 / 128), 256, GEMM_SMEM>>>(
        fc1_h, wfc2_h, fc2_b, xm, out, nullptr, MROWS2, Cc, 4096, 0);
    (void)in_sizes; (void)n_in; (void)out_size;
}

// round 14
// speedup vs baseline: 5.1042x; 1.0736x over previous
#include <cuda_runtime.h>
#include <cuda_bf16.h>
#include <cuda_fp16.h>
#include <math.h>
#include <cstdint>

// Problem constants
#define Bb 16
#define Nn 1024
#define Cc 1024
#define Hh 16
#define HD 64
#define Rr 128
#define NH (Nn/2)          // 512
#define NU (NH - Rr)       // 384 unmerged
#define NM (NU + NH)       // 896 merged tokens
#define MROWS (Bb*Nn)      // 16384
#define MROWS2 (Bb*NM)     // 14336

// ---------------- scratch (static device globals) ----------------
__device__ float  g_xln  [(size_t)MROWS * Cc];           // fp32 (metric path)
__device__ __half g_xln_h[(size_t)MROWS * Cc];
__device__ __half g_qkv_h[(size_t)MROWS * 3 * Cc];
__device__ __half g_attno_h[(size_t)MROWS * Cc];
__device__ float  g_xres [(size_t)MROWS * Cc];
__device__ __half g_h2_h [(size_t)MROWS2 * Cc];
__device__ __half g_fc1_h[(size_t)MROWS2 * 4 * Cc];
__device__ __half g_wqkv_h[(size_t)3 * Cc * Cc];
__device__ __half g_wproj_h[(size_t)Cc * Cc];
__device__ __half g_wfc1_h[(size_t)4 * Cc * Cc];
__device__ __half g_wfc2_h[(size_t)Cc * 4 * Cc];
__device__ float g_wm   [64 * 1024];
__device__ float g_wmb  [64];
__device__ float g_metric[(size_t)Bb * Nn * HD];
__device__ float g_nodemax[Bb * NH];
__device__ int   g_nodeidx[Bb * NH];
__device__ int   g_srcidx[Bb * Rr];
__device__ int   g_dstidx[Bb * Rr];
__device__ int   g_unmidx[Bb * NU];
__device__ float g_xm   [(size_t)MROWS2 * Cc];

__device__ __forceinline__ uint32_t packh2(float x, float y) {
    __half2 h = __floats2half2_rn(x, y);
    return *(uint32_t*)&h;
}
__device__ __forceinline__ uint32_t smem_u32(const void* p) {
    uint32_t a;
    asm("{ .reg .u64 t; cvta.to.shared.u64 t, %1; cvt.u32.u64 %0, t; }" : "=r"(a) : "l"(p));
    return a;
}
#define CPA16(dst, src) \
    asm volatile("cp.async.cg.shared.global [%0], [%1], 16;" :: "r"(dst), "l"(src))
#define CP_COMMIT() asm volatile("cp.async.commit_group;" ::: "memory")
#define CP_WAIT1()  asm volatile("cp.async.wait_group 1;" ::: "memory")
#define LDMX4(r0, r1, r2, r3, addr) \
    asm volatile("ldmatrix.sync.aligned.m8n8.x4.shared.b16 {%0,%1,%2,%3}, [%4];" \
        : "=r"(r0), "=r"(r1), "=r"(r2), "=r"(r3) : "r"(addr))

__device__ __forceinline__ void mma_f16(float& d0, float& d1, float& d2, float& d3,
                                        uint32_t a0, uint32_t a1, uint32_t a2, uint32_t a3,
                                        uint32_t b0, uint32_t b1)
{
    asm volatile(
        "mma.sync.aligned.m16n8k16.row.col.f32.f16.f16.f32 "
        "{%0,%1,%2,%3}, {%4,%5,%6,%7}, {%8,%9}, {%0,%1,%2,%3};\n"
        : "+f"(d0), "+f"(d1), "+f"(d2), "+f"(d3)
        : "r"(a0), "r"(a1), "r"(a2), "r"(a3), "r"(b0), "r"(b1));
}

// ---------------- fused f32 -> f16 converter (all 4 weights) ----------------
#define CVT_N0 (3*1024*1024/4)
#define CVT_N1 (1024*1024/4)
#define CVT_N2 (4*1024*1024/4)
#define CVT_N3 (4*1024*1024/4)
__global__ void __launch_bounds__(256) cvt_all(
    const float* __restrict__ s0, __half* __restrict__ d0,
    const float* __restrict__ s1, __half* __restrict__ d1,
    const float* __restrict__ s2, __half* __restrict__ d2,
    const float* __restrict__ s3, __half* __restrict__ d3)
{
    int i = blockIdx.x * 256 + threadIdx.x;
    const float* src; __half* dst;
    if (i < CVT_N0) { src = s0; dst = d0; }
    else if ((i -= CVT_N0) < CVT_N1) { src = s1; dst = d1; }
    else if ((i -= CVT_N1) < CVT_N2) { src = s2; dst = d2; }
    else if ((i -= CVT_N2) < CVT_N3) { src = s3; dst = d3; }
    else return;
    float4 v = *(const float4*)(src + (size_t)i * 4);
    uint2 p = make_uint2(packh2(v.x, v.y), packh2(v.z, v.w));
    *(uint2*)(dst + (size_t)i * 4) = p;
}

// ================= fp16 GEMM: ldmatrix + XOR swizzle + cp.async, 2 CTA/SM =====
#define GEMM_BUFB 16384                 // 128 rows * 128 B
#define GEMM_SMEM (3 * 2 * GEMM_BUFB)   // 96 KB

__global__ void __launch_bounds__(256, 2) fp16_gemm(
    const __half* __restrict__ A, const __half* __restrict__ W,
    const float* __restrict__ bias, const float* __restrict__ res,
    float* __restrict__ out32, __half* __restrict__ out16,
    int M, int N, int K, int act)
{
    extern __shared__ char smg[];
    const uint32_t sA = smem_u32(smg);
    const uint32_t sB = sA + 3 * GEMM_BUFB;

    const int tid = threadIdx.x;
    const int wid = tid >> 5;
    const int lane = tid & 31;
    const int g = lane >> 2;
    const int tg = lane & 3;
    const int wm = wid & 3;
    const int wn = wid >> 2;
    const int bm = blockIdx.y * 128;
    const int bn = blockIdx.x * 128;

    uint32_t dstoff[4]; size_t srcoffA[4], srcoffW[4];
#pragma unroll
    for (int i = 0; i < 4; i++) {
        int idx = tid + i * 256;
        int row = idx >> 3, c = idx & 7;
        dstoff[i] = row * 128 + ((c ^ (row & 7)) << 4);
        srcoffA[i] = (size_t)(bm + row) * K + c * 8;
        srcoffW[i] = (size_t)(bn + row) * K + c * 8;
    }

    const int sel = lane >> 3;
    const int lrow = lane & 7;
    const int csel = sel >> 1;
    const int rsel = sel & 1;
    uint32_t aBase[2]; int aRow7[2];
#pragma unroll
    for (int mt = 0; mt < 2; mt++) {
        int ra = wm * 32 + mt * 16 + rsel * 8 + lrow;
        aBase[mt] = ra * 128; aRow7[mt] = ra & 7;
    }
    uint32_t bBase[4]; int bRow7[4];
#pragma unroll
    for (int p = 0; p < 4; p++) {
        int nb = wn * 64 + p * 16 + rsel * 8 + lrow;
        bBase[p] = nb * 128; bRow7[p] = nb & 7;
    }

    float acc[2][8][4];
#pragma unroll
    for (int i = 0; i < 2; i++)
#pragma unroll
        for (int j = 0; j < 8; j++)
#pragma unroll
            for (int v = 0; v < 4; v++) acc[i][j][v] = 0.f;

    const int NS = K >> 6;
    {
#pragma unroll
        for (int i = 0; i < 4; i++) {
            CPA16(sA + dstoff[i], A + srcoffA[i]);
            CPA16(sB + dstoff[i], W + srcoffW[i]);
        }
        CP_COMMIT();
        if (NS > 1) {
#pragma unroll
            for (int i = 0; i < 4; i++) {
                CPA16(sA + GEMM_BUFB + dstoff[i], A + srcoffA[i] + 64);
                CPA16(sB + GEMM_BUFB + dstoff[i], W + srcoffW[i] + 64);
            }
        }
        CP_COMMIT();
        CP_WAIT1();
        __syncthreads();
    }

    for (int s = 0; s < NS; s++) {
        const uint32_t bufA = sA + (s % 3) * GEMM_BUFB;
        const uint32_t bufB = sB + (s % 3) * GEMM_BUFB;
#pragma unroll
        for (int kq = 0; kq < 4; kq++) {
            const int cc = kq * 2 + csel;
            uint32_t a[2][4];
#pragma unroll
            for (int mt = 0; mt < 2; mt++)
                LDMX4(a[mt][0], a[mt][1], a[mt][2], a[mt][3],
                      bufA + aBase[mt] + (uint32_t)(((cc ^ aRow7[mt])) << 4));
            uint32_t bm4[4][4];
#pragma unroll
            for (int p = 0; p < 4; p++)
                LDMX4(bm4[p][0], bm4[p][1], bm4[p][2], bm4[p][3],
                      bufB + bBase[p] + (uint32_t)(((cc ^ bRow7[p])) << 4));
#pragma unroll
            for (int mt = 0; mt < 2; mt++)
#pragma unroll
                for (int p = 0; p < 4; p++) {
                    mma_f16(acc[mt][2 * p][0], acc[mt][2 * p][1],
                            acc[mt][2 * p][2], acc[mt][2 * p][3],
                            a[mt][0], a[mt][1], a[mt][2], a[mt][3],
                            bm4[p][0], bm4[p][2]);
                    mma_f16(acc[mt][2 * p + 1][0], acc[mt][2 * p + 1][1],
                            acc[mt][2 * p + 1][2], acc[mt][2 * p + 1][3],
                            a[mt][0], a[mt][1], a[mt][2], a[mt][3],
                            bm4[p][1], bm4[p][3]);
                }
        }
        if (s + 1 < NS) {
            if (s + 2 < NS) {
                uint32_t qA = sA + ((s + 2) % 3) * GEMM_BUFB;
                uint32_t qB = sB + ((s + 2) % 3) * GEMM_BUFB;
                size_t k0 = (size_t)(s + 2) << 6;
#pragma unroll
                for (int i = 0; i < 4; i++) {
                    CPA16(qA + dstoff[i], A + srcoffA[i] + k0);
                    CPA16(qB + dstoff[i], W + srcoffW[i] + k0);
                }
            }
            CP_COMMIT();
            CP_WAIT1();
            __syncthreads();
        }
    }

#pragma unroll
    for (int mt = 0; mt < 2; mt++) {
        int r0 = bm + wm * 32 + mt * 16 + g;
#pragma unroll
        for (int nt = 0; nt < 8; nt++) {
            int col = bn + wn * 64 + nt * 8 + tg * 2;
            float b0 = bias[col], b1 = bias[col + 1];
            float v0 = acc[mt][nt][0] + b0;
            float v1 = acc[mt][nt][1] + b1;
            float v2 = acc[mt][nt][2] + b0;
            float v3 = acc[mt][nt][3] + b1;
            if (act) {
                v0 = 0.5f * v0 * (1.f + erff(v0 * 0.70710678118654752f));
                v1 = 0.5f * v1 * (1.f + erff(v1 * 0.70710678118654752f));
                v2 = 0.5f * v2 * (1.f + erff(v2 * 0.70710678118654752f));
                v3 = 0.5f * v3 * (1.f + erff(v3 * 0.70710678118654752f));
            }
            if (res) {
                const float* rp0 = res + (size_t)r0 * N + col;
                const float* rp1 = rp0 + (size_t)8 * N;
                v0 += rp0[0]; v1 += rp0[1];
                v2 += rp1[0]; v3 += rp1[1];
            }
            if (out32) {
                *(float2*)(out32 + (size_t)r0 * N + col) = make_float2(v0, v1);
                *(float2*)(out32 + (size_t)(r0 + 8) * N + col) = make_float2(v2, v3);
            } else {
                *(uint32_t*)(out16 + (size_t)r0 * N + col) = packh2(v0, v1);
                *(uint32_t*)(out16 + (size_t)(r0 + 8) * N + col) = packh2(v2, v3);
            }
        }
    }
}

// ================= fused flash attention, fp16 mma (verified R10) =================
#define QS_ST 36
#define KP_ST 68
#define VS_ST 68
#define FLASH_SMEM ((128*QS_ST + 128*KP_ST + 64*VS_ST + 1024 + 256 + 256) * 4)

__global__ void __launch_bounds__(256) flash_attn(
    const __half* __restrict__ qkv, const float* __restrict__ sz, __half* __restrict__ out)
{
    extern __shared__ uint32_t smw[];
    uint32_t* Qs = smw;
    uint32_t* KP = Qs + 128 * QS_ST;
    uint32_t* Vs = KP + 128 * KP_ST;
    float* logls = (float*)(Vs + 64 * VS_ST);
    float* redm  = logls + 1024;
    float* reds  = redm + 256;
    __half* Vs_h = (__half*)Vs;

    const int tid = threadIdx.x;
    const int wid = tid >> 5, lane = tid & 31;
    const int g = lane >> 2, tg = lane & 3;
    const int wm = wid & 3;
    const int wnn = wid >> 2;
    const int bh = blockIdx.y;
    const int b = bh >> 4, h = bh & 15;
    const int n0 = blockIdx.x * 128;
    const __half* qb = qkv + (size_t)b * Nn * 3072 + h * 64;
    const __half* kb = qb + 1024;
    const __half* vb = qb + 2048;

    for (int i = tid; i < 1024; i += 256)
        logls[i] = __logf(sz[b * Nn + i]);

#pragma unroll
    for (int i = 0; i < 4; i++) {
        int idx = tid + i * 256;
        int row = idx >> 3;
        int seg = idx & 7;
        *(uint4*)&Qs[row * QS_ST + seg * 4] =
            *(const uint4*)(qb + (size_t)(n0 + row) * 3072 + seg * 8);
    }

    float m_i[2][2], l_i[2][2];
    float acc[2][4][4];
#pragma unroll
    for (int mt = 0; mt < 2; mt++)
#pragma unroll
        for (int rh = 0; rh < 2; rh++) { m_i[mt][rh] = -INFINITY; l_i[mt][rh] = 0.f; }
#pragma unroll
    for (int mt = 0; mt < 2; mt++)
#pragma unroll
        for (int nt = 0; nt < 4; nt++)
#pragma unroll
            for (int v = 0; v < 4; v++) acc[mt][nt][v] = 0.f;

    for (int m0 = 0; m0 < Nn; m0 += 128) {
        __syncthreads();
#pragma unroll
        for (int i = 0; i < 4; i++) {
            int idx = tid + i * 256;
            int row = idx >> 3;
            int seg = idx & 7;
            *(uint4*)&KP[row * KP_ST + seg * 4] =
                *(const uint4*)(kb + (size_t)(m0 + row) * 3072 + seg * 8);
            uint4 vv = *(const uint4*)(vb + (size_t)(m0 + row) * 3072 + seg * 8);
            const __half* vh = (const __half*)&vv;
#pragma unroll
            for (int j = 0; j < 8; j++)
                Vs_h[(seg * 8 + j) * (VS_ST * 2) + row] = vh[j];
        }
        __syncthreads();

        float s[2][8][4];
#pragma unroll
        for (int mt = 0; mt < 2; mt++)
#pragma unroll
            for (int nt = 0; nt < 8; nt++)
#pragma unroll
                for (int v = 0; v < 4; v++) s[mt][nt][v] = 0.f;
#pragma unroll
        for (int ks = 0; ks < 32; ks += 8) {
            uint32_t af[2][4];
#pragma unroll
            for (int mt = 0; mt < 2; mt++) {
                int ra = wm * 32 + mt * 16 + g;
                af[mt][0] = Qs[ra * QS_ST + ks + tg];
                af[mt][1] = Qs[(ra + 8) * QS_ST + ks + tg];
                af[mt][2] = Qs[ra * QS_ST + ks + tg + 4];
                af[mt][3] = Qs[(ra + 8) * QS_ST + ks + tg + 4];
            }
            uint32_t bf[8][2];
#pragma unroll
            for (int nt = 0; nt < 8; nt++) {
                int cb = wnn * 64 + nt * 8 + g;
                bf[nt][0] = KP[cb * KP_ST + ks + tg];
                bf[nt][1] = KP[cb * KP_ST + ks + tg + 4];
            }
#pragma unroll
            for (int mt = 0; mt < 2; mt++)
#pragma unroll
                for (int nt = 0; nt < 8; nt++)
                    mma_f16(s[mt][nt][0], s[mt][nt][1], s[mt][nt][2], s[mt][nt][3],
                            af[mt][0], af[mt][1], af[mt][2], af[mt][3],
                            bf[nt][0], bf[nt][1]);
        }

        float tmax[2][2];
#pragma unroll
        for (int mt = 0; mt < 2; mt++) { tmax[mt][0] = -INFINITY; tmax[mt][1] = -INFINITY; }
#pragma unroll
        for (int mt = 0; mt < 2; mt++)
#pragma unroll
            for (int nt = 0; nt < 8; nt++) {
                int col = wnn * 64 + nt * 8 + tg * 2;
                float ls0 = logls[m0 + col];
                float ls1 = logls[m0 + col + 1];
                s[mt][nt][0] = s[mt][nt][0] * 0.125f + ls0;
                s[mt][nt][1] = s[mt][nt][1] * 0.125f + ls1;
                s[mt][nt][2] = s[mt][nt][2] * 0.125f + ls0;
                s[mt][nt][3] = s[mt][nt][3] * 0.125f + ls1;
                tmax[mt][0] = fmaxf(tmax[mt][0], fmaxf(s[mt][nt][0], s[mt][nt][1]));
                tmax[mt][1] = fmaxf(tmax[mt][1], fmaxf(s[mt][nt][2], s[mt][nt][3]));
            }
#pragma unroll
        for (int mt = 0; mt < 2; mt++)
#pragma unroll
            for (int rh = 0; rh < 2; rh++) {
                float v = tmax[mt][rh];
                v = fmaxf(v, __shfl_xor_sync(~0u, v, 1));
                v = fmaxf(v, __shfl_xor_sync(~0u, v, 2));
                tmax[mt][rh] = v;
            }
        if (tg == 0) {
#pragma unroll
            for (int mt = 0; mt < 2; mt++)
#pragma unroll
                for (int rh = 0; rh < 2; rh++)
                    redm[wnn * 128 + wm * 32 + mt * 16 + rh * 8 + g] = tmax[mt][rh];
        }
        __syncthreads();

        float sc[2][2];
#pragma unroll
        for (int mt = 0; mt < 2; mt++)
#pragma unroll
            for (int rh = 0; rh < 2; rh++) {
                int row = wm * 32 + mt * 16 + rh * 8 + g;
                float mx = fmaxf(redm[row], redm[128 + row]);
                float mnew = fmaxf(m_i[mt][rh], mx);
                sc[mt][rh] = __expf(m_i[mt][rh] - mnew);
                m_i[mt][rh] = mnew;
                l_i[mt][rh] *= sc[mt][rh];
            }
#pragma unroll
        for (int mt = 0; mt < 2; mt++)
#pragma unroll
            for (int nt = 0; nt < 4; nt++) {
                acc[mt][nt][0] *= sc[mt][0];
                acc[mt][nt][1] *= sc[mt][0];
                acc[mt][nt][2] *= sc[mt][1];
                acc[mt][nt][3] *= sc[mt][1];
            }

        float tsum[2][2];
#pragma unroll
        for (int mt = 0; mt < 2; mt++) { tsum[mt][0] = 0.f; tsum[mt][1] = 0.f; }
#pragma unroll
        for (int mt = 0; mt < 2; mt++) {
            int r0 = wm * 32 + mt * 16 + g;
#pragma unroll
            for (int nt = 0; nt < 8; nt++) {
                int w2 = wnn * 32 + nt * 4 + tg;
                float p0 = __expf(s[mt][nt][0] - m_i[mt][0]);
                float p1 = __expf(s[mt][nt][1] - m_i[mt][0]);
                float p2 = __expf(s[mt][nt][2] - m_i[mt][1]);
                float p3 = __expf(s[mt][nt][3] - m_i[mt][1]);
                tsum[mt][0] += p0 + p1;
                tsum[mt][1] += p2 + p3;
                KP[r0 * KP_ST + w2] = packh2(p0, p1);
                KP[(r0 + 8) * KP_ST + w2] = packh2(p2, p3);
            }
        }
#pragma unroll
        for (int mt = 0; mt < 2; mt++)
#pragma unroll
            for (int rh = 0; rh < 2; rh++) {
                float v = tsum[mt][rh];
                v += __shfl_xor_sync(~0u, v, 1);
                v += __shfl_xor_sync(~0u, v, 2);
                tsum[mt][rh] = v;
            }
        if (tg == 0) {
#pragma unroll
            for (int mt = 0; mt < 2; mt++)
#pragma unroll
                for (int rh = 0; rh < 2; rh++)
                    reds[wnn * 128 + wm * 32 + mt * 16 + rh * 8 + g] = tsum[mt][rh];
        }
        __syncthreads();
#pragma unroll
        for (int mt = 0; mt < 2; mt++)
#pragma unroll
            for (int rh = 0; rh < 2; rh++) {
                int row = wm * 32 + mt * 16 + rh * 8 + g;
                l_i[mt][rh] += reds[row] + reds[128 + row];
            }

#pragma unroll
        for (int ks = 0; ks < 64; ks += 8) {
            uint32_t af[2][4];
#pragma unroll
            for (int mt = 0; mt < 2; mt++) {
                int ra = wm * 32 + mt * 16 + g;
                af[mt][0] = KP[ra * KP_ST + ks + tg];
                af[mt][1] = KP[(ra + 8) * KP_ST + ks + tg];
                af[mt][2] = KP[ra * KP_ST + ks + tg + 4];
                af[mt][3] = KP[(ra + 8) * KP_ST + ks + tg + 4];
            }
            uint32_t bf[4][2];
#pragma unroll
            for (int nt = 0; nt < 4; nt++) {
                int cb = wnn * 32 + nt * 8 + g;
                bf[nt][0] = Vs[cb * VS_ST + ks + tg];
                bf[nt][1] = Vs[cb * VS_ST + ks + tg + 4];
            }
#pragma unroll
            for (int mt = 0; mt < 2; mt++)
#pragma unroll
                for (int nt = 0; nt < 4; nt++)
                    mma_f16(acc[mt][nt][0], acc[mt][nt][1], acc[mt][nt][2], acc[mt][nt][3],
                            af[mt][0], af[mt][1], af[mt][2], af[mt][3],
                            bf[nt][0], bf[nt][1]);
        }
    }

#pragma unroll
    for (int mt = 0; mt < 2; mt++) {
        float inv0 = 1.f / l_i[mt][0];
        float inv1 = 1.f / l_i[mt][1];
        int r0 = n0 + wm * 32 + mt * 16 + g;
#pragma unroll
        for (int nt = 0; nt < 4; nt++) {
            int col = h * 64 + wnn * 32 + nt * 8 + tg * 2;
            *(uint32_t*)(out + ((size_t)b * Nn + r0) * Cc + col) =
                packh2(acc[mt][nt][0] * inv0, acc[mt][nt][1] * inv0);
            *(uint32_t*)(out + ((size_t)b * Nn + r0 + 8) * Cc + col) =
                packh2(acc[mt][nt][2] * inv1, acc[mt][nt][3] * inv1);
        }
    }
}

// ---------------- single-pass LayerNorm (float4, 1 barrier) ----------------
__global__ void __launch_bounds__(256) ln_kernel(
    const float* __restrict__ x, const float* __restrict__ g,
    const float* __restrict__ bta, float* __restrict__ out32,
    __half* __restrict__ out16, int C)
{
    size_t row = blockIdx.x;
    int tid = threadIdx.x;
    float4 v = ((const float4*)(x + row * 1024))[tid];
    float s = v.x + v.y + v.z + v.w;
    float s2 = v.x * v.x + v.y * v.y + v.z * v.z + v.w * v.w;
#pragma unroll
    for (int o = 16; o; o >>= 1) {
        s += __shfl_xor_sync(~0u, s, o);
        s2 += __shfl_xor_sync(~0u, s2, o);
    }
    __shared__ float ws[8], wq[8];
    int w = tid >> 5, l = tid & 31;
    if (l == 0) { ws[w] = s; wq[w] = s2; }
    __syncthreads();
    float S = 0.f, S2 = 0.f;
#pragma unroll
    for (int i = 0; i < 8; i++) { S += ws[i]; S2 += wq[i]; }
    float mean = S * (1.f / 1024.f);
    float var  = S2 * (1.f / 1024.f) - mean * mean;
    float inv  = rsqrtf(var + 1e-5f);
    float4 gg = ((const float4*)g)[tid];
    float4 bb = ((const float4*)bta)[tid];
    float4 o;
    o.x = (v.x - mean) * inv * gg.x + bb.x;
    o.y = (v.y - mean) * inv * gg.y + bb.y;
    o.z = (v.z - mean) * inv * gg.z + bb.z;
    o.w = (v.w - mean) * inv * gg.w + bb.w;
    if (out32) ((float4*)(out32 + row * 1024))[tid] = o;
    uint2 p = make_uint2(packh2(o.x, o.y), packh2(o.z, o.w));
    *(uint2*)(out16 + row * 1024 + tid * 4) = p;
    (void)C;
}

// ---------------- pooled K weight (exact fp32 metric path) ----------------
__global__ void __launch_bounds__(256) pool_wk(
    const float* __restrict__ qkv_w, const float* __restrict__ qkv_b,
    float* __restrict__ wm, float* __restrict__ wmb)
{
    int idx = blockIdx.x * 256 + threadIdx.x;
    if (idx < 64 * 1024) {
        int d = idx >> 10, k = idx & 1023;
        float s = 0.f;
#pragma unroll
        for (int h = 0; h < 16; h++) s += qkv_w[(size_t)(1024 + h * 64 + d) * 1024 + k];
        wm[idx] = s * (1.f / 16.f);
    }
    if (idx < 64) {
        float s = 0.f;
#pragma unroll
        for (int h = 0; h < 16; h++) s += qkv_b[1024 + h * 64 + idx];
        wmb[idx] = s * (1.f / 16.f);
    }
}

// ---------------- fp32 metric GEMM + fused row normalize ----------------
__global__ void __launch_bounds__(256) metric_gemm(
    const float* __restrict__ xln, const float* __restrict__ wm,
    const float* __restrict__ wmb, float* __restrict__ metric)
{
    __shared__ float Xs[32][68];
    __shared__ float Ws[32][68];
    const int bm = blockIdx.x * 64;
    const int tid = threadIdx.x;
    const int ty = tid >> 3;
    const int tx = tid & 7;
    float acc[2][8];
#pragma unroll
    for (int i = 0; i < 2; i++)
#pragma unroll
        for (int j = 0; j < 8; j++) acc[i][j] = 0.f;

    for (int k0 = 0; k0 < 1024; k0 += 32) {
#pragma unroll
        for (int i = 0; i < 2; i++) {
            int idx = tid + i * 256;
            int row = idx >> 3;
            int kq = (idx & 7) << 2;
            float4 v = *(const float4*)(xln + (size_t)(bm + row) * 1024 + k0 + kq);
            Xs[kq][row] = v.x; Xs[kq + 1][row] = v.y; Xs[kq + 2][row] = v.z; Xs[kq + 3][row] = v.w;
        }
        for (int idx = tid; idx < 512; idx += 256) {
            int d = idx >> 3;
            int kq = (idx & 7) << 2;
            float4 v = *(const float4*)(wm + (size_t)d * 1024 + k0 + kq);
            Ws[kq][d] = v.x; Ws[kq + 1][d] = v.y; Ws[kq + 2][d] = v.z; Ws[kq + 3][d] = v.w;
        }
        __syncthreads();
#pragma unroll
        for (int kk = 0; kk < 32; kk++) {
            float a[2], w[8];
#pragma unroll
            for (int i = 0; i < 2; i++) a[i] = Xs[kk][ty * 2 + i];
#pragma unroll
            for (int j = 0; j < 8; j++) w[j] = Ws[kk][tx * 8 + j];
#pragma unroll
            for (int i = 0; i < 2; i++)
#pragma unroll
                for (int j = 0; j < 8; j++) acc[i][j] += a[i] * w[j];
        }
        __syncthreads();
    }
    // fused normalize: each row's 64 dims live on 8 consecutive lanes (tx=0..7)
#pragma unroll
    for (int i = 0; i < 2; i++) {
        float vloc[8];
        float ssq = 0.f;
#pragma unroll
        for (int j = 0; j < 8; j++) {
            vloc[j] = acc[i][j] + wmb[tx * 8 + j];
            ssq += vloc[j] * vloc[j];
        }
        ssq += __shfl_xor_sync(~0u, ssq, 1);
        ssq += __shfl_xor_sync(~0u, ssq, 2);
        ssq += __shfl_xor_sync(~0u, ssq, 4);
        float inv = rsqrtf(ssq);
        int row = bm + ty * 2 + i;
#pragma unroll
        for (int j = 0; j < 8; j++)
            metric[(size_t)row * 64 + tx * 8 + j] = vloc[j] * inv;
    }
}

// ---------------- matching ----------------
__global__ void __launch_bounds__(256) match_scores(
    const float* __restrict__ metric, float* __restrict__ nodemax, int* __restrict__ nodeidx)
{
    int t = blockIdx.x;
    int b = blockIdx.y;
    const float* mb = metric + (size_t)b * Nn * 64;
    __shared__ float av[64];
    int tid = threadIdx.x;
    if (tid < 64) av[tid] = mb[(size_t)(2 * t) * 64 + tid];
    __syncthreads();
    float best = -INFINITY; int bi = 0;
    for (int s = tid; s < NH; s += 256) {
        const float* bp = mb + (size_t)(2 * s + 1) * 64;
        float dot = 0.f;
#pragma unroll
        for (int d = 0; d < 64; d++) dot += av[d] * bp[d];
        if (dot > best) { best = dot; bi = s; }
    }
    __shared__ float sv[256]; __shared__ int si[256];
    sv[tid] = best; si[tid] = bi; __syncthreads();
    for (int off = 128; off; off >>= 1) {
        if (tid < off) {
            if (sv[tid + off] > sv[tid] ||
                (sv[tid + off] == sv[tid] && si[tid + off] < si[tid])) {
                sv[tid] = sv[tid + off]; si[tid] = si[tid + off];
            }
        }
        __syncthreads();
    }
    if (tid == 0) {
        if (t == 0) { nodemax[b * NH] = -INFINITY; nodeidx[b * NH] = 0; }
        else { nodemax[b * NH + t] = sv[0]; nodeidx[b * NH + t] = si[0]; }
    }
}

__global__ void __launch_bounds__(512) match_sort(
    const float* __restrict__ nodemax, const int* __restrict__ nodeidx,
    int* __restrict__ srcidx, int* __restrict__ dstidx, int* __restrict__ unmidx)
{
    int b = blockIdx.x, t = threadIdx.x;
    __shared__ float v[NH]; __shared__ int rk[NH];
    v[t] = nodemax[b * NH + t]; __syncthreads();
    float vt = v[t]; int r = 0;
    for (int j = 0; j < NH; j++) {
        float vj = v[j];
        r += (vj > vt) || (vj == vt && j < t);
    }
    rk[t] = r; __syncthreads();
    if (r < Rr) {
        srcidx[b * Rr + r] = t;
        dstidx[b * Rr + r] = nodeidx[b * NH + t];
    } else {
        int pos = 0;
        for (int j = 0; j < t; j++) pos += (rk[j] >= Rr);
        unmidx[b * NU + pos] = t;
    }
}

// ---------------- weighted merge + divide by new size (match-list) ----------
__global__ void __launch_bounds__(256) merge_kernel(
    const float* __restrict__ xres, const float* __restrict__ sz,
    const int* __restrict__ srcidx, const int* __restrict__ dstidx,
    const int* __restrict__ unmidx, float* __restrict__ xm)
{
    int row = blockIdx.x;
    int b = blockIdx.y;
    int tid = threadIdx.x;
    const float* xb = xres + (size_t)b * Nn * Cc;
    const float* szb = sz + b * Nn;
    float* ob = xm + ((size_t)b * NM + row) * Cc;

    if (row < NU) {
        int t = 2 * unmidx[b * NU + row];
        float s = szb[t];
        float inv = 1.f / s;
        for (int c = tid; c < Cc; c += 256)
            ob[c] = (xb[(size_t)t * Cc + c] * s) * inv;
    } else {
        int j = row - NU;
        __shared__ int sd[Rr], ss[Rr];
        __shared__ int mls[Rr]; __shared__ float msz[Rr];
        __shared__ int nmz; __shared__ float nsz;
        if (tid < Rr) { ss[tid] = srcidx[b * Rr + tid]; sd[tid] = dstidx[b * Rr + tid]; }
        __syncthreads();
        int t = 2 * j + 1;
        if (tid == 0) {
            int n = 0;
            float ns = szb[t];
            for (int i = 0; i < Rr; i++) {
                if (sd[i] == j) {
                    int ts = 2 * ss[i];
                    float s2 = szb[ts];
                    mls[n] = ts; msz[n] = s2; ns += s2; n++;
                }
            }
            nmz = n; nsz = ns;
        }
        __syncthreads();
        int nm = nmz;
        float inv = 1.f / nsz;
        float st = szb[t];
        for (int c = tid; c < Cc; c += 256) {
            float val = xb[(size_t)t * Cc + c] * st;
            for (int i = 0; i < nm; i++)
                val += xb[(size_t)mls[i] * Cc + c] * msz[i];
            ob[c] = val * inv;
        }
    }
}

// ---------------- launch ----------------
template <typename T>
static T* sym_addr(const void* sym) {
    void* p = nullptr;
    cudaGetSymbolAddress(&p, sym);
    return (T*)p;
}

extern "C" void kernel_launch(void* const* d_in, const int* in_sizes, int n_in,
                              void* d_out, int out_size)
{
    const float* x      = (const float*)d_in[0];
    const float* sz     = (const float*)d_in[1];
    const float* qkv_w  = (const float*)d_in[3];
    const float* qkv_b  = (const float*)d_in[4];
    const float* proj_w = (const float*)d_in[5];
    const float* proj_b = (const float*)d_in[6];
    const float* n1g    = (const float*)d_in[7];
    const float* n1b    = (const float*)d_in[8];
    const float* n2g    = (const float*)d_in[9];
    const float* n2b    = (const float*)d_in[10];
    const float* fc1_w  = (const float*)d_in[11];
    const float* fc1_b  = (const float*)d_in[12];
    const float* fc2_w  = (const float*)d_in[13];
    const float* fc2_b  = (const float*)d_in[14];
    float* out = (float*)d_out;

    float*  xln    = sym_addr<float>(g_xln);
    __half* xln_h  = sym_addr<__half>(g_xln_h);
    __half* qkv_h  = sym_addr<__half>(g_qkv_h);
    __half* attno_h= sym_addr<__half>(g_attno_h);
    float*  xres   = sym_addr<float>(g_xres);
    __half* h2_h   = sym_addr<__half>(g_h2_h);
    __half* fc1_h  = sym_addr<__half>(g_fc1_h);
    __half* wqkv_h = sym_addr<__half>(g_wqkv_h);
    __half* wproj_h= sym_addr<__half>(g_wproj_h);
    __half* wfc1_h = sym_addr<__half>(g_wfc1_h);
    __half* wfc2_h = sym_addr<__half>(g_wfc2_h);
    float* wm    = sym_addr<float>(g_wm);
    float* wmb   = sym_addr<float>(g_wmb);
    float* metric= sym_addr<float>(g_metric);
    float* nmax  = sym_addr<float>(g_nodemax);
    int*   nidx  = sym_addr<int>(g_nodeidx);
    int*   sidx  = sym_addr<int>(g_srcidx);
    int*   didx  = sym_addr<int>(g_dstidx);
    int*   uidx  = sym_addr<int>(g_unmidx);
    float* xm    = sym_addr<float>(g_xm);

    cudaFuncSetAttribute(flash_attn, cudaFuncAttributeMaxDynamicSharedMemorySize, FLASH_SMEM);
    cudaFuncSetAttribute(fp16_gemm, cudaFuncAttributeMaxDynamicSharedMemorySize, GEMM_SMEM);

    // 0. weight conversion (fp32 -> fp16), single fused launch
    {
        int total = CVT_N0 + CVT_N1 + CVT_N2 + CVT_N3;
        cvt_all<<<(total + 255) / 256, 256>>>(qkv_w, wqkv_h, proj_w, wproj_h,
                                              fc1_w, wfc1_h, fc2_w, wfc2_h);
    }

    // 1. LN1 (dual output)
    ln_kernel<<<MROWS, 256>>>(x, n1g, n1b, xln, xln_h, Cc);
    // 2. QKV GEMM -> half
    fp16_gemm<<<dim3(3072 / 128, MROWS / 128), 256, GEMM_SMEM>>>(
        xln_h, wqkv_h, qkv_b, nullptr, nullptr, qkv_h, MROWS, 3072, Cc, 0);
    // 3. exact fp32 metric path (norm fused into GEMM epilogue)
    pool_wk<<<256, 256>>>(qkv_w, qkv_b, wm, wmb);
    metric_gemm<<<MROWS / 64, 256>>>(xln, wm, wmb, metric);
    // 4. fused flash attention (fp16) -> half
    flash_attn<<<dim3(8, Bb * Hh), 256, FLASH_SMEM>>>(qkv_h, sz, attno_h);
    // 5. proj + residual -> fp32
    fp16_gemm<<<dim3(Cc / 128, MROWS / 128), 256, GEMM_SMEM>>>(
        attno_h, wproj_h, proj_b, x, xres, nullptr, MROWS, Cc, Cc, 0);
    // 6. matching
    match_scores<<<dim3(NH, Bb), 256>>>(metric, nmax, nidx);
    match_sort<<<Bb, NH>>>(nmax, nidx, sidx, didx, uidx);
    // 7. merge
    merge_kernel<<<dim3(NM, Bb), 256>>>(xres, sz, sidx, didx, uidx, xm);
    // 8. LN2 -> half only
    ln_kernel<<<MROWS2, 256>>>(xm, n2g, n2b, nullptr, h2_h, Cc);
    // 9. fc1 + GELU -> half
    fp16_gemm<<<dim3(4096 / 128, MROWS2 / 128), 256, GEMM_SMEM>>>(
        h2_h, wfc1_h, fc1_b, nullptr, nullptr, fc1_h, MROWS2, 4096, Cc, 1);
    // 10. fc2 + residual -> out (fp32)
    fp16_gemm<<<dim3(Cc / 128, MROWS2 / 128), 256, GEMM_SMEM>>>(
        fc1_h, wfc2_h, fc2_b, xm, out, nullptr, MROWS2, Cc, 4096, 0);
    (void)in_sizes; (void)n_in; (void)out_size;
}

// round 15
// speedup vs baseline: 5.1182x; 1.0027x over previous
#include <cuda_runtime.h>
#include <cuda_bf16.h>
#include <cuda_fp16.h>
#include <math.h>
#include <cstdint>

// Problem constants
#define Bb 16
#define Nn 1024
#define Cc 1024
#define Hh 16
#define HD 64
#define Rr 128
#define NH (Nn/2)          // 512
#define NU (NH - Rr)       // 384 unmerged
#define NM (NU + NH)       // 896 merged tokens
#define MROWS (Bb*Nn)      // 16384
#define MROWS2 (Bb*NM)     // 14336

// ---------------- scratch (static device globals) ----------------
__device__ float  g_xln  [(size_t)MROWS * Cc];           // fp32 (metric path)
__device__ __half g_xln_h[(size_t)MROWS * Cc];
__device__ __half g_qkv_h[(size_t)MROWS * 3 * Cc];
__device__ __half g_attno_h[(size_t)MROWS * Cc];
__device__ float  g_xres [(size_t)MROWS * Cc];
__device__ __half g_h2_h [(size_t)MROWS2 * Cc];
__device__ __half g_fc1_h[(size_t)MROWS2 * 4 * Cc];
__device__ __half g_wqkv_h[(size_t)3 * Cc * Cc];
__device__ __half g_wproj_h[(size_t)Cc * Cc];
__device__ __half g_wfc1_h[(size_t)4 * Cc * Cc];
__device__ __half g_wfc2_h[(size_t)Cc * 4 * Cc];
__device__ float g_wm   [64 * 1024];
__device__ float g_wmb  [64];
__device__ float g_metric[(size_t)Bb * Nn * HD];
__device__ float g_nodemax[Bb * NH];
__device__ int   g_nodeidx[Bb * NH];
__device__ int   g_srcidx[Bb * Rr];
__device__ int   g_dstidx[Bb * Rr];
__device__ int   g_unmidx[Bb * NU];
__device__ float g_xm   [(size_t)MROWS2 * Cc];

__device__ __forceinline__ uint32_t packh2(float x, float y) {
    __half2 h = __floats2half2_rn(x, y);
    return *(uint32_t*)&h;
}
__device__ __forceinline__ uint32_t smem_u32(const void* p) {
    uint32_t a;
    asm("{ .reg .u64 t; cvta.to.shared.u64 t, %1; cvt.u32.u64 %0, t; }" : "=r"(a) : "l"(p));
    return a;
}
#define CPA16(dst, src) \
    asm volatile("cp.async.cg.shared.global [%0], [%1], 16;" :: "r"(dst), "l"(src))
#define CP_COMMIT() asm volatile("cp.async.commit_group;" ::: "memory")
#define CP_WAIT1()  asm volatile("cp.async.wait_group 1;" ::: "memory")
#define LDMX4(r0, r1, r2, r3, addr) \
    asm volatile("ldmatrix.sync.aligned.m8n8.x4.shared.b16 {%0,%1,%2,%3}, [%4];" \
        : "=r"(r0), "=r"(r1), "=r"(r2), "=r"(r3) : "r"(addr))

__device__ __forceinline__ void mma_f16(float& d0, float& d1, float& d2, float& d3,
                                        uint32_t a0, uint32_t a1, uint32_t a2, uint32_t a3,
                                        uint32_t b0, uint32_t b1)
{
    asm volatile(
        "mma.sync.aligned.m16n8k16.row.col.f32.f16.f16.f32 "
        "{%0,%1,%2,%3}, {%4,%5,%6,%7}, {%8,%9}, {%0,%1,%2,%3};\n"
        : "+f"(d0), "+f"(d1), "+f"(d2), "+f"(d3)
        : "r"(a0), "r"(a1), "r"(a2), "r"(a3), "r"(b0), "r"(b1));
}

// ---------------- fused f32 -> f16 converter (all 4 weights) ----------------
#define CVT_N0 (3*1024*1024/4)
#define CVT_N1 (1024*1024/4)
#define CVT_N2 (4*1024*1024/4)
#define CVT_N3 (4*1024*1024/4)
__global__ void __launch_bounds__(256) cvt_all(
    const float* __restrict__ s0, __half* __restrict__ d0,
    const float* __restrict__ s1, __half* __restrict__ d1,
    const float* __restrict__ s2, __half* __restrict__ d2,
    const float* __restrict__ s3, __half* __restrict__ d3)
{
    int i = blockIdx.x * 256 + threadIdx.x;
    const float* src; __half* dst;
    if (i < CVT_N0) { src = s0; dst = d0; }
    else if ((i -= CVT_N0) < CVT_N1) { src = s1; dst = d1; }
    else if ((i -= CVT_N1) < CVT_N2) { src = s2; dst = d2; }
    else if ((i -= CVT_N2) < CVT_N3) { src = s3; dst = d3; }
    else return;
    float4 v = *(const float4*)(src + (size_t)i * 4);
    uint2 p = make_uint2(packh2(v.x, v.y), packh2(v.z, v.w));
    *(uint2*)(dst + (size_t)i * 4) = p;
}

// ================= fp16 GEMM: ldmatrix + XOR swizzle + cp.async, 2 CTA/SM =====
#define GEMM_BUFB 16384                 // 128 rows * 128 B
#define GEMM_SMEM (3 * 2 * GEMM_BUFB)   // 96 KB

__global__ void __launch_bounds__(256, 2) fp16_gemm(
    const __half* __restrict__ A, const __half* __restrict__ W,
    const float* __restrict__ bias, const float* __restrict__ res,
    float* __restrict__ out32, __half* __restrict__ out16,
    int M, int N, int K, int act)
{
    extern __shared__ char smg[];
    const uint32_t sA = smem_u32(smg);
    const uint32_t sB = sA + 3 * GEMM_BUFB;

    const int tid = threadIdx.x;
    const int wid = tid >> 5;
    const int lane = tid & 31;
    const int g = lane >> 2;
    const int tg = lane & 3;
    const int wm = wid & 3;
    const int wn = wid >> 2;
    const int bm = blockIdx.y * 128;
    const int bn = blockIdx.x * 128;

    uint32_t dstoff[4]; size_t srcoffA[4], srcoffW[4];
#pragma unroll
    for (int i = 0; i < 4; i++) {
        int idx = tid + i * 256;
        int row = idx >> 3, c = idx & 7;
        dstoff[i] = row * 128 + ((c ^ (row & 7)) << 4);
        srcoffA[i] = (size_t)(bm + row) * K + c * 8;
        srcoffW[i] = (size_t)(bn + row) * K + c * 8;
    }

    const int sel = lane >> 3;
    const int lrow = lane & 7;
    const int csel = sel >> 1;
    const int rsel = sel & 1;
    uint32_t aBase[2]; int aRow7[2];
#pragma unroll
    for (int mt = 0; mt < 2; mt++) {
        int ra = wm * 32 + mt * 16 + rsel * 8 + lrow;
        aBase[mt] = ra * 128; aRow7[mt] = ra & 7;
    }
    uint32_t bBase[4]; int bRow7[4];
#pragma unroll
    for (int p = 0; p < 4; p++) {
        int nb = wn * 64 + p * 16 + rsel * 8 + lrow;
        bBase[p] = nb * 128; bRow7[p] = nb & 7;
    }

    float acc[2][8][4];
#pragma unroll
    for (int i = 0; i < 2; i++)
#pragma unroll
        for (int j = 0; j < 8; j++)
#pragma unroll
            for (int v = 0; v < 4; v++) acc[i][j][v] = 0.f;

    const int NS = K >> 6;
    {
#pragma unroll
        for (int i = 0; i < 4; i++) {
            CPA16(sA + dstoff[i], A + srcoffA[i]);
            CPA16(sB + dstoff[i], W + srcoffW[i]);
        }
        CP_COMMIT();
        if (NS > 1) {
#pragma unroll
            for (int i = 0; i < 4; i++) {
                CPA16(sA + GEMM_BUFB + dstoff[i], A + srcoffA[i] + 64);
                CPA16(sB + GEMM_BUFB + dstoff[i], W + srcoffW[i] + 64);
            }
        }
        CP_COMMIT();
        CP_WAIT1();
        __syncthreads();
    }

    for (int s = 0; s < NS; s++) {
        const uint32_t bufA = sA + (s % 3) * GEMM_BUFB;
        const uint32_t bufB = sB + (s % 3) * GEMM_BUFB;
#pragma unroll
        for (int kq = 0; kq < 4; kq++) {
            const int cc = kq * 2 + csel;
            uint32_t a[2][4];
#pragma unroll
            for (int mt = 0; mt < 2; mt++)
                LDMX4(a[mt][0], a[mt][1], a[mt][2], a[mt][3],
                      bufA + aBase[mt] + (uint32_t)(((cc ^ aRow7[mt])) << 4));
            uint32_t bm4[4][4];
#pragma unroll
            for (int p = 0; p < 4; p++)
                LDMX4(bm4[p][0], bm4[p][1], bm4[p][2], bm4[p][3],
                      bufB + bBase[p] + (uint32_t)(((cc ^ bRow7[p])) << 4));
#pragma unroll
            for (int mt = 0; mt < 2; mt++)
#pragma unroll
                for (int p = 0; p < 4; p++) {
                    mma_f16(acc[mt][2 * p][0], acc[mt][2 * p][1],
                            acc[mt][2 * p][2], acc[mt][2 * p][3],
                            a[mt][0], a[mt][1], a[mt][2], a[mt][3],
                            bm4[p][0], bm4[p][2]);
                    mma_f16(acc[mt][2 * p + 1][0], acc[mt][2 * p + 1][1],
                            acc[mt][2 * p + 1][2], acc[mt][2 * p + 1][3],
                            a[mt][0], a[mt][1], a[mt][2], a[mt][3],
                            bm4[p][1], bm4[p][3]);
                }
        }
        if (s + 1 < NS) {
            if (s + 2 < NS) {
                uint32_t qA = sA + ((s + 2) % 3) * GEMM_BUFB;
                uint32_t qB = sB + ((s + 2) % 3) * GEMM_BUFB;
                size_t k0 = (size_t)(s + 2) << 6;
#pragma unroll
                for (int i = 0; i < 4; i++) {
                    CPA16(qA + dstoff[i], A + srcoffA[i] + k0);
                    CPA16(qB + dstoff[i], W + srcoffW[i] + k0);
                }
            }
            CP_COMMIT();
            CP_WAIT1();
            __syncthreads();
        }
    }

#pragma unroll
    for (int mt = 0; mt < 2; mt++) {
        int r0 = bm + wm * 32 + mt * 16 + g;
#pragma unroll
        for (int nt = 0; nt < 8; nt++) {
            int col = bn + wn * 64 + nt * 8 + tg * 2;
            float b0 = bias[col], b1 = bias[col + 1];
            float v0 = acc[mt][nt][0] + b0;
            float v1 = acc[mt][nt][1] + b1;
            float v2 = acc[mt][nt][2] + b0;
            float v3 = acc[mt][nt][3] + b1;
            if (act) {
                v0 = 0.5f * v0 * (1.f + erff(v0 * 0.70710678118654752f));
                v1 = 0.5f * v1 * (1.f + erff(v1 * 0.70710678118654752f));
                v2 = 0.5f * v2 * (1.f + erff(v2 * 0.70710678118654752f));
                v3 = 0.5f * v3 * (1.f + erff(v3 * 0.70710678118654752f));
            }
            if (res) {
                const float* rp0 = res + (size_t)r0 * N + col;
                const float* rp1 = rp0 + (size_t)8 * N;
                v0 += rp0[0]; v1 += rp0[1];
                v2 += rp1[0]; v3 += rp1[1];
            }
            if (out32) {
                *(float2*)(out32 + (size_t)r0 * N + col) = make_float2(v0, v1);
                *(float2*)(out32 + (size_t)(r0 + 8) * N + col) = make_float2(v2, v3);
            } else {
                *(uint32_t*)(out16 + (size_t)r0 * N + col) = packh2(v0, v1);
                *(uint32_t*)(out16 + (size_t)(r0 + 8) * N + col) = packh2(v2, v3);
            }
        }
    }
}

// ================= fused flash attention, fp16 mma, 2 CTA/SM =================
#define QS_ST 36
#define KP_ST 68
#define VS_ST 68
#define FLASH_SMEM ((128*QS_ST + 128*KP_ST + 64*VS_ST + 1024 + 256 + 256) * 4)

__global__ void __launch_bounds__(256, 2) flash_attn(
    const __half* __restrict__ qkv, const float* __restrict__ sz, __half* __restrict__ out)
{
    extern __shared__ uint32_t smw[];
    uint32_t* Qs = smw;
    uint32_t* KP = Qs + 128 * QS_ST;
    uint32_t* Vs = KP + 128 * KP_ST;
    float* logls = (float*)(Vs + 64 * VS_ST);
    float* redm  = logls + 1024;
    float* reds  = redm + 256;
    __half* Vs_h = (__half*)Vs;

    const int tid = threadIdx.x;
    const int wid = tid >> 5, lane = tid & 31;
    const int g = lane >> 2, tg = lane & 3;
    const int wm = wid & 3;
    const int wnn = wid >> 2;
    const int bh = blockIdx.y;
    const int b = bh >> 4, h = bh & 15;
    const int n0 = blockIdx.x * 128;
    const __half* qb = qkv + (size_t)b * Nn * 3072 + h * 64;
    const __half* kb = qb + 1024;
    const __half* vb = qb + 2048;

    for (int i = tid; i < 1024; i += 256)
        logls[i] = __logf(sz[b * Nn + i]);

#pragma unroll
    for (int i = 0; i < 4; i++) {
        int idx = tid + i * 256;
        int row = idx >> 3;
        int seg = idx & 7;
        *(uint4*)&Qs[row * QS_ST + seg * 4] =
            *(const uint4*)(qb + (size_t)(n0 + row) * 3072 + seg * 8);
    }

    float m_i[2][2], l_i[2][2];
    float acc[2][4][4];
#pragma unroll
    for (int mt = 0; mt < 2; mt++)
#pragma unroll
        for (int rh = 0; rh < 2; rh++) { m_i[mt][rh] = -INFINITY; l_i[mt][rh] = 0.f; }
#pragma unroll
    for (int mt = 0; mt < 2; mt++)
#pragma unroll
        for (int nt = 0; nt < 4; nt++)
#pragma unroll
            for (int v = 0; v < 4; v++) acc[mt][nt][v] = 0.f;

    for (int m0 = 0; m0 < Nn; m0 += 128) {
        __syncthreads();
#pragma unroll
        for (int i = 0; i < 4; i++) {
            int idx = tid + i * 256;
            int row = idx >> 3;
            int seg = idx & 7;
            *(uint4*)&KP[row * KP_ST + seg * 4] =
                *(const uint4*)(kb + (size_t)(m0 + row) * 3072 + seg * 8);
            uint4 vv = *(const uint4*)(vb + (size_t)(m0 + row) * 3072 + seg * 8);
            const __half* vh = (const __half*)&vv;
#pragma unroll
            for (int j = 0; j < 8; j++)
                Vs_h[(seg * 8 + j) * (VS_ST * 2) + row] = vh[j];
        }
        __syncthreads();

        float s[2][8][4];
#pragma unroll
        for (int mt = 0; mt < 2; mt++)
#pragma unroll
            for (int nt = 0; nt < 8; nt++)
#pragma unroll
                for (int v = 0; v < 4; v++) s[mt][nt][v] = 0.f;
#pragma unroll
        for (int ks = 0; ks < 32; ks += 8) {
            uint32_t af[2][4];
#pragma unroll
            for (int mt = 0; mt < 2; mt++) {
                int ra = wm * 32 + mt * 16 + g;
                af[mt][0] = Qs[ra * QS_ST + ks + tg];
                af[mt][1] = Qs[(ra + 8) * QS_ST + ks + tg];
                af[mt][2] = Qs[ra * QS_ST + ks + tg + 4];
                af[mt][3] = Qs[(ra + 8) * QS_ST + ks + tg + 4];
            }
            uint32_t bf[8][2];
#pragma unroll
            for (int nt = 0; nt < 8; nt++) {
                int cb = wnn * 64 + nt * 8 + g;
                bf[nt][0] = KP[cb * KP_ST + ks + tg];
                bf[nt][1] = KP[cb * KP_ST + ks + tg + 4];
            }
#pragma unroll
            for (int mt = 0; mt < 2; mt++)
#pragma unroll
                for (int nt = 0; nt < 8; nt++)
                    mma_f16(s[mt][nt][0], s[mt][nt][1], s[mt][nt][2], s[mt][nt][3],
                            af[mt][0], af[mt][1], af[mt][2], af[mt][3],
                            bf[nt][0], bf[nt][1]);
        }

        float tmax[2][2];
#pragma unroll
        for (int mt = 0; mt < 2; mt++) { tmax[mt][0] = -INFINITY; tmax[mt][1] = -INFINITY; }
#pragma unroll
        for (int mt = 0; mt < 2; mt++)
#pragma unroll
            for (int nt = 0; nt < 8; nt++) {
                int col = wnn * 64 + nt * 8 + tg * 2;
                float ls0 = logls[m0 + col];
                float ls1 = logls[m0 + col + 1];
                s[mt][nt][0] = s[mt][nt][0] * 0.125f + ls0;
                s[mt][nt][1] = s[mt][nt][1] * 0.125f + ls1;
                s[mt][nt][2] = s[mt][nt][2] * 0.125f + ls0;
                s[mt][nt][3] = s[mt][nt][3] * 0.125f + ls1;
                tmax[mt][0] = fmaxf(tmax[mt][0], fmaxf(s[mt][nt][0], s[mt][nt][1]));
                tmax[mt][1] = fmaxf(tmax[mt][1], fmaxf(s[mt][nt][2], s[mt][nt][3]));
            }
#pragma unroll
        for (int mt = 0; mt < 2; mt++)
#pragma unroll
            for (int rh = 0; rh < 2; rh++) {
                float v = tmax[mt][rh];
                v = fmaxf(v, __shfl_xor_sync(~0u, v, 1));
                v = fmaxf(v, __shfl_xor_sync(~0u, v, 2));
                tmax[mt][rh] = v;
            }
        if (tg == 0) {
#pragma unroll
            for (int mt = 0; mt < 2; mt++)
#pragma unroll
                for (int rh = 0; rh < 2; rh++)
                    redm[wnn * 128 + wm * 32 + mt * 16 + rh * 8 + g] = tmax[mt][rh];
        }
        __syncthreads();

        float sc[2][2];
#pragma unroll
        for (int mt = 0; mt < 2; mt++)
#pragma unroll
            for (int rh = 0; rh < 2; rh++) {
                int row = wm * 32 + mt * 16 + rh * 8 + g;
                float mx = fmaxf(redm[row], redm[128 + row]);
                float mnew = fmaxf(m_i[mt][rh], mx);
                sc[mt][rh] = __expf(m_i[mt][rh] - mnew);
                m_i[mt][rh] = mnew;
                l_i[mt][rh] *= sc[mt][rh];
            }
#pragma unroll
        for (int mt = 0; mt < 2; mt++)
#pragma unroll
            for (int nt = 0; nt < 4; nt++) {
                acc[mt][nt][0] *= sc[mt][0];
                acc[mt][nt][1] *= sc[mt][0];
                acc[mt][nt][2] *= sc[mt][1];
                acc[mt][nt][3] *= sc[mt][1];
            }

        float tsum[2][2];
#pragma unroll
        for (int mt = 0; mt < 2; mt++) { tsum[mt][0] = 0.f; tsum[mt][1] = 0.f; }
#pragma unroll
        for (int mt = 0; mt < 2; mt++) {
            int r0 = wm * 32 + mt * 16 + g;
#pragma unroll
            for (int nt = 0; nt < 8; nt++) {
                int w2 = wnn * 32 + nt * 4 + tg;
                float p0 = __expf(s[mt][nt][0] - m_i[mt][0]);
                float p1 = __expf(s[mt][nt][1] - m_i[mt][0]);
                float p2 = __expf(s[mt][nt][2] - m_i[mt][1]);
                float p3 = __expf(s[mt][nt][3] - m_i[mt][1]);
                tsum[mt][0] += p0 + p1;
                tsum[mt][1] += p2 + p3;
                KP[r0 * KP_ST + w2] = packh2(p0, p1);
                KP[(r0 + 8) * KP_ST + w2] = packh2(p2, p3);
            }
        }
#pragma unroll
        for (int mt = 0; mt < 2; mt++)
#pragma unroll
            for (int rh = 0; rh < 2; rh++) {
                float v = tsum[mt][rh];
                v += __shfl_xor_sync(~0u, v, 1);
                v += __shfl_xor_sync(~0u, v, 2);
                tsum[mt][rh] = v;
            }
        if (tg == 0) {
#pragma unroll
            for (int mt = 0; mt < 2; mt++)
#pragma unroll
                for (int rh = 0; rh < 2; rh++)
                    reds[wnn * 128 + wm * 32 + mt * 16 + rh * 8 + g] = tsum[mt][rh];
        }
        __syncthreads();
#pragma unroll
        for (int mt = 0; mt < 2; mt++)
#pragma unroll
            for (int rh = 0; rh < 2; rh++) {
                int row = wm * 32 + mt * 16 + rh * 8 + g;
                l_i[mt][rh] += reds[row] + reds[128 + row];
            }

#pragma unroll
        for (int ks = 0; ks < 64; ks += 8) {
            uint32_t af[2][4];
#pragma unroll
            for (int mt = 0; mt < 2; mt++) {
                int ra = wm * 32 + mt * 16 + g;
                af[mt][0] = KP[ra * KP_ST + ks + tg];
                af[mt][1] = KP[(ra + 8) * KP_ST + ks + tg];
                af[mt][2] = KP[ra * KP_ST + ks + tg + 4];
                af[mt][3] = KP[(ra + 8) * KP_ST + ks + tg + 4];
            }
            uint32_t bf[4][2];
#pragma unroll
            for (int nt = 0; nt < 4; nt++) {
                int cb = wnn * 32 + nt * 8 + g;
                bf[nt][0] = Vs[cb * VS_ST + ks + tg];
                bf[nt][1] = Vs[cb * VS_ST + ks + tg + 4];
            }
#pragma unroll
            for (int mt = 0; mt < 2; mt++)
#pragma unroll
                for (int nt = 0; nt < 4; nt++)
                    mma_f16(acc[mt][nt][0], acc[mt][nt][1], acc[mt][nt][2], acc[mt][nt][3],
                            af[mt][0], af[mt][1], af[mt][2], af[mt][3],
                            bf[nt][0], bf[nt][1]);
        }
    }

#pragma unroll
    for (int mt = 0; mt < 2; mt++) {
        float inv0 = 1.f / l_i[mt][0];
        float inv1 = 1.f / l_i[mt][1];
        int r0 = n0 + wm * 32 + mt * 16 + g;
#pragma unroll
        for (int nt = 0; nt < 4; nt++) {
            int col = h * 64 + wnn * 32 + nt * 8 + tg * 2;
            *(uint32_t*)(out + ((size_t)b * Nn + r0) * Cc + col) =
                packh2(acc[mt][nt][0] * inv0, acc[mt][nt][1] * inv0);
            *(uint32_t*)(out + ((size_t)b * Nn + r0 + 8) * Cc + col) =
                packh2(acc[mt][nt][2] * inv1, acc[mt][nt][3] * inv1);
        }
    }
}

// ---------------- single-pass LayerNorm (float4, 1 barrier) ----------------
__global__ void __launch_bounds__(256) ln_kernel(
    const float* __restrict__ x, const float* __restrict__ g,
    const float* __restrict__ bta, float* __restrict__ out32,
    __half* __restrict__ out16, int C)
{
    size_t row = blockIdx.x;
    int tid = threadIdx.x;
    float4 v = ((const float4*)(x + row * 1024))[tid];
    float s = v.x + v.y + v.z + v.w;
    float s2 = v.x * v.x + v.y * v.y + v.z * v.z + v.w * v.w;
#pragma unroll
    for (int o = 16; o; o >>= 1) {
        s += __shfl_xor_sync(~0u, s, o);
        s2 += __shfl_xor_sync(~0u, s2, o);
    }
    __shared__ float ws[8], wq[8];
    int w = tid >> 5, l = tid & 31;
    if (l == 0) { ws[w] = s; wq[w] = s2; }
    __syncthreads();
    float S = 0.f, S2 = 0.f;
#pragma unroll
    for (int i = 0; i < 8; i++) { S += ws[i]; S2 += wq[i]; }
    float mean = S * (1.f / 1024.f);
    float var  = S2 * (1.f / 1024.f) - mean * mean;
    float inv  = rsqrtf(var + 1e-5f);
    float4 gg = ((const float4*)g)[tid];
    float4 bb = ((const float4*)bta)[tid];
    float4 o;
    o.x = (v.x - mean) * inv * gg.x + bb.x;
    o.y = (v.y - mean) * inv * gg.y + bb.y;
    o.z = (v.z - mean) * inv * gg.z + bb.z;
    o.w = (v.w - mean) * inv * gg.w + bb.w;
    if (out32) ((float4*)(out32 + row * 1024))[tid] = o;
    uint2 p = make_uint2(packh2(o.x, o.y), packh2(o.z, o.w));
    *(uint2*)(out16 + row * 1024 + tid * 4) = p;
    (void)C;
}

// ---------------- pooled K weight (exact fp32 metric path) ----------------
__global__ void __launch_bounds__(256) pool_wk(
    const float* __restrict__ qkv_w, const float* __restrict__ qkv_b,
    float* __restrict__ wm, float* __restrict__ wmb)
{
    int idx = blockIdx.x * 256 + threadIdx.x;
    if (idx < 64 * 1024) {
        int d = idx >> 10, k = idx & 1023;
        float s = 0.f;
#pragma unroll
        for (int h = 0; h < 16; h++) s += qkv_w[(size_t)(1024 + h * 64 + d) * 1024 + k];
        wm[idx] = s * (1.f / 16.f);
    }
    if (idx < 64) {
        float s = 0.f;
#pragma unroll
        for (int h = 0; h < 16; h++) s += qkv_b[1024 + h * 64 + idx];
        wmb[idx] = s * (1.f / 16.f);
    }
}

// ---------------- fp32 metric GEMM + fused row normalize ----------------
__global__ void __launch_bounds__(256) metric_gemm(
    const float* __restrict__ xln, const float* __restrict__ wm,
    const float* __restrict__ wmb, float* __restrict__ metric)
{
    __shared__ float Xs[32][68];
    __shared__ float Ws[32][68];
    const int bm = blockIdx.x * 64;
    const int tid = threadIdx.x;
    const int ty = tid >> 3;
    const int tx = tid & 7;
    float acc[2][8];
#pragma unroll
    for (int i = 0; i < 2; i++)
#pragma unroll
        for (int j = 0; j < 8; j++) acc[i][j] = 0.f;

    for (int k0 = 0; k0 < 1024; k0 += 32) {
#pragma unroll
        for (int i = 0; i < 2; i++) {
            int idx = tid + i * 256;
            int row = idx >> 3;
            int kq = (idx & 7) << 2;
            float4 v = *(const float4*)(xln + (size_t)(bm + row) * 1024 + k0 + kq);
            Xs[kq][row] = v.x; Xs[kq + 1][row] = v.y; Xs[kq + 2][row] = v.z; Xs[kq + 3][row] = v.w;
        }
        for (int idx = tid; idx < 512; idx += 256) {
            int d = idx >> 3;
            int kq = (idx & 7) << 2;
            float4 v = *(const float4*)(wm + (size_t)d * 1024 + k0 + kq);
            Ws[kq][d] = v.x; Ws[kq + 1][d] = v.y; Ws[kq + 2][d] = v.z; Ws[kq + 3][d] = v.w;
        }
        __syncthreads();
#pragma unroll
        for (int kk = 0; kk < 32; kk++) {
            float a[2], w[8];
#pragma unroll
            for (int i = 0; i < 2; i++) a[i] = Xs[kk][ty * 2 + i];
#pragma unroll
            for (int j = 0; j < 8; j++) w[j] = Ws[kk][tx * 8 + j];
#pragma unroll
            for (int i = 0; i < 2; i++)
#pragma unroll
                for (int j = 0; j < 8; j++) acc[i][j] += a[i] * w[j];
        }
        __syncthreads();
    }
#pragma unroll
    for (int i = 0; i < 2; i++) {
        float vloc[8];
        float ssq = 0.f;
#pragma unroll
        for (int j = 0; j < 8; j++) {
            vloc[j] = acc[i][j] + wmb[tx * 8 + j];
            ssq += vloc[j] * vloc[j];
        }
        ssq += __shfl_xor_sync(~0u, ssq, 1);
        ssq += __shfl_xor_sync(~0u, ssq, 2);
        ssq += __shfl_xor_sync(~0u, ssq, 4);
        float inv = rsqrtf(ssq);
        int row = bm + ty * 2 + i;
#pragma unroll
        for (int j = 0; j < 8; j++)
            metric[(size_t)row * 64 + tx * 8 + j] = vloc[j] * inv;
    }
}

// ---------------- matching ----------------
__global__ void __launch_bounds__(256) match_scores(
    const float* __restrict__ metric, float* __restrict__ nodemax, int* __restrict__ nodeidx)
{
    int t = blockIdx.x;
    int b = blockIdx.y;
    const float* mb = metric + (size_t)b * Nn * 64;
    __shared__ float av[64];
    int tid = threadIdx.x;
    if (tid < 64) av[tid] = mb[(size_t)(2 * t) * 64 + tid];
    __syncthreads();
    float best = -INFINITY; int bi = 0;
    for (int s = tid; s < NH; s += 256) {
        const float* bp = mb + (size_t)(2 * s + 1) * 64;
        float dot = 0.f;
#pragma unroll
        for (int d = 0; d < 64; d++) dot += av[d] * bp[d];
        if (dot > best) { best = dot; bi = s; }
    }
    __shared__ float sv[256]; __shared__ int si[256];
    sv[tid] = best; si[tid] = bi; __syncthreads();
    for (int off = 128; off; off >>= 1) {
        if (tid < off) {
            if (sv[tid + off] > sv[tid] ||
                (sv[tid + off] == sv[tid] && si[tid + off] < si[tid])) {
                sv[tid] = sv[tid + off]; si[tid] = si[tid + off];
            }
        }
        __syncthreads();
    }
    if (tid == 0) {
        if (t == 0) { nodemax[b * NH] = -INFINITY; nodeidx[b * NH] = 0; }
        else { nodemax[b * NH + t] = sv[0]; nodeidx[b * NH + t] = si[0]; }
    }
}

__global__ void __launch_bounds__(512) match_sort(
    const float* __restrict__ nodemax, const int* __restrict__ nodeidx,
    int* __restrict__ srcidx, int* __restrict__ dstidx, int* __restrict__ unmidx)
{
    int b = blockIdx.x, t = threadIdx.x;
    __shared__ float v[NH]; __shared__ int rk[NH];
    v[t] = nodemax[b * NH + t]; __syncthreads();
    float vt = v[t]; int r = 0;
    for (int j = 0; j < NH; j++) {
        float vj = v[j];
        r += (vj > vt) || (vj == vt && j < t);
    }
    rk[t] = r; __syncthreads();
    if (r < Rr) {
        srcidx[b * Rr + r] = t;
        dstidx[b * Rr + r] = nodeidx[b * NH + t];
    } else {
        int pos = 0;
        for (int j = 0; j < t; j++) pos += (rk[j] >= Rr);
        unmidx[b * NU + pos] = t;
    }
}

// ---------------- weighted merge + divide by new size (match-list) ----------
__global__ void __launch_bounds__(256) merge_kernel(
    const float* __restrict__ xres, const float* __restrict__ sz,
    const int* __restrict__ srcidx, const int* __restrict__ dstidx,
    const int* __restrict__ unmidx, float* __restrict__ xm)
{
    int row = blockIdx.x;
    int b = blockIdx.y;
    int tid = threadIdx.x;
    const float* xb = xres + (size_t)b * Nn * Cc;
    const float* szb = sz + b * Nn;
    float* ob = xm + ((size_t)b * NM + row) * Cc;

    if (row < NU) {
        int t = 2 * unmidx[b * NU + row];
        float s = szb[t];
        float inv = 1.f / s;
        for (int c = tid; c < Cc; c += 256)
            ob[c] = (xb[(size_t)t * Cc + c] * s) * inv;
    } else {
        int j = row - NU;
        __shared__ int sd[Rr], ss[Rr];
        __shared__ int mls[Rr]; __shared__ float msz[Rr];
        __shared__ int nmz; __shared__ float nsz;
        if (tid < Rr) { ss[tid] = srcidx[b * Rr + tid]; sd[tid] = dstidx[b * Rr + tid]; }
        __syncthreads();
        int t = 2 * j + 1;
        if (tid == 0) {
            int n = 0;
            float ns = szb[t];
            for (int i = 0; i < Rr; i++) {
                if (sd[i] == j) {
                    int ts = 2 * ss[i];
                    float s2 = szb[ts];
                    mls[n] = ts; msz[n] = s2; ns += s2; n++;
                }
            }
            nmz = n; nsz = ns;
        }
        __syncthreads();
        int nm = nmz;
        float inv = 1.f / nsz;
        float st = szb[t];
        for (int c = tid; c < Cc; c += 256) {
            float val = xb[(size_t)t * Cc + c] * st;
            for (int i = 0; i < nm; i++)
                val += xb[(size_t)mls[i] * Cc + c] * msz[i];
            ob[c] = val * inv;
        }
    }
}

// ---------------- launch ----------------
template <typename T>
static T* sym_addr(const void* sym) {
    void* p = nullptr;
    cudaGetSymbolAddress(&p, sym);
    return (T*)p;
}

extern "C" void kernel_launch(void* const* d_in, const int* in_sizes, int n_in,
                              void* d_out, int out_size)
{
    const float* x      = (const float*)d_in[0];
    const float* sz     = (const float*)d_in[1];
    const float* qkv_w  = (const float*)d_in[3];
    const float* qkv_b  = (const float*)d_in[4];
    const float* proj_w = (const float*)d_in[5];
    const float* proj_b = (const float*)d_in[6];
    const float* n1g    = (const float*)d_in[7];
    const float* n1b    = (const float*)d_in[8];
    const float* n2g    = (const float*)d_in[9];
    const float* n2b    = (const float*)d_in[10];
    const float* fc1_w  = (const float*)d_in[11];
    const float* fc1_b  = (const float*)d_in[12];
    const float* fc2_w  = (const float*)d_in[13];
    const float* fc2_b  = (const float*)d_in[14];
    float* out = (float*)d_out;

    float*  xln    = sym_addr<float>(g_xln);
    __half* xln_h  = sym_addr<__half>(g_xln_h);
    __half* qkv_h  = sym_addr<__half>(g_qkv_h);
    __half* attno_h= sym_addr<__half>(g_attno_h);
    float*  xres   = sym_addr<float>(g_xres);
    __half* h2_h   = sym_addr<__half>(g_h2_h);
    __half* fc1_h  = sym_addr<__half>(g_fc1_h);
    __half* wqkv_h = sym_addr<__half>(g_wqkv_h);
    __half* wproj_h= sym_addr<__half>(g_wproj_h);
    __half* wfc1_h = sym_addr<__half>(g_wfc1_h);
    __half* wfc2_h = sym_addr<__half>(g_wfc2_h);
    float* wm    = sym_addr<float>(g_wm);
    float* wmb   = sym_addr<float>(g_wmb);
    float* metric= sym_addr<float>(g_metric);
    float* nmax  = sym_addr<float>(g_nodemax);
    int*   nidx  = sym_addr<int>(g_nodeidx);
    int*   sidx  = sym_addr<int>(g_srcidx);
    int*   didx  = sym_addr<int>(g_dstidx);
    int*   uidx  = sym_addr<int>(g_unmidx);
    float* xm    = sym_addr<float>(g_xm);

    cudaFuncSetAttribute(flash_attn, cudaFuncAttributeMaxDynamicSharedMemorySize, FLASH_SMEM);
    cudaFuncSetAttribute(fp16_gemm, cudaFuncAttributeMaxDynamicSharedMemorySize, GEMM_SMEM);

    // 0. weight conversion (fp32 -> fp16), single fused launch
    {
        int total = CVT_N0 + CVT_N1 + CVT_N2 + CVT_N3;
        cvt_all<<<(total + 255) / 256, 256>>>(qkv_w, wqkv_h, proj_w, wproj_h,
                                              fc1_w, wfc1_h, fc2_w, wfc2_h);
    }

    // 1. LN1 (dual output)
    ln_kernel<<<MROWS, 256>>>(x, n1g, n1b, xln, xln_h, Cc);
    // 2. QKV GEMM -> half
    fp16_gemm<<<dim3(3072 / 128, MROWS / 128), 256, GEMM_SMEM>>>(
        xln_h, wqkv_h, qkv_b, nullptr, nullptr, qkv_h, MROWS, 3072, Cc, 0);
    // 3. exact fp32 metric path (norm fused into GEMM epilogue)
    pool_wk<<<256, 256>>>(qkv_w, qkv_b, wm, wmb);
    metric_gemm<<<MROWS / 64, 256>>>(xln, wm, wmb, metric);
    // 4. fused flash attention (fp16, 2 CTA/SM) -> half
    flash_attn<<<dim3(8, Bb * Hh), 256, FLASH_SMEM>>>(qkv_h, sz, attno_h);
    // 5. proj + residual -> fp32
    fp16_gemm<<<dim3(Cc / 128, MROWS / 128), 256, GEMM_SMEM>>>(
        attno_h, wproj_h, proj_b, x, xres, nullptr, MROWS, Cc, Cc, 0);
    // 6. matching
    match_scores<<<dim3(NH, Bb), 256>>>(metric, nmax, nidx);
    match_sort<<<Bb, NH>>>(nmax, nidx, sidx, didx, uidx);
    // 7. merge
    merge_kernel<<<dim3(NM, Bb), 256>>>(xres, sz, sidx, didx, uidx, xm);
    // 8. LN2 -> half only
    ln_kernel<<<MROWS2, 256>>>(xm, n2g, n2b, nullptr, h2_h, Cc);
    // 9. fc1 + GELU -> half
    fp16_gemm<<<dim3(4096 / 128, MROWS2 / 128), 256, GEMM_SMEM>>>(
        h2_h, wfc1_h, fc1_b, nullptr, nullptr, fc1_h, MROWS2, 4096, Cc, 1);
    // 10. fc2 + residual -> out (fp32)
    fp16_gemm<<<dim3(Cc / 128, MROWS2 / 128), 256, GEMM_SMEM>>>(
        fc1_h, wfc2_h, fc2_b, xm, out, nullptr, MROWS2, Cc, 4096, 0);
    (void)in_sizes; (void)n_in; (void)out_size;
}

// round 16
// speedup vs baseline: 7.3722x; 1.4404x over previous
#include <cuda_runtime.h>
#include <cuda_bf16.h>
#include <cuda_fp16.h>
#include <math.h>
#include <cstdint>

// Problem constants
#define Bb 16
#define Nn 1024
#define Cc 1024
#define Hh 16
#define HD 64
#define Rr 128
#define NH (Nn/2)          // 512
#define NU (NH - Rr)       // 384 unmerged
#define NM (NU + NH)       // 896 merged tokens
#define MROWS (Bb*Nn)      // 16384
#define MROWS2 (Bb*NM)     // 14336

// ---------------- scratch (static device globals) ----------------
__device__ float  g_xln  [(size_t)MROWS * Cc];           // fp32 (metric path)
__device__ __half g_xln_h[(size_t)MROWS * Cc];
__device__ __half g_qkv_h[(size_t)MROWS * 3 * Cc];
__device__ __half g_attno_h[(size_t)MROWS * Cc];
__device__ float  g_xres [(size_t)MROWS * Cc];
__device__ __half g_h2_h [(size_t)MROWS2 * Cc];
__device__ __half g_fc1_h[(size_t)MROWS2 * 4 * Cc];
__device__ __half g_wqkv_h[(size_t)3 * Cc * Cc];
__device__ __half g_wproj_h[(size_t)Cc * Cc];
__device__ __half g_wfc1_h[(size_t)4 * Cc * Cc];
__device__ __half g_wfc2_h[(size_t)Cc * 4 * Cc];
__device__ float g_wm   [64 * 1024];
__device__ float g_wmb  [64];
__device__ float g_metric[(size_t)Bb * Nn * HD];
__device__ float g_nodemax[Bb * NH];
__device__ int   g_nodeidx[Bb * NH];
__device__ int   g_srcidx[Bb * Rr];
__device__ int   g_dstidx[Bb * Rr];
__device__ int   g_unmidx[Bb * NU];
__device__ float g_xm   [(size_t)MROWS2 * Cc];

__device__ __forceinline__ uint32_t packh2(float x, float y) {
    __half2 h = __floats2half2_rn(x, y);
    return *(uint32_t*)&h;
}
__device__ __forceinline__ uint32_t smem_u32(const void* p) {
    uint32_t a;
    asm("{ .reg .u64 t; cvta.to.shared.u64 t, %1; cvt.u32.u64 %0, t; }" : "=r"(a) : "l"(p));
    return a;
}
#define CPA16(dst, src) \
    asm volatile("cp.async.cg.shared.global [%0], [%1], 16;" :: "r"(dst), "l"(src))
#define CP_COMMIT() asm volatile("cp.async.commit_group;" ::: "memory")
#define CP_WAIT1()  asm volatile("cp.async.wait_group 1;" ::: "memory")
#define LDMX4(r0, r1, r2, r3, addr) \
    asm volatile("ldmatrix.sync.aligned.m8n8.x4.shared.b16 {%0,%1,%2,%3}, [%4];" \
        : "=r"(r0), "=r"(r1), "=r"(r2), "=r"(r3) : "r"(addr))

__device__ __forceinline__ void mma_f16(float& d0, float& d1, float& d2, float& d3,
                                        uint32_t a0, uint32_t a1, uint32_t a2, uint32_t a3,
                                        uint32_t b0, uint32_t b1)
{
    asm volatile(
        "mma.sync.aligned.m16n8k16.row.col.f32.f16.f16.f32 "
        "{%0,%1,%2,%3}, {%4,%5,%6,%7}, {%8,%9}, {%0,%1,%2,%3};\n"
        : "+f"(d0), "+f"(d1), "+f"(d2), "+f"(d3)
        : "r"(a0), "r"(a1), "r"(a2), "r"(a3), "r"(b0), "r"(b1));
}

// ---------------- fused f32 -> f16 converter (all 4 weights) ----------------
#define CVT_N0 (3*1024*1024/4)
#define CVT_N1 (1024*1024/4)
#define CVT_N2 (4*1024*1024/4)
#define CVT_N3 (4*1024*1024/4)
__global__ void __launch_bounds__(256) cvt_all(
    const float* __restrict__ s0, __half* __restrict__ d0,
    const float* __restrict__ s1, __half* __restrict__ d1,
    const float* __restrict__ s2, __half* __restrict__ d2,
    const float* __restrict__ s3, __half* __restrict__ d3)
{
    int i = blockIdx.x * 256 + threadIdx.x;
    const float* src; __half* dst;
    if (i < CVT_N0) { src = s0; dst = d0; }
    else if ((i -= CVT_N0) < CVT_N1) { src = s1; dst = d1; }
    else if ((i -= CVT_N1) < CVT_N2) { src = s2; dst = d2; }
    else if ((i -= CVT_N2) < CVT_N3) { src = s3; dst = d3; }
    else return;
    float4 v = *(const float4*)(src + (size_t)i * 4);
    uint2 p = make_uint2(packh2(v.x, v.y), packh2(v.z, v.w));
    *(uint2*)(dst + (size_t)i * 4) = p;
}

// ================= fp16 GEMM: ldmatrix + XOR swizzle + cp.async, 2 CTA/SM =====
#define GEMM_BUFB 16384                 // 128 rows * 128 B
#define GEMM_SMEM (3 * 2 * GEMM_BUFB)   // 96 KB

__global__ void __launch_bounds__(256, 2) fp16_gemm(
    const __half* __restrict__ A, const __half* __restrict__ W,
    const float* __restrict__ bias, const float* __restrict__ res,
    float* __restrict__ out32, __half* __restrict__ out16,
    int M, int N, int K, int act)
{
    extern __shared__ char smg[];
    const uint32_t sA = smem_u32(smg);
    const uint32_t sB = sA + 3 * GEMM_BUFB;

    const int tid = threadIdx.x;
    const int wid = tid >> 5;
    const int lane = tid & 31;
    const int g = lane >> 2;
    const int tg = lane & 3;
    const int wm = wid & 3;
    const int wn = wid >> 2;
    const int bm = blockIdx.y * 128;
    const int bn = blockIdx.x * 128;

    uint32_t dstoff[4]; size_t srcoffA[4], srcoffW[4];
#pragma unroll
    for (int i = 0; i < 4; i++) {
        int idx = tid + i * 256;
        int row = idx >> 3, c = idx & 7;
        dstoff[i] = row * 128 + ((c ^ (row & 7)) << 4);
        srcoffA[i] = (size_t)(bm + row) * K + c * 8;
        srcoffW[i] = (size_t)(bn + row) * K + c * 8;
    }

    const int sel = lane >> 3;
    const int lrow = lane & 7;
    const int csel = sel >> 1;
    const int rsel = sel & 1;
    uint32_t aBase[2]; int aRow7[2];
#pragma unroll
    for (int mt = 0; mt < 2; mt++) {
        int ra = wm * 32 + mt * 16 + rsel * 8 + lrow;
        aBase[mt] = ra * 128; aRow7[mt] = ra & 7;
    }
    uint32_t bBase[4]; int bRow7[4];
#pragma unroll
    for (int p = 0; p < 4; p++) {
        int nb = wn * 64 + p * 16 + rsel * 8 + lrow;
        bBase[p] = nb * 128; bRow7[p] = nb & 7;
    }

    float acc[2][8][4];
#pragma unroll
    for (int i = 0; i < 2; i++)
#pragma unroll
        for (int j = 0; j < 8; j++)
#pragma unroll
            for (int v = 0; v < 4; v++) acc[i][j][v] = 0.f;

    const int NS = K >> 6;
    {
#pragma unroll
        for (int i = 0; i < 4; i++) {
            CPA16(sA + dstoff[i], A + srcoffA[i]);
            CPA16(sB + dstoff[i], W + srcoffW[i]);
        }
        CP_COMMIT();
        if (NS > 1) {
#pragma unroll
            for (int i = 0; i < 4; i++) {
                CPA16(sA + GEMM_BUFB + dstoff[i], A + srcoffA[i] + 64);
                CPA16(sB + GEMM_BUFB + dstoff[i], W + srcoffW[i] + 64);
            }
        }
        CP_COMMIT();
        CP_WAIT1();
        __syncthreads();
    }

    for (int s = 0; s < NS; s++) {
        const uint32_t bufA = sA + (s % 3) * GEMM_BUFB;
        const uint32_t bufB = sB + (s % 3) * GEMM_BUFB;
#pragma unroll
        for (int kq = 0; kq < 4; kq++) {
            const int cc = kq * 2 + csel;
            uint32_t a[2][4];
#pragma unroll
            for (int mt = 0; mt < 2; mt++)
                LDMX4(a[mt][0], a[mt][1], a[mt][2], a[mt][3],
                      bufA + aBase[mt] + (uint32_t)(((cc ^ aRow7[mt])) << 4));
            uint32_t bm4[4][4];
#pragma unroll
            for (int p = 0; p < 4; p++)
                LDMX4(bm4[p][0], bm4[p][1], bm4[p][2], bm4[p][3],
                      bufB + bBase[p] + (uint32_t)(((cc ^ bRow7[p])) << 4));
#pragma unroll
            for (int mt = 0; mt < 2; mt++)
#pragma unroll
                for (int p = 0; p < 4; p++) {
                    mma_f16(acc[mt][2 * p][0], acc[mt][2 * p][1],
                            acc[mt][2 * p][2], acc[mt][2 * p][3],
                            a[mt][0], a[mt][1], a[mt][2], a[mt][3],
                            bm4[p][0], bm4[p][2]);
                    mma_f16(acc[mt][2 * p + 1][0], acc[mt][2 * p + 1][1],
                            acc[mt][2 * p + 1][2], acc[mt][2 * p + 1][3],
                            a[mt][0], a[mt][1], a[mt][2], a[mt][3],
                            bm4[p][1], bm4[p][3]);
                }
        }
        if (s + 1 < NS) {
            if (s + 2 < NS) {
                uint32_t qA = sA + ((s + 2) % 3) * GEMM_BUFB;
                uint32_t qB = sB + ((s + 2) % 3) * GEMM_BUFB;
                size_t k0 = (size_t)(s + 2) << 6;
#pragma unroll
                for (int i = 0; i < 4; i++) {
                    CPA16(qA + dstoff[i], A + srcoffA[i] + k0);
                    CPA16(qB + dstoff[i], W + srcoffW[i] + k0);
                }
            }
            CP_COMMIT();
            CP_WAIT1();
            __syncthreads();
        }
    }

#pragma unroll
    for (int mt = 0; mt < 2; mt++) {
        int r0 = bm + wm * 32 + mt * 16 + g;
#pragma unroll
        for (int nt = 0; nt < 8; nt++) {
            int col = bn + wn * 64 + nt * 8 + tg * 2;
            float b0 = bias[col], b1 = bias[col + 1];
            float v0 = acc[mt][nt][0] + b0;
            float v1 = acc[mt][nt][1] + b1;
            float v2 = acc[mt][nt][2] + b0;
            float v3 = acc[mt][nt][3] + b1;
            if (act) {
                v0 = 0.5f * v0 * (1.f + erff(v0 * 0.70710678118654752f));
                v1 = 0.5f * v1 * (1.f + erff(v1 * 0.70710678118654752f));
                v2 = 0.5f * v2 * (1.f + erff(v2 * 0.70710678118654752f));
                v3 = 0.5f * v3 * (1.f + erff(v3 * 0.70710678118654752f));
            }
            if (res) {
                const float* rp0 = res + (size_t)r0 * N + col;
                const float* rp1 = rp0 + (size_t)8 * N;
                v0 += rp0[0]; v1 += rp0[1];
                v2 += rp1[0]; v3 += rp1[1];
            }
            if (out32) {
                *(float2*)(out32 + (size_t)r0 * N + col) = make_float2(v0, v1);
                *(float2*)(out32 + (size_t)(r0 + 8) * N + col) = make_float2(v2, v3);
            } else {
                *(uint32_t*)(out16 + (size_t)r0 * N + col) = packh2(v0, v1);
                *(uint32_t*)(out16 + (size_t)(r0 + 8) * N + col) = packh2(v2, v3);
            }
        }
    }
}

// ================= fused flash attention, fp16 mma =================
#define QS_ST 36
#define KP_ST 68
#define VS_ST 68
#define FLASH_SMEM ((128*QS_ST + 128*KP_ST + 64*VS_ST + 1024 + 256 + 256) * 4)

__global__ void __launch_bounds__(256, 2) flash_attn(
    const __half* __restrict__ qkv, const float* __restrict__ sz, __half* __restrict__ out)
{
    extern __shared__ uint32_t smw[];
    uint32_t* Qs = smw;
    uint32_t* KP = Qs + 128 * QS_ST;
    uint32_t* Vs = KP + 128 * KP_ST;
    float* logls = (float*)(Vs + 64 * VS_ST);
    float* redm  = logls + 1024;
    float* reds  = redm + 256;
    __half* Vs_h = (__half*)Vs;

    const int tid = threadIdx.x;
    const int wid = tid >> 5, lane = tid & 31;
    const int g = lane >> 2, tg = lane & 3;
    const int wm = wid & 3;
    const int wnn = wid >> 2;
    const int bh = blockIdx.y;
    const int b = bh >> 4, h = bh & 15;
    const int n0 = blockIdx.x * 128;
    const __half* qb = qkv + (size_t)b * Nn * 3072 + h * 64;
    const __half* kb = qb + 1024;
    const __half* vb = qb + 2048;

    for (int i = tid; i < 1024; i += 256)
        logls[i] = __logf(sz[b * Nn + i]);

#pragma unroll
    for (int i = 0; i < 4; i++) {
        int idx = tid + i * 256;
        int row = idx >> 3;
        int seg = idx & 7;
        *(uint4*)&Qs[row * QS_ST + seg * 4] =
            *(const uint4*)(qb + (size_t)(n0 + row) * 3072 + seg * 8);
    }

    float m_i[2][2], l_i[2][2];
    float acc[2][4][4];
#pragma unroll
    for (int mt = 0; mt < 2; mt++)
#pragma unroll
        for (int rh = 0; rh < 2; rh++) { m_i[mt][rh] = -INFINITY; l_i[mt][rh] = 0.f; }
#pragma unroll
    for (int mt = 0; mt < 2; mt++)
#pragma unroll
        for (int nt = 0; nt < 4; nt++)
#pragma unroll
            for (int v = 0; v < 4; v++) acc[mt][nt][v] = 0.f;

    for (int m0 = 0; m0 < Nn; m0 += 128) {
        __syncthreads();
#pragma unroll
        for (int i = 0; i < 4; i++) {
            int idx = tid + i * 256;
            int row = idx >> 3;
            int seg = idx & 7;
            *(uint4*)&KP[row * KP_ST + seg * 4] =
                *(const uint4*)(kb + (size_t)(m0 + row) * 3072 + seg * 8);
            uint4 vv = *(const uint4*)(vb + (size_t)(m0 + row) * 3072 + seg * 8);
            const __half* vh = (const __half*)&vv;
#pragma unroll
            for (int j = 0; j < 8; j++)
                Vs_h[(seg * 8 + j) * (VS_ST * 2) + row] = vh[j];
        }
        __syncthreads();

        float s[2][8][4];
#pragma unroll
        for (int mt = 0; mt < 2; mt++)
#pragma unroll
            for (int nt = 0; nt < 8; nt++)
#pragma unroll
                for (int v = 0; v < 4; v++) s[mt][nt][v] = 0.f;
#pragma unroll
        for (int ks = 0; ks < 32; ks += 8) {
            uint32_t af[2][4];
#pragma unroll
            for (int mt = 0; mt < 2; mt++) {
                int ra = wm * 32 + mt * 16 + g;
                af[mt][0] = Qs[ra * QS_ST + ks + tg];
                af[mt][1] = Qs[(ra + 8) * QS_ST + ks + tg];
                af[mt][2] = Qs[ra * QS_ST + ks + tg + 4];
                af[mt][3] = Qs[(ra + 8) * QS_ST + ks + tg + 4];
            }
            uint32_t bf[8][2];
#pragma unroll
            for (int nt = 0; nt < 8; nt++) {
                int cb = wnn * 64 + nt * 8 + g;
                bf[nt][0] = KP[cb * KP_ST + ks + tg];
                bf[nt][1] = KP[cb * KP_ST + ks + tg + 4];
            }
#pragma unroll
            for (int mt = 0; mt < 2; mt++)
#pragma unroll
                for (int nt = 0; nt < 8; nt++)
                    mma_f16(s[mt][nt][0], s[mt][nt][1], s[mt][nt][2], s[mt][nt][3],
                            af[mt][0], af[mt][1], af[mt][2], af[mt][3],
                            bf[nt][0], bf[nt][1]);
        }

        float tmax[2][2];
#pragma unroll
        for (int mt = 0; mt < 2; mt++) { tmax[mt][0] = -INFINITY; tmax[mt][1] = -INFINITY; }
#pragma unroll
        for (int mt = 0; mt < 2; mt++)
#pragma unroll
            for (int nt = 0; nt < 8; nt++) {
                int col = wnn * 64 + nt * 8 + tg * 2;
                float ls0 = logls[m0 + col];
                float ls1 = logls[m0 + col + 1];
                s[mt][nt][0] = s[mt][nt][0] * 0.125f + ls0;
                s[mt][nt][1] = s[mt][nt][1] * 0.125f + ls1;
                s[mt][nt][2] = s[mt][nt][2] * 0.125f + ls0;
                s[mt][nt][3] = s[mt][nt][3] * 0.125f + ls1;
                tmax[mt][0] = fmaxf(tmax[mt][0], fmaxf(s[mt][nt][0], s[mt][nt][1]));
                tmax[mt][1] = fmaxf(tmax[mt][1], fmaxf(s[mt][nt][2], s[mt][nt][3]));
            }
#pragma unroll
        for (int mt = 0; mt < 2; mt++)
#pragma unroll
            for (int rh = 0; rh < 2; rh++) {
                float v = tmax[mt][rh];
                v = fmaxf(v, __shfl_xor_sync(~0u, v, 1));
                v = fmaxf(v, __shfl_xor_sync(~0u, v, 2));
                tmax[mt][rh] = v;
            }
        if (tg == 0) {
#pragma unroll
            for (int mt = 0; mt < 2; mt++)
#pragma unroll
                for (int rh = 0; rh < 2; rh++)
                    redm[wnn * 128 + wm * 32 + mt * 16 + rh * 8 + g] = tmax[mt][rh];
        }
        __syncthreads();

        float sc[2][2];
#pragma unroll
        for (int mt = 0; mt < 2; mt++)
#pragma unroll
            for (int rh = 0; rh < 2; rh++) {
                int row = wm * 32 + mt * 16 + rh * 8 + g;
                float mx = fmaxf(redm[row], redm[128 + row]);
                float mnew = fmaxf(m_i[mt][rh], mx);
                sc[mt][rh] = __expf(m_i[mt][rh] - mnew);
                m_i[mt][rh] = mnew;
                l_i[mt][rh] *= sc[mt][rh];
            }
#pragma unroll
        for (int mt = 0; mt < 2; mt++)
#pragma unroll
            for (int nt = 0; nt < 4; nt++) {
                acc[mt][nt][0] *= sc[mt][0];
                acc[mt][nt][1] *= sc[mt][0];
                acc[mt][nt][2] *= sc[mt][1];
                acc[mt][nt][3] *= sc[mt][1];
            }

        float tsum[2][2];
#pragma unroll
        for (int mt = 0; mt < 2; mt++) { tsum[mt][0] = 0.f; tsum[mt][1] = 0.f; }
#pragma unroll
        for (int mt = 0; mt < 2; mt++) {
            int r0 = wm * 32 + mt * 16 + g;
#pragma unroll
            for (int nt = 0; nt < 8; nt++) {
                int w2 = wnn * 32 + nt * 4 + tg;
                float p0 = __expf(s[mt][nt][0] - m_i[mt][0]);
                float p1 = __expf(s[mt][nt][1] - m_i[mt][0]);
                float p2 = __expf(s[mt][nt][2] - m_i[mt][1]);
                float p3 = __expf(s[mt][nt][3] - m_i[mt][1]);
                tsum[mt][0] += p0 + p1;
                tsum[mt][1] += p2 + p3;
                KP[r0 * KP_ST + w2] = packh2(p0, p1);
                KP[(r0 + 8) * KP_ST + w2] = packh2(p2, p3);
            }
        }
#pragma unroll
        for (int mt = 0; mt < 2; mt++)
#pragma unroll
            for (int rh = 0; rh < 2; rh++) {
                float v = tsum[mt][rh];
                v += __shfl_xor_sync(~0u, v, 1);
                v += __shfl_xor_sync(~0u, v, 2);
                tsum[mt][rh] = v;
            }
        if (tg == 0) {
#pragma unroll
            for (int mt = 0; mt < 2; mt++)
#pragma unroll
                for (int rh = 0; rh < 2; rh++)
                    reds[wnn * 128 + wm * 32 + mt * 16 + rh * 8 + g] = tsum[mt][rh];
        }
        __syncthreads();
#pragma unroll
        for (int mt = 0; mt < 2; mt++)
#pragma unroll
            for (int rh = 0; rh < 2; rh++) {
                int row = wm * 32 + mt * 16 + rh * 8 + g;
                l_i[mt][rh] += reds[row] + reds[128 + row];
            }

#pragma unroll
        for (int ks = 0; ks < 64; ks += 8) {
            uint32_t af[2][4];
#pragma unroll
            for (int mt = 0; mt < 2; mt++) {
                int ra = wm * 32 + mt * 16 + g;
                af[mt][0] = KP[ra * KP_ST + ks + tg];
                af[mt][1] = KP[(ra + 8) * KP_ST + ks + tg];
                af[mt][2] = KP[ra * KP_ST + ks + tg + 4];
                af[mt][3] = KP[(ra + 8) * KP_ST + ks + tg + 4];
            }
            uint32_t bf[4][2];
#pragma unroll
            for (int nt = 0; nt < 4; nt++) {
                int cb = wnn * 32 + nt * 8 + g;
                bf[nt][0] = Vs[cb * VS_ST + ks + tg];
                bf[nt][1] = Vs[cb * VS_ST + ks + tg + 4];
            }
#pragma unroll
            for (int mt = 0; mt < 2; mt++)
#pragma unroll
                for (int nt = 0; nt < 4; nt++)
                    mma_f16(acc[mt][nt][0], acc[mt][nt][1], acc[mt][nt][2], acc[mt][nt][3],
                            af[mt][0], af[mt][1], af[mt][2], af[mt][3],
                            bf[nt][0], bf[nt][1]);
        }
    }

#pragma unroll
    for (int mt = 0; mt < 2; mt++) {
        float inv0 = 1.f / l_i[mt][0];
        float inv1 = 1.f / l_i[mt][1];
        int r0 = n0 + wm * 32 + mt * 16 + g;
#pragma unroll
        for (int nt = 0; nt < 4; nt++) {
            int col = h * 64 + wnn * 32 + nt * 8 + tg * 2;
            *(uint32_t*)(out + ((size_t)b * Nn + r0) * Cc + col) =
                packh2(acc[mt][nt][0] * inv0, acc[mt][nt][1] * inv0);
            *(uint32_t*)(out + ((size_t)b * Nn + r0 + 8) * Cc + col) =
                packh2(acc[mt][nt][2] * inv1, acc[mt][nt][3] * inv1);
        }
    }
}

// ---------------- single-pass LayerNorm (float4, 1 barrier) ----------------
__global__ void __launch_bounds__(256) ln_kernel(
    const float* __restrict__ x, const float* __restrict__ g,
    const float* __restrict__ bta, float* __restrict__ out32,
    __half* __restrict__ out16, int C)
{
    size_t row = blockIdx.x;
    int tid = threadIdx.x;
    float4 v = ((const float4*)(x + row * 1024))[tid];
    float s = v.x + v.y + v.z + v.w;
    float s2 = v.x * v.x + v.y * v.y + v.z * v.z + v.w * v.w;
#pragma unroll
    for (int o = 16; o; o >>= 1) {
        s += __shfl_xor_sync(~0u, s, o);
        s2 += __shfl_xor_sync(~0u, s2, o);
    }
    __shared__ float ws[8], wq[8];
    int w = tid >> 5, l = tid & 31;
    if (l == 0) { ws[w] = s; wq[w] = s2; }
    __syncthreads();
    float S = 0.f, S2 = 0.f;
#pragma unroll
    for (int i = 0; i < 8; i++) { S += ws[i]; S2 += wq[i]; }
    float mean = S * (1.f / 1024.f);
    float var  = S2 * (1.f / 1024.f) - mean * mean;
    float inv  = rsqrtf(var + 1e-5f);
    float4 gg = ((const float4*)g)[tid];
    float4 bb = ((const float4*)bta)[tid];
    float4 o;
    o.x = (v.x - mean) * inv * gg.x + bb.x;
    o.y = (v.y - mean) * inv * gg.y + bb.y;
    o.z = (v.z - mean) * inv * gg.z + bb.z;
    o.w = (v.w - mean) * inv * gg.w + bb.w;
    if (out32) ((float4*)(out32 + row * 1024))[tid] = o;
    uint2 p = make_uint2(packh2(o.x, o.y), packh2(o.z, o.w));
    *(uint2*)(out16 + row * 1024 + tid * 4) = p;
    (void)C;
}

// ---------------- pooled K weight (exact fp32 metric path) ----------------
__global__ void __launch_bounds__(256) pool_wk(
    const float* __restrict__ qkv_w, const float* __restrict__ qkv_b,
    float* __restrict__ wm, float* __restrict__ wmb)
{
    int idx = blockIdx.x * 256 + threadIdx.x;
    if (idx < 64 * 1024) {
        int d = idx >> 10, k = idx & 1023;
        float s = 0.f;
#pragma unroll
        for (int h = 0; h < 16; h++) s += qkv_w[(size_t)(1024 + h * 64 + d) * 1024 + k];
        wm[idx] = s * (1.f / 16.f);
    }
    if (idx < 64) {
        float s = 0.f;
#pragma unroll
        for (int h = 0; h < 16; h++) s += qkv_b[1024 + h * 64 + idx];
        wmb[idx] = s * (1.f / 16.f);
    }
}

// ---------------- fp32 metric GEMM + fused row normalize ----------------
__global__ void __launch_bounds__(256) metric_gemm(
    const float* __restrict__ xln, const float* __restrict__ wm,
    const float* __restrict__ wmb, float* __restrict__ metric)
{
    __shared__ float Xs[32][68];
    __shared__ float Ws[32][68];
    const int bm = blockIdx.x * 64;
    const int tid = threadIdx.x;
    const int ty = tid >> 3;
    const int tx = tid & 7;
    float acc[2][8];
#pragma unroll
    for (int i = 0; i < 2; i++)
#pragma unroll
        for (int j = 0; j < 8; j++) acc[i][j] = 0.f;

    for (int k0 = 0; k0 < 1024; k0 += 32) {
#pragma unroll
        for (int i = 0; i < 2; i++) {
            int idx = tid + i * 256;
            int row = idx >> 3;
            int kq = (idx & 7) << 2;
            float4 v = *(const float4*)(xln + (size_t)(bm + row) * 1024 + k0 + kq);
            Xs[kq][row] = v.x; Xs[kq + 1][row] = v.y; Xs[kq + 2][row] = v.z; Xs[kq + 3][row] = v.w;
        }
        for (int idx = tid; idx < 512; idx += 256) {
            int d = idx >> 3;
            int kq = (idx & 7) << 2;
            float4 v = *(const float4*)(wm + (size_t)d * 1024 + k0 + kq);
            Ws[kq][d] = v.x; Ws[kq + 1][d] = v.y; Ws[kq + 2][d] = v.z; Ws[kq + 3][d] = v.w;
        }
        __syncthreads();
#pragma unroll
        for (int kk = 0; kk < 32; kk++) {
            float a[2], w[8];
#pragma unroll
            for (int i = 0; i < 2; i++) a[i] = Xs[kk][ty * 2 + i];
#pragma unroll
            for (int j = 0; j < 8; j++) w[j] = Ws[kk][tx * 8 + j];
#pragma unroll
            for (int i = 0; i < 2; i++)
#pragma unroll
                for (int j = 0; j < 8; j++) acc[i][j] += a[i] * w[j];
        }
        __syncthreads();
    }
#pragma unroll
    for (int i = 0; i < 2; i++) {
        float vloc[8];
        float ssq = 0.f;
#pragma unroll
        for (int j = 0; j < 8; j++) {
            vloc[j] = acc[i][j] + wmb[tx * 8 + j];
            ssq += vloc[j] * vloc[j];
        }
        ssq += __shfl_xor_sync(~0u, ssq, 1);
        ssq += __shfl_xor_sync(~0u, ssq, 2);
        ssq += __shfl_xor_sync(~0u, ssq, 4);
        float inv = rsqrtf(ssq);
        int row = bm + ty * 2 + i;
#pragma unroll
        for (int j = 0; j < 8; j++)
            metric[(size_t)row * 64 + tx * 8 + j] = vloc[j] * inv;
    }
}

// ---------------- matching: tiled max/argmax (8 t-rows per CTA) ----------------
// Exact per-dot FMA order (d=0..63) and argmax-first tie semantics preserved.
__global__ void __launch_bounds__(256) match_scores(
    const float* __restrict__ metric, float* __restrict__ nodemax, int* __restrict__ nodeidx)
{
    __shared__ float bs[64 * 65];     // bset tile: 64 rows x 64 dims, stride 65
    __shared__ float avs[8 * 64];
    const int b = blockIdx.y;
    const int t0 = blockIdx.x * 8;
    const int tid = threadIdx.x;
    const int w = tid >> 5, lane = tid & 31;
    const float* mb = metric + (size_t)b * Nn * 64;

    // coalesced load of 8 a-rows (rows 2*(t0+r))
    for (int i = tid; i < 512; i += 256) {
        int r = i >> 6, d = i & 63;
        avs[r * 64 + d] = mb[(size_t)(2 * (t0 + r)) * 64 + d];
    }
    __syncthreads();
    float av[64];
#pragma unroll
    for (int d = 0; d < 64; d++) av[d] = avs[w * 64 + d];   // warp-broadcast reads

    float best0 = -INFINITY, best1 = -INFINITY;
    int bi0 = 0, bi1 = 0;

    for (int s0 = 0; s0 < NH; s0 += 64) {
        __syncthreads();   // previous tile reads done
        for (int i = tid; i < 4096; i += 256) {
            int r = i >> 6, d = i & 63;
            bs[r * 65 + d] = mb[(size_t)(2 * (s0 + r) + 1) * 64 + d];
        }
        __syncthreads();
        float d0 = 0.f, d1 = 0.f;
        const float* b0p = &bs[lane * 65];
        const float* b1p = &bs[(lane + 32) * 65];
#pragma unroll
        for (int d = 0; d < 64; d++) {
            d0 += av[d] * b0p[d];
            d1 += av[d] * b1p[d];
        }
        int sA = s0 + lane, sB = s0 + lane + 32;
        if (d0 > best0) { best0 = d0; bi0 = sA; }
        if (d1 > best1) { best1 = d1; bi1 = sB; }
    }
    // combine the two per-lane streams (first-max: equal -> smaller index)
    float bv = best0; int bix = bi0;
    if (best1 > bv || (best1 == bv && bi1 < bix)) { bv = best1; bix = bi1; }
    // warp reduction with min-index tiebreak
#pragma unroll
    for (int o = 16; o; o >>= 1) {
        float ov = __shfl_xor_sync(~0u, bv, o);
        int oi = __shfl_xor_sync(~0u, bix, o);
        if (ov > bv || (ov == bv && oi < bix)) { bv = ov; bix = oi; }
    }
    if (lane == 0) {
        int t = t0 + w;
        if (t == 0) { nodemax[b * NH] = -INFINITY; nodeidx[b * NH] = 0; }
        else { nodemax[b * NH + t] = bv; nodeidx[b * NH + t] = bix; }
    }
}

__global__ void __launch_bounds__(512) match_sort(
    const float* __restrict__ nodemax, const int* __restrict__ nodeidx,
    int* __restrict__ srcidx, int* __restrict__ dstidx, int* __restrict__ unmidx)
{
    int b = blockIdx.x, t = threadIdx.x;
    __shared__ float v[NH]; __shared__ int rk[NH];
    v[t] = nodemax[b * NH + t]; __syncthreads();
    float vt = v[t]; int r = 0;
    for (int j = 0; j < NH; j++) {
        float vj = v[j];
        r += (vj > vt) || (vj == vt && j < t);
    }
    rk[t] = r; __syncthreads();
    if (r < Rr) {
        srcidx[b * Rr + r] = t;
        dstidx[b * Rr + r] = nodeidx[b * NH + t];
    } else {
        int pos = 0;
        for (int j = 0; j < t; j++) pos += (rk[j] >= Rr);
        unmidx[b * NU + pos] = t;
    }
}

// ---------------- weighted merge + divide by new size (float4) ----------------
__global__ void __launch_bounds__(256) merge_kernel(
    const float* __restrict__ xres, const float* __restrict__ sz,
    const int* __restrict__ srcidx, const int* __restrict__ dstidx,
    const int* __restrict__ unmidx, float* __restrict__ xm)
{
    int row = blockIdx.x;
    int b = blockIdx.y;
    int tid = threadIdx.x;
    const float4* xb4 = (const float4*)(xres + (size_t)b * Nn * Cc);
    const float* szb = sz + b * Nn;
    float4* ob4 = (float4*)(xm + ((size_t)b * NM + row) * Cc);

    if (row < NU) {
        int t = 2 * unmidx[b * NU + row];
        float s = szb[t];
        float inv = 1.f / s;
        float4 v = xb4[(size_t)t * 256 + tid];
        ob4[tid] = make_float4((v.x * s) * inv, (v.y * s) * inv,
                               (v.z * s) * inv, (v.w * s) * inv);
    } else {
        int j = row - NU;
        __shared__ int sd[Rr], ss[Rr];
        __shared__ int mls[Rr]; __shared__ float msz[Rr];
        __shared__ int nmz; __shared__ float nsz;
        if (tid < Rr) { ss[tid] = srcidx[b * Rr + tid]; sd[tid] = dstidx[b * Rr + tid]; }
        __syncthreads();
        int t = 2 * j + 1;
        if (tid == 0) {
            int n = 0;
            float ns = szb[t];
            for (int i = 0; i < Rr; i++) {
                if (sd[i] == j) {
                    int ts = 2 * ss[i];
                    float s2 = szb[ts];
                    mls[n] = ts; msz[n] = s2; ns += s2; n++;
                }
            }
            nmz = n; nsz = ns;
        }
        __syncthreads();
        int nm = nmz;
        float inv = 1.f / nsz;
        float st = szb[t];
        float4 v = xb4[(size_t)t * 256 + tid];
        float4 val = make_float4(v.x * st, v.y * st, v.z * st, v.w * st);
        for (int i = 0; i < nm; i++) {
            float4 u = xb4[(size_t)mls[i] * 256 + tid];
            float m = msz[i];
            val.x += u.x * m; val.y += u.y * m;
            val.z += u.z * m; val.w += u.w * m;
        }
        ob4[tid] = make_float4(val.x * inv, val.y * inv, val.z * inv, val.w * inv);
    }
}

// ---------------- launch ----------------
template <typename T>
static T* sym_addr(const void* sym) {
    void* p = nullptr;
    cudaGetSymbolAddress(&p, sym);
    return (T*)p;
}

extern "C" void kernel_launch(void* const* d_in, const int* in_sizes, int n_in,
                              void* d_out, int out_size)
{
    const float* x      = (const float*)d_in[0];
    const float* sz     = (const float*)d_in[1];
    const float* qkv_w  = (const float*)d_in[3];
    const float* qkv_b  = (const float*)d_in[4];
    const float* proj_w = (const float*)d_in[5];
    const float* proj_b = (const float*)d_in[6];
    const float* n1g    = (const float*)d_in[7];
    const float* n1b    = (const float*)d_in[8];
    const float* n2g    = (const float*)d_in[9];
    const float* n2b    = (const float*)d_in[10];
    const float* fc1_w  = (const float*)d_in[11];
    const float* fc1_b  = (const float*)d_in[12];
    const float* fc2_w  = (const float*)d_in[13];
    const float* fc2_b  = (const float*)d_in[14];
    float* out = (float*)d_out;

    float*  xln    = sym_addr<float>(g_xln);
    __half* xln_h  = sym_addr<__half>(g_xln_h);
    __half* qkv_h  = sym_addr<__half>(g_qkv_h);
    __half* attno_h= sym_addr<__half>(g_attno_h);
    float*  xres   = sym_addr<float>(g_xres);
    __half* h2_h   = sym_addr<__half>(g_h2_h);
    __half* fc1_h  = sym_addr<__half>(g_fc1_h);
    __half* wqkv_h = sym_addr<__half>(g_wqkv_h);
    __half* wproj_h= sym_addr<__half>(g_wproj_h);
    __half* wfc1_h = sym_addr<__half>(g_wfc1_h);
    __half* wfc2_h = sym_addr<__half>(g_wfc2_h);
    float* wm    = sym_addr<float>(g_wm);
    float* wmb   = sym_addr<float>(g_wmb);
    float* metric= sym_addr<float>(g_metric);
    float* nmax  = sym_addr<float>(g_nodemax);
    int*   nidx  = sym_addr<int>(g_nodeidx);
    int*   sidx  = sym_addr<int>(g_srcidx);
    int*   didx  = sym_addr<int>(g_dstidx);
    int*   uidx  = sym_addr<int>(g_unmidx);
    float* xm    = sym_addr<float>(g_xm);

    cudaFuncSetAttribute(flash_attn, cudaFuncAttributeMaxDynamicSharedMemorySize, FLASH_SMEM);
    cudaFuncSetAttribute(fp16_gemm, cudaFuncAttributeMaxDynamicSharedMemorySize, GEMM_SMEM);

    // 0. weight conversion (fp32 -> fp16), single fused launch
    {
        int total = CVT_N0 + CVT_N1 + CVT_N2 + CVT_N3;
        cvt_all<<<(total + 255) / 256, 256>>>(qkv_w, wqkv_h, proj_w, wproj_h,
                                              fc1_w, wfc1_h, fc2_w, wfc2_h);
    }

    // 1. LN1 (dual output)
    ln_kernel<<<MROWS, 256>>>(x, n1g, n1b, xln, xln_h, Cc);
    // 2. QKV GEMM -> half
    fp16_gemm<<<dim3(3072 / 128, MROWS / 128), 256, GEMM_SMEM>>>(
        xln_h, wqkv_h, qkv_b, nullptr, nullptr, qkv_h, MROWS, 3072, Cc, 0);
    // 3. exact fp32 metric path (norm fused into GEMM epilogue)
    pool_wk<<<256, 256>>>(qkv_w, qkv_b, wm, wmb);
    metric_gemm<<<MROWS / 64, 256>>>(xln, wm, wmb, metric);
    // 4. fused flash attention (fp16) -> half
    flash_attn<<<dim3(8, Bb * Hh), 256, FLASH_SMEM>>>(qkv_h, sz, attno_h);
    // 5. proj + residual -> fp32
    fp16_gemm<<<dim3(Cc / 128, MROWS / 128), 256, GEMM_SMEM>>>(
        attno_h, wproj_h, proj_b, x, xres, nullptr, MROWS, Cc, Cc, 0);
    // 6. matching (tiled)
    match_scores<<<dim3(NH / 8, Bb), 256>>>(metric, nmax, nidx);
    match_sort<<<Bb, NH>>>(nmax, nidx, sidx, didx, uidx);
    // 7. merge (float4)
    merge_kernel<<<dim3(NM, Bb), 256>>>(xres, sz, sidx, didx, uidx, xm);
    // 8. LN2 -> half only
    ln_kernel<<<MROWS2, 256>>>(xm, n2g, n2b, nullptr, h2_h, Cc);
    // 9. fc1 + GELU -> half
    fp16_gemm<<<dim3(4096 / 128, MROWS2 / 128), 256, GEMM_SMEM>>>(
        h2_h, wfc1_h, fc1_b, nullptr, nullptr, fc1_h, MROWS2, 4096, Cc, 1);
    // 10. fc2 + residual -> out (fp32)
    fp16_gemm<<<dim3(Cc / 128, MROWS2 / 128), 256, GEMM_SMEM>>>(
        fc1_h, wfc2_h, fc2_b, xm, out, nullptr, MROWS2, Cc, 4096, 0);
    (void)in_sizes; (void)n_in; (void)out_size;
}

// round 17
// speedup vs baseline: 7.4095x; 1.0051x over previous
#include <cuda_runtime.h>
#include <cuda_bf16.h>
#include <cuda_fp16.h>
#include <math.h>
#include <cstdint>

// Problem constants
#define Bb 16
#define Nn 1024
#define Cc 1024
#define Hh 16
#define HD 64
#define Rr 128
#define NH (Nn/2)          // 512
#define NU (NH - Rr)       // 384 unmerged
#define NM (NU + NH)       // 896 merged tokens
#define MROWS (Bb*Nn)      // 16384
#define MROWS2 (Bb*NM)     // 14336

// ---------------- scratch (static device globals) ----------------
__device__ float  g_xln  [(size_t)MROWS * Cc];           // fp32 (metric path)
__device__ __half g_xln_h[(size_t)MROWS * Cc];
__device__ __half g_qkv_h[(size_t)MROWS * 3 * Cc];
__device__ __half g_attno_h[(size_t)MROWS * Cc];
__device__ float  g_xres [(size_t)MROWS * Cc];
__device__ __half g_h2_h [(size_t)MROWS2 * Cc];
__device__ __half g_fc1_h[(size_t)MROWS2 * 4 * Cc];
__device__ __half g_wqkv_h[(size_t)3 * Cc * Cc];
__device__ __half g_wproj_h[(size_t)Cc * Cc];
__device__ __half g_wfc1_h[(size_t)4 * Cc * Cc];
__device__ __half g_wfc2_h[(size_t)Cc * 4 * Cc];
__device__ float g_wm   [64 * 1024];
__device__ float g_wmb  [64];
__device__ float g_metric[(size_t)Bb * Nn * HD];
__device__ float g_nodemax[Bb * NH];
__device__ int   g_nodeidx[Bb * NH];
__device__ int   g_srcidx[Bb * Rr];
__device__ int   g_dstidx[Bb * Rr];
__device__ int   g_unmidx[Bb * NU];
__device__ float g_xm   [(size_t)MROWS2 * Cc];

__device__ __forceinline__ uint32_t packh2(float x, float y) {
    __half2 h = __floats2half2_rn(x, y);
    return *(uint32_t*)&h;
}
__device__ __forceinline__ uint32_t smem_u32(const void* p) {
    uint32_t a;
    asm("{ .reg .u64 t; cvta.to.shared.u64 t, %1; cvt.u32.u64 %0, t; }" : "=r"(a) : "l"(p));
    return a;
}
#define CPA16(dst, src) \
    asm volatile("cp.async.cg.shared.global [%0], [%1], 16;" :: "r"(dst), "l"(src))
#define CP_COMMIT() asm volatile("cp.async.commit_group;" ::: "memory")
#define CP_WAIT1()  asm volatile("cp.async.wait_group 1;" ::: "memory")
#define LDMX4(r0, r1, r2, r3, addr) \
    asm volatile("ldmatrix.sync.aligned.m8n8.x4.shared.b16 {%0,%1,%2,%3}, [%4];" \
        : "=r"(r0), "=r"(r1), "=r"(r2), "=r"(r3) : "r"(addr))

__device__ __forceinline__ void mma_f16(float& d0, float& d1, float& d2, float& d3,
                                        uint32_t a0, uint32_t a1, uint32_t a2, uint32_t a3,
                                        uint32_t b0, uint32_t b1)
{
    asm volatile(
        "mma.sync.aligned.m16n8k16.row.col.f32.f16.f16.f32 "
        "{%0,%1,%2,%3}, {%4,%5,%6,%7}, {%8,%9}, {%0,%1,%2,%3};\n"
        : "+f"(d0), "+f"(d1), "+f"(d2), "+f"(d3)
        : "r"(a0), "r"(a1), "r"(a2), "r"(a3), "r"(b0), "r"(b1));
}

// ---------------- fused f32->f16 converter + pooled K weight ----------------
#define CVT_N0 (3*1024*1024/4)
#define CVT_N1 (1024*1024/4)
#define CVT_N2 (4*1024*1024/4)
#define CVT_N3 (4*1024*1024/4)
#define CVT_BLOCKS ((CVT_N0 + CVT_N1 + CVT_N2 + CVT_N3 + 255) / 256)
__global__ void __launch_bounds__(256) cvt_all(
    const float* __restrict__ s0, __half* __restrict__ d0,
    const float* __restrict__ s1, __half* __restrict__ d1,
    const float* __restrict__ s2, __half* __restrict__ d2,
    const float* __restrict__ s3, __half* __restrict__ d3,
    const float* __restrict__ qkv_b, float* __restrict__ wm, float* __restrict__ wmb)
{
    if (blockIdx.x >= CVT_BLOCKS) {
        // pooled K weight: blocks CVT_BLOCKS .. CVT_BLOCKS+255
        int idx = (blockIdx.x - CVT_BLOCKS) * 256 + threadIdx.x;
        if (idx < 64 * 1024) {
            int d = idx >> 10, k = idx & 1023;
            float s = 0.f;
#pragma unroll
            for (int h = 0; h < 16; h++) s += s0[(size_t)(1024 + h * 64 + d) * 1024 + k];
            wm[idx] = s * (1.f / 16.f);
        }
        if (idx < 64) {
            float s = 0.f;
#pragma unroll
            for (int h = 0; h < 16; h++) s += qkv_b[1024 + h * 64 + idx];
            wmb[idx] = s * (1.f / 16.f);
        }
        return;
    }
    int i = blockIdx.x * 256 + threadIdx.x;
    const float* src; __half* dst;
    if (i < CVT_N0) { src = s0; dst = d0; }
    else if ((i -= CVT_N0) < CVT_N1) { src = s1; dst = d1; }
    else if ((i -= CVT_N1) < CVT_N2) { src = s2; dst = d2; }
    else if ((i -= CVT_N2) < CVT_N3) { src = s3; dst = d3; }
    else return;
    float4 v = *(const float4*)(src + (size_t)i * 4);
    uint2 p = make_uint2(packh2(v.x, v.y), packh2(v.z, v.w));
    *(uint2*)(dst + (size_t)i * 4) = p;
}

// ================= fp16 GEMM: ldmatrix + XOR swizzle + cp.async, 2 CTA/SM =====
#define GEMM_BUFB 16384                 // 128 rows * 128 B
#define GEMM_SMEM (3 * 2 * GEMM_BUFB)   // 96 KB

__global__ void __launch_bounds__(256, 2) fp16_gemm(
    const __half* __restrict__ A, const __half* __restrict__ W,
    const float* __restrict__ bias, const float* __restrict__ res,
    float* __restrict__ out32, __half* __restrict__ out16,
    int M, int N, int K, int act)
{
    extern __shared__ char smg[];
    const uint32_t sA = smem_u32(smg);
    const uint32_t sB = sA + 3 * GEMM_BUFB;

    const int tid = threadIdx.x;
    const int wid = tid >> 5;
    const int lane = tid & 31;
    const int g = lane >> 2;
    const int tg = lane & 3;
    const int wm = wid & 3;
    const int wn = wid >> 2;
    const int bm = blockIdx.y * 128;
    const int bn = blockIdx.x * 128;

    uint32_t dstoff[4]; size_t srcoffA[4], srcoffW[4];
#pragma unroll
    for (int i = 0; i < 4; i++) {
        int idx = tid + i * 256;
        int row = idx >> 3, c = idx & 7;
        dstoff[i] = row * 128 + ((c ^ (row & 7)) << 4);
        srcoffA[i] = (size_t)(bm + row) * K + c * 8;
        srcoffW[i] = (size_t)(bn + row) * K + c * 8;
    }

    const int sel = lane >> 3;
    const int lrow = lane & 7;
    const int csel = sel >> 1;
    const int rsel = sel & 1;
    uint32_t aBase[2]; int aRow7[2];
#pragma unroll
    for (int mt = 0; mt < 2; mt++) {
        int ra = wm * 32 + mt * 16 + rsel * 8 + lrow;
        aBase[mt] = ra * 128; aRow7[mt] = ra & 7;
    }
    uint32_t bBase[4]; int bRow7[4];
#pragma unroll
    for (int p = 0; p < 4; p++) {
        int nb = wn * 64 + p * 16 + rsel * 8 + lrow;
        bBase[p] = nb * 128; bRow7[p] = nb & 7;
    }

    float acc[2][8][4];
#pragma unroll
    for (int i = 0; i < 2; i++)
#pragma unroll
        for (int j = 0; j < 8; j++)
#pragma unroll
            for (int v = 0; v < 4; v++) acc[i][j][v] = 0.f;

    const int NS = K >> 6;
    {
#pragma unroll
        for (int i = 0; i < 4; i++) {
            CPA16(sA + dstoff[i], A + srcoffA[i]);
            CPA16(sB + dstoff[i], W + srcoffW[i]);
        }
        CP_COMMIT();
        if (NS > 1) {
#pragma unroll
            for (int i = 0; i < 4; i++) {
                CPA16(sA + GEMM_BUFB + dstoff[i], A + srcoffA[i] + 64);
                CPA16(sB + GEMM_BUFB + dstoff[i], W + srcoffW[i] + 64);
            }
        }
        CP_COMMIT();
        CP_WAIT1();
        __syncthreads();
    }

    for (int s = 0; s < NS; s++) {
        const uint32_t bufA = sA + (s % 3) * GEMM_BUFB;
        const uint32_t bufB = sB + (s % 3) * GEMM_BUFB;
#pragma unroll
        for (int kq = 0; kq < 4; kq++) {
            const int cc = kq * 2 + csel;
            uint32_t a[2][4];
#pragma unroll
            for (int mt = 0; mt < 2; mt++)
                LDMX4(a[mt][0], a[mt][1], a[mt][2], a[mt][3],
                      bufA + aBase[mt] + (uint32_t)(((cc ^ aRow7[mt])) << 4));
            uint32_t bm4[4][4];
#pragma unroll
            for (int p = 0; p < 4; p++)
                LDMX4(bm4[p][0], bm4[p][1], bm4[p][2], bm4[p][3],
                      bufB + bBase[p] + (uint32_t)(((cc ^ bRow7[p])) << 4));
#pragma unroll
            for (int mt = 0; mt < 2; mt++)
#pragma unroll
                for (int p = 0; p < 4; p++) {
                    mma_f16(acc[mt][2 * p][0], acc[mt][2 * p][1],
                            acc[mt][2 * p][2], acc[mt][2 * p][3],
                            a[mt][0], a[mt][1], a[mt][2], a[mt][3],
                            bm4[p][0], bm4[p][2]);
                    mma_f16(acc[mt][2 * p + 1][0], acc[mt][2 * p + 1][1],
                            acc[mt][2 * p + 1][2], acc[mt][2 * p + 1][3],
                            a[mt][0], a[mt][1], a[mt][2], a[mt][3],
                            bm4[p][1], bm4[p][3]);
                }
        }
        if (s + 1 < NS) {
            if (s + 2 < NS) {
                uint32_t qA = sA + ((s + 2) % 3) * GEMM_BUFB;
                uint32_t qB = sB + ((s + 2) % 3) * GEMM_BUFB;
                size_t k0 = (size_t)(s + 2) << 6;
#pragma unroll
                for (int i = 0; i < 4; i++) {
                    CPA16(qA + dstoff[i], A + srcoffA[i] + k0);
                    CPA16(qB + dstoff[i], W + srcoffW[i] + k0);
                }
            }
            CP_COMMIT();
            CP_WAIT1();
            __syncthreads();
        }
    }

#pragma unroll
    for (int mt = 0; mt < 2; mt++) {
        int r0 = bm + wm * 32 + mt * 16 + g;
#pragma unroll
        for (int nt = 0; nt < 8; nt++) {
            int col = bn + wn * 64 + nt * 8 + tg * 2;
            float b0 = bias[col], b1 = bias[col + 1];
            float v0 = acc[mt][nt][0] + b0;
            float v1 = acc[mt][nt][1] + b1;
            float v2 = acc[mt][nt][2] + b0;
            float v3 = acc[mt][nt][3] + b1;
            if (act) {
                v0 = 0.5f * v0 * (1.f + erff(v0 * 0.70710678118654752f));
                v1 = 0.5f * v1 * (1.f + erff(v1 * 0.70710678118654752f));
                v2 = 0.5f * v2 * (1.f + erff(v2 * 0.70710678118654752f));
                v3 = 0.5f * v3 * (1.f + erff(v3 * 0.70710678118654752f));
            }
            if (res) {
                const float* rp0 = res + (size_t)r0 * N + col;
                const float* rp1 = rp0 + (size_t)8 * N;
                v0 += rp0[0]; v1 += rp0[1];
                v2 += rp1[0]; v3 += rp1[1];
            }
            if (out32) {
                *(float2*)(out32 + (size_t)r0 * N + col) = make_float2(v0, v1);
                *(float2*)(out32 + (size_t)(r0 + 8) * N + col) = make_float2(v2, v3);
            } else {
                *(uint32_t*)(out16 + (size_t)r0 * N + col) = packh2(v0, v1);
                *(uint32_t*)(out16 + (size_t)(r0 + 8) * N + col) = packh2(v2, v3);
            }
        }
    }
}

// ================= fused flash attention, fp16 mma =================
#define QS_ST 36
#define KP_ST 68
#define VS_ST 68
#define FLASH_SMEM ((128*QS_ST + 128*KP_ST + 64*VS_ST + 1024 + 256 + 256) * 4)

__global__ void __launch_bounds__(256, 2) flash_attn(
    const __half* __restrict__ qkv, const float* __restrict__ sz, __half* __restrict__ out)
{
    extern __shared__ uint32_t smw[];
    uint32_t* Qs = smw;
    uint32_t* KP = Qs + 128 * QS_ST;
    uint32_t* Vs = KP + 128 * KP_ST;
    float* logls = (float*)(Vs + 64 * VS_ST);
    float* redm  = logls + 1024;
    float* reds  = redm + 256;
    __half* Vs_h = (__half*)Vs;

    const int tid = threadIdx.x;
    const int wid = tid >> 5, lane = tid & 31;
    const int g = lane >> 2, tg = lane & 3;
    const int wm = wid & 3;
    const int wnn = wid >> 2;
    const int bh = blockIdx.y;
    const int b = bh >> 4, h = bh & 15;
    const int n0 = blockIdx.x * 128;
    const __half* qb = qkv + (size_t)b * Nn * 3072 + h * 64;
    const __half* kb = qb + 1024;
    const __half* vb = qb + 2048;

    for (int i = tid; i < 1024; i += 256)
        logls[i] = __logf(sz[b * Nn + i]);

#pragma unroll
    for (int i = 0; i < 4; i++) {
        int idx = tid + i * 256;
        int row = idx >> 3;
        int seg = idx & 7;
        *(uint4*)&Qs[row * QS_ST + seg * 4] =
            *(const uint4*)(qb + (size_t)(n0 + row) * 3072 + seg * 8);
    }

    float m_i[2][2], l_i[2][2];
    float acc[2][4][4];
#pragma unroll
    for (int mt = 0; mt < 2; mt++)
#pragma unroll
        for (int rh = 0; rh < 2; rh++) { m_i[mt][rh] = -INFINITY; l_i[mt][rh] = 0.f; }
#pragma unroll
    for (int mt = 0; mt < 2; mt++)
#pragma unroll
        for (int nt = 0; nt < 4; nt++)
#pragma unroll
            for (int v = 0; v < 4; v++) acc[mt][nt][v] = 0.f;

    for (int m0 = 0; m0 < Nn; m0 += 128) {
        __syncthreads();
#pragma unroll
        for (int i = 0; i < 4; i++) {
            int idx = tid + i * 256;
            int row = idx >> 3;
            int seg = idx & 7;
            *(uint4*)&KP[row * KP_ST + seg * 4] =
                *(const uint4*)(kb + (size_t)(m0 + row) * 3072 + seg * 8);
            uint4 vv = *(const uint4*)(vb + (size_t)(m0 + row) * 3072 + seg * 8);
            const __half* vh = (const __half*)&vv;
#pragma unroll
            for (int j = 0; j < 8; j++)
                Vs_h[(seg * 8 + j) * (VS_ST * 2) + row] = vh[j];
        }
        __syncthreads();

        float s[2][8][4];
#pragma unroll
        for (int mt = 0; mt < 2; mt++)
#pragma unroll
            for (int nt = 0; nt < 8; nt++)
#pragma unroll
                for (int v = 0; v < 4; v++) s[mt][nt][v] = 0.f;
#pragma unroll
        for (int ks = 0; ks < 32; ks += 8) {
            uint32_t af[2][4];
#pragma unroll
            for (int mt = 0; mt < 2; mt++) {
                int ra = wm * 32 + mt * 16 + g;
                af[mt][0] = Qs[ra * QS_ST + ks + tg];
                af[mt][1] = Qs[(ra + 8) * QS_ST + ks + tg];
                af[mt][2] = Qs[ra * QS_ST + ks + tg + 4];
                af[mt][3] = Qs[(ra + 8) * QS_ST + ks + tg + 4];
            }
            uint32_t bf[8][2];
#pragma unroll
            for (int nt = 0; nt < 8; nt++) {
                int cb = wnn * 64 + nt * 8 + g;
                bf[nt][0] = KP[cb * KP_ST + ks + tg];
                bf[nt][1] = KP[cb * KP_ST + ks + tg + 4];
            }
#pragma unroll
            for (int mt = 0; mt < 2; mt++)
#pragma unroll
                for (int nt = 0; nt < 8; nt++)
                    mma_f16(s[mt][nt][0], s[mt][nt][1], s[mt][nt][2], s[mt][nt][3],
                            af[mt][0], af[mt][1], af[mt][2], af[mt][3],
                            bf[nt][0], bf[nt][1]);
        }

        float tmax[2][2];
#pragma unroll
        for (int mt = 0; mt < 2; mt++) { tmax[mt][0] = -INFINITY; tmax[mt][1] = -INFINITY; }
#pragma unroll
        for (int mt = 0; mt < 2; mt++)
#pragma unroll
            for (int nt = 0; nt < 8; nt++) {
                int col = wnn * 64 + nt * 8 + tg * 2;
                float ls0 = logls[m0 + col];
                float ls1 = logls[m0 + col + 1];
                s[mt][nt][0] = s[mt][nt][0] * 0.125f + ls0;
                s[mt][nt][1] = s[mt][nt][1] * 0.125f + ls1;
                s[mt][nt][2] = s[mt][nt][2] * 0.125f + ls0;
                s[mt][nt][3] = s[mt][nt][3] * 0.125f + ls1;
                tmax[mt][0] = fmaxf(tmax[mt][0], fmaxf(s[mt][nt][0], s[mt][nt][1]));
                tmax[mt][1] = fmaxf(tmax[mt][1], fmaxf(s[mt][nt][2], s[mt][nt][3]));
            }
#pragma unroll
        for (int mt = 0; mt < 2; mt++)
#pragma unroll
            for (int rh = 0; rh < 2; rh++) {
                float v = tmax[mt][rh];
                v = fmaxf(v, __shfl_xor_sync(~0u, v, 1));
                v = fmaxf(v, __shfl_xor_sync(~0u, v, 2));
                tmax[mt][rh] = v;
            }
        if (tg == 0) {
#pragma unroll
            for (int mt = 0; mt < 2; mt++)
#pragma unroll
                for (int rh = 0; rh < 2; rh++)
                    redm[wnn * 128 + wm * 32 + mt * 16 + rh * 8 + g] = tmax[mt][rh];
        }
        __syncthreads();

        float sc[2][2];
#pragma unroll
        for (int mt = 0; mt < 2; mt++)
#pragma unroll
            for (int rh = 0; rh < 2; rh++) {
                int row = wm * 32 + mt * 16 + rh * 8 + g;
                float mx = fmaxf(redm[row], redm[128 + row]);
                float mnew = fmaxf(m_i[mt][rh], mx);
                sc[mt][rh] = __expf(m_i[mt][rh] - mnew);
                m_i[mt][rh] = mnew;
                l_i[mt][rh] *= sc[mt][rh];
            }
#pragma unroll
        for (int mt = 0; mt < 2; mt++)
#pragma unroll
            for (int nt = 0; nt < 4; nt++) {
                acc[mt][nt][0] *= sc[mt][0];
                acc[mt][nt][1] *= sc[mt][0];
                acc[mt][nt][2] *= sc[mt][1];
                acc[mt][nt][3] *= sc[mt][1];
            }

        float tsum[2][2];
#pragma unroll
        for (int mt = 0; mt < 2; mt++) { tsum[mt][0] = 0.f; tsum[mt][1] = 0.f; }
#pragma unroll
        for (int mt = 0; mt < 2; mt++) {
            int r0 = wm * 32 + mt * 16 + g;
#pragma unroll
            for (int nt = 0; nt < 8; nt++) {
                int w2 = wnn * 32 + nt * 4 + tg;
                float p0 = __expf(s[mt][nt][0] - m_i[mt][0]);
                float p1 = __expf(s[mt][nt][1] - m_i[mt][0]);
                float p2 = __expf(s[mt][nt][2] - m_i[mt][1]);
                float p3 = __expf(s[mt][nt][3] - m_i[mt][1]);
                tsum[mt][0] += p0 + p1;
                tsum[mt][1] += p2 + p3;
                KP[r0 * KP_ST + w2] = packh2(p0, p1);
                KP[(r0 + 8) * KP_ST + w2] = packh2(p2, p3);
            }
        }
#pragma unroll
        for (int mt = 0; mt < 2; mt++)
#pragma unroll
            for (int rh = 0; rh < 2; rh++) {
                float v = tsum[mt][rh];
                v += __shfl_xor_sync(~0u, v, 1);
                v += __shfl_xor_sync(~0u, v, 2);
                tsum[mt][rh] = v;
            }
        if (tg == 0) {
#pragma unroll
            for (int mt = 0; mt < 2; mt++)
#pragma unroll
                for (int rh = 0; rh < 2; rh++)
                    reds[wnn * 128 + wm * 32 + mt * 16 + rh * 8 + g] = tsum[mt][rh];
        }
        __syncthreads();
#pragma unroll
        for (int mt = 0; mt < 2; mt++)
#pragma unroll
            for (int rh = 0; rh < 2; rh++) {
                int row = wm * 32 + mt * 16 + rh * 8 + g;
                l_i[mt][rh] += reds[row] + reds[128 + row];
            }

#pragma unroll
        for (int ks = 0; ks < 64; ks += 8) {
            uint32_t af[2][4];
#pragma unroll
            for (int mt = 0; mt < 2; mt++) {
                int ra = wm * 32 + mt * 16 + g;
                af[mt][0] = KP[ra * KP_ST + ks + tg];
                af[mt][1] = KP[(ra + 8) * KP_ST + ks + tg];
                af[mt][2] = KP[ra * KP_ST + ks + tg + 4];
                af[mt][3] = KP[(ra + 8) * KP_ST + ks + tg + 4];
            }
            uint32_t bf[4][2];
#pragma unroll
            for (int nt = 0; nt < 4; nt++) {
                int cb = wnn * 32 + nt * 8 + g;
                bf[nt][0] = Vs[cb * VS_ST + ks + tg];
                bf[nt][1] = Vs[cb * VS_ST + ks + tg + 4];
            }
#pragma unroll
            for (int mt = 0; mt < 2; mt++)
#pragma unroll
                for (int nt = 0; nt < 4; nt++)
                    mma_f16(acc[mt][nt][0], acc[mt][nt][1], acc[mt][nt][2], acc[mt][nt][3],
                            af[mt][0], af[mt][1], af[mt][2], af[mt][3],
                            bf[nt][0], bf[nt][1]);
        }
    }

#pragma unroll
    for (int mt = 0; mt < 2; mt++) {
        float inv0 = 1.f / l_i[mt][0];
        float inv1 = 1.f / l_i[mt][1];
        int r0 = n0 + wm * 32 + mt * 16 + g;
#pragma unroll
        for (int nt = 0; nt < 4; nt++) {
            int col = h * 64 + wnn * 32 + nt * 8 + tg * 2;
            *(uint32_t*)(out + ((size_t)b * Nn + r0) * Cc + col) =
                packh2(acc[mt][nt][0] * inv0, acc[mt][nt][1] * inv0);
            *(uint32_t*)(out + ((size_t)b * Nn + r0 + 8) * Cc + col) =
                packh2(acc[mt][nt][2] * inv1, acc[mt][nt][3] * inv1);
        }
    }
}

// ---------------- single-pass LayerNorm (float4, 1 barrier) ----------------
__global__ void __launch_bounds__(256) ln_kernel(
    const float* __restrict__ x, const float* __restrict__ g,
    const float* __restrict__ bta, float* __restrict__ out32,
    __half* __restrict__ out16, int C)
{
    size_t row = blockIdx.x;
    int tid = threadIdx.x;
    float4 v = ((const float4*)(x + row * 1024))[tid];
    float s = v.x + v.y + v.z + v.w;
    float s2 = v.x * v.x + v.y * v.y + v.z * v.z + v.w * v.w;
#pragma unroll
    for (int o = 16; o; o >>= 1) {
        s += __shfl_xor_sync(~0u, s, o);
        s2 += __shfl_xor_sync(~0u, s2, o);
    }
    __shared__ float ws[8], wq[8];
    int w = tid >> 5, l = tid & 31;
    if (l == 0) { ws[w] = s; wq[w] = s2; }
    __syncthreads();
    float S = 0.f, S2 = 0.f;
#pragma unroll
    for (int i = 0; i < 8; i++) { S += ws[i]; S2 += wq[i]; }
    float mean = S * (1.f / 1024.f);
    float var  = S2 * (1.f / 1024.f) - mean * mean;
    float inv  = rsqrtf(var + 1e-5f);
    float4 gg = ((const float4*)g)[tid];
    float4 bb = ((const float4*)bta)[tid];
    float4 o;
    o.x = (v.x - mean) * inv * gg.x + bb.x;
    o.y = (v.y - mean) * inv * gg.y + bb.y;
    o.z = (v.z - mean) * inv * gg.z + bb.z;
    o.w = (v.w - mean) * inv * gg.w + bb.w;
    if (out32) ((float4*)(out32 + row * 1024))[tid] = o;
    uint2 p = make_uint2(packh2(o.x, o.y), packh2(o.z, o.w));
    *(uint2*)(out16 + row * 1024 + tid * 4) = p;
    (void)C;
}

// ---------------- fp32 metric GEMM + fused row normalize ----------------
__global__ void __launch_bounds__(256) metric_gemm(
    const float* __restrict__ xln, const float* __restrict__ wm,
    const float* __restrict__ wmb, float* __restrict__ metric)
{
    __shared__ float Xs[32][68];
    __shared__ float Ws[32][68];
    const int bm = blockIdx.x * 64;
    const int tid = threadIdx.x;
    const int ty = tid >> 3;
    const int tx = tid & 7;
    float acc[2][8];
#pragma unroll
    for (int i = 0; i < 2; i++)
#pragma unroll
        for (int j = 0; j < 8; j++) acc[i][j] = 0.f;

    for (int k0 = 0; k0 < 1024; k0 += 32) {
#pragma unroll
        for (int i = 0; i < 2; i++) {
            int idx = tid + i * 256;
            int row = idx >> 3;
            int kq = (idx & 7) << 2;
            float4 v = *(const float4*)(xln + (size_t)(bm + row) * 1024 + k0 + kq);
            Xs[kq][row] = v.x; Xs[kq + 1][row] = v.y; Xs[kq + 2][row] = v.z; Xs[kq + 3][row] = v.w;
        }
        for (int idx = tid; idx < 512; idx += 256) {
            int d = idx >> 3;
            int kq = (idx & 7) << 2;
            float4 v = *(const float4*)(wm + (size_t)d * 1024 + k0 + kq);
            Ws[kq][d] = v.x; Ws[kq + 1][d] = v.y; Ws[kq + 2][d] = v.z; Ws[kq + 3][d] = v.w;
        }
        __syncthreads();
#pragma unroll
        for (int kk = 0; kk < 32; kk++) {
            float a[2], w[8];
#pragma unroll
            for (int i = 0; i < 2; i++) a[i] = Xs[kk][ty * 2 + i];
#pragma unroll
            for (int j = 0; j < 8; j++) w[j] = Ws[kk][tx * 8 + j];
#pragma unroll
            for (int i = 0; i < 2; i++)
#pragma unroll
                for (int j = 0; j < 8; j++) acc[i][j] += a[i] * w[j];
        }
        __syncthreads();
    }
#pragma unroll
    for (int i = 0; i < 2; i++) {
        float vloc[8];
        float ssq = 0.f;
#pragma unroll
        for (int j = 0; j < 8; j++) {
            vloc[j] = acc[i][j] + wmb[tx * 8 + j];
            ssq += vloc[j] * vloc[j];
        }
        ssq += __shfl_xor_sync(~0u, ssq, 1);
        ssq += __shfl_xor_sync(~0u, ssq, 2);
        ssq += __shfl_xor_sync(~0u, ssq, 4);
        float inv = rsqrtf(ssq);
        int row = bm + ty * 2 + i;
#pragma unroll
        for (int j = 0; j < 8; j++)
            metric[(size_t)row * 64 + tx * 8 + j] = vloc[j] * inv;
    }
}

// ---------------- matching: tiled max/argmax (8 t-rows per CTA) ----------------
__global__ void __launch_bounds__(256) match_scores(
    const float* __restrict__ metric, float* __restrict__ nodemax, int* __restrict__ nodeidx)
{
    __shared__ float bs[64 * 65];
    __shared__ float avs[8 * 64];
    const int b = blockIdx.y;
    const int t0 = blockIdx.x * 8;
    const int tid = threadIdx.x;
    const int w = tid >> 5, lane = tid & 31;
    const float* mb = metric + (size_t)b * Nn * 64;

    for (int i = tid; i < 512; i += 256) {
        int r = i >> 6, d = i & 63;
        avs[r * 64 + d] = mb[(size_t)(2 * (t0 + r)) * 64 + d];
    }
    __syncthreads();
    float av[64];
#pragma unroll
    for (int d = 0; d < 64; d++) av[d] = avs[w * 64 + d];

    float best0 = -INFINITY, best1 = -INFINITY;
    int bi0 = 0, bi1 = 0;

    for (int s0 = 0; s0 < NH; s0 += 64) {
        __syncthreads();
        for (int i = tid; i < 4096; i += 256) {
            int r = i >> 6, d = i & 63;
            bs[r * 65 + d] = mb[(size_t)(2 * (s0 + r) + 1) * 64 + d];
        }
        __syncthreads();
        float d0 = 0.f, d1 = 0.f;
        const float* b0p = &bs[lane * 65];
        const float* b1p = &bs[(lane + 32) * 65];
#pragma unroll
        for (int d = 0; d < 64; d++) {
            d0 += av[d] * b0p[d];
            d1 += av[d] * b1p[d];
        }
        int sA = s0 + lane, sB = s0 + lane + 32;
        if (d0 > best0) { best0 = d0; bi0 = sA; }
        if (d1 > best1) { best1 = d1; bi1 = sB; }
    }
    float bv = best0; int bix = bi0;
    if (best1 > bv || (best1 == bv && bi1 < bix)) { bv = best1; bix = bi1; }
#pragma unroll
    for (int o = 16; o; o >>= 1) {
        float ov = __shfl_xor_sync(~0u, bv, o);
        int oi = __shfl_xor_sync(~0u, bix, o);
        if (ov > bv || (ov == bv && oi < bix)) { bv = ov; bix = oi; }
    }
    if (lane == 0) {
        int t = t0 + w;
        if (t == 0) { nodemax[b * NH] = -INFINITY; nodeidx[b * NH] = 0; }
        else { nodemax[b * NH + t] = bv; nodeidx[b * NH + t] = bix; }
    }
}

__global__ void __launch_bounds__(512) match_sort(
    const float* __restrict__ nodemax, const int* __restrict__ nodeidx,
    int* __restrict__ srcidx, int* __restrict__ dstidx, int* __restrict__ unmidx)
{
    int b = blockIdx.x, t = threadIdx.x;
    __shared__ float v[NH]; __shared__ int rk[NH];
    v[t] = nodemax[b * NH + t]; __syncthreads();
    float vt = v[t]; int r = 0;
    for (int j = 0; j < NH; j++) {
        float vj = v[j];
        r += (vj > vt) || (vj == vt && j < t);
    }
    rk[t] = r; __syncthreads();
    if (r < Rr) {
        srcidx[b * Rr + r] = t;
        dstidx[b * Rr + r] = nodeidx[b * NH + t];
    } else {
        int pos = 0;
        for (int j = 0; j < t; j++) pos += (rk[j] >= Rr);
        unmidx[b * NU + pos] = t;
    }
}

// ---------------- weighted merge + LN2 fused (float4) ----------------
// Writes xm (fp32, for fc2 residual) AND h2_h = LayerNorm(xm) (fp16 for fc1).
__global__ void __launch_bounds__(256) merge_ln_kernel(
    const float* __restrict__ xres, const float* __restrict__ sz,
    const int* __restrict__ srcidx, const int* __restrict__ dstidx,
    const int* __restrict__ unmidx, float* __restrict__ xm,
    const float* __restrict__ n2g, const float* __restrict__ n2b,
    __half* __restrict__ h2)
{
    int row = blockIdx.x;
    int b = blockIdx.y;
    int tid = threadIdx.x;
    const float4* xb4 = (const float4*)(xres + (size_t)b * Nn * Cc);
    const float* szb = sz + b * Nn;
    const size_t orow = (size_t)b * NM + row;
    float4* ob4 = (float4*)(xm + orow * Cc);

    float4 val;
    if (row < NU) {
        int t = 2 * unmidx[b * NU + row];
        float s = szb[t];
        float inv = 1.f / s;
        float4 v = xb4[(size_t)t * 256 + tid];
        val = make_float4((v.x * s) * inv, (v.y * s) * inv,
                          (v.z * s) * inv, (v.w * s) * inv);
    } else {
        int j = row - NU;
        __shared__ int sd[Rr], ss[Rr];
        __shared__ int mls[Rr]; __shared__ float msz[Rr];
        __shared__ int nmz; __shared__ float nsz;
        if (tid < Rr) { ss[tid] = srcidx[b * Rr + tid]; sd[tid] = dstidx[b * Rr + tid]; }
        __syncthreads();
        int t = 2 * j + 1;
        if (tid == 0) {
            int n = 0;
            float ns = szb[t];
            for (int i = 0; i < Rr; i++) {
                if (sd[i] == j) {
                    int ts = 2 * ss[i];
                    float s2 = szb[ts];
                    mls[n] = ts; msz[n] = s2; ns += s2; n++;
                }
            }
            nmz = n; nsz = ns;
        }
        __syncthreads();
        int nm = nmz;
        float inv = 1.f / nsz;
        float st = szb[t];
        float4 v = xb4[(size_t)t * 256 + tid];
        val = make_float4(v.x * st, v.y * st, v.z * st, v.w * st);
        for (int i = 0; i < nm; i++) {
            float4 u = xb4[(size_t)mls[i] * 256 + tid];
            float m = msz[i];
            val.x += u.x * m; val.y += u.y * m;
            val.z += u.z * m; val.w += u.w * m;
        }
        val = make_float4(val.x * inv, val.y * inv, val.z * inv, val.w * inv);
    }
    ob4[tid] = val;

    // fused LN2 (identical reduction structure to ln_kernel)
    float s = val.x + val.y + val.z + val.w;
    float s2 = val.x * val.x + val.y * val.y + val.z * val.z + val.w * val.w;
#pragma unroll
    for (int o = 16; o; o >>= 1) {
        s += __shfl_xor_sync(~0u, s, o);
        s2 += __shfl_xor_sync(~0u, s2, o);
    }
    __shared__ float ws[8], wq[8];
    int w = tid >> 5, l = tid & 31;
    if (l == 0) { ws[w] = s; wq[w] = s2; }
    __syncthreads();
    float S = 0.f, S2 = 0.f;
#pragma unroll
    for (int i = 0; i < 8; i++) { S += ws[i]; S2 += wq[i]; }
    float mean = S * (1.f / 1024.f);
    float var  = S2 * (1.f / 1024.f) - mean * mean;
    float inv  = rsqrtf(var + 1e-5f);
    float4 gg = ((const float4*)n2g)[tid];
    float4 bb = ((const float4*)n2b)[tid];
    float4 o;
    o.x = (val.x - mean) * inv * gg.x + bb.x;
    o.y = (val.y - mean) * inv * gg.y + bb.y;
    o.z = (val.z - mean) * inv * gg.z + bb.z;
    o.w = (val.w - mean) * inv * gg.w + bb.w;
    uint2 p = make_uint2(packh2(o.x, o.y), packh2(o.z, o.w));
    *(uint2*)(h2 + orow * Cc + tid * 4) = p;
}

// ---------------- launch ----------------
template <typename T>
static T* sym_addr(const void* sym) {
    void* p = nullptr;
    cudaGetSymbolAddress(&p, sym);
    return (T*)p;
}

extern "C" void kernel_launch(void* const* d_in, const int* in_sizes, int n_in,
                              void* d_out, int out_size)
{
    const float* x      = (const float*)d_in[0];
    const float* sz     = (const float*)d_in[1];
    const float* qkv_w  = (const float*)d_in[3];
    const float* qkv_b  = (const float*)d_in[4];
    const float* proj_w = (const float*)d_in[5];
    const float* proj_b = (const float*)d_in[6];
    const float* n1g    = (const float*)d_in[7];
    const float* n1b    = (const float*)d_in[8];
    const float* n2g    = (const float*)d_in[9];
    const float* n2b    = (const float*)d_in[10];
    const float* fc1_w  = (const float*)d_in[11];
    const float* fc1_b  = (const float*)d_in[12];
    const float* fc2_w  = (const float*)d_in[13];
    const float* fc2_b  = (const float*)d_in[14];
    float* out = (float*)d_out;

    float*  xln    = sym_addr<float>(g_xln);
    __half* xln_h  = sym_addr<__half>(g_xln_h);
    __half* qkv_h  = sym_addr<__half>(g_qkv_h);
    __half* attno_h= sym_addr<__half>(g_attno_h);
    float*  xres   = sym_addr<float>(g_xres);
    __half* h2_h   = sym_addr<__half>(g_h2_h);
    __half* fc1_h  = sym_addr<__half>(g_fc1_h);
    __half* wqkv_h = sym_addr<__half>(g_wqkv_h);
    __half* wproj_h= sym_addr<__half>(g_wproj_h);
    __half* wfc1_h = sym_addr<__half>(g_wfc1_h);
    __half* wfc2_h = sym_addr<__half>(g_wfc2_h);
    float* wm    = sym_addr<float>(g_wm);
    float* wmb   = sym_addr<float>(g_wmb);
    float* metric= sym_addr<float>(g_metric);
    float* nmax  = sym_addr<float>(g_nodemax);
    int*   nidx  = sym_addr<int>(g_nodeidx);
    int*   sidx  = sym_addr<int>(g_srcidx);
    int*   didx  = sym_addr<int>(g_dstidx);
    int*   uidx  = sym_addr<int>(g_unmidx);
    float* xm    = sym_addr<float>(g_xm);

    cudaFuncSetAttribute(flash_attn, cudaFuncAttributeMaxDynamicSharedMemorySize, FLASH_SMEM);
    cudaFuncSetAttribute(fp16_gemm, cudaFuncAttributeMaxDynamicSharedMemorySize, GEMM_SMEM);

    // 0. weight conversion + pooled K weight, single fused launch
    cvt_all<<<CVT_BLOCKS + 256, 256>>>(qkv_w, wqkv_h, proj_w, wproj_h,
                                       fc1_w, wfc1_h, fc2_w, wfc2_h,
                                       qkv_b, wm, wmb);

    // 1. LN1 (dual output)
    ln_kernel<<<MROWS, 256>>>(x, n1g, n1b, xln, xln_h, Cc);
    // 2. QKV GEMM -> half
    fp16_gemm<<<dim3(3072 / 128, MROWS / 128), 256, GEMM_SMEM>>>(
        xln_h, wqkv_h, qkv_b, nullptr, nullptr, qkv_h, MROWS, 3072, Cc, 0);
    // 3. exact fp32 metric path (norm fused into GEMM epilogue)
    metric_gemm<<<MROWS / 64, 256>>>(xln, wm, wmb, metric);
    // 4. fused flash attention (fp16) -> half
    flash_attn<<<dim3(8, Bb * Hh), 256, FLASH_SMEM>>>(qkv_h, sz, attno_h);
    // 5. proj + residual -> fp32
    fp16_gemm<<<dim3(Cc / 128, MROWS / 128), 256, GEMM_SMEM>>>(
        attno_h, wproj_h, proj_b, x, xres, nullptr, MROWS, Cc, Cc, 0);
    // 6. matching (tiled)
    match_scores<<<dim3(NH / 8, Bb), 256>>>(metric, nmax, nidx);
    match_sort<<<Bb, NH>>>(nmax, nidx, sidx, didx, uidx);
    // 7. merge + LN2 fused
    merge_ln_kernel<<<dim3(NM, Bb), 256>>>(xres, sz, sidx, didx, uidx, xm,
                                           n2g, n2b, h2_h);
    // 8. fc1 + GELU -> half
    fp16_gemm<<<dim3(4096 / 128, MROWS2 / 128), 256, GEMM_SMEM>>>(
        h2_h, wfc1_h, fc1_b, nullptr, nullptr, fc1_h, MROWS2, 4096, Cc, 1);
    // 9. fc2 + residual -> out (fp32)
    fp16_gemm<<<dim3(Cc / 128, MROWS2 / 128), 256, GEMM_SMEM>>>(
        fc1_h, wfc2_h, fc2_b, xm, out, nullptr, MROWS2, Cc, 4096, 0);
    (void)in_sizes; (void)n_in; (void)out_size;
}